// round 3
// baseline (speedup 1.0000x reference)
#include <cuda_runtime.h>
#include <math.h>

// ------------------------------ scratch ------------------------------
__device__ float g_b0[16777216];
__device__ float g_b1[16777216];
__device__ float g_f4c[2097152];
__device__ float g_f4s[2097152];
__device__ float g_f4t[2097152];
__device__ float g_f4e[2097152];
__device__ float g_dec[786432];
__device__ float g_fT[4194304];      // [8][1024][512]
__device__ float g_cent[12288];      // [8][3][512]
__device__ int   g_asg[8192];        // [8][1024]
__device__ float g_cnt[24];          // [8][3]
__device__ float g_aw[12582912];     // Aw (24x512x1024) / NS Z-pong / tpts (12x512x1024)
__device__ float g_cov[6291456];     // cov (24x512x512) / NS Y-pong
__device__ float g_Y[6291456];
__device__ float g_Z[6291456];
__device__ float g_Tt[6291456];
__device__ float g_nrm[24];
__device__ float g_Tm[3145728];      // 12x512x512
__device__ float g_vv[6144];         // 12x512
__device__ float g_st[15360];        // [4][3840] : sm, ss, em, es
__device__ float g_cl[1];

// ------------------------------ conv 3x3 SAME ------------------------------
__global__ void __launch_bounds__(256) k_conv(const float* __restrict__ in,
    const float* __restrict__ w, const float* __restrict__ bias,
    float* __restrict__ out, int Cin, int Cout, int H, int relu)
{
    __shared__ float sI[34][36];
    __shared__ float sW[8][9];
    int tiles = H >> 5;
    int bx = blockIdx.x % tiles, by = blockIdx.x / tiles;
    int x0 = bx * 32, y0 = by * 32;
    int oc0 = blockIdx.y * 8, b = blockIdx.z;
    int tid = threadIdx.x;
    int lx = (tid & 15) * 2, ly = (tid >> 4) * 2;
    float acc[8][4];
#pragma unroll
    for (int o = 0; o < 8; o++) { acc[o][0]=0.f; acc[o][1]=0.f; acc[o][2]=0.f; acc[o][3]=0.f; }
    const float* ib = in + (size_t)b * Cin * H * H;
    for (int ic = 0; ic < Cin; ic++) {
        __syncthreads();
        const float* ip = ib + (size_t)ic * H * H;
        for (int i = tid; i < 34 * 34; i += 256) {
            int yy = i / 34, xx = i - yy * 34;
            int gy = y0 + yy - 1, gx = x0 + xx - 1;
            sI[yy][xx] = (gy >= 0 && gy < H && gx >= 0 && gx < H) ? ip[gy * H + gx] : 0.f;
        }
        if (tid < 72) {
            int oc = tid / 9, t = tid - oc * 9;
            sW[oc][t] = (oc0 + oc < Cout) ? w[((size_t)(oc0 + oc) * Cin + ic) * 9 + t] : 0.f;
        }
        __syncthreads();
        float win[4][4];
#pragma unroll
        for (int r = 0; r < 4; r++)
#pragma unroll
            for (int s = 0; s < 4; s++) win[r][s] = sI[ly + r][lx + s];
#pragma unroll
        for (int o = 0; o < 8; o++) {
            float w0=sW[o][0],w1=sW[o][1],w2=sW[o][2],w3=sW[o][3],w4=sW[o][4];
            float w5=sW[o][5],w6=sW[o][6],w7=sW[o][7],w8=sW[o][8];
#pragma unroll
            for (int p = 0; p < 4; p++) {
                int pr = p >> 1, pc = p & 1;
                acc[o][p] += win[pr][pc]*w0 + win[pr][pc+1]*w1 + win[pr][pc+2]*w2
                           + win[pr+1][pc]*w3 + win[pr+1][pc+1]*w4 + win[pr+1][pc+2]*w5
                           + win[pr+2][pc]*w6 + win[pr+2][pc+1]*w7 + win[pr+2][pc+2]*w8;
            }
        }
    }
#pragma unroll
    for (int o = 0; o < 8; o++) {
        int oc = oc0 + o;
        if (oc >= Cout) break;
        float bv = bias[oc];
        float* op = out + ((size_t)b * Cout + oc) * H * H;
#pragma unroll
        for (int p = 0; p < 4; p++) {
            float v = acc[o][p] + bv;
            if (relu) v = fmaxf(v, 0.f);
            op[(y0 + ly + (p >> 1)) * H + x0 + lx + (p & 1)] = v;
        }
    }
}

__global__ void k_pool(const float* __restrict__ in, float* __restrict__ out, int C, int Ho) {
    int i = blockIdx.x * 256 + threadIdx.x;
    int tot = 4 * C * Ho * Ho; if (i >= tot) return;
    int x = i % Ho, y = (i / Ho) % Ho; int bc = i / (Ho * Ho);
    int Hi = Ho * 2;
    const float* p = in + (size_t)bc * Hi * Hi;
    out[i] = (p[(2*y)*Hi + 2*x] + p[(2*y)*Hi + 2*x+1] + p[(2*y+1)*Hi + 2*x] + p[(2*y+1)*Hi + 2*x+1]) * 0.25f;
}

__global__ void k_up(const float* __restrict__ in, float* __restrict__ out, int C, int Ho) {
    int i = blockIdx.x * 256 + threadIdx.x;
    int tot = 4 * C * Ho * Ho; if (i >= tot) return;
    int x = i % Ho, y = (i / Ho) % Ho; int bc = i / (Ho * Ho);
    int Hi = Ho >> 1;
    out[i] = in[(size_t)bc * Hi * Hi + (y >> 1) * Hi + (x >> 1)];
}

// per-(b,c) spatial mean / std (ddof=0)
__global__ void __launch_bounds__(256) k_stats(const float* __restrict__ in, int HW,
                                               float* __restrict__ mo, float* __restrict__ so) {
    __shared__ double red[256];
    int bc = blockIdx.x;
    const float* p = in + (size_t)bc * HW;
    double s = 0;
    for (int i = threadIdx.x; i < HW; i += 256) s += p[i];
    red[threadIdx.x] = s; __syncthreads();
    for (int o = 128; o > 0; o >>= 1) { if (threadIdx.x < o) red[threadIdx.x] += red[threadIdx.x + o]; __syncthreads(); }
    double m = red[0] / HW;
    __syncthreads();
    double v = 0;
    for (int i = threadIdx.x; i < HW; i += 256) { double d = p[i] - m; v += d * d; }
    red[threadIdx.x] = v; __syncthreads();
    for (int o = 128; o > 0; o >>= 1) { if (threadIdx.x < o) red[threadIdx.x] += red[threadIdx.x + o]; __syncthreads(); }
    if (threadIdx.x == 0) { mo[bc] = (float)m; so[bc] = (float)sqrt(red[0] / HW); }
}

// ------------------------------ k-means ------------------------------
__global__ void k_transp() { // fT[sb][n][c] = f[sb][c][n]
    __shared__ float t[32][33];
    int sb = blockIdx.x, c0 = blockIdx.y * 32, n0 = blockIdx.z * 32;
    const float* f = (sb >= 4 ? g_f4s + (size_t)(sb - 4) * 524288 : g_f4c + (size_t)sb * 524288);
    int tx = threadIdx.x, ty = threadIdx.y;
    for (int j = 0; j < 32; j += 8) t[ty + j][tx] = f[(c0 + ty + j) * 1024 + n0 + tx];
    __syncthreads();
    for (int j = 0; j < 32; j += 8) g_fT[(size_t)sb * 524288 + (size_t)(n0 + ty + j) * 512 + c0 + tx] = t[tx][ty + j];
}

__global__ void k_cent0() {
    int i = blockIdx.x * 256 + threadIdx.x;
    if (i >= 12288) return;
    int c = i & 511, k = (i >> 9) % 3, sb = i / 1536;
    const float* f = (sb >= 4 ? g_f4s + (size_t)(sb - 4) * 524288 : g_f4c + (size_t)sb * 524288);
    g_cent[i] = f[c * 1024 + k];
}

__global__ void __launch_bounds__(1024) k_assign() {
    __shared__ float sc[3][512];
    int sb = blockIdx.x, n = threadIdx.x;
    for (int i = n; i < 1536; i += 1024) ((float*)sc)[i] = g_cent[sb * 1536 + i];
    __syncthreads();
    const float* f = (sb >= 4 ? g_f4s + (size_t)(sb - 4) * 524288 : g_f4c + (size_t)sb * 524288);
    float d0 = 0, d1 = 0, d2 = 0;
    for (int c = 0; c < 512; c++) {
        float v = f[c * 1024 + n];
        float a = v - sc[0][c], b = v - sc[1][c], e = v - sc[2][c];
        d0 += a * a; d1 += b * b; d2 += e * e;
    }
    int a = 0; float best = d0;
    if (d1 < best) { best = d1; a = 1; }
    if (d2 < best) { a = 2; }
    g_asg[sb * 1024 + n] = a;
}

__global__ void __launch_bounds__(512) k_update() {
    __shared__ int sa[1024];
    int sb = blockIdx.x, c = threadIdx.x;
    for (int i = c; i < 1024; i += 512) sa[i] = g_asg[sb * 1024 + i];
    __syncthreads();
    float s0 = 0, s1 = 0, s2 = 0; int c0 = 0, c1 = 0, c2 = 0;
    const float* ft = g_fT + (size_t)sb * 524288;
    for (int n = 0; n < 1024; n++) {
        float v = ft[n * 512 + c];
        int a = sa[n];
        if (a == 0) { s0 += v; c0++; } else if (a == 1) { s1 += v; c1++; } else { s2 += v; c2++; }
    }
    g_cent[sb * 1536 + c]        = s0 / ((float)c0 + 1e-6f);
    g_cent[sb * 1536 + 512 + c]  = s1 / ((float)c1 + 1e-6f);
    g_cent[sb * 1536 + 1024 + c] = s2 / ((float)c2 + 1e-6f);
    if (c < 3) g_cnt[sb * 3 + c] = (float)(c == 0 ? c0 : (c == 1 ? c1 : c2));
}

// ------------------------------ cov ------------------------------
__global__ void k_aw() { // Aw[m][c][n] = (asg==k) * (f[c,n]-mu[c])
    int i = blockIdx.x * 256 + threadIdx.x;
    if (i >= 12582912) return;
    int n = i & 1023, c = (i >> 10) & 511, m = i >> 19;
    int k = m % 3, sb = m / 3;
    const float* f = (sb >= 4 ? g_f4s + (size_t)(sb - 4) * 524288 : g_f4c + (size_t)sb * 524288);
    int a = g_asg[sb * 1024 + n];
    g_aw[i] = (a == k) ? f[c * 1024 + n] - g_cent[sb * 1536 + k * 512 + c] : 0.f;
}

__global__ void __launch_bounds__(256) k_cov() { // cov = Aw@Aw^T/nc + 0.1I, 64x64 tiles
    __shared__ float sA[16][68], sB[16][68];
    int m = blockIdx.z;
    const float* A = g_aw + (size_t)m * 524288;
    int i0 = blockIdx.y * 64, j0 = blockIdx.x * 64;
    int tid = threadIdx.x;
    int r = tid >> 4, c2 = tid & 15;
    int ty = tid >> 4, tx = tid & 15;
    float acc[4][4];
#pragma unroll
    for (int a = 0; a < 4; a++)
#pragma unroll
        for (int b = 0; b < 4; b++) acc[a][b] = 0.f;
    for (int k0 = 0; k0 < 1024; k0 += 16) {
        __syncthreads();
#pragma unroll
        for (int q = 0; q < 4; q++) {
            int row = r + q * 16;
            sA[c2][row] = A[(size_t)(i0 + row) * 1024 + k0 + c2];
            sB[c2][row] = A[(size_t)(j0 + row) * 1024 + k0 + c2];
        }
        __syncthreads();
#pragma unroll
        for (int kk = 0; kk < 16; kk++) {
            float av[4], bv[4];
#pragma unroll
            for (int a = 0; a < 4; a++) av[a] = sA[kk][ty * 4 + a];
#pragma unroll
            for (int b = 0; b < 4; b++) bv[b] = sB[kk][tx * 4 + b];
#pragma unroll
            for (int a = 0; a < 4; a++)
#pragma unroll
                for (int b = 0; b < 4; b++) acc[a][b] += av[a] * bv[b];
        }
    }
    float nc = g_cnt[m] + 1e-6f;
    float* C = g_cov + (size_t)m * 262144;
#pragma unroll
    for (int a = 0; a < 4; a++)
#pragma unroll
        for (int b = 0; b < 4; b++) {
            int gi = i0 + ty * 4 + a, gj = j0 + tx * 4 + b;
            C[gi * 512 + gj] = acc[a][b] / nc + (gi == gj ? 0.1f : 0.f);
        }
}

__global__ void __launch_bounds__(256) k_norm() { // inf-norm per matrix
    __shared__ float red[256];
    int m = blockIdx.x;
    const float* A = g_cov + (size_t)m * 262144;
    float mx = 0;
    for (int r = threadIdx.x; r < 512; r += 256) {
        float s = 0;
        for (int c = 0; c < 512; c++) s += fabsf(A[r * 512 + c]);
        mx = fmaxf(mx, s);
    }
    red[threadIdx.x] = mx; __syncthreads();
    for (int o = 128; o > 0; o >>= 1) { if (threadIdx.x < o) red[threadIdx.x] = fmaxf(red[threadIdx.x], red[threadIdx.x + o]); __syncthreads(); }
    if (threadIdx.x == 0) g_nrm[m] = red[0];
}

__global__ void k_nsinit() {
    int i = blockIdx.x * 256 + threadIdx.x;
    if (i >= 6291456) return;
    int m = i >> 18;
    g_Y[i] = g_cov[i] / g_nrm[m];
    int rc = i & 262143;
    g_Z[i] = ((rc >> 9) == (rc & 511)) ? 1.f : 0.f;
}

// ------------------------------ batched SGEMM (M=512, K=512) ------------------------------
// C = alpha * A@B + delta*I ; if nrmmode: alpha = sqrt(nrm[12+z]/nrm[z])
__global__ void __launch_bounds__(256) k_gemm(
    const float* __restrict__ A, int strA, const float* __restrict__ B, int strB, int bdiv,
    float* __restrict__ C, int strC, int N, float alpha, float delta, int nrmmode)
{
    __shared__ float sA[8][128], sB[8][128];
    int z = blockIdx.z;
    const float* Ab = A + (size_t)z * strA;
    const float* Bb = B + (size_t)(bdiv ? z / 3 : z) * strB;
    float* Cb = C + (size_t)z * strC;
    if (nrmmode) alpha = sqrtf(g_nrm[12 + z] / g_nrm[z]);
    int m0 = blockIdx.y * 128, n0 = blockIdx.x * 128;
    int tid = threadIdx.x;
    float acc[8][8];
#pragma unroll
    for (int a = 0; a < 8; a++)
#pragma unroll
        for (int b = 0; b < 8; b++) acc[a][b] = 0.f;
    int ar = tid >> 1, ac = (tid & 1) * 4;
    int br = tid >> 5, bc = (tid & 31) * 4;
    int ry = tid >> 4, rx = tid & 15;
    for (int k0 = 0; k0 < 512; k0 += 8) {
        __syncthreads();
        float4 av = *(const float4*)&Ab[(size_t)(m0 + ar) * 512 + k0 + ac];
        sA[ac][ar] = av.x; sA[ac + 1][ar] = av.y; sA[ac + 2][ar] = av.z; sA[ac + 3][ar] = av.w;
        *(float4*)&sB[br][bc] = *(const float4*)&Bb[(size_t)(k0 + br) * N + n0 + bc];
        __syncthreads();
#pragma unroll
        for (int k = 0; k < 8; k++) {
            float4 a0 = *(float4*)&sA[k][ry * 8], a1 = *(float4*)&sA[k][ry * 8 + 4];
            float4 b0 = *(float4*)&sB[k][rx * 8], b1 = *(float4*)&sB[k][rx * 8 + 4];
            float ax[8] = {a0.x, a0.y, a0.z, a0.w, a1.x, a1.y, a1.z, a1.w};
            float bx[8] = {b0.x, b0.y, b0.z, b0.w, b1.x, b1.y, b1.z, b1.w};
#pragma unroll
            for (int a = 0; a < 8; a++)
#pragma unroll
                for (int b = 0; b < 8; b++) acc[a][b] += ax[a] * bx[b];
        }
    }
#pragma unroll
    for (int a = 0; a < 8; a++) {
        int gm = m0 + ry * 8 + a;
#pragma unroll
        for (int b = 0; b < 8; b++) {
            int gn = n0 + rx * 8 + b;
            Cb[(size_t)gm * N + gn] = alpha * acc[a][b] + ((delta != 0.f && gm == gn) ? delta : 0.f);
        }
    }
}

// v[z] = Tm[z] @ mu_c[z]
__global__ void __launch_bounds__(512) k_gemv() {
    __shared__ float mu[512];
    int z = blockIdx.x;
    mu[threadIdx.x] = g_cent[z * 512 + (z / 3) * 1536 - (z / 3) * 1536 + 0];  // placeholder fixed below
    __syncthreads();
    // recompute properly (avoid the above hack): z = b*3+k -> content offset b*1536 + k*512
    int b = z / 3, k = z % 3;
    mu[threadIdx.x] = g_cent[b * 1536 + k * 512 + threadIdx.x];
    __syncthreads();
    const float* T = g_Tm + (size_t)z * 262144;
    float s = 0;
    int c = threadIdx.x;
    for (int d = 0; d < 512; d++) s += T[c * 512 + d] * mu[d];
    g_vv[z * 512 + c] = s;
}

__global__ void k_comb() { // fcs gather + alpha blend ; tpts lives in g_aw
    int i = blockIdx.x * 256 + threadIdx.x;
    if (i >= 2097152) return;
    int n = i & 1023, c = (i >> 10) & 511, b = i >> 19;
    int a = g_asg[b * 1024 + n];
    int z = b * 3 + a;
    float val = g_aw[(size_t)z * 524288 + c * 1024 + n] - g_vv[z * 512 + c]
              + g_cent[(4 + b) * 1536 + a * 512 + c];
    g_f4t[i] = 0.6f * val + 0.4f * g_f4c[i];
}

__global__ void __launch_bounds__(1024) k_closs() {
    __shared__ double red[1024];
    double s = 0;
    for (int i = threadIdx.x; i < 2097152; i += 1024) {
        float d = g_f4e[i] - g_f4c[i]; s += (double)d * d;
    }
    red[threadIdx.x] = s; __syncthreads();
    for (int o = 512; o > 0; o >>= 1) { if (threadIdx.x < o) red[threadIdx.x] += red[threadIdx.x + o]; __syncthreads(); }
    if (threadIdx.x == 0) g_cl[0] = (float)(red[0] / 2097152.0);
}

__global__ void __launch_bounds__(256) k_final(float* out) {
    __shared__ double red[256];
    __shared__ double slv;
    const int off[5] = {0, 256, 768, 1792, 3840};
    if (threadIdx.x == 0) slv = 0;
    __syncthreads();
    for (int l = 0; l < 4; l++) {
        int o0 = off[l], sz = off[l + 1] - off[l];
        double s = 0;
        for (int i = threadIdx.x; i < sz; i += 256) {
            float dm = g_st[2 * 3840 + o0 + i] - g_st[0 * 3840 + o0 + i];
            float ds = g_st[3 * 3840 + o0 + i] - g_st[1 * 3840 + o0 + i];
            s += (double)dm * dm + (double)ds * ds;
        }
        red[threadIdx.x] = s; __syncthreads();
        for (int o = 128; o > 0; o >>= 1) { if (threadIdx.x < o) red[threadIdx.x] += red[threadIdx.x + o]; __syncthreads(); }
        if (threadIdx.x == 0) slv += red[0] / sz;
        __syncthreads();
    }
    if (threadIdx.x == 0) out[0] = g_cl[0] + 0.01f * (float)slv;
}

// ------------------------------ host ------------------------------
extern "C" void kernel_launch(void* const* d_in, const int* in_sizes, int n_in,
                              void* d_out, int out_size) {
    (void)in_sizes; (void)n_in; (void)out_size;
    const float* in[18];
    for (int i = 0; i < 18; i++) in[i] = (const float*)d_in[i];

    float *b0, *b1, *f4c, *f4s, *f4t, *f4e, *dec, *Y, *Z, *Tt, *cov, *aw, *Tm;
    cudaGetSymbolAddress((void**)&b0, g_b0);
    cudaGetSymbolAddress((void**)&b1, g_b1);
    cudaGetSymbolAddress((void**)&f4c, g_f4c);
    cudaGetSymbolAddress((void**)&f4s, g_f4s);
    cudaGetSymbolAddress((void**)&f4t, g_f4t);
    cudaGetSymbolAddress((void**)&f4e, g_f4e);
    cudaGetSymbolAddress((void**)&dec, g_dec);
    cudaGetSymbolAddress((void**)&Y, g_Y);
    cudaGetSymbolAddress((void**)&Z, g_Z);
    cudaGetSymbolAddress((void**)&Tt, g_Tt);
    cudaGetSymbolAddress((void**)&cov, g_cov);
    cudaGetSymbolAddress((void**)&aw, g_aw);
    cudaGetSymbolAddress((void**)&Tm, g_Tm);
    float* st; cudaGetSymbolAddress((void**)&st, g_st);

    auto conv = [&](const float* i0, float* o, const float* w, const float* bb,
                    int Cin, int Cout, int H, int relu) {
        dim3 g((H / 32) * (H / 32), (Cout + 7) / 8, 4);
        k_conv<<<g, 256>>>(i0, w, bb, o, Cin, Cout, H, relu);
    };
    auto pool = [&](const float* i0, float* o, int C, int Ho) {
        int tot = 4 * C * Ho * Ho; k_pool<<<(tot + 255) / 256, 256>>>(i0, o, C, Ho);
    };
    auto up = [&](const float* i0, float* o, int C, int Ho) {
        int tot = 4 * C * Ho * Ho; k_up<<<(tot + 255) / 256, 256>>>(i0, o, C, Ho);
    };
    auto enc = [&](const float* x, float* f4, float* mo, float* so) {
        conv(x, b0, in[2], in[3], 3, 64, 256, 1);
        if (mo) k_stats<<<4 * 64, 256>>>(b0, 65536, mo, so);
        pool(b0, b1, 64, 128);
        conv(b1, b0, in[4], in[5], 64, 128, 128, 1);
        if (mo) k_stats<<<4 * 128, 256>>>(b0, 16384, mo + 256, so + 256);
        pool(b0, b1, 128, 64);
        conv(b1, b0, in[6], in[7], 128, 256, 64, 1);
        if (mo) k_stats<<<4 * 256, 256>>>(b0, 4096, mo + 768, so + 768);
        pool(b0, b1, 256, 32);
        conv(b1, f4, in[8], in[9], 256, 512, 32, 1);
        if (mo) k_stats<<<4 * 512, 256>>>(f4, 1024, mo + 1792, so + 1792);
    };

    // encodes
    enc(in[0], f4c, 0, 0);
    enc(in[1], f4s, st + 0, st + 3840);

    // k-means (11 assigns / 11 updates; 11th update = final mu & counts)
    k_transp<<<dim3(8, 16, 32), dim3(32, 8)>>>();
    k_cent0<<<48, 256>>>();
    for (int it = 0; it < 11; it++) {
        k_assign<<<8, 1024>>>();
        k_update<<<8, 512>>>();
    }

    // covariances
    k_aw<<<(12582912 + 255) / 256, 256>>>();
    k_cov<<<dim3(8, 8, 24), 256>>>();
    k_norm<<<24, 256>>>();
    k_nsinit<<<(6291456 + 255) / 256, 256>>>();

    // coupled Newton-Schulz: Y -> (A/c)^1/2, Z -> (A/c)^-1/2
    float *Yc = Y, *Yn = cov, *Zc = Z, *Zn = aw;
    for (int it = 0; it < 34; it++) {
        k_gemm<<<dim3(4, 4, 24), 256>>>(Zc, 262144, Yc, 262144, 0, Tt, 262144, 512, -0.5f, 1.5f, 0);
        k_gemm<<<dim3(4, 4, 24), 256>>>(Yc, 262144, Tt, 262144, 0, Yn, 262144, 512, 1.f, 0.f, 0);
        k_gemm<<<dim3(4, 4, 24), 256>>>(Tt, 262144, Zc, 262144, 0, Zn, 262144, 512, 1.f, 0.f, 0);
        float* t0 = Yc; Yc = Yn; Yn = t0;
        float* t1 = Zc; Zc = Zn; Zn = t1;
    }

    // Tm = sqrt(c_s/c_c) * Y_s @ Z_c   (12 batches, z = b*3+k)
    k_gemm<<<dim3(4, 4, 12), 256>>>(Yc + (size_t)12 * 262144, 262144, Zc, 262144, 0,
                                    Tm, 262144, 512, 1.f, 0.f, 1);
    // tpts[z] = Tm[z] @ f_b  (writes g_aw; Aw is dead)
    k_gemm<<<dim3(8, 4, 12), 256>>>(Tm, 262144, f4c, 524288, 1, aw, 524288, 1024, 1.f, 0.f, 0);
    k_gemv<<<12, 512>>>();
    k_comb<<<(2097152 + 255) / 256, 256>>>();

    // decode
    conv(f4t, b0, in[10], in[11], 512, 256, 32, 1);
    up(b0, b1, 256, 64);
    conv(b1, b0, in[12], in[13], 256, 128, 64, 1);
    up(b0, b1, 128, 128);
    conv(b1, b0, in[14], in[15], 128, 64, 128, 1);
    up(b0, b1, 64, 256);
    conv(b1, dec, in[16], in[17], 64, 3, 256, 0);

    // encode(dec) with stats
    enc(dec, f4e, st + 2 * 3840, st + 3 * 3840);

    // losses
    k_closs<<<1, 1024>>>();
    k_final<<<1, 256>>>((float*)d_out);
}

// round 4
// speedup vs baseline: 1.3905x; 1.3905x over previous
#include <cuda_runtime.h>
#include <math.h>

// ------------------------------ scratch ------------------------------
__device__ float g_b0[16777216];
__device__ float g_b1[16777216];
__device__ float g_f4c[2097152];
__device__ float g_f4s[2097152];
__device__ float g_f4t[2097152];
__device__ float g_f4e[2097152];
__device__ float g_dec[786432];
__device__ float g_fT[4194304];      // [8][1024][512]
__device__ float g_cent[12288];      // [8][3][512]
__device__ int   g_asg[8192];        // [8][1024]
__device__ float g_cnt[24];          // [8][3]
__device__ float g_aw[12582912];     // Aw (24x512x1024) / two NS scratch halves / tpts
__device__ float g_cov[6291456];     // cov (24x512x512) / NS scratch
__device__ float g_Y[6291456];
__device__ float g_Z[6291456];
__device__ float g_Tt[6291456];
__device__ float g_nrm[24];
__device__ float g_Tm[3145728];      // 12x512x512
__device__ float g_vv[6144];         // 12x512
__device__ float g_st[15360];        // [4][3840] : sm, ss, em, es
__device__ float g_cl[1];

__constant__ int c_pi[10] = {0,0,0,0,1,1,1,2,2,3};
__constant__ int c_pj[10] = {0,1,2,3,1,2,3,2,3,3};

// ------------------------------ conv 3x3 SAME ------------------------------
__global__ void __launch_bounds__(256) k_conv(const float* __restrict__ in,
    const float* __restrict__ w, const float* __restrict__ bias,
    float* __restrict__ out, int Cin, int Cout, int H, int relu)
{
    __shared__ float sI[34][36];
    __shared__ float sW[8][9];
    int tiles = H >> 5;
    int bx = blockIdx.x % tiles, by = blockIdx.x / tiles;
    int x0 = bx * 32, y0 = by * 32;
    int oc0 = blockIdx.y * 8, b = blockIdx.z;
    int tid = threadIdx.x;
    int lx = (tid & 15) * 2, ly = (tid >> 4) * 2;
    float acc[8][4];
#pragma unroll
    for (int o = 0; o < 8; o++) { acc[o][0]=0.f; acc[o][1]=0.f; acc[o][2]=0.f; acc[o][3]=0.f; }
    const float* ib = in + (size_t)b * Cin * H * H;
    for (int ic = 0; ic < Cin; ic++) {
        __syncthreads();
        const float* ip = ib + (size_t)ic * H * H;
        for (int i = tid; i < 34 * 34; i += 256) {
            int yy = i / 34, xx = i - yy * 34;
            int gy = y0 + yy - 1, gx = x0 + xx - 1;
            sI[yy][xx] = (gy >= 0 && gy < H && gx >= 0 && gx < H) ? ip[gy * H + gx] : 0.f;
        }
        if (tid < 72) {
            int oc = tid / 9, t = tid - oc * 9;
            sW[oc][t] = (oc0 + oc < Cout) ? w[((size_t)(oc0 + oc) * Cin + ic) * 9 + t] : 0.f;
        }
        __syncthreads();
        float win[4][4];
#pragma unroll
        for (int r = 0; r < 4; r++)
#pragma unroll
            for (int s = 0; s < 4; s++) win[r][s] = sI[ly + r][lx + s];
#pragma unroll
        for (int o = 0; o < 8; o++) {
            float w0=sW[o][0],w1=sW[o][1],w2=sW[o][2],w3=sW[o][3],w4=sW[o][4];
            float w5=sW[o][5],w6=sW[o][6],w7=sW[o][7],w8=sW[o][8];
#pragma unroll
            for (int p = 0; p < 4; p++) {
                int pr = p >> 1, pc = p & 1;
                acc[o][p] += win[pr][pc]*w0 + win[pr][pc+1]*w1 + win[pr][pc+2]*w2
                           + win[pr+1][pc]*w3 + win[pr+1][pc+1]*w4 + win[pr+1][pc+2]*w5
                           + win[pr+2][pc]*w6 + win[pr+2][pc+1]*w7 + win[pr+2][pc+2]*w8;
            }
        }
    }
#pragma unroll
    for (int o = 0; o < 8; o++) {
        int oc = oc0 + o;
        if (oc >= Cout) break;
        float bv = bias[oc];
        float* op = out + ((size_t)b * Cout + oc) * H * H;
#pragma unroll
        for (int p = 0; p < 4; p++) {
            float v = acc[o][p] + bv;
            if (relu) v = fmaxf(v, 0.f);
            op[(y0 + ly + (p >> 1)) * H + x0 + lx + (p & 1)] = v;
        }
    }
}

__global__ void k_pool(const float* __restrict__ in, float* __restrict__ out, int C, int Ho) {
    int i = blockIdx.x * 256 + threadIdx.x;
    int tot = 4 * C * Ho * Ho; if (i >= tot) return;
    int x = i % Ho, y = (i / Ho) % Ho; int bc = i / (Ho * Ho);
    int Hi = Ho * 2;
    const float* p = in + (size_t)bc * Hi * Hi;
    out[i] = (p[(2*y)*Hi + 2*x] + p[(2*y)*Hi + 2*x+1] + p[(2*y+1)*Hi + 2*x] + p[(2*y+1)*Hi + 2*x+1]) * 0.25f;
}

__global__ void k_up(const float* __restrict__ in, float* __restrict__ out, int C, int Ho) {
    int i = blockIdx.x * 256 + threadIdx.x;
    int tot = 4 * C * Ho * Ho; if (i >= tot) return;
    int x = i % Ho, y = (i / Ho) % Ho; int bc = i / (Ho * Ho);
    int Hi = Ho >> 1;
    out[i] = in[(size_t)bc * Hi * Hi + (y >> 1) * Hi + (x >> 1)];
}

__global__ void __launch_bounds__(256) k_stats(const float* __restrict__ in, int HW,
                                               float* __restrict__ mo, float* __restrict__ so) {
    __shared__ double red[256];
    int bc = blockIdx.x;
    const float* p = in + (size_t)bc * HW;
    double s = 0;
    for (int i = threadIdx.x; i < HW; i += 256) s += p[i];
    red[threadIdx.x] = s; __syncthreads();
    for (int o = 128; o > 0; o >>= 1) { if (threadIdx.x < o) red[threadIdx.x] += red[threadIdx.x + o]; __syncthreads(); }
    double m = red[0] / HW;
    __syncthreads();
    double v = 0;
    for (int i = threadIdx.x; i < HW; i += 256) { double d = p[i] - m; v += d * d; }
    red[threadIdx.x] = v; __syncthreads();
    for (int o = 128; o > 0; o >>= 1) { if (threadIdx.x < o) red[threadIdx.x] += red[threadIdx.x + o]; __syncthreads(); }
    if (threadIdx.x == 0) { mo[bc] = (float)m; so[bc] = (float)sqrt(red[0] / HW); }
}

// ------------------------------ k-means ------------------------------
__global__ void k_transp() {
    __shared__ float t[32][33];
    int sb = blockIdx.x, c0 = blockIdx.y * 32, n0 = blockIdx.z * 32;
    const float* f = (sb >= 4 ? g_f4s + (size_t)(sb - 4) * 524288 : g_f4c + (size_t)sb * 524288);
    int tx = threadIdx.x, ty = threadIdx.y;
    for (int j = 0; j < 32; j += 8) t[ty + j][tx] = f[(c0 + ty + j) * 1024 + n0 + tx];
    __syncthreads();
    for (int j = 0; j < 32; j += 8) g_fT[(size_t)sb * 524288 + (size_t)(n0 + ty + j) * 512 + c0 + tx] = t[tx][ty + j];
}

__global__ void k_cent0() {
    int i = blockIdx.x * 256 + threadIdx.x;
    if (i >= 12288) return;
    int c = i & 511, k = (i >> 9) % 3, sb = i / 1536;
    const float* f = (sb >= 4 ? g_f4s + (size_t)(sb - 4) * 524288 : g_f4c + (size_t)sb * 524288);
    g_cent[i] = f[c * 1024 + k];
}

__global__ void __launch_bounds__(1024) k_assign() {
    __shared__ float sc[3][512];
    int sb = blockIdx.x, n = threadIdx.x;
    for (int i = n; i < 1536; i += 1024) ((float*)sc)[i] = g_cent[sb * 1536 + i];
    __syncthreads();
    const float* f = (sb >= 4 ? g_f4s + (size_t)(sb - 4) * 524288 : g_f4c + (size_t)sb * 524288);
    float d0 = 0, d1 = 0, d2 = 0;
    for (int c = 0; c < 512; c++) {
        float v = f[c * 1024 + n];
        float a = v - sc[0][c], b = v - sc[1][c], e = v - sc[2][c];
        d0 += a * a; d1 += b * b; d2 += e * e;
    }
    int a = 0; float best = d0;
    if (d1 < best) { best = d1; a = 1; }
    if (d2 < best) { a = 2; }
    g_asg[sb * 1024 + n] = a;
}

__global__ void __launch_bounds__(512) k_update() {
    __shared__ int sa[1024];
    int sb = blockIdx.x, c = threadIdx.x;
    for (int i = c; i < 1024; i += 512) sa[i] = g_asg[sb * 1024 + i];
    __syncthreads();
    float s0 = 0, s1 = 0, s2 = 0; int c0 = 0, c1 = 0, c2 = 0;
    const float* ft = g_fT + (size_t)sb * 524288;
    for (int n = 0; n < 1024; n++) {
        float v = ft[n * 512 + c];
        int a = sa[n];
        if (a == 0) { s0 += v; c0++; } else if (a == 1) { s1 += v; c1++; } else { s2 += v; c2++; }
    }
    g_cent[sb * 1536 + c]        = s0 / ((float)c0 + 1e-6f);
    g_cent[sb * 1536 + 512 + c]  = s1 / ((float)c1 + 1e-6f);
    g_cent[sb * 1536 + 1024 + c] = s2 / ((float)c2 + 1e-6f);
    if (c < 3) g_cnt[sb * 3 + c] = (float)(c == 0 ? c0 : (c == 1 ? c1 : c2));
}

// ------------------------------ cov ------------------------------
__global__ void k_aw() {
    int i = blockIdx.x * 256 + threadIdx.x;
    if (i >= 12582912) return;
    int n = i & 1023, c = (i >> 10) & 511, m = i >> 19;
    int k = m % 3, sb = m / 3;
    const float* f = (sb >= 4 ? g_f4s + (size_t)(sb - 4) * 524288 : g_f4c + (size_t)sb * 524288);
    int a = g_asg[sb * 1024 + n];
    g_aw[i] = (a == k) ? f[c * 1024 + n] - g_cent[sb * 1536 + k * 512 + c] : 0.f;
}

// cov = Aw@Aw^T/nc + 0.1I, 128x128 tiles, symmetric: 10 tile-pairs + mirror
__global__ void __launch_bounds__(256) k_covg() {
    __shared__ float sA[16][128], sB[16][128];
    int m = blockIdx.z;
    const float* A = g_aw + (size_t)m * 524288;
    int bi = c_pi[blockIdx.x], bj = c_pj[blockIdx.x];
    int i0 = bi * 128, j0 = bj * 128;
    int tid = threadIdx.x;
    int ar = tid >> 1, ac = (tid & 1) * 8;
    int ty = tid >> 4, tx = tid & 15;
    float acc[8][8];
#pragma unroll
    for (int a = 0; a < 8; a++)
#pragma unroll
        for (int b = 0; b < 8; b++) acc[a][b] = 0.f;
    float4 ra0 = *(const float4*)&A[(size_t)(i0 + ar) * 1024 + ac];
    float4 ra1 = *(const float4*)&A[(size_t)(i0 + ar) * 1024 + ac + 4];
    float4 rb0 = *(const float4*)&A[(size_t)(j0 + ar) * 1024 + ac];
    float4 rb1 = *(const float4*)&A[(size_t)(j0 + ar) * 1024 + ac + 4];
    for (int k0 = 0; k0 < 1024; k0 += 16) {
        sA[ac+0][ar]=ra0.x; sA[ac+1][ar]=ra0.y; sA[ac+2][ar]=ra0.z; sA[ac+3][ar]=ra0.w;
        sA[ac+4][ar]=ra1.x; sA[ac+5][ar]=ra1.y; sA[ac+6][ar]=ra1.z; sA[ac+7][ar]=ra1.w;
        sB[ac+0][ar]=rb0.x; sB[ac+1][ar]=rb0.y; sB[ac+2][ar]=rb0.z; sB[ac+3][ar]=rb0.w;
        sB[ac+4][ar]=rb1.x; sB[ac+5][ar]=rb1.y; sB[ac+6][ar]=rb1.z; sB[ac+7][ar]=rb1.w;
        __syncthreads();
        if (k0 + 16 < 1024) {
            ra0 = *(const float4*)&A[(size_t)(i0 + ar) * 1024 + k0 + 16 + ac];
            ra1 = *(const float4*)&A[(size_t)(i0 + ar) * 1024 + k0 + 16 + ac + 4];
            rb0 = *(const float4*)&A[(size_t)(j0 + ar) * 1024 + k0 + 16 + ac];
            rb1 = *(const float4*)&A[(size_t)(j0 + ar) * 1024 + k0 + 16 + ac + 4];
        }
#pragma unroll
        for (int k = 0; k < 16; k++) {
            float av[8], bv[8];
            *(float4*)av = *(float4*)&sA[k][ty * 8]; *(float4*)(av+4) = *(float4*)&sA[k][ty * 8 + 4];
            *(float4*)bv = *(float4*)&sB[k][tx * 8]; *(float4*)(bv+4) = *(float4*)&sB[k][tx * 8 + 4];
#pragma unroll
            for (int a = 0; a < 8; a++)
#pragma unroll
                for (int b = 0; b < 8; b++) acc[a][b] += av[a] * bv[b];
        }
        __syncthreads();
    }
    float nc = g_cnt[m] + 1e-6f;
    float* C = g_cov + (size_t)m * 262144;
#pragma unroll
    for (int a = 0; a < 8; a++)
#pragma unroll
        for (int b = 0; b < 8; b++) {
            int gi = i0 + ty * 8 + a, gj = j0 + tx * 8 + b;
            float v = acc[a][b] / nc + (gi == gj ? 0.1f : 0.f);
            C[gi * 512 + gj] = v;
            if (bi != bj) C[gj * 512 + gi] = v;
        }
}

__global__ void __launch_bounds__(256) k_norm() {
    __shared__ float red[256];
    int m = blockIdx.x;
    const float* A = g_cov + (size_t)m * 262144;
    float mx = 0;
    for (int r = threadIdx.x; r < 512; r += 256) {
        float s = 0;
        for (int c = 0; c < 512; c++) s += fabsf(A[r * 512 + c]);
        mx = fmaxf(mx, s);
    }
    red[threadIdx.x] = mx; __syncthreads();
    for (int o = 128; o > 0; o >>= 1) { if (threadIdx.x < o) red[threadIdx.x] = fmaxf(red[threadIdx.x], red[threadIdx.x + o]); __syncthreads(); }
    if (threadIdx.x == 0) g_nrm[m] = red[0];
}

__global__ void k_nsinit() {
    int i = blockIdx.x * 256 + threadIdx.x;
    if (i >= 6291456) return;
    int m = i >> 18;
    g_Y[i] = g_cov[i] / g_nrm[m];
}

// P = (15 I - 10 M + 3 M2) / 8  (elementwise; in-place over M2 allowed)
__global__ void k_poly(const float* __restrict__ M, const float* __restrict__ M2,
                       float* __restrict__ P) {
    int i = blockIdx.x * 256 + threadIdx.x;
    if (i >= 6291456) return;
    int rc = i & 262143;
    float d = ((rc >> 9) == (rc & 511)) ? 15.f : 0.f;
    P[i] = (d - 10.f * M[i] + 3.f * M2[i]) * 0.125f;
}

// ---------------- batched SGEMM: C = alpha * A@B ; M=512, K=512, pipelined k16 ----------
__global__ void __launch_bounds__(256) k_gemm16(
    const float* __restrict__ A, int strA, const float* __restrict__ B, int strB, int bdiv,
    float* __restrict__ C, int strC, int N, float alpha, int nrmmode)
{
    __shared__ float sA[16][128], sB[16][128];
    int z = blockIdx.z;
    const float* Ab = A + (size_t)z * strA;
    const float* Bb = B + (size_t)(bdiv ? z / 3 : z) * strB;
    float* Cb = C + (size_t)z * strC;
    if (nrmmode) alpha = sqrtf(g_nrm[12 + z] / g_nrm[z]);
    int m0 = blockIdx.y * 128, n0 = blockIdx.x * 128;
    int tid = threadIdx.x;
    int ar = tid >> 1, ac = (tid & 1) * 8;
    int br = tid >> 4, bc = (tid & 15) * 8;
    int ty = tid >> 4, tx = tid & 15;
    float acc[8][8];
#pragma unroll
    for (int a = 0; a < 8; a++)
#pragma unroll
        for (int b = 0; b < 8; b++) acc[a][b] = 0.f;
    float4 ra0 = *(const float4*)&Ab[(size_t)(m0 + ar) * 512 + ac];
    float4 ra1 = *(const float4*)&Ab[(size_t)(m0 + ar) * 512 + ac + 4];
    float4 rb0 = *(const float4*)&Bb[(size_t)br * N + n0 + bc];
    float4 rb1 = *(const float4*)&Bb[(size_t)br * N + n0 + bc + 4];
    for (int k0 = 0; k0 < 512; k0 += 16) {
        sA[ac+0][ar]=ra0.x; sA[ac+1][ar]=ra0.y; sA[ac+2][ar]=ra0.z; sA[ac+3][ar]=ra0.w;
        sA[ac+4][ar]=ra1.x; sA[ac+5][ar]=ra1.y; sA[ac+6][ar]=ra1.z; sA[ac+7][ar]=ra1.w;
        *(float4*)&sB[br][bc] = rb0; *(float4*)&sB[br][bc + 4] = rb1;
        __syncthreads();
        if (k0 + 16 < 512) {
            ra0 = *(const float4*)&Ab[(size_t)(m0 + ar) * 512 + k0 + 16 + ac];
            ra1 = *(const float4*)&Ab[(size_t)(m0 + ar) * 512 + k0 + 16 + ac + 4];
            rb0 = *(const float4*)&Bb[(size_t)(k0 + 16 + br) * N + n0 + bc];
            rb1 = *(const float4*)&Bb[(size_t)(k0 + 16 + br) * N + n0 + bc + 4];
        }
#pragma unroll
        for (int k = 0; k < 16; k++) {
            float av[8], bv[8];
            *(float4*)av = *(float4*)&sA[k][ty * 8]; *(float4*)(av+4) = *(float4*)&sA[k][ty * 8 + 4];
            *(float4*)bv = *(float4*)&sB[k][tx * 8]; *(float4*)(bv+4) = *(float4*)&sB[k][tx * 8 + 4];
#pragma unroll
            for (int a = 0; a < 8; a++)
#pragma unroll
                for (int b = 0; b < 8; b++) acc[a][b] += av[a] * bv[b];
        }
        __syncthreads();
    }
#pragma unroll
    for (int a = 0; a < 8; a++) {
        int gm = m0 + ty * 8 + a;
#pragma unroll
        for (int b = 0; b < 8; b++) {
            int gn = n0 + tx * 8 + b;
            Cb[(size_t)gm * N + gn] = alpha * acc[a][b];
        }
    }
}

// v[z] = Tm[z] @ mu_c[z]  (warp-per-row, coalesced)
__global__ void __launch_bounds__(512) k_gemv() {
    __shared__ float mu[512];
    int z = blockIdx.x;
    int b = z / 3, k = z % 3;
    int tid = threadIdx.x;
    mu[tid] = g_cent[b * 1536 + k * 512 + tid];
    __syncthreads();
    const float* T = g_Tm + (size_t)z * 262144;
    int warp = tid >> 5, lane = tid & 31;
    for (int c = warp; c < 512; c += 16) {
        float s = 0;
        for (int d = lane; d < 512; d += 32) s += T[c * 512 + d] * mu[d];
#pragma unroll
        for (int o = 16; o > 0; o >>= 1) s += __shfl_down_sync(0xffffffff, s, o);
        if (lane == 0) g_vv[z * 512 + c] = s;
    }
}

__global__ void k_comb(const float* __restrict__ tp) {
    int i = blockIdx.x * 256 + threadIdx.x;
    if (i >= 2097152) return;
    int n = i & 1023, c = (i >> 10) & 511, b = i >> 19;
    int a = g_asg[b * 1024 + n];
    int z = b * 3 + a;
    float val = tp[(size_t)z * 524288 + c * 1024 + n] - g_vv[z * 512 + c]
              + g_cent[(4 + b) * 1536 + a * 512 + c];
    g_f4t[i] = 0.6f * val + 0.4f * g_f4c[i];
}

__global__ void __launch_bounds__(1024) k_closs() {
    __shared__ double red[1024];
    double s = 0;
    for (int i = threadIdx.x; i < 2097152; i += 1024) {
        float d = g_f4e[i] - g_f4c[i]; s += (double)d * d;
    }
    red[threadIdx.x] = s; __syncthreads();
    for (int o = 512; o > 0; o >>= 1) { if (threadIdx.x < o) red[threadIdx.x] += red[threadIdx.x + o]; __syncthreads(); }
    if (threadIdx.x == 0) g_cl[0] = (float)(red[0] / 2097152.0);
}

__global__ void __launch_bounds__(256) k_final(float* out) {
    __shared__ double red[256];
    __shared__ double slv;
    const int off[5] = {0, 256, 768, 1792, 3840};
    if (threadIdx.x == 0) slv = 0;
    __syncthreads();
    for (int l = 0; l < 4; l++) {
        int o0 = off[l], sz = off[l + 1] - off[l];
        double s = 0;
        for (int i = threadIdx.x; i < sz; i += 256) {
            float dm = g_st[2 * 3840 + o0 + i] - g_st[0 * 3840 + o0 + i];
            float ds = g_st[3 * 3840 + o0 + i] - g_st[1 * 3840 + o0 + i];
            s += (double)dm * dm + (double)ds * ds;
        }
        red[threadIdx.x] = s; __syncthreads();
        for (int o = 128; o > 0; o >>= 1) { if (threadIdx.x < o) red[threadIdx.x] += red[threadIdx.x + o]; __syncthreads(); }
        if (threadIdx.x == 0) slv += red[0] / sz;
        __syncthreads();
    }
    if (threadIdx.x == 0) out[0] = g_cl[0] + 0.01f * (float)slv;
}

// ------------------------------ host ------------------------------
extern "C" void kernel_launch(void* const* d_in, const int* in_sizes, int n_in,
                              void* d_out, int out_size) {
    (void)in_sizes; (void)n_in; (void)out_size;
    const float* in[18];
    for (int i = 0; i < 18; i++) in[i] = (const float*)d_in[i];

    float *b0, *b1, *f4c, *f4s, *f4t, *f4e, *dec, *Y, *Z, *Tt, *cov, *aw, *Tm;
    cudaGetSymbolAddress((void**)&b0, g_b0);
    cudaGetSymbolAddress((void**)&b1, g_b1);
    cudaGetSymbolAddress((void**)&f4c, g_f4c);
    cudaGetSymbolAddress((void**)&f4s, g_f4s);
    cudaGetSymbolAddress((void**)&f4t, g_f4t);
    cudaGetSymbolAddress((void**)&f4e, g_f4e);
    cudaGetSymbolAddress((void**)&dec, g_dec);
    cudaGetSymbolAddress((void**)&Y, g_Y);
    cudaGetSymbolAddress((void**)&Z, g_Z);
    cudaGetSymbolAddress((void**)&Tt, g_Tt);
    cudaGetSymbolAddress((void**)&cov, g_cov);
    cudaGetSymbolAddress((void**)&aw, g_aw);
    cudaGetSymbolAddress((void**)&Tm, g_Tm);
    float* st; cudaGetSymbolAddress((void**)&st, g_st);
    float* aw1 = aw + 6291456;

    auto conv = [&](const float* i0, float* o, const float* w, const float* bb,
                    int Cin, int Cout, int H, int relu) {
        dim3 g((H / 32) * (H / 32), (Cout + 7) / 8, 4);
        k_conv<<<g, 256>>>(i0, w, bb, o, Cin, Cout, H, relu);
    };
    auto pool = [&](const float* i0, float* o, int C, int Ho) {
        int tot = 4 * C * Ho * Ho; k_pool<<<(tot + 255) / 256, 256>>>(i0, o, C, Ho);
    };
    auto up = [&](const float* i0, float* o, int C, int Ho) {
        int tot = 4 * C * Ho * Ho; k_up<<<(tot + 255) / 256, 256>>>(i0, o, C, Ho);
    };
    auto enc = [&](const float* x, float* f4, float* mo, float* so) {
        conv(x, b0, in[2], in[3], 3, 64, 256, 1);
        if (mo) k_stats<<<4 * 64, 256>>>(b0, 65536, mo, so);
        pool(b0, b1, 64, 128);
        conv(b1, b0, in[4], in[5], 64, 128, 128, 1);
        if (mo) k_stats<<<4 * 128, 256>>>(b0, 16384, mo + 256, so + 256);
        pool(b0, b1, 128, 64);
        conv(b1, b0, in[6], in[7], 128, 256, 64, 1);
        if (mo) k_stats<<<4 * 256, 256>>>(b0, 4096, mo + 768, so + 768);
        pool(b0, b1, 256, 32);
        conv(b1, f4, in[8], in[9], 256, 512, 32, 1);
        if (mo) k_stats<<<4 * 512, 256>>>(f4, 1024, mo + 1792, so + 1792);
    };
    const int P6M = (6291456 + 255) / 256;

    // encodes
    enc(in[0], f4c, 0, 0);
    enc(in[1], f4s, st + 0, st + 3840);

    // k-means
    k_transp<<<dim3(8, 16, 32), dim3(32, 8)>>>();
    k_cent0<<<48, 256>>>();
    for (int it = 0; it < 11; it++) {
        k_assign<<<8, 1024>>>();
        k_update<<<8, 512>>>();
    }

    // covariances + norm + init
    k_aw<<<(12582912 + 255) / 256, 256>>>();
    k_covg<<<dim3(10, 1, 24), 256>>>();
    k_norm<<<24, 256>>>();
    k_nsinit<<<P6M, 256>>>();

    // order-3 coupled Newton-Schulz: Y -> A_n^(1/2), Z -> A_n^(-1/2)
    // iter 1 special (Z0 = I): M = Y; M2 = Y@Y; P = poly; Y1 = Y@P; Z1 = P
    k_gemm16<<<dim3(4, 4, 24), 256>>>(Y, 262144, Y, 262144, 0, cov, 262144, 512, 1.f, 0);
    k_poly<<<P6M, 256>>>(Y, cov, cov);
    k_gemm16<<<dim3(4, 4, 24), 256>>>(Y, 262144, cov, 262144, 0, aw, 262144, 512, 1.f, 0);
    float* Yc = aw; float* Zc = cov;
    float* fr[4] = {Y, Z, Tt, aw1};
    for (int it = 0; it < 14; it++) {
        float* M = fr[0]; float* P = fr[1]; float* Yn = fr[2]; float* Zn = fr[3];
        k_gemm16<<<dim3(4, 4, 24), 256>>>(Zc, 262144, Yc, 262144, 0, M, 262144, 512, 1.f, 0);
        k_gemm16<<<dim3(4, 4, 24), 256>>>(M, 262144, M, 262144, 0, P, 262144, 512, 1.f, 0);
        k_poly<<<P6M, 256>>>(M, P, P);
        k_gemm16<<<dim3(4, 4, 24), 256>>>(Yc, 262144, P, 262144, 0, Yn, 262144, 512, 1.f, 0);
        k_gemm16<<<dim3(4, 4, 24), 256>>>(P, 262144, Zc, 262144, 0, Zn, 262144, 512, 1.f, 0);
        fr[0] = Yc; fr[1] = Zc; fr[2] = M; fr[3] = P;
        Yc = Yn; Zc = Zn;
    }

    // Tm = sqrt(c_s/c_c) * Y_s @ Z_c
    k_gemm16<<<dim3(4, 4, 12), 256>>>(Yc + (size_t)12 * 262144, 262144, Zc, 262144, 0,
                                      Tm, 262144, 512, 1.f, 1);
    // tpts[z] = Tm[z] @ f_b  -> free buffer fr[0]
    float* tp = fr[0];
    k_gemm16<<<dim3(8, 4, 12), 256>>>(Tm, 262144, f4c, 524288, 1, tp, 524288, 1024, 1.f, 0);
    k_gemv<<<12, 512>>>();
    k_comb<<<(2097152 + 255) / 256, 256>>>(tp);

    // decode
    conv(f4t, b0, in[10], in[11], 512, 256, 32, 1);
    up(b0, b1, 256, 64);
    conv(b1, b0, in[12], in[13], 256, 128, 64, 1);
    up(b0, b1, 128, 128);
    conv(b1, b0, in[14], in[15], 128, 64, 128, 1);
    up(b0, b1, 64, 256);
    conv(b1, dec, in[16], in[17], 64, 3, 256, 0);

    // encode(dec) with stats
    enc(dec, f4e, st + 2 * 3840, st + 3 * 3840);

    // losses
    k_closs<<<1, 1024>>>();
    k_final<<<1, 256>>>((float*)d_out);
}

// round 5
// speedup vs baseline: 1.5091x; 1.0853x over previous
#include <cuda_runtime.h>
#include <math.h>

// ------------------------------ scratch ------------------------------
__device__ float g_b0[16777216];
__device__ float g_b1[16777216];
__device__ float g_f4c[2097152];
__device__ float g_f4s[2097152];
__device__ float g_f4t[2097152];
__device__ float g_f4e[2097152];
__device__ float g_dec[786432];
__device__ float g_fT[4194304];      // [8][1024][512]
__device__ float g_cent[12288];      // [8][3][512]
__device__ int   g_asg[8192];        // [8][1024]
__device__ float g_cnt[24];          // [8][3]
__device__ float g_aw[12582912];     // Aw (24x512x1024) / two NS halves / tpts
__device__ float g_cov[6291456];
__device__ float g_Y[6291456];
__device__ float g_Z[6291456];
__device__ float g_Tt[6291456];
__device__ float g_nrm[24];
__device__ float g_Tm[3145728];      // 12x512x512
__device__ float g_vv[6144];         // 12x512
__device__ float g_st[15360];        // [4][3840]
__device__ float g_cl[1];

__constant__ int c_pi[10] = {0,0,0,0,1,1,1,2,2,3};
__constant__ int c_pj[10] = {0,1,2,3,1,2,3,2,3,3};

// ------------------------------ conv 3x3 SAME (OCB oc/block) ------------------------------
template<int OCB>
__global__ void __launch_bounds__(256) k_conv(const float* __restrict__ in,
    const float* __restrict__ w, const float* __restrict__ bias,
    float* __restrict__ out, int Cin, int Cout, int H, int relu)
{
    __shared__ float sI[34][36];
    __shared__ float sW[OCB][9];
    int tiles = H >> 5;
    int bx = blockIdx.x % tiles, by = blockIdx.x / tiles;
    int x0 = bx * 32, y0 = by * 32;
    int oc0 = blockIdx.y * OCB, b = blockIdx.z;
    int tid = threadIdx.x;
    int lx = (tid & 15) * 2, ly = (tid >> 4) * 2;
    float acc[OCB][4];
#pragma unroll
    for (int o = 0; o < OCB; o++) { acc[o][0]=0.f; acc[o][1]=0.f; acc[o][2]=0.f; acc[o][3]=0.f; }
    const float* ib = in + (size_t)b * Cin * H * H;
    for (int ic = 0; ic < Cin; ic++) {
        __syncthreads();
        const float* ip = ib + (size_t)ic * H * H;
        for (int i = tid; i < 34 * 34; i += 256) {
            int yy = i / 34, xx = i - yy * 34;
            int gy = y0 + yy - 1, gx = x0 + xx - 1;
            sI[yy][xx] = (gy >= 0 && gy < H && gx >= 0 && gx < H) ? ip[gy * H + gx] : 0.f;
        }
        if (tid < OCB * 9) {
            int oc = tid / 9, t = tid - oc * 9;
            sW[oc][t] = (oc0 + oc < Cout) ? w[((size_t)(oc0 + oc) * Cin + ic) * 9 + t] : 0.f;
        }
        __syncthreads();
        float win[4][4];
#pragma unroll
        for (int r = 0; r < 4; r++)
#pragma unroll
            for (int s = 0; s < 4; s++) win[r][s] = sI[ly + r][lx + s];
#pragma unroll
        for (int o = 0; o < OCB; o++) {
            float w0=sW[o][0],w1=sW[o][1],w2=sW[o][2],w3=sW[o][3],w4=sW[o][4];
            float w5=sW[o][5],w6=sW[o][6],w7=sW[o][7],w8=sW[o][8];
#pragma unroll
            for (int p = 0; p < 4; p++) {
                int pr = p >> 1, pc = p & 1;
                acc[o][p] += win[pr][pc]*w0 + win[pr][pc+1]*w1 + win[pr][pc+2]*w2
                           + win[pr+1][pc]*w3 + win[pr+1][pc+1]*w4 + win[pr+1][pc+2]*w5
                           + win[pr+2][pc]*w6 + win[pr+2][pc+1]*w7 + win[pr+2][pc+2]*w8;
            }
        }
    }
#pragma unroll
    for (int o = 0; o < OCB; o++) {
        int oc = oc0 + o;
        if (oc >= Cout) break;
        float bv = bias[oc];
        float* op = out + ((size_t)b * Cout + oc) * H * H;
#pragma unroll
        for (int p = 0; p < 4; p++) {
            float v = acc[o][p] + bv;
            if (relu) v = fmaxf(v, 0.f);
            op[(y0 + ly + (p >> 1)) * H + x0 + lx + (p & 1)] = v;
        }
    }
}

__global__ void k_pool(const float* __restrict__ in, float* __restrict__ out, int C, int Ho) {
    int i = blockIdx.x * 256 + threadIdx.x;
    int tot = 4 * C * Ho * Ho; if (i >= tot) return;
    int x = i % Ho, y = (i / Ho) % Ho; int bc = i / (Ho * Ho);
    int Hi = Ho * 2;
    const float* p = in + (size_t)bc * Hi * Hi;
    out[i] = (p[(2*y)*Hi + 2*x] + p[(2*y)*Hi + 2*x+1] + p[(2*y+1)*Hi + 2*x] + p[(2*y+1)*Hi + 2*x+1]) * 0.25f;
}

__global__ void k_up(const float* __restrict__ in, float* __restrict__ out, int C, int Ho) {
    int i = blockIdx.x * 256 + threadIdx.x;
    int tot = 4 * C * Ho * Ho; if (i >= tot) return;
    int x = i % Ho, y = (i / Ho) % Ho; int bc = i / (Ho * Ho);
    int Hi = Ho >> 1;
    out[i] = in[(size_t)bc * Hi * Hi + (y >> 1) * Hi + (x >> 1)];
}

__global__ void __launch_bounds__(256) k_stats(const float* __restrict__ in, int HW,
                                               float* __restrict__ mo, float* __restrict__ so) {
    __shared__ double red[256];
    int bc = blockIdx.x;
    const float* p = in + (size_t)bc * HW;
    double s = 0;
    for (int i = threadIdx.x; i < HW; i += 256) s += p[i];
    red[threadIdx.x] = s; __syncthreads();
    for (int o = 128; o > 0; o >>= 1) { if (threadIdx.x < o) red[threadIdx.x] += red[threadIdx.x + o]; __syncthreads(); }
    double m = red[0] / HW;
    __syncthreads();
    double v = 0;
    for (int i = threadIdx.x; i < HW; i += 256) { double d = p[i] - m; v += d * d; }
    red[threadIdx.x] = v; __syncthreads();
    for (int o = 128; o > 0; o >>= 1) { if (threadIdx.x < o) red[threadIdx.x] += red[threadIdx.x + o]; __syncthreads(); }
    if (threadIdx.x == 0) { mo[bc] = (float)m; so[bc] = (float)sqrt(red[0] / HW); }
}

// ------------------------------ k-means ------------------------------
__global__ void k_transp() {
    __shared__ float t[32][33];
    int sb = blockIdx.x, c0 = blockIdx.y * 32, n0 = blockIdx.z * 32;
    const float* f = (sb >= 4 ? g_f4s + (size_t)(sb - 4) * 524288 : g_f4c + (size_t)sb * 524288);
    int tx = threadIdx.x, ty = threadIdx.y;
    for (int j = 0; j < 32; j += 8) t[ty + j][tx] = f[(c0 + ty + j) * 1024 + n0 + tx];
    __syncthreads();
    for (int j = 0; j < 32; j += 8) g_fT[(size_t)sb * 524288 + (size_t)(n0 + ty + j) * 512 + c0 + tx] = t[tx][ty + j];
}

__global__ void k_cent0() {
    int i = blockIdx.x * 256 + threadIdx.x;
    if (i >= 12288) return;
    int c = i & 511, k = (i >> 9) % 3, sb = i / 1536;
    const float* f = (sb >= 4 ? g_f4s + (size_t)(sb - 4) * 524288 : g_f4c + (size_t)sb * 524288);
    g_cent[i] = f[c * 1024 + k];
}

__global__ void __launch_bounds__(1024) k_assign() {
    __shared__ float sc[3][512];
    int sb = blockIdx.x, n = threadIdx.x;
    for (int i = n; i < 1536; i += 1024) ((float*)sc)[i] = g_cent[sb * 1536 + i];
    __syncthreads();
    const float* f = (sb >= 4 ? g_f4s + (size_t)(sb - 4) * 524288 : g_f4c + (size_t)sb * 524288);
    float d0 = 0, d1 = 0, d2 = 0;
    for (int c = 0; c < 512; c++) {
        float v = f[c * 1024 + n];
        float a = v - sc[0][c], b = v - sc[1][c], e = v - sc[2][c];
        d0 += a * a; d1 += b * b; d2 += e * e;
    }
    int a = 0; float best = d0;
    if (d1 < best) { best = d1; a = 1; }
    if (d2 < best) { a = 2; }
    g_asg[sb * 1024 + n] = a;
}

__global__ void __launch_bounds__(512) k_update() {
    __shared__ int sa[1024];
    int sb = blockIdx.x, c = threadIdx.x;
    for (int i = c; i < 1024; i += 512) sa[i] = g_asg[sb * 1024 + i];
    __syncthreads();
    float s0 = 0, s1 = 0, s2 = 0; int c0 = 0, c1 = 0, c2 = 0;
    const float* ft = g_fT + (size_t)sb * 524288;
    for (int n = 0; n < 1024; n++) {
        float v = ft[n * 512 + c];
        int a = sa[n];
        if (a == 0) { s0 += v; c0++; } else if (a == 1) { s1 += v; c1++; } else { s2 += v; c2++; }
    }
    g_cent[sb * 1536 + c]        = s0 / ((float)c0 + 1e-6f);
    g_cent[sb * 1536 + 512 + c]  = s1 / ((float)c1 + 1e-6f);
    g_cent[sb * 1536 + 1024 + c] = s2 / ((float)c2 + 1e-6f);
    if (c < 3) g_cnt[sb * 3 + c] = (float)(c == 0 ? c0 : (c == 1 ? c1 : c2));
}

// ------------------------------ cov ------------------------------
__global__ void k_aw() {
    int i = blockIdx.x * 256 + threadIdx.x;
    if (i >= 12582912) return;
    int n = i & 1023, c = (i >> 10) & 511, m = i >> 19;
    int k = m % 3, sb = m / 3;
    const float* f = (sb >= 4 ? g_f4s + (size_t)(sb - 4) * 524288 : g_f4c + (size_t)sb * 524288);
    int a = g_asg[sb * 1024 + n];
    g_aw[i] = (a == k) ? f[c * 1024 + n] - g_cent[sb * 1536 + k * 512 + c] : 0.f;
}

__global__ void __launch_bounds__(256) k_covg() {
    __shared__ float sA[16][128], sB[16][128];
    int m = blockIdx.z;
    const float* A = g_aw + (size_t)m * 524288;
    int bi = c_pi[blockIdx.x], bj = c_pj[blockIdx.x];
    int i0 = bi * 128, j0 = bj * 128;
    int tid = threadIdx.x;
    int ar = tid >> 1, ac = (tid & 1) * 8;
    int ty = tid >> 4, tx = tid & 15;
    float acc[8][8];
#pragma unroll
    for (int a = 0; a < 8; a++)
#pragma unroll
        for (int b = 0; b < 8; b++) acc[a][b] = 0.f;
    float4 ra0 = *(const float4*)&A[(size_t)(i0 + ar) * 1024 + ac];
    float4 ra1 = *(const float4*)&A[(size_t)(i0 + ar) * 1024 + ac + 4];
    float4 rb0 = *(const float4*)&A[(size_t)(j0 + ar) * 1024 + ac];
    float4 rb1 = *(const float4*)&A[(size_t)(j0 + ar) * 1024 + ac + 4];
    for (int k0 = 0; k0 < 1024; k0 += 16) {
        sA[ac+0][ar]=ra0.x; sA[ac+1][ar]=ra0.y; sA[ac+2][ar]=ra0.z; sA[ac+3][ar]=ra0.w;
        sA[ac+4][ar]=ra1.x; sA[ac+5][ar]=ra1.y; sA[ac+6][ar]=ra1.z; sA[ac+7][ar]=ra1.w;
        sB[ac+0][ar]=rb0.x; sB[ac+1][ar]=rb0.y; sB[ac+2][ar]=rb0.z; sB[ac+3][ar]=rb0.w;
        sB[ac+4][ar]=rb1.x; sB[ac+5][ar]=rb1.y; sB[ac+6][ar]=rb1.z; sB[ac+7][ar]=rb1.w;
        __syncthreads();
        if (k0 + 16 < 1024) {
            ra0 = *(const float4*)&A[(size_t)(i0 + ar) * 1024 + k0 + 16 + ac];
            ra1 = *(const float4*)&A[(size_t)(i0 + ar) * 1024 + k0 + 16 + ac + 4];
            rb0 = *(const float4*)&A[(size_t)(j0 + ar) * 1024 + k0 + 16 + ac];
            rb1 = *(const float4*)&A[(size_t)(j0 + ar) * 1024 + k0 + 16 + ac + 4];
        }
#pragma unroll
        for (int k = 0; k < 16; k++) {
            float av[8], bv[8];
            *(float4*)av = *(float4*)&sA[k][ty * 8]; *(float4*)(av+4) = *(float4*)&sA[k][ty * 8 + 4];
            *(float4*)bv = *(float4*)&sB[k][tx * 8]; *(float4*)(bv+4) = *(float4*)&sB[k][tx * 8 + 4];
#pragma unroll
            for (int a = 0; a < 8; a++)
#pragma unroll
                for (int b = 0; b < 8; b++) acc[a][b] += av[a] * bv[b];
        }
        __syncthreads();
    }
    float nc = g_cnt[m] + 1e-6f;
    float* C = g_cov + (size_t)m * 262144;
#pragma unroll
    for (int a = 0; a < 8; a++)
#pragma unroll
        for (int b = 0; b < 8; b++) {
            int gi = i0 + ty * 8 + a, gj = j0 + tx * 8 + b;
            float v = acc[a][b] / nc + (gi == gj ? 0.1f : 0.f);
            C[gi * 512 + gj] = v;
            if (bi != bj) C[gj * 512 + gi] = v;
        }
}

__global__ void __launch_bounds__(256) k_norm() {
    __shared__ float red[256];
    int m = blockIdx.x;
    const float* A = g_cov + (size_t)m * 262144;
    float mx = 0;
    for (int r = threadIdx.x; r < 512; r += 256) {
        float s = 0;
        for (int c = 0; c < 512; c++) s += fabsf(A[r * 512 + c]);
        mx = fmaxf(mx, s);
    }
    red[threadIdx.x] = mx; __syncthreads();
    for (int o = 128; o > 0; o >>= 1) { if (threadIdx.x < o) red[threadIdx.x] = fmaxf(red[threadIdx.x], red[threadIdx.x + o]); __syncthreads(); }
    if (threadIdx.x == 0) g_nrm[m] = red[0];
}

__global__ void k_nsinit() {
    int i = blockIdx.x * 256 + threadIdx.x;
    if (i >= 6291456) return;
    int m = i >> 18;
    g_Y[i] = g_cov[i] / g_nrm[m];
}

// ---------- symmetric batched SGEMM 512x512x512, double-buffered ----------
// C = A@B (symmetric output, 10 upper tiles + mirror); polymode:
//   C = (15I - 10*Mp + 3*(A@B)) / 8
__global__ void __launch_bounds__(256) k_gemmsym(
    const float* __restrict__ A, const float* __restrict__ B,
    float* __restrict__ C, const float* __restrict__ Mp, int polymode)
{
    __shared__ float sA[2][16][128], sB[2][16][128];
    int z = blockIdx.z;
    const float* Ab = A + (size_t)z * 262144;
    const float* Bb = B + (size_t)z * 262144;
    float* Cb = C + (size_t)z * 262144;
    const float* Mb = Mp + (size_t)z * 262144;
    int bi = c_pi[blockIdx.x], bj = c_pj[blockIdx.x];
    int m0 = bi * 128, n0 = bj * 128;
    int tid = threadIdx.x;
    int ar = tid >> 1, ac = (tid & 1) * 8;
    int br = tid >> 4, bc = (tid & 15) * 8;
    int ty = tid >> 4, tx = tid & 15;
    float acc[8][8];
#pragma unroll
    for (int a = 0; a < 8; a++)
#pragma unroll
        for (int b = 0; b < 8; b++) acc[a][b] = 0.f;
    float4 ra0 = *(const float4*)&Ab[(size_t)(m0 + ar) * 512 + ac];
    float4 ra1 = *(const float4*)&Ab[(size_t)(m0 + ar) * 512 + ac + 4];
    float4 rb0 = *(const float4*)&Bb[(size_t)br * 512 + n0 + bc];
    float4 rb1 = *(const float4*)&Bb[(size_t)br * 512 + n0 + bc + 4];
    sA[0][ac+0][ar]=ra0.x; sA[0][ac+1][ar]=ra0.y; sA[0][ac+2][ar]=ra0.z; sA[0][ac+3][ar]=ra0.w;
    sA[0][ac+4][ar]=ra1.x; sA[0][ac+5][ar]=ra1.y; sA[0][ac+6][ar]=ra1.z; sA[0][ac+7][ar]=ra1.w;
    *(float4*)&sB[0][br][bc] = rb0; *(float4*)&sB[0][br][bc + 4] = rb1;
    __syncthreads();
    for (int s = 0; s < 32; s++) {
        int buf = s & 1;
        if (s < 31) {
            int k0 = (s + 1) * 16;
            ra0 = *(const float4*)&Ab[(size_t)(m0 + ar) * 512 + k0 + ac];
            ra1 = *(const float4*)&Ab[(size_t)(m0 + ar) * 512 + k0 + ac + 4];
            rb0 = *(const float4*)&Bb[(size_t)(k0 + br) * 512 + n0 + bc];
            rb1 = *(const float4*)&Bb[(size_t)(k0 + br) * 512 + n0 + bc + 4];
        }
#pragma unroll
        for (int k = 0; k < 16; k++) {
            float av[8], bv[8];
            *(float4*)av = *(float4*)&sA[buf][k][ty * 8]; *(float4*)(av+4) = *(float4*)&sA[buf][k][ty * 8 + 4];
            *(float4*)bv = *(float4*)&sB[buf][k][tx * 8]; *(float4*)(bv+4) = *(float4*)&sB[buf][k][tx * 8 + 4];
#pragma unroll
            for (int a = 0; a < 8; a++)
#pragma unroll
                for (int b = 0; b < 8; b++) acc[a][b] += av[a] * bv[b];
        }
        if (s < 31) {
            int nb = buf ^ 1;
            sA[nb][ac+0][ar]=ra0.x; sA[nb][ac+1][ar]=ra0.y; sA[nb][ac+2][ar]=ra0.z; sA[nb][ac+3][ar]=ra0.w;
            sA[nb][ac+4][ar]=ra1.x; sA[nb][ac+5][ar]=ra1.y; sA[nb][ac+6][ar]=ra1.z; sA[nb][ac+7][ar]=ra1.w;
            *(float4*)&sB[nb][br][bc] = rb0; *(float4*)&sB[nb][br][bc + 4] = rb1;
            __syncthreads();
        }
    }
#pragma unroll
    for (int a = 0; a < 8; a++) {
        int gi = m0 + ty * 8 + a;
#pragma unroll
        for (int b = 0; b < 8; b++) {
            int gj = n0 + tx * 8 + b;
            float v = acc[a][b];
            if (polymode)
                v = ((gi == gj ? 15.f : 0.f) - 10.f * Mb[(size_t)gi * 512 + gj] + 3.f * v) * 0.125f;
            Cb[(size_t)gi * 512 + gj] = v;
            if (bi != bj) Cb[(size_t)gj * 512 + gi] = v;
        }
    }
}

// ---------- general batched SGEMM (M=512,K=512), double-buffered ----------
__global__ void __launch_bounds__(256) k_gemm16(
    const float* __restrict__ A, int strA, const float* __restrict__ B, int strB, int bdiv,
    float* __restrict__ C, int strC, int N, float alpha, int nrmmode)
{
    __shared__ float sA[2][16][128], sB[2][16][128];
    int z = blockIdx.z;
    const float* Ab = A + (size_t)z * strA;
    const float* Bb = B + (size_t)(bdiv ? z / 3 : z) * strB;
    float* Cb = C + (size_t)z * strC;
    if (nrmmode) alpha = sqrtf(g_nrm[12 + z] / g_nrm[z]);
    int m0 = blockIdx.y * 128, n0 = blockIdx.x * 128;
    int tid = threadIdx.x;
    int ar = tid >> 1, ac = (tid & 1) * 8;
    int br = tid >> 4, bc = (tid & 15) * 8;
    int ty = tid >> 4, tx = tid & 15;
    float acc[8][8];
#pragma unroll
    for (int a = 0; a < 8; a++)
#pragma unroll
        for (int b = 0; b < 8; b++) acc[a][b] = 0.f;
    float4 ra0 = *(const float4*)&Ab[(size_t)(m0 + ar) * 512 + ac];
    float4 ra1 = *(const float4*)&Ab[(size_t)(m0 + ar) * 512 + ac + 4];
    float4 rb0 = *(const float4*)&Bb[(size_t)br * N + n0 + bc];
    float4 rb1 = *(const float4*)&Bb[(size_t)br * N + n0 + bc + 4];
    sA[0][ac+0][ar]=ra0.x; sA[0][ac+1][ar]=ra0.y; sA[0][ac+2][ar]=ra0.z; sA[0][ac+3][ar]=ra0.w;
    sA[0][ac+4][ar]=ra1.x; sA[0][ac+5][ar]=ra1.y; sA[0][ac+6][ar]=ra1.z; sA[0][ac+7][ar]=ra1.w;
    *(float4*)&sB[0][br][bc] = rb0; *(float4*)&sB[0][br][bc + 4] = rb1;
    __syncthreads();
    for (int s = 0; s < 32; s++) {
        int buf = s & 1;
        if (s < 31) {
            int k0 = (s + 1) * 16;
            ra0 = *(const float4*)&Ab[(size_t)(m0 + ar) * 512 + k0 + ac];
            ra1 = *(const float4*)&Ab[(size_t)(m0 + ar) * 512 + k0 + ac + 4];
            rb0 = *(const float4*)&Bb[(size_t)(k0 + br) * N + n0 + bc];
            rb1 = *(const float4*)&Bb[(size_t)(k0 + br) * N + n0 + bc + 4];
        }
#pragma unroll
        for (int k = 0; k < 16; k++) {
            float av[8], bv[8];
            *(float4*)av = *(float4*)&sA[buf][k][ty * 8]; *(float4*)(av+4) = *(float4*)&sA[buf][k][ty * 8 + 4];
            *(float4*)bv = *(float4*)&sB[buf][k][tx * 8]; *(float4*)(bv+4) = *(float4*)&sB[buf][k][tx * 8 + 4];
#pragma unroll
            for (int a = 0; a < 8; a++)
#pragma unroll
                for (int b = 0; b < 8; b++) acc[a][b] += av[a] * bv[b];
        }
        if (s < 31) {
            int nb = buf ^ 1;
            sA[nb][ac+0][ar]=ra0.x; sA[nb][ac+1][ar]=ra0.y; sA[nb][ac+2][ar]=ra0.z; sA[nb][ac+3][ar]=ra0.w;
            sA[nb][ac+4][ar]=ra1.x; sA[nb][ac+5][ar]=ra1.y; sA[nb][ac+6][ar]=ra1.z; sA[nb][ac+7][ar]=ra1.w;
            *(float4*)&sB[nb][br][bc] = rb0; *(float4*)&sB[nb][br][bc + 4] = rb1;
            __syncthreads();
        }
    }
#pragma unroll
    for (int a = 0; a < 8; a++) {
        int gm = m0 + ty * 8 + a;
#pragma unroll
        for (int b = 0; b < 8; b++) {
            int gn = n0 + tx * 8 + b;
            Cb[(size_t)gm * N + gn] = alpha * acc[a][b];
        }
    }
}

__global__ void __launch_bounds__(512) k_gemv() {
    __shared__ float mu[512];
    int z = blockIdx.x;
    int b = z / 3, k = z % 3;
    int tid = threadIdx.x;
    mu[tid] = g_cent[b * 1536 + k * 512 + tid];
    __syncthreads();
    const float* T = g_Tm + (size_t)z * 262144;
    int warp = tid >> 5, lane = tid & 31;
    for (int c = warp; c < 512; c += 16) {
        float s = 0;
        for (int d = lane; d < 512; d += 32) s += T[c * 512 + d] * mu[d];
#pragma unroll
        for (int o = 16; o > 0; o >>= 1) s += __shfl_down_sync(0xffffffff, s, o);
        if (lane == 0) g_vv[z * 512 + c] = s;
    }
}

__global__ void k_comb(const float* __restrict__ tp) {
    int i = blockIdx.x * 256 + threadIdx.x;
    if (i >= 2097152) return;
    int n = i & 1023, c = (i >> 10) & 511, b = i >> 19;
    int a = g_asg[b * 1024 + n];
    int z = b * 3 + a;
    float val = tp[(size_t)z * 524288 + c * 1024 + n] - g_vv[z * 512 + c]
              + g_cent[(4 + b) * 1536 + a * 512 + c];
    g_f4t[i] = 0.6f * val + 0.4f * g_f4c[i];
}

__global__ void __launch_bounds__(1024) k_closs() {
    __shared__ double red[1024];
    double s = 0;
    for (int i = threadIdx.x; i < 2097152; i += 1024) {
        float d = g_f4e[i] - g_f4c[i]; s += (double)d * d;
    }
    red[threadIdx.x] = s; __syncthreads();
    for (int o = 512; o > 0; o >>= 1) { if (threadIdx.x < o) red[threadIdx.x] += red[threadIdx.x + o]; __syncthreads(); }
    if (threadIdx.x == 0) g_cl[0] = (float)(red[0] / 2097152.0);
}

__global__ void __launch_bounds__(256) k_final(float* out) {
    __shared__ double red[256];
    __shared__ double slv;
    const int off[5] = {0, 256, 768, 1792, 3840};
    if (threadIdx.x == 0) slv = 0;
    __syncthreads();
    for (int l = 0; l < 4; l++) {
        int o0 = off[l], sz = off[l + 1] - off[l];
        double s = 0;
        for (int i = threadIdx.x; i < sz; i += 256) {
            float dm = g_st[2 * 3840 + o0 + i] - g_st[0 * 3840 + o0 + i];
            float ds = g_st[3 * 3840 + o0 + i] - g_st[1 * 3840 + o0 + i];
            s += (double)dm * dm + (double)ds * ds;
        }
        red[threadIdx.x] = s; __syncthreads();
        for (int o = 128; o > 0; o >>= 1) { if (threadIdx.x < o) red[threadIdx.x] += red[threadIdx.x + o]; __syncthreads(); }
        if (threadIdx.x == 0) slv += red[0] / sz;
        __syncthreads();
    }
    if (threadIdx.x == 0) out[0] = g_cl[0] + 0.01f * (float)slv;
}

// ------------------------------ host ------------------------------
extern "C" void kernel_launch(void* const* d_in, const int* in_sizes, int n_in,
                              void* d_out, int out_size) {
    (void)in_sizes; (void)n_in; (void)out_size;
    const float* in[18];
    for (int i = 0; i < 18; i++) in[i] = (const float*)d_in[i];

    float *b0, *b1, *f4c, *f4s, *f4t, *f4e, *dec, *Y, *Z, *Tt, *cov, *aw, *Tm;
    cudaGetSymbolAddress((void**)&b0, g_b0);
    cudaGetSymbolAddress((void**)&b1, g_b1);
    cudaGetSymbolAddress((void**)&f4c, g_f4c);
    cudaGetSymbolAddress((void**)&f4s, g_f4s);
    cudaGetSymbolAddress((void**)&f4t, g_f4t);
    cudaGetSymbolAddress((void**)&f4e, g_f4e);
    cudaGetSymbolAddress((void**)&dec, g_dec);
    cudaGetSymbolAddress((void**)&Y, g_Y);
    cudaGetSymbolAddress((void**)&Z, g_Z);
    cudaGetSymbolAddress((void**)&Tt, g_Tt);
    cudaGetSymbolAddress((void**)&cov, g_cov);
    cudaGetSymbolAddress((void**)&aw, g_aw);
    cudaGetSymbolAddress((void**)&Tm, g_Tm);
    float* st; cudaGetSymbolAddress((void**)&st, g_st);
    float* aw1 = aw + 6291456;

    auto conv = [&](const float* i0, float* o, const float* w, const float* bb,
                    int Cin, int Cout, int H, int relu) {
        if (H >= 64) {
            dim3 g((H / 32) * (H / 32), (Cout + 15) / 16, 4);
            k_conv<16><<<g, 256>>>(i0, w, bb, o, Cin, Cout, H, relu);
        } else {
            dim3 g((H / 32) * (H / 32), (Cout + 7) / 8, 4);
            k_conv<8><<<g, 256>>>(i0, w, bb, o, Cin, Cout, H, relu);
        }
    };
    auto pool = [&](const float* i0, float* o, int C, int Ho) {
        int tot = 4 * C * Ho * Ho; k_pool<<<(tot + 255) / 256, 256>>>(i0, o, C, Ho);
    };
    auto up = [&](const float* i0, float* o, int C, int Ho) {
        int tot = 4 * C * Ho * Ho; k_up<<<(tot + 255) / 256, 256>>>(i0, o, C, Ho);
    };
    auto enc = [&](const float* x, float* f4, float* mo, float* so) {
        conv(x, b0, in[2], in[3], 3, 64, 256, 1);
        if (mo) k_stats<<<4 * 64, 256>>>(b0, 65536, mo, so);
        pool(b0, b1, 64, 128);
        conv(b1, b0, in[4], in[5], 64, 128, 128, 1);
        if (mo) k_stats<<<4 * 128, 256>>>(b0, 16384, mo + 256, so + 256);
        pool(b0, b1, 128, 64);
        conv(b1, b0, in[6], in[7], 128, 256, 64, 1);
        if (mo) k_stats<<<4 * 256, 256>>>(b0, 4096, mo + 768, so + 768);
        pool(b0, b1, 256, 32);
        conv(b1, f4, in[8], in[9], 256, 512, 32, 1);
        if (mo) k_stats<<<4 * 512, 256>>>(f4, 1024, mo + 1792, so + 1792);
    };

    // encodes
    enc(in[0], f4c, 0, 0);
    enc(in[1], f4s, st + 0, st + 3840);

    // k-means
    k_transp<<<dim3(8, 16, 32), dim3(32, 8)>>>();
    k_cent0<<<48, 256>>>();
    for (int it = 0; it < 11; it++) {
        k_assign<<<8, 1024>>>();
        k_update<<<8, 512>>>();
    }

    // covariances + norm + init
    k_aw<<<(12582912 + 255) / 256, 256>>>();
    k_covg<<<dim3(10, 1, 24), 256>>>();
    k_norm<<<24, 256>>>();
    k_nsinit<<<((6291456 + 255) / 256), 256>>>();

    // order-3 coupled Newton-Schulz (symmetric GEMMs, poly fused into M@M)
    dim3 gs(10, 1, 24);
    // iter 1 special (Z0 = I): P = poly(Y, Y@Y); Y1 = Y@P; Z1 = P
    k_gemmsym<<<gs, 256>>>(Y, Y, cov, Y, 1);          // cov = P
    k_gemmsym<<<gs, 256>>>(Y, cov, aw, cov, 0);       // aw  = Y@P
    float* Yc = aw; float* Zc = cov;
    float* fr[4] = {Y, Z, Tt, aw1};
    for (int it = 0; it < 14; it++) {
        float* M = fr[0]; float* P = fr[1]; float* Yn = fr[2]; float* Zn = fr[3];
        k_gemmsym<<<gs, 256>>>(Zc, Yc, M, Zc, 0);     // M  = Z@Y
        k_gemmsym<<<gs, 256>>>(M, M, P, M, 1);        // P  = poly(M, M@M)
        k_gemmsym<<<gs, 256>>>(Yc, P, Yn, Yc, 0);     // Yn = Y@P
        k_gemmsym<<<gs, 256>>>(P, Zc, Zn, P, 0);      // Zn = P@Z
        fr[0] = Yc; fr[1] = Zc; fr[2] = M; fr[3] = P;
        Yc = Yn; Zc = Zn;
    }

    // Tm = sqrt(c_s/c_c) * Y_s @ Z_c
    k_gemm16<<<dim3(4, 4, 12), 256>>>(Yc + (size_t)12 * 262144, 262144, Zc, 262144, 0,
                                      Tm, 262144, 512, 1.f, 1);
    // tpts[z] = Tm[z] @ f_b
    float* tp = fr[0];
    k_gemm16<<<dim3(8, 4, 12), 256>>>(Tm, 262144, f4c, 524288, 1, tp, 524288, 1024, 1.f, 0);
    k_gemv<<<12, 512>>>();
    k_comb<<<(2097152 + 255) / 256, 256>>>(tp);

    // decode
    conv(f4t, b0, in[10], in[11], 512, 256, 32, 1);
    up(b0, b1, 256, 64);
    conv(b1, b0, in[12], in[13], 256, 128, 64, 1);
    up(b0, b1, 128, 128);
    conv(b1, b0, in[14], in[15], 128, 64, 128, 1);
    up(b0, b1, 64, 256);
    conv(b1, dec, in[16], in[17], 64, 3, 256, 0);

    // encode(dec) with stats
    enc(dec, f4e, st + 2 * 3840, st + 3 * 3840);

    // losses
    k_closs<<<1, 1024>>>();
    k_final<<<1, 256>>>((float*)d_out);
}

// round 6
// speedup vs baseline: 1.5712x; 1.0411x over previous
#include <cuda_runtime.h>
#include <math.h>

// ------------------------------ scratch ------------------------------
__device__ float g_b0[16777216];
__device__ float g_b1[16777216];
__device__ float g_f4c[2097152];
__device__ float g_f4s[2097152];
__device__ float g_f4t[2097152];
__device__ float g_f4e[2097152];
__device__ float g_dec[786432];
__device__ float g_fT[4194304];      // [8][1024][512]
__device__ float g_cent[12288];      // [8][3][512]
__device__ int   g_asg[8192];        // [8][1024]
__device__ float g_cnt[24];          // [8][3]
__device__ float g_aw[12582912];     // Aw (24x512x1024) / two NS halves / tpts
__device__ float g_cov[6291456];
__device__ float g_Y[6291456];
__device__ float g_Z[6291456];
__device__ float g_Tt[6291456];
__device__ float g_nrm[24];
__device__ float g_Tm[3145728];      // 12x512x512
__device__ float g_vv[6144];         // 12x512
__device__ float g_st[15360];        // [4][3840]
__device__ float g_cl[1];

__constant__ int c_pi[10] = {0,0,0,0,1,1,1,2,2,3};
__constant__ int c_pj[10] = {0,1,2,3,1,2,3,2,3,3};

// ------------------------------ conv 3x3 SAME (OCB oc/block) ------------------------------
template<int OCB>
__global__ void __launch_bounds__(256) k_conv(const float* __restrict__ in,
    const float* __restrict__ w, const float* __restrict__ bias,
    float* __restrict__ out, int Cin, int Cout, int H, int relu)
{
    __shared__ float sI[34][36];
    __shared__ float sW[OCB][9];
    int tiles = H >> 5;
    int bx = blockIdx.x % tiles, by = blockIdx.x / tiles;
    int x0 = bx * 32, y0 = by * 32;
    int oc0 = blockIdx.y * OCB, b = blockIdx.z;
    int tid = threadIdx.x;
    int lx = (tid & 15) * 2, ly = (tid >> 4) * 2;
    float acc[OCB][4];
#pragma unroll
    for (int o = 0; o < OCB; o++) { acc[o][0]=0.f; acc[o][1]=0.f; acc[o][2]=0.f; acc[o][3]=0.f; }
    const float* ib = in + (size_t)b * Cin * H * H;
    for (int ic = 0; ic < Cin; ic++) {
        __syncthreads();
        const float* ip = ib + (size_t)ic * H * H;
        for (int i = tid; i < 34 * 34; i += 256) {
            int yy = i / 34, xx = i - yy * 34;
            int gy = y0 + yy - 1, gx = x0 + xx - 1;
            sI[yy][xx] = (gy >= 0 && gy < H && gx >= 0 && gx < H) ? ip[gy * H + gx] : 0.f;
        }
        if (tid < OCB * 9) {
            int oc = tid / 9, t = tid - oc * 9;
            sW[oc][t] = (oc0 + oc < Cout) ? w[((size_t)(oc0 + oc) * Cin + ic) * 9 + t] : 0.f;
        }
        __syncthreads();
        float win[4][4];
#pragma unroll
        for (int r = 0; r < 4; r++)
#pragma unroll
            for (int s = 0; s < 4; s++) win[r][s] = sI[ly + r][lx + s];
#pragma unroll
        for (int o = 0; o < OCB; o++) {
            float w0=sW[o][0],w1=sW[o][1],w2=sW[o][2],w3=sW[o][3],w4=sW[o][4];
            float w5=sW[o][5],w6=sW[o][6],w7=sW[o][7],w8=sW[o][8];
#pragma unroll
            for (int p = 0; p < 4; p++) {
                int pr = p >> 1, pc = p & 1;
                acc[o][p] += win[pr][pc]*w0 + win[pr][pc+1]*w1 + win[pr][pc+2]*w2
                           + win[pr+1][pc]*w3 + win[pr+1][pc+1]*w4 + win[pr+1][pc+2]*w5
                           + win[pr+2][pc]*w6 + win[pr+2][pc+1]*w7 + win[pr+2][pc+2]*w8;
            }
        }
    }
#pragma unroll
    for (int o = 0; o < OCB; o++) {
        int oc = oc0 + o;
        if (oc >= Cout) break;
        float bv = bias[oc];
        float* op = out + ((size_t)b * Cout + oc) * H * H;
#pragma unroll
        for (int p = 0; p < 4; p++) {
            float v = acc[o][p] + bv;
            if (relu) v = fmaxf(v, 0.f);
            op[(y0 + ly + (p >> 1)) * H + x0 + lx + (p & 1)] = v;
        }
    }
}

__global__ void k_pool(const float* __restrict__ in, float* __restrict__ out, int C, int Ho) {
    int i = blockIdx.x * 256 + threadIdx.x;
    int tot = 4 * C * Ho * Ho; if (i >= tot) return;
    int x = i % Ho, y = (i / Ho) % Ho; int bc = i / (Ho * Ho);
    int Hi = Ho * 2;
    const float* p = in + (size_t)bc * Hi * Hi;
    out[i] = (p[(2*y)*Hi + 2*x] + p[(2*y)*Hi + 2*x+1] + p[(2*y+1)*Hi + 2*x] + p[(2*y+1)*Hi + 2*x+1]) * 0.25f;
}

__global__ void k_up(const float* __restrict__ in, float* __restrict__ out, int C, int Ho) {
    int i = blockIdx.x * 256 + threadIdx.x;
    int tot = 4 * C * Ho * Ho; if (i >= tot) return;
    int x = i % Ho, y = (i / Ho) % Ho; int bc = i / (Ho * Ho);
    int Hi = Ho >> 1;
    out[i] = in[(size_t)bc * Hi * Hi + (y >> 1) * Hi + (x >> 1)];
}

__global__ void __launch_bounds__(256) k_stats(const float* __restrict__ in, int HW,
                                               float* __restrict__ mo, float* __restrict__ so) {
    __shared__ double red[256];
    int bc = blockIdx.x;
    const float* p = in + (size_t)bc * HW;
    double s = 0;
    for (int i = threadIdx.x; i < HW; i += 256) s += p[i];
    red[threadIdx.x] = s; __syncthreads();
    for (int o = 128; o > 0; o >>= 1) { if (threadIdx.x < o) red[threadIdx.x] += red[threadIdx.x + o]; __syncthreads(); }
    double m = red[0] / HW;
    __syncthreads();
    double v = 0;
    for (int i = threadIdx.x; i < HW; i += 256) { double d = p[i] - m; v += d * d; }
    red[threadIdx.x] = v; __syncthreads();
    for (int o = 128; o > 0; o >>= 1) { if (threadIdx.x < o) red[threadIdx.x] += red[threadIdx.x + o]; __syncthreads(); }
    if (threadIdx.x == 0) { mo[bc] = (float)m; so[bc] = (float)sqrt(red[0] / HW); }
}

// ------------------------------ k-means ------------------------------
__global__ void k_transp() {
    __shared__ float t[32][33];
    int sb = blockIdx.x, c0 = blockIdx.y * 32, n0 = blockIdx.z * 32;
    const float* f = (sb >= 4 ? g_f4s + (size_t)(sb - 4) * 524288 : g_f4c + (size_t)sb * 524288);
    int tx = threadIdx.x, ty = threadIdx.y;
    for (int j = 0; j < 32; j += 8) t[ty + j][tx] = f[(c0 + ty + j) * 1024 + n0 + tx];
    __syncthreads();
    for (int j = 0; j < 32; j += 8) g_fT[(size_t)sb * 524288 + (size_t)(n0 + ty + j) * 512 + c0 + tx] = t[tx][ty + j];
}

__global__ void k_cent0() {
    int i = blockIdx.x * 256 + threadIdx.x;
    if (i >= 12288) return;
    int c = i & 511, k = (i >> 9) % 3, sb = i / 1536;
    const float* f = (sb >= 4 ? g_f4s + (size_t)(sb - 4) * 524288 : g_f4c + (size_t)sb * 524288);
    g_cent[i] = f[c * 1024 + k];
}

__global__ void __launch_bounds__(1024) k_assign() {
    __shared__ float sc[3][512];
    int sb = blockIdx.x, n = threadIdx.x;
    for (int i = n; i < 1536; i += 1024) ((float*)sc)[i] = g_cent[sb * 1536 + i];
    __syncthreads();
    const float* f = (sb >= 4 ? g_f4s + (size_t)(sb - 4) * 524288 : g_f4c + (size_t)sb * 524288);
    float d0 = 0, d1 = 0, d2 = 0;
    for (int c = 0; c < 512; c++) {
        float v = f[c * 1024 + n];
        float a = v - sc[0][c], b = v - sc[1][c], e = v - sc[2][c];
        d0 += a * a; d1 += b * b; d2 += e * e;
    }
    int a = 0; float best = d0;
    if (d1 < best) { best = d1; a = 1; }
    if (d2 < best) { a = 2; }
    g_asg[sb * 1024 + n] = a;
}

__global__ void __launch_bounds__(512) k_update() {
    __shared__ int sa[1024];
    int sb = blockIdx.x, c = threadIdx.x;
    for (int i = c; i < 1024; i += 512) sa[i] = g_asg[sb * 1024 + i];
    __syncthreads();
    float s0 = 0, s1 = 0, s2 = 0; int c0 = 0, c1 = 0, c2 = 0;
    const float* ft = g_fT + (size_t)sb * 524288;
    for (int n = 0; n < 1024; n++) {
        float v = ft[n * 512 + c];
        int a = sa[n];
        if (a == 0) { s0 += v; c0++; } else if (a == 1) { s1 += v; c1++; } else { s2 += v; c2++; }
    }
    g_cent[sb * 1536 + c]        = s0 / ((float)c0 + 1e-6f);
    g_cent[sb * 1536 + 512 + c]  = s1 / ((float)c1 + 1e-6f);
    g_cent[sb * 1536 + 1024 + c] = s2 / ((float)c2 + 1e-6f);
    if (c < 3) g_cnt[sb * 3 + c] = (float)(c == 0 ? c0 : (c == 1 ? c1 : c2));
}

// ------------------------------ cov ------------------------------
__global__ void k_aw() {
    int i = blockIdx.x * 256 + threadIdx.x;
    if (i >= 12582912) return;
    int n = i & 1023, c = (i >> 10) & 511, m = i >> 19;
    int k = m % 3, sb = m / 3;
    const float* f = (sb >= 4 ? g_f4s + (size_t)(sb - 4) * 524288 : g_f4c + (size_t)sb * 524288);
    int a = g_asg[sb * 1024 + n];
    g_aw[i] = (a == k) ? f[c * 1024 + n] - g_cent[sb * 1536 + k * 512 + c] : 0.f;
}

__global__ void __launch_bounds__(256) k_covg() {
    __shared__ float sA[16][128], sB[16][128];
    int m = blockIdx.z;
    const float* A = g_aw + (size_t)m * 524288;
    int bi = c_pi[blockIdx.x], bj = c_pj[blockIdx.x];
    int i0 = bi * 128, j0 = bj * 128;
    int tid = threadIdx.x;
    int ar = tid >> 1, ac = (tid & 1) * 8;
    int ty = tid >> 4, tx = tid & 15;
    float acc[8][8];
#pragma unroll
    for (int a = 0; a < 8; a++)
#pragma unroll
        for (int b = 0; b < 8; b++) acc[a][b] = 0.f;
    float4 ra0 = *(const float4*)&A[(size_t)(i0 + ar) * 1024 + ac];
    float4 ra1 = *(const float4*)&A[(size_t)(i0 + ar) * 1024 + ac + 4];
    float4 rb0 = *(const float4*)&A[(size_t)(j0 + ar) * 1024 + ac];
    float4 rb1 = *(const float4*)&A[(size_t)(j0 + ar) * 1024 + ac + 4];
    for (int k0 = 0; k0 < 1024; k0 += 16) {
        sA[ac+0][ar]=ra0.x; sA[ac+1][ar]=ra0.y; sA[ac+2][ar]=ra0.z; sA[ac+3][ar]=ra0.w;
        sA[ac+4][ar]=ra1.x; sA[ac+5][ar]=ra1.y; sA[ac+6][ar]=ra1.z; sA[ac+7][ar]=ra1.w;
        sB[ac+0][ar]=rb0.x; sB[ac+1][ar]=rb0.y; sB[ac+2][ar]=rb0.z; sB[ac+3][ar]=rb0.w;
        sB[ac+4][ar]=rb1.x; sB[ac+5][ar]=rb1.y; sB[ac+6][ar]=rb1.z; sB[ac+7][ar]=rb1.w;
        __syncthreads();
        if (k0 + 16 < 1024) {
            ra0 = *(const float4*)&A[(size_t)(i0 + ar) * 1024 + k0 + 16 + ac];
            ra1 = *(const float4*)&A[(size_t)(i0 + ar) * 1024 + k0 + 16 + ac + 4];
            rb0 = *(const float4*)&A[(size_t)(j0 + ar) * 1024 + k0 + 16 + ac];
            rb1 = *(const float4*)&A[(size_t)(j0 + ar) * 1024 + k0 + 16 + ac + 4];
        }
#pragma unroll
        for (int k = 0; k < 16; k++) {
            float av[8], bv[8];
            *(float4*)av = *(float4*)&sA[k][ty * 8]; *(float4*)(av+4) = *(float4*)&sA[k][ty * 8 + 4];
            *(float4*)bv = *(float4*)&sB[k][tx * 8]; *(float4*)(bv+4) = *(float4*)&sB[k][tx * 8 + 4];
#pragma unroll
            for (int a = 0; a < 8; a++)
#pragma unroll
                for (int b = 0; b < 8; b++) acc[a][b] += av[a] * bv[b];
        }
        __syncthreads();
    }
    float nc = g_cnt[m] + 1e-6f;
    float* C = g_cov + (size_t)m * 262144;
#pragma unroll
    for (int a = 0; a < 8; a++)
#pragma unroll
        for (int b = 0; b < 8; b++) {
            int gi = i0 + ty * 8 + a, gj = j0 + tx * 8 + b;
            float v = acc[a][b] / nc + (gi == gj ? 0.1f : 0.f);
            C[gi * 512 + gj] = v;
            if (bi != bj) C[gj * 512 + gi] = v;
        }
}

__global__ void __launch_bounds__(256) k_norm() {
    __shared__ float red[256];
    int m = blockIdx.x;
    const float* A = g_cov + (size_t)m * 262144;
    float mx = 0;
    for (int r = threadIdx.x; r < 512; r += 256) {
        float s = 0;
        for (int c = 0; c < 512; c++) s += fabsf(A[r * 512 + c]);
        mx = fmaxf(mx, s);
    }
    red[threadIdx.x] = mx; __syncthreads();
    for (int o = 128; o > 0; o >>= 1) { if (threadIdx.x < o) red[threadIdx.x] = fmaxf(red[threadIdx.x], red[threadIdx.x + o]); __syncthreads(); }
    if (threadIdx.x == 0) g_nrm[m] = red[0];
}

__global__ void k_nsinit() {
    int i = blockIdx.x * 256 + threadIdx.x;
    if (i >= 6291456) return;
    int m = i >> 18;
    g_Y[i] = g_cov[i] / g_nrm[m];
}

// ---------- symmetric batched SGEMM 512x512x512, double-buffered ----------
// C = A@B (symmetric output, 10 upper tiles + mirror); polymode:
//   C = (15I - 10*Mp + 3*(A@B)) / 8
__global__ void __launch_bounds__(256) k_gemmsym(
    const float* __restrict__ A, const float* __restrict__ B,
    float* __restrict__ C, const float* __restrict__ Mp, int polymode)
{
    __shared__ float sA[2][16][128], sB[2][16][128];
    int z = blockIdx.z;
    const float* Ab = A + (size_t)z * 262144;
    const float* Bb = B + (size_t)z * 262144;
    float* Cb = C + (size_t)z * 262144;
    const float* Mb = Mp + (size_t)z * 262144;
    int bi = c_pi[blockIdx.x], bj = c_pj[blockIdx.x];
    int m0 = bi * 128, n0 = bj * 128;
    int tid = threadIdx.x;
    int ar = tid >> 1, ac = (tid & 1) * 8;
    int br = tid >> 4, bc = (tid & 15) * 8;
    int ty = tid >> 4, tx = tid & 15;
    float acc[8][8];
#pragma unroll
    for (int a = 0; a < 8; a++)
#pragma unroll
        for (int b = 0; b < 8; b++) acc[a][b] = 0.f;
    float4 ra0 = *(const float4*)&Ab[(size_t)(m0 + ar) * 512 + ac];
    float4 ra1 = *(const float4*)&Ab[(size_t)(m0 + ar) * 512 + ac + 4];
    float4 rb0 = *(const float4*)&Bb[(size_t)br * 512 + n0 + bc];
    float4 rb1 = *(const float4*)&Bb[(size_t)br * 512 + n0 + bc + 4];
    sA[0][ac+0][ar]=ra0.x; sA[0][ac+1][ar]=ra0.y; sA[0][ac+2][ar]=ra0.z; sA[0][ac+3][ar]=ra0.w;
    sA[0][ac+4][ar]=ra1.x; sA[0][ac+5][ar]=ra1.y; sA[0][ac+6][ar]=ra1.z; sA[0][ac+7][ar]=ra1.w;
    *(float4*)&sB[0][br][bc] = rb0; *(float4*)&sB[0][br][bc + 4] = rb1;
    __syncthreads();
    for (int s = 0; s < 32; s++) {
        int buf = s & 1;
        if (s < 31) {
            int k0 = (s + 1) * 16;
            ra0 = *(const float4*)&Ab[(size_t)(m0 + ar) * 512 + k0 + ac];
            ra1 = *(const float4*)&Ab[(size_t)(m0 + ar) * 512 + k0 + ac + 4];
            rb0 = *(const float4*)&Bb[(size_t)(k0 + br) * 512 + n0 + bc];
            rb1 = *(const float4*)&Bb[(size_t)(k0 + br) * 512 + n0 + bc + 4];
        }
#pragma unroll
        for (int k = 0; k < 16; k++) {
            float av[8], bv[8];
            *(float4*)av = *(float4*)&sA[buf][k][ty * 8]; *(float4*)(av+4) = *(float4*)&sA[buf][k][ty * 8 + 4];
            *(float4*)bv = *(float4*)&sB[buf][k][tx * 8]; *(float4*)(bv+4) = *(float4*)&sB[buf][k][tx * 8 + 4];
#pragma unroll
            for (int a = 0; a < 8; a++)
#pragma unroll
                for (int b = 0; b < 8; b++) acc[a][b] += av[a] * bv[b];
        }
        if (s < 31) {
            int nb = buf ^ 1;
            sA[nb][ac+0][ar]=ra0.x; sA[nb][ac+1][ar]=ra0.y; sA[nb][ac+2][ar]=ra0.z; sA[nb][ac+3][ar]=ra0.w;
            sA[nb][ac+4][ar]=ra1.x; sA[nb][ac+5][ar]=ra1.y; sA[nb][ac+6][ar]=ra1.z; sA[nb][ac+7][ar]=ra1.w;
            *(float4*)&sB[nb][br][bc] = rb0; *(float4*)&sB[nb][br][bc + 4] = rb1;
            __syncthreads();
        }
    }
#pragma unroll
    for (int a = 0; a < 8; a++) {
        int gi = m0 + ty * 8 + a;
#pragma unroll
        for (int b = 0; b < 8; b++) {
            int gj = n0 + tx * 8 + b;
            float v = acc[a][b];
            if (polymode)
                v = ((gi == gj ? 15.f : 0.f) - 10.f * Mb[(size_t)gi * 512 + gj] + 3.f * v) * 0.125f;
            Cb[(size_t)gi * 512 + gj] = v;
            if (bi != bj) Cb[(size_t)gj * 512 + gi] = v;
        }
    }
}

// ---------- general batched SGEMM (M=512,K=512), double-buffered ----------
__global__ void __launch_bounds__(256) k_gemm16(
    const float* __restrict__ A, int strA, const float* __restrict__ B, int strB, int bdiv,
    float* __restrict__ C, int strC, int N, float alpha, int nrmmode)
{
    __shared__ float sA[2][16][128], sB[2][16][128];
    int z = blockIdx.z;
    const float* Ab = A + (size_t)z * strA;
    const float* Bb = B + (size_t)(bdiv ? z / 3 : z) * strB;
    float* Cb = C + (size_t)z * strC;
    if (nrmmode) alpha = sqrtf(g_nrm[12 + z] / g_nrm[z]);
    int m0 = blockIdx.y * 128, n0 = blockIdx.x * 128;
    int tid = threadIdx.x;
    int ar = tid >> 1, ac = (tid & 1) * 8;
    int br = tid >> 4, bc = (tid & 15) * 8;
    int ty = tid >> 4, tx = tid & 15;
    float acc[8][8];
#pragma unroll
    for (int a = 0; a < 8; a++)
#pragma unroll
        for (int b = 0; b < 8; b++) acc[a][b] = 0.f;
    float4 ra0 = *(const float4*)&Ab[(size_t)(m0 + ar) * 512 + ac];
    float4 ra1 = *(const float4*)&Ab[(size_t)(m0 + ar) * 512 + ac + 4];
    float4 rb0 = *(const float4*)&Bb[(size_t)br * N + n0 + bc];
    float4 rb1 = *(const float4*)&Bb[(size_t)br * N + n0 + bc + 4];
    sA[0][ac+0][ar]=ra0.x; sA[0][ac+1][ar]=ra0.y; sA[0][ac+2][ar]=ra0.z; sA[0][ac+3][ar]=ra0.w;
    sA[0][ac+4][ar]=ra1.x; sA[0][ac+5][ar]=ra1.y; sA[0][ac+6][ar]=ra1.z; sA[0][ac+7][ar]=ra1.w;
    *(float4*)&sB[0][br][bc] = rb0; *(float4*)&sB[0][br][bc + 4] = rb1;
    __syncthreads();
    for (int s = 0; s < 32; s++) {
        int buf = s & 1;
        if (s < 31) {
            int k0 = (s + 1) * 16;
            ra0 = *(const float4*)&Ab[(size_t)(m0 + ar) * 512 + k0 + ac];
            ra1 = *(const float4*)&Ab[(size_t)(m0 + ar) * 512 + k0 + ac + 4];
            rb0 = *(const float4*)&Bb[(size_t)(k0 + br) * N + n0 + bc];
            rb1 = *(const float4*)&Bb[(size_t)(k0 + br) * N + n0 + bc + 4];
        }
#pragma unroll
        for (int k = 0; k < 16; k++) {
            float av[8], bv[8];
            *(float4*)av = *(float4*)&sA[buf][k][ty * 8]; *(float4*)(av+4) = *(float4*)&sA[buf][k][ty * 8 + 4];
            *(float4*)bv = *(float4*)&sB[buf][k][tx * 8]; *(float4*)(bv+4) = *(float4*)&sB[buf][k][tx * 8 + 4];
#pragma unroll
            for (int a = 0; a < 8; a++)
#pragma unroll
                for (int b = 0; b < 8; b++) acc[a][b] += av[a] * bv[b];
        }
        if (s < 31) {
            int nb = buf ^ 1;
            sA[nb][ac+0][ar]=ra0.x; sA[nb][ac+1][ar]=ra0.y; sA[nb][ac+2][ar]=ra0.z; sA[nb][ac+3][ar]=ra0.w;
            sA[nb][ac+4][ar]=ra1.x; sA[nb][ac+5][ar]=ra1.y; sA[nb][ac+6][ar]=ra1.z; sA[nb][ac+7][ar]=ra1.w;
            *(float4*)&sB[nb][br][bc] = rb0; *(float4*)&sB[nb][br][bc + 4] = rb1;
            __syncthreads();
        }
    }
#pragma unroll
    for (int a = 0; a < 8; a++) {
        int gm = m0 + ty * 8 + a;
#pragma unroll
        for (int b = 0; b < 8; b++) {
            int gn = n0 + tx * 8 + b;
            Cb[(size_t)gm * N + gn] = alpha * acc[a][b];
        }
    }
}

__global__ void __launch_bounds__(512) k_gemv() {
    __shared__ float mu[512];
    int z = blockIdx.x;
    int b = z / 3, k = z % 3;
    int tid = threadIdx.x;
    mu[tid] = g_cent[b * 1536 + k * 512 + tid];
    __syncthreads();
    const float* T = g_Tm + (size_t)z * 262144;
    int warp = tid >> 5, lane = tid & 31;
    for (int c = warp; c < 512; c += 16) {
        float s = 0;
        for (int d = lane; d < 512; d += 32) s += T[c * 512 + d] * mu[d];
#pragma unroll
        for (int o = 16; o > 0; o >>= 1) s += __shfl_down_sync(0xffffffff, s, o);
        if (lane == 0) g_vv[z * 512 + c] = s;
    }
}

__global__ void k_comb(const float* __restrict__ tp) {
    int i = blockIdx.x * 256 + threadIdx.x;
    if (i >= 2097152) return;
    int n = i & 1023, c = (i >> 10) & 511, b = i >> 19;
    int a = g_asg[b * 1024 + n];
    int z = b * 3 + a;
    float val = tp[(size_t)z * 524288 + c * 1024 + n] - g_vv[z * 512 + c]
              + g_cent[(4 + b) * 1536 + a * 512 + c];
    g_f4t[i] = 0.6f * val + 0.4f * g_f4c[i];
}

__global__ void __launch_bounds__(1024) k_closs() {
    __shared__ double red[1024];
    double s = 0;
    for (int i = threadIdx.x; i < 2097152; i += 1024) {
        float d = g_f4e[i] - g_f4c[i]; s += (double)d * d;
    }
    red[threadIdx.x] = s; __syncthreads();
    for (int o = 512; o > 0; o >>= 1) { if (threadIdx.x < o) red[threadIdx.x] += red[threadIdx.x + o]; __syncthreads(); }
    if (threadIdx.x == 0) g_cl[0] = (float)(red[0] / 2097152.0);
}

__global__ void __launch_bounds__(256) k_final(float* out) {
    __shared__ double red[256];
    __shared__ double slv;
    const int off[5] = {0, 256, 768, 1792, 3840};
    if (threadIdx.x == 0) slv = 0;
    __syncthreads();
    for (int l = 0; l < 4; l++) {
        int o0 = off[l], sz = off[l + 1] - off[l];
        double s = 0;
        for (int i = threadIdx.x; i < sz; i += 256) {
            float dm = g_st[2 * 3840 + o0 + i] - g_st[0 * 3840 + o0 + i];
            float ds = g_st[3 * 3840 + o0 + i] - g_st[1 * 3840 + o0 + i];
            s += (double)dm * dm + (double)ds * ds;
        }
        red[threadIdx.x] = s; __syncthreads();
        for (int o = 128; o > 0; o >>= 1) { if (threadIdx.x < o) red[threadIdx.x] += red[threadIdx.x + o]; __syncthreads(); }
        if (threadIdx.x == 0) slv += red[0] / sz;
        __syncthreads();
    }
    if (threadIdx.x == 0) out[0] = g_cl[0] + 0.01f * (float)slv;
}

// ------------------------------ host ------------------------------
extern "C" void kernel_launch(void* const* d_in, const int* in_sizes, int n_in,
                              void* d_out, int out_size) {
    (void)in_sizes; (void)n_in; (void)out_size;
    const float* in[18];
    for (int i = 0; i < 18; i++) in[i] = (const float*)d_in[i];

    float *b0, *b1, *f4c, *f4s, *f4t, *f4e, *dec, *Y, *Z, *Tt, *cov, *aw, *Tm;
    cudaGetSymbolAddress((void**)&b0, g_b0);
    cudaGetSymbolAddress((void**)&b1, g_b1);
    cudaGetSymbolAddress((void**)&f4c, g_f4c);
    cudaGetSymbolAddress((void**)&f4s, g_f4s);
    cudaGetSymbolAddress((void**)&f4t, g_f4t);
    cudaGetSymbolAddress((void**)&f4e, g_f4e);
    cudaGetSymbolAddress((void**)&dec, g_dec);
    cudaGetSymbolAddress((void**)&Y, g_Y);
    cudaGetSymbolAddress((void**)&Z, g_Z);
    cudaGetSymbolAddress((void**)&Tt, g_Tt);
    cudaGetSymbolAddress((void**)&cov, g_cov);
    cudaGetSymbolAddress((void**)&aw, g_aw);
    cudaGetSymbolAddress((void**)&Tm, g_Tm);
    float* st; cudaGetSymbolAddress((void**)&st, g_st);
    float* aw1 = aw + 6291456;

    auto conv = [&](const float* i0, float* o, const float* w, const float* bb,
                    int Cin, int Cout, int H, int relu) {
        if (H >= 64) {
            dim3 g((H / 32) * (H / 32), (Cout + 15) / 16, 4);
            k_conv<16><<<g, 256>>>(i0, w, bb, o, Cin, Cout, H, relu);
        } else {
            dim3 g((H / 32) * (H / 32), (Cout + 7) / 8, 4);
            k_conv<8><<<g, 256>>>(i0, w, bb, o, Cin, Cout, H, relu);
        }
    };
    auto pool = [&](const float* i0, float* o, int C, int Ho) {
        int tot = 4 * C * Ho * Ho; k_pool<<<(tot + 255) / 256, 256>>>(i0, o, C, Ho);
    };
    auto up = [&](const float* i0, float* o, int C, int Ho) {
        int tot = 4 * C * Ho * Ho; k_up<<<(tot + 255) / 256, 256>>>(i0, o, C, Ho);
    };
    auto enc = [&](const float* x, float* f4, float* mo, float* so) {
        conv(x, b0, in[2], in[3], 3, 64, 256, 1);
        if (mo) k_stats<<<4 * 64, 256>>>(b0, 65536, mo, so);
        pool(b0, b1, 64, 128);
        conv(b1, b0, in[4], in[5], 64, 128, 128, 1);
        if (mo) k_stats<<<4 * 128, 256>>>(b0, 16384, mo + 256, so + 256);
        pool(b0, b1, 128, 64);
        conv(b1, b0, in[6], in[7], 128, 256, 64, 1);
        if (mo) k_stats<<<4 * 256, 256>>>(b0, 4096, mo + 768, so + 768);
        pool(b0, b1, 256, 32);
        conv(b1, f4, in[8], in[9], 256, 512, 32, 1);
        if (mo) k_stats<<<4 * 512, 256>>>(f4, 1024, mo + 1792, so + 1792);
    };

    // encodes
    enc(in[0], f4c, 0, 0);
    enc(in[1], f4s, st + 0, st + 3840);

    // k-means
    k_transp<<<dim3(8, 16, 32), dim3(32, 8)>>>();
    k_cent0<<<48, 256>>>();
    for (int it = 0; it < 11; it++) {
        k_assign<<<8, 1024>>>();
        k_update<<<8, 512>>>();
    }

    // covariances + norm + init
    k_aw<<<(12582912 + 255) / 256, 256>>>();
    k_covg<<<dim3(10, 1, 24), 256>>>();
    k_norm<<<24, 256>>>();
    k_nsinit<<<((6291456 + 255) / 256), 256>>>();

    // order-3 coupled Newton-Schulz (symmetric GEMMs, poly fused into M@M)
    dim3 gs(10, 1, 24);
    // iter 1 special (Z0 = I): P = poly(Y, Y@Y); Y1 = Y@P; Z1 = P
    k_gemmsym<<<gs, 256>>>(Y, Y, cov, Y, 1);          // cov = P
    k_gemmsym<<<gs, 256>>>(Y, cov, aw, cov, 0);       // aw  = Y@P
    float* Yc = aw; float* Zc = cov;
    float* fr[4] = {Y, Z, Tt, aw1};
    for (int it = 0; it < 14; it++) {
        float* M = fr[0]; float* P = fr[1]; float* Yn = fr[2]; float* Zn = fr[3];
        k_gemmsym<<<gs, 256>>>(Zc, Yc, M, Zc, 0);     // M  = Z@Y
        k_gemmsym<<<gs, 256>>>(M, M, P, M, 1);        // P  = poly(M, M@M)
        k_gemmsym<<<gs, 256>>>(Yc, P, Yn, Yc, 0);     // Yn = Y@P
        k_gemmsym<<<gs, 256>>>(P, Zc, Zn, P, 0);      // Zn = P@Z
        fr[0] = Yc; fr[1] = Zc; fr[2] = M; fr[3] = P;
        Yc = Yn; Zc = Zn;
    }

    // Tm = sqrt(c_s/c_c) * Y_s @ Z_c
    k_gemm16<<<dim3(4, 4, 12), 256>>>(Yc + (size_t)12 * 262144, 262144, Zc, 262144, 0,
                                      Tm, 262144, 512, 1.f, 1);
    // tpts[z] = Tm[z] @ f_b
    float* tp = fr[0];
    k_gemm16<<<dim3(8, 4, 12), 256>>>(Tm, 262144, f4c, 524288, 1, tp, 524288, 1024, 1.f, 0);
    k_gemv<<<12, 512>>>();
    k_comb<<<(2097152 + 255) / 256, 256>>>(tp);

    // decode
    conv(f4t, b0, in[10], in[11], 512, 256, 32, 1);
    up(b0, b1, 256, 64);
    conv(b1, b0, in[12], in[13], 256, 128, 64, 1);
    up(b0, b1, 128, 128);
    conv(b1, b0, in[14], in[15], 128, 64, 128, 1);
    up(b0, b1, 64, 256);
    conv(b1, dec, in[16], in[17], 64, 3, 256, 0);

    // encode(dec) with stats
    enc(dec, f4e, st + 2 * 3840, st + 3 * 3840);

    // losses
    k_closs<<<1, 1024>>>();
    k_final<<<1, 256>>>((float*)d_out);
}

// round 8
// speedup vs baseline: 1.6551x; 1.0534x over previous
#include <cuda_runtime.h>
#include <math.h>

#define MS 262144
__device__ float g_b0[16777216];
__device__ float g_b1[16777216];
__device__ float g_f4c[2097152];
__device__ float g_f4s[2097152];
__device__ float g_f4t[2097152];
__device__ float g_f4e[2097152];
__device__ float g_dec[786432];
__device__ float g_fT[4194304];
__device__ float g_cent[12288];
__device__ int   g_asg[8192];
__device__ float g_cnt[24];
__device__ float g_aw[12582912];
__device__ float g_cov[6291456];
__device__ float g_Y[6291456];
__device__ float g_Z[6291456];
__device__ float g_Tt[6291456];
__device__ float g_nrm[24];
__device__ float g_Tm[3145728];
__device__ float g_vv[6144];
__device__ float g_st[15360];
__device__ float g_cl[1];

__constant__ int c_pi[10] = {0,0,0,0,1,1,1,2,2,3};
__constant__ int c_pj[10] = {0,1,2,3,1,2,3,2,3,3};

// ---------- implicit-GEMM conv 3x3 SAME (Cin>=64, Cout>=64) ----------
__global__ void __launch_bounds__(256) k_cgemm(
    const float* __restrict__ in, const float* __restrict__ w,
    const float* __restrict__ bias, float* __restrict__ out,
    int Cin, int Cout, int H, int relu)
{
    __shared__ float sA[2][16][128], sB[2][16][128];
    int K = Cin * 9, HH = H * H;
    int m0 = blockIdx.y * 128, n0 = blockIdx.x * 128;
    int tid = threadIdx.x;
    int ar = tid >> 1, ac = (tid & 1) * 8;
    int brk = tid >> 4, bcg = (tid & 15) * 8;
    int ty = tid >> 4, tx = tid & 15;
    int b = n0 / HH, rem0 = n0 - b * HH;
    int cy[8], cx[8];
#pragma unroll
    for (int j = 0; j < 8; j++) {
        int rem = rem0 + bcg + j;
        int yy = rem / H;
        cy[j] = yy; cx[j] = rem - yy * H;
    }
    const float* inb = in + (size_t)b * Cin * HH;
    float acc[8][8];
#pragma unroll
    for (int a = 0; a < 8; a++)
#pragma unroll
        for (int q = 0; q < 8; q++) acc[a][q] = 0.f;
    float ra[8], rb[8];
    int aok = (m0 + ar) < Cout;
    const float* awp = w + (size_t)(aok ? m0 + ar : 0) * K + ac;

    // prefetch slab 0
    if (aok) { *(float4*)ra = *(const float4*)awp; *(float4*)(ra+4) = *(const float4*)(awp+4); }
    else { for (int i = 0; i < 8; i++) ra[i] = 0.f; }
    {
        int k = brk;
        int ic = k / 9, rs = k - ic * 9;
        int dy = rs / 3 - 1, dx = rs - (rs / 3) * 3 - 1;
        const float* ip = inb + (size_t)ic * HH;
#pragma unroll
        for (int j = 0; j < 8; j++) {
            int yy = cy[j] + dy, xx = cx[j] + dx;
            rb[j] = (yy >= 0 && yy < H && xx >= 0 && xx < H) ? ip[yy * H + xx] : 0.f;
        }
    }
    int nk = K / 16;
#pragma unroll
    for (int i = 0; i < 8; i++) sA[0][ac + i][ar] = ra[i];
#pragma unroll
    for (int j = 0; j < 8; j++) sB[0][brk][bcg + j] = rb[j];
    __syncthreads();
    for (int s = 0; s < nk; s++) {
        int buf = s & 1;
        if (s + 1 < nk) {
            int k0 = (s + 1) * 16;
            if (aok) { *(float4*)ra = *(const float4*)(awp + k0); *(float4*)(ra+4) = *(const float4*)(awp + k0 + 4); }
            int k = k0 + brk;
            int ic = k / 9, rs = k - ic * 9;
            int dy = rs / 3 - 1, dx = rs - (rs / 3) * 3 - 1;
            const float* ip = inb + (size_t)ic * HH;
#pragma unroll
            for (int j = 0; j < 8; j++) {
                int yy = cy[j] + dy, xx = cx[j] + dx;
                rb[j] = (yy >= 0 && yy < H && xx >= 0 && xx < H) ? ip[yy * H + xx] : 0.f;
            }
        }
#pragma unroll
        for (int k = 0; k < 16; k++) {
            float av[8], bv[8];
            *(float4*)av = *(float4*)&sA[buf][k][ty * 8]; *(float4*)(av+4) = *(float4*)&sA[buf][k][ty * 8 + 4];
            *(float4*)bv = *(float4*)&sB[buf][k][tx * 8]; *(float4*)(bv+4) = *(float4*)&sB[buf][k][tx * 8 + 4];
#pragma unroll
            for (int a = 0; a < 8; a++)
#pragma unroll
                for (int q = 0; q < 8; q++) acc[a][q] += av[a] * bv[q];
        }
        if (s + 1 < nk) {
            int nb = buf ^ 1;
#pragma unroll
            for (int i = 0; i < 8; i++) sA[nb][ac + i][ar] = ra[i];
#pragma unroll
            for (int j = 0; j < 8; j++) sB[nb][brk][bcg + j] = rb[j];
            __syncthreads();
        }
    }
#pragma unroll
    for (int a = 0; a < 8; a++) {
        int oc = m0 + ty * 8 + a;
        if (oc >= Cout) break;
        float bv = bias[oc];
        float* op = out + ((size_t)b * Cout + oc) * HH;
#pragma unroll
        for (int q = 0; q < 8; q++) {
            float v = acc[a][q] + bv;
            if (relu) v = fmaxf(v, 0.f);
            op[rem0 + tx * 8 + q] = v;
        }
    }
}

// ---------- direct conv (small Cin or Cout) ----------
template<int OCB>
__global__ void __launch_bounds__(256) k_conv(const float* __restrict__ in,
    const float* __restrict__ w, const float* __restrict__ bias,
    float* __restrict__ out, int Cin, int Cout, int H, int relu)
{
    __shared__ float sI[34][36];
    __shared__ float sW[OCB][9];
    int tiles = H >> 5;
    int bx = blockIdx.x % tiles, by = blockIdx.x / tiles;
    int x0 = bx * 32, y0 = by * 32;
    int oc0 = blockIdx.y * OCB, b = blockIdx.z;
    int tid = threadIdx.x;
    int lx = (tid & 15) * 2, ly = (tid >> 4) * 2;
    float acc[OCB][4];
#pragma unroll
    for (int o = 0; o < OCB; o++) { acc[o][0]=0.f; acc[o][1]=0.f; acc[o][2]=0.f; acc[o][3]=0.f; }
    const float* ib = in + (size_t)b * Cin * H * H;
    for (int ic = 0; ic < Cin; ic++) {
        __syncthreads();
        const float* ip = ib + (size_t)ic * H * H;
        for (int i = tid; i < 34 * 34; i += 256) {
            int yy = i / 34, xx = i - yy * 34;
            int gy = y0 + yy - 1, gx = x0 + xx - 1;
            sI[yy][xx] = (gy >= 0 && gy < H && gx >= 0 && gx < H) ? ip[gy * H + gx] : 0.f;
        }
        if (tid < OCB * 9) {
            int oc = tid / 9, tt = tid - oc * 9;
            sW[oc][tt] = (oc0 + oc < Cout) ? w[((size_t)(oc0 + oc) * Cin + ic) * 9 + tt] : 0.f;
        }
        __syncthreads();
        float win[4][4];
#pragma unroll
        for (int r = 0; r < 4; r++)
#pragma unroll
            for (int s = 0; s < 4; s++) win[r][s] = sI[ly + r][lx + s];
#pragma unroll
        for (int o = 0; o < OCB; o++) {
            float w0=sW[o][0],w1=sW[o][1],w2=sW[o][2],w3=sW[o][3],w4=sW[o][4];
            float w5=sW[o][5],w6=sW[o][6],w7=sW[o][7],w8=sW[o][8];
#pragma unroll
            for (int p = 0; p < 4; p++) {
                int pr = p >> 1, pc = p & 1;
                acc[o][p] += win[pr][pc]*w0 + win[pr][pc+1]*w1 + win[pr][pc+2]*w2
                           + win[pr+1][pc]*w3 + win[pr+1][pc+1]*w4 + win[pr+1][pc+2]*w5
                           + win[pr+2][pc]*w6 + win[pr+2][pc+1]*w7 + win[pr+2][pc+2]*w8;
            }
        }
    }
#pragma unroll
    for (int o = 0; o < OCB; o++) {
        int oc = oc0 + o;
        if (oc >= Cout) break;
        float bv = bias[oc];
        float* op = out + ((size_t)b * Cout + oc) * H * H;
#pragma unroll
        for (int p = 0; p < 4; p++) {
            float v = acc[o][p] + bv;
            if (relu) v = fmaxf(v, 0.f);
            op[(y0 + ly + (p >> 1)) * H + x0 + lx + (p & 1)] = v;
        }
    }
}

__global__ void k_pool(const float* __restrict__ in, float* __restrict__ out, int C, int Ho) {
    int i = blockIdx.x * 256 + threadIdx.x;
    int tot = 4 * C * Ho * Ho; if (i >= tot) return;
    int x = i % Ho, y = (i / Ho) % Ho; int bc = i / (Ho * Ho);
    int Hi = Ho * 2;
    const float* p = in + (size_t)bc * Hi * Hi;
    out[i] = (p[(2*y)*Hi + 2*x] + p[(2*y)*Hi + 2*x+1] + p[(2*y+1)*Hi + 2*x] + p[(2*y+1)*Hi + 2*x+1]) * 0.25f;
}

__global__ void k_up(const float* __restrict__ in, float* __restrict__ out, int C, int Ho) {
    int i = blockIdx.x * 256 + threadIdx.x;
    int tot = 4 * C * Ho * Ho; if (i >= tot) return;
    int x = i % Ho, y = (i / Ho) % Ho; int bc = i / (Ho * Ho);
    int Hi = Ho >> 1;
    out[i] = in[(size_t)bc * Hi * Hi + (y >> 1) * Hi + (x >> 1)];
}

__global__ void __launch_bounds__(256) k_stats(const float* __restrict__ in, int HW,
                                               float* __restrict__ mo, float* __restrict__ so) {
    __shared__ double red[256];
    int bc = blockIdx.x;
    const float* p = in + (size_t)bc * HW;
    double s = 0;
    for (int i = threadIdx.x; i < HW; i += 256) s += p[i];
    red[threadIdx.x] = s; __syncthreads();
    for (int o = 128; o > 0; o >>= 1) { if (threadIdx.x < o) red[threadIdx.x] += red[threadIdx.x + o]; __syncthreads(); }
    double m = red[0] / HW;
    __syncthreads();
    double v = 0;
    for (int i = threadIdx.x; i < HW; i += 256) { double d = p[i] - m; v += d * d; }
    red[threadIdx.x] = v; __syncthreads();
    for (int o = 128; o > 0; o >>= 1) { if (threadIdx.x < o) red[threadIdx.x] += red[threadIdx.x + o]; __syncthreads(); }
    if (threadIdx.x == 0) { mo[bc] = (float)m; so[bc] = (float)sqrt(red[0] / HW); }
}

__global__ void k_transp() {
    __shared__ float t[32][33];
    int sb = blockIdx.x, c0 = blockIdx.y * 32, n0 = blockIdx.z * 32;
    const float* f = (sb >= 4 ? g_f4s + (size_t)(sb - 4) * 524288 : g_f4c + (size_t)sb * 524288);
    int tx = threadIdx.x, ty = threadIdx.y;
    for (int j = 0; j < 32; j += 8) t[ty + j][tx] = f[(c0 + ty + j) * 1024 + n0 + tx];
    __syncthreads();
    for (int j = 0; j < 32; j += 8) g_fT[(size_t)sb * 524288 + (size_t)(n0 + ty + j) * 512 + c0 + tx] = t[tx][ty + j];
}

__global__ void k_cent0() {
    int i = blockIdx.x * 256 + threadIdx.x;
    if (i >= 12288) return;
    int c = i & 511, k = (i >> 9) % 3, sb = i / 1536;
    const float* f = (sb >= 4 ? g_f4s + (size_t)(sb - 4) * 524288 : g_f4c + (size_t)sb * 524288);
    g_cent[i] = f[c * 1024 + k];
}

__global__ void __launch_bounds__(1024) k_assign() {
    __shared__ float sc[3][512];
    int sb = blockIdx.x, n = threadIdx.x;
    for (int i = n; i < 1536; i += 1024) ((float*)sc)[i] = g_cent[sb * 1536 + i];
    __syncthreads();
    const float* f = (sb >= 4 ? g_f4s + (size_t)(sb - 4) * 524288 : g_f4c + (size_t)sb * 524288);
    float d0 = 0, d1 = 0, d2 = 0;
    for (int c = 0; c < 512; c++) {
        float v = f[c * 1024 + n];
        float a = v - sc[0][c], b = v - sc[1][c], e = v - sc[2][c];
        d0 += a * a; d1 += b * b; d2 += e * e;
    }
    int a = 0; float best = d0;
    if (d1 < best) { best = d1; a = 1; }
    if (d2 < best) { a = 2; }
    g_asg[sb * 1024 + n] = a;
}

__global__ void __launch_bounds__(512) k_update() {
    __shared__ int sa[1024];
    int sb = blockIdx.x, c = threadIdx.x;
    for (int i = c; i < 1024; i += 512) sa[i] = g_asg[sb * 1024 + i];
    __syncthreads();
    float s0 = 0, s1 = 0, s2 = 0; int c0 = 0, c1 = 0, c2 = 0;
    const float* ft = g_fT + (size_t)sb * 524288;
    for (int n = 0; n < 1024; n++) {
        float v = ft[n * 512 + c];
        int a = sa[n];
        if (a == 0) { s0 += v; c0++; } else if (a == 1) { s1 += v; c1++; } else { s2 += v; c2++; }
    }
    g_cent[sb * 1536 + c]        = s0 / ((float)c0 + 1e-6f);
    g_cent[sb * 1536 + 512 + c]  = s1 / ((float)c1 + 1e-6f);
    g_cent[sb * 1536 + 1024 + c] = s2 / ((float)c2 + 1e-6f);
    if (c < 3) g_cnt[sb * 3 + c] = (float)(c == 0 ? c0 : (c == 1 ? c1 : c2));
}

__global__ void k_aw() {
    int i = blockIdx.x * 256 + threadIdx.x;
    if (i >= 12582912) return;
    int n = i & 1023, c = (i >> 10) & 511, m = i >> 19;
    int k = m % 3, sb = m / 3;
    const float* f = (sb >= 4 ? g_f4s + (size_t)(sb - 4) * 524288 : g_f4c + (size_t)sb * 524288);
    int a = g_asg[sb * 1024 + n];
    g_aw[i] = (a == k) ? f[c * 1024 + n] - g_cent[sb * 1536 + k * 512 + c] : 0.f;
}

__global__ void __launch_bounds__(256) k_covg() {
    __shared__ float sA[16][128], sB[16][128];
    int m = blockIdx.z;
    const float* A = g_aw + (size_t)m * 524288;
    int bi = c_pi[blockIdx.x], bj = c_pj[blockIdx.x];
    int i0 = bi * 128, j0 = bj * 128;
    int tid = threadIdx.x;
    int ar = tid >> 1, ac = (tid & 1) * 8;
    int ty = tid >> 4, tx = tid & 15;
    float acc[8][8];
#pragma unroll
    for (int a = 0; a < 8; a++)
#pragma unroll
        for (int b = 0; b < 8; b++) acc[a][b] = 0.f;
    float4 ra0 = *(const float4*)&A[(size_t)(i0 + ar) * 1024 + ac];
    float4 ra1 = *(const float4*)&A[(size_t)(i0 + ar) * 1024 + ac + 4];
    float4 rb0 = *(const float4*)&A[(size_t)(j0 + ar) * 1024 + ac];
    float4 rb1 = *(const float4*)&A[(size_t)(j0 + ar) * 1024 + ac + 4];
    for (int k0 = 0; k0 < 1024; k0 += 16) {
        sA[ac+0][ar]=ra0.x; sA[ac+1][ar]=ra0.y; sA[ac+2][ar]=ra0.z; sA[ac+3][ar]=ra0.w;
        sA[ac+4][ar]=ra1.x; sA[ac+5][ar]=ra1.y; sA[ac+6][ar]=ra1.z; sA[ac+7][ar]=ra1.w;
        sB[ac+0][ar]=rb0.x; sB[ac+1][ar]=rb0.y; sB[ac+2][ar]=rb0.z; sB[ac+3][ar]=rb0.w;
        sB[ac+4][ar]=rb1.x; sB[ac+5][ar]=rb1.y; sB[ac+6][ar]=rb1.z; sB[ac+7][ar]=rb1.w;
        __syncthreads();
        if (k0 + 16 < 1024) {
            ra0 = *(const float4*)&A[(size_t)(i0 + ar) * 1024 + k0 + 16 + ac];
            ra1 = *(const float4*)&A[(size_t)(i0 + ar) * 1024 + k0 + 16 + ac + 4];
            rb0 = *(const float4*)&A[(size_t)(j0 + ar) * 1024 + k0 + 16 + ac];
            rb1 = *(const float4*)&A[(size_t)(j0 + ar) * 1024 + k0 + 16 + ac + 4];
        }
#pragma unroll
        for (int k = 0; k < 16; k++) {
            float av[8], bv[8];
            *(float4*)av = *(float4*)&sA[k][ty * 8]; *(float4*)(av+4) = *(float4*)&sA[k][ty * 8 + 4];
            *(float4*)bv = *(float4*)&sB[k][tx * 8]; *(float4*)(bv+4) = *(float4*)&sB[k][tx * 8 + 4];
#pragma unroll
            for (int a = 0; a < 8; a++)
#pragma unroll
                for (int b = 0; b < 8; b++) acc[a][b] += av[a] * bv[b];
        }
        __syncthreads();
    }
    float nc = g_cnt[m] + 1e-6f;
    float* C = g_cov + (size_t)m * MS;
#pragma unroll
    for (int a = 0; a < 8; a++)
#pragma unroll
        for (int b = 0; b < 8; b++) {
            int gi = i0 + ty * 8 + a, gj = j0 + tx * 8 + b;
            float v = acc[a][b] / nc + (gi == gj ? 0.1f : 0.f);
            C[gi * 512 + gj] = v;
            if (bi != bj) C[gj * 512 + gi] = v;
        }
}

__global__ void __launch_bounds__(256) k_norm() {
    __shared__ float red[256];
    int m = blockIdx.x;
    const float* A = g_cov + (size_t)m * MS;
    float mx = 0;
    for (int r = threadIdx.x; r < 512; r += 256) {
        float s = 0;
        for (int c = 0; c < 512; c++) s += fabsf(A[r * 512 + c]);
        mx = fmaxf(mx, s);
    }
    red[threadIdx.x] = mx; __syncthreads();
    for (int o = 128; o > 0; o >>= 1) { if (threadIdx.x < o) red[threadIdx.x] = fmaxf(red[threadIdx.x], red[threadIdx.x + o]); __syncthreads(); }
    if (threadIdx.x == 0) g_nrm[m] = red[0];
}

__global__ void k_nsinit() {
    int i = blockIdx.x * 256 + threadIdx.x;
    if (i >= 6291456) return;
    int m = i >> 18;
    g_Y[i] = g_cov[i] / g_nrm[m];
}

// symmetric batched SGEMM 512^3, double-buffered; polymode: C=(15I-10Mp+3AB)/8
__global__ void __launch_bounds__(256) k_gemmsym(
    const float* __restrict__ A, const float* __restrict__ B,
    float* __restrict__ C, const float* __restrict__ Mp, int polymode)
{
    __shared__ float sA[2][16][128], sB[2][16][128];
    int z = blockIdx.z;
    const float* Ab = A + (size_t)z * MS;
    const float* Bb = B + (size_t)z * MS;
    float* Cb = C + (size_t)z * MS;
    const float* Mb = Mp + (size_t)z * MS;
    int bi = c_pi[blockIdx.x], bj = c_pj[blockIdx.x];
    int m0 = bi * 128, n0 = bj * 128;
    int tid = threadIdx.x;
    int ar = tid >> 1, ac = (tid & 1) * 8;
    int br = tid >> 4, bc = (tid & 15) * 8;
    int ty = tid >> 4, tx = tid & 15;
    float acc[8][8];
#pragma unroll
    for (int a = 0; a < 8; a++)
#pragma unroll
        for (int b = 0; b < 8; b++) acc[a][b] = 0.f;
    float4 ra0 = *(const float4*)&Ab[(size_t)(m0 + ar) * 512 + ac];
    float4 ra1 = *(const float4*)&Ab[(size_t)(m0 + ar) * 512 + ac + 4];
    float4 rb0 = *(const float4*)&Bb[(size_t)br * 512 + n0 + bc];
    float4 rb1 = *(const float4*)&Bb[(size_t)br * 512 + n0 + bc + 4];
    sA[0][ac+0][ar]=ra0.x; sA[0][ac+1][ar]=ra0.y; sA[0][ac+2][ar]=ra0.z; sA[0][ac+3][ar]=ra0.w;
    sA[0][ac+4][ar]=ra1.x; sA[0][ac+5][ar]=ra1.y; sA[0][ac+6][ar]=ra1.z; sA[0][ac+7][ar]=ra1.w;
    *(float4*)&sB[0][br][bc] = rb0; *(float4*)&sB[0][br][bc + 4] = rb1;
    __syncthreads();
    for (int s = 0; s < 32; s++) {
        int buf = s & 1;
        if (s < 31) {
            int k0 = (s + 1) * 16;
            ra0 = *(const float4*)&Ab[(size_t)(m0 + ar) * 512 + k0 + ac];
            ra1 = *(const float4*)&Ab[(size_t)(m0 + ar) * 512 + k0 + ac + 4];
            rb0 = *(const float4*)&Bb[(size_t)(k0 + br) * 512 + n0 + bc];
            rb1 = *(const float4*)&Bb[(size_t)(k0 + br) * 512 + n0 + bc + 4];
        }
#pragma unroll
        for (int k = 0; k < 16; k++) {
            float av[8], bv[8];
            *(float4*)av = *(float4*)&sA[buf][k][ty * 8]; *(float4*)(av+4) = *(float4*)&sA[buf][k][ty * 8 + 4];
            *(float4*)bv = *(float4*)&sB[buf][k][tx * 8]; *(float4*)(bv+4) = *(float4*)&sB[buf][k][tx * 8 + 4];
#pragma unroll
            for (int a = 0; a < 8; a++)
#pragma unroll
                for (int b = 0; b < 8; b++) acc[a][b] += av[a] * bv[b];
        }
        if (s < 31) {
            int nb = buf ^ 1;
            sA[nb][ac+0][ar]=ra0.x; sA[nb][ac+1][ar]=ra0.y; sA[nb][ac+2][ar]=ra0.z; sA[nb][ac+3][ar]=ra0.w;
            sA[nb][ac+4][ar]=ra1.x; sA[nb][ac+5][ar]=ra1.y; sA[nb][ac+6][ar]=ra1.z; sA[nb][ac+7][ar]=ra1.w;
            *(float4*)&sB[nb][br][bc] = rb0; *(float4*)&sB[nb][br][bc + 4] = rb1;
            __syncthreads();
        }
    }
#pragma unroll
    for (int a = 0; a < 8; a++) {
        int gi = m0 + ty * 8 + a;
#pragma unroll
        for (int b = 0; b < 8; b++) {
            int gj = n0 + tx * 8 + b;
            float v = acc[a][b];
            if (polymode)
                v = ((gi == gj ? 15.f : 0.f) - 10.f * Mb[(size_t)gi * 512 + gj] + 3.f * v) * 0.125f;
            Cb[(size_t)gi * 512 + gj] = v;
            if (bi != bj) Cb[(size_t)gj * 512 + gi] = v;
        }
    }
}

__global__ void __launch_bounds__(256) k_gemm16(
    const float* __restrict__ A, int strA, const float* __restrict__ B, int strB, int bdiv,
    float* __restrict__ C, int strC, int N, float alpha, int nrmmode)
{
    __shared__ float sA[2][16][128], sB[2][16][128];
    int z = blockIdx.z;
    const float* Ab = A + (size_t)z * strA;
    const float* Bb = B + (size_t)(bdiv ? z / 3 : z) * strB;
    float* Cb = C + (size_t)z * strC;
    if (nrmmode) alpha = sqrtf(g_nrm[12 + z] / g_nrm[z]);
    int m0 = blockIdx.y * 128, n0 = blockIdx.x * 128;
    int tid = threadIdx.x;
    int ar = tid >> 1, ac = (tid & 1) * 8;
    int br = tid >> 4, bc = (tid & 15) * 8;
    int ty = tid >> 4, tx = tid & 15;
    float acc[8][8];
#pragma unroll
    for (int a = 0; a < 8; a++)
#pragma unroll
        for (int b = 0; b < 8; b++) acc[a][b] = 0.f;
    float4 ra0 = *(const float4*)&Ab[(size_t)(m0 + ar) * 512 + ac];
    float4 ra1 = *(const float4*)&Ab[(size_t)(m0 + ar) * 512 + ac + 4];
    float4 rb0 = *(const float4*)&Bb[(size_t)br * N + n0 + bc];
    float4 rb1 = *(const float4*)&Bb[(size_t)br * N + n0 + bc + 4];
    sA[0][ac+0][ar]=ra0.x; sA[0][ac+1][ar]=ra0.y; sA[0][ac+2][ar]=ra0.z; sA[0][ac+3][ar]=ra0.w;
    sA[0][ac+4][ar]=ra1.x; sA[0][ac+5][ar]=ra1.y; sA[0][ac+6][ar]=ra1.z; sA[0][ac+7][ar]=ra1.w;
    *(float4*)&sB[0][br][bc] = rb0; *(float4*)&sB[0][br][bc + 4] = rb1;
    __syncthreads();
    for (int s = 0; s < 32; s++) {
        int buf = s & 1;
        if (s < 31) {
            int k0 = (s + 1) * 16;
            ra0 = *(const float4*)&Ab[(size_t)(m0 + ar) * 512 + k0 + ac];
            ra1 = *(const float4*)&Ab[(size_t)(m0 + ar) * 512 + k0 + ac + 4];
            rb0 = *(const float4*)&Bb[(size_t)(k0 + br) * N + n0 + bc];
            rb1 = *(const float4*)&Bb[(size_t)(k0 + br) * N + n0 + bc + 4];
        }
#pragma unroll
        for (int k = 0; k < 16; k++) {
            float av[8], bv[8];
            *(float4*)av = *(float4*)&sA[buf][k][ty * 8]; *(float4*)(av+4) = *(float4*)&sA[buf][k][ty * 8 + 4];
            *(float4*)bv = *(float4*)&sB[buf][k][tx * 8]; *(float4*)(bv+4) = *(float4*)&sB[buf][k][tx * 8 + 4];
#pragma unroll
            for (int a = 0; a < 8; a++)
#pragma unroll
                for (int b = 0; b < 8; b++) acc[a][b] += av[a] * bv[b];
        }
        if (s < 31) {
            int nb = buf ^ 1;
            sA[nb][ac+0][ar]=ra0.x; sA[nb][ac+1][ar]=ra0.y; sA[nb][ac+2][ar]=ra0.z; sA[nb][ac+3][ar]=ra0.w;
            sA[nb][ac+4][ar]=ra1.x; sA[nb][ac+5][ar]=ra1.y; sA[nb][ac+6][ar]=ra1.z; sA[nb][ac+7][ar]=ra1.w;
            *(float4*)&sB[nb][br][bc] = rb0; *(float4*)&sB[nb][br][bc + 4] = rb1;
            __syncthreads();
        }
    }
#pragma unroll
    for (int a = 0; a < 8; a++) {
        int gm = m0 + ty * 8 + a;
#pragma unroll
        for (int b = 0; b < 8; b++) {
            int gn = n0 + tx * 8 + b;
            Cb[(size_t)gm * N + gn] = alpha * acc[a][b];
        }
    }
}

__global__ void __launch_bounds__(512) k_gemv() {
    __shared__ float mu[512];
    int z = blockIdx.x;
    int b = z / 3, k = z % 3;
    int tid = threadIdx.x;
    mu[tid] = g_cent[b * 1536 + k * 512 + tid];
    __syncthreads();
    const float* T = g_Tm + (size_t)z * MS;
    int warp = tid >> 5, lane = tid & 31;
    for (int c = warp; c < 512; c += 16) {
        float s = 0;
        for (int d = lane; d < 512; d += 32) s += T[c * 512 + d] * mu[d];
#pragma unroll
        for (int o = 16; o > 0; o >>= 1) s += __shfl_down_sync(0xffffffff, s, o);
        if (lane == 0) g_vv[z * 512 + c] = s;
    }
}

__global__ void k_comb(const float* __restrict__ tp) {
    int i = blockIdx.x * 256 + threadIdx.x;
    if (i >= 2097152) return;
    int n = i & 1023, c = (i >> 10) & 511, b = i >> 19;
    int a = g_asg[b * 1024 + n];
    int z = b * 3 + a;
    float val = tp[(size_t)z * 524288 + c * 1024 + n] - g_vv[z * 512 + c]
              + g_cent[(4 + b) * 1536 + a * 512 + c];
    g_f4t[i] = 0.6f * val + 0.4f * g_f4c[i];
}

__global__ void __launch_bounds__(1024) k_closs() {
    __shared__ double red[1024];
    double s = 0;
    for (int i = threadIdx.x; i < 2097152; i += 1024) {
        float d = g_f4e[i] - g_f4c[i]; s += (double)d * d;
    }
    red[threadIdx.x] = s; __syncthreads();
    for (int o = 512; o > 0; o >>= 1) { if (threadIdx.x < o) red[threadIdx.x] += red[threadIdx.x + o]; __syncthreads(); }
    if (threadIdx.x == 0) g_cl[0] = (float)(red[0] / 2097152.0);
}

__global__ void __launch_bounds__(256) k_final(float* out) {
    __shared__ double red[256];
    __shared__ double slv;
    const int off[5] = {0, 256, 768, 1792, 3840};
    if (threadIdx.x == 0) slv = 0;
    __syncthreads();
    for (int l = 0; l < 4; l++) {
        int o0 = off[l], sz = off[l + 1] - off[l];
        double s = 0;
        for (int i = threadIdx.x; i < sz; i += 256) {
            float dm = g_st[2 * 3840 + o0 + i] - g_st[0 * 3840 + o0 + i];
            float ds = g_st[3 * 3840 + o0 + i] - g_st[1 * 3840 + o0 + i];
            s += (double)dm * dm + (double)ds * ds;
        }
        red[threadIdx.x] = s; __syncthreads();
        for (int o = 128; o > 0; o >>= 1) { if (threadIdx.x < o) red[threadIdx.x] += red[threadIdx.x + o]; __syncthreads(); }
        if (threadIdx.x == 0) slv += red[0] / sz;
        __syncthreads();
    }
    if (threadIdx.x == 0) out[0] = g_cl[0] + 0.01f * (float)slv;
}

extern "C" void kernel_launch(void* const* d_in, const int* in_sizes, int n_in,
                              void* d_out, int out_size) {
    (void)in_sizes; (void)n_in; (void)out_size;
    const float* in[18];
    for (int i = 0; i < 18; i++) in[i] = (const float*)d_in[i];

    float *b0, *b1, *f4c, *f4s, *f4t, *f4e, *dec, *Y, *Z, *Tt, *cov, *aw, *Tm, *st;
    cudaGetSymbolAddress((void**)&b0, g_b0);
    cudaGetSymbolAddress((void**)&b1, g_b1);
    cudaGetSymbolAddress((void**)&f4c, g_f4c);
    cudaGetSymbolAddress((void**)&f4s, g_f4s);
    cudaGetSymbolAddress((void**)&f4t, g_f4t);
    cudaGetSymbolAddress((void**)&f4e, g_f4e);
    cudaGetSymbolAddress((void**)&dec, g_dec);
    cudaGetSymbolAddress((void**)&Y, g_Y);
    cudaGetSymbolAddress((void**)&Z, g_Z);
    cudaGetSymbolAddress((void**)&Tt, g_Tt);
    cudaGetSymbolAddress((void**)&cov, g_cov);
    cudaGetSymbolAddress((void**)&aw, g_aw);
    cudaGetSymbolAddress((void**)&Tm, g_Tm);
    cudaGetSymbolAddress((void**)&st, g_st);
    float* aw1 = aw + 6291456;

    auto conv = [&](const float* i0, float* o, const float* w, const float* bb,
                    int Cin, int Cout, int H, int relu) {
        if (Cin >= 64 && Cout >= 64) {
            dim3 g((4 * H * H) / 128, (Cout + 127) / 128, 1);
            k_cgemm<<<g, 256>>>(i0, w, bb, o, Cin, Cout, H, relu);
        } else if (H >= 64) {
            dim3 g((H / 32) * (H / 32), (Cout + 15) / 16, 4);
            k_conv<16><<<g, 256>>>(i0, w, bb, o, Cin, Cout, H, relu);
        } else {
            dim3 g((H / 32) * (H / 32), (Cout + 7) / 8, 4);
            k_conv<8><<<g, 256>>>(i0, w, bb, o, Cin, Cout, H, relu);
        }
    };
    auto pool = [&](const float* i0, float* o, int C, int Ho) {
        int tot = 4 * C * Ho * Ho; k_pool<<<(tot + 255) / 256, 256>>>(i0, o, C, Ho);
    };
    auto up = [&](const float* i0, float* o, int C, int Ho) {
        int tot = 4 * C * Ho * Ho; k_up<<<(tot + 255) / 256, 256>>>(i0, o, C, Ho);
    };
    auto enc = [&](const float* x, float* f4, float* mo, float* so) {
        conv(x, b0, in[2], in[3], 3, 64, 256, 1);
        if (mo) k_stats<<<4 * 64, 256>>>(b0, 65536, mo, so);
        pool(b0, b1, 64, 128);
        conv(b1, b0, in[4], in[5], 64, 128, 128, 1);
        if (mo) k_stats<<<4 * 128, 256>>>(b0, 16384, mo + 256, so + 256);
        pool(b0, b1, 128, 64);
        conv(b1, b0, in[6], in[7], 128, 256, 64, 1);
        if (mo) k_stats<<<4 * 256, 256>>>(b0, 4096, mo + 768, so + 768);
        pool(b0, b1, 256, 32);
        conv(b1, f4, in[8], in[9], 256, 512, 32, 1);
        if (mo) k_stats<<<4 * 512, 256>>>(f4, 1024, mo + 1792, so + 1792);
    };

    enc(in[0], f4c, 0, 0);
    enc(in[1], f4s, st + 0, st + 3840);

    k_transp<<<dim3(8, 16, 32), dim3(32, 8)>>>();
    k_cent0<<<48, 256>>>();
    for (int it = 0; it < 11; it++) {
        k_assign<<<8, 1024>>>();
        k_update<<<8, 512>>>();
    }

    k_aw<<<(12582912 + 255) / 256, 256>>>();
    k_covg<<<dim3(10, 1, 24), 256>>>();
    k_norm<<<24, 256>>>();
    k_nsinit<<<((6291456 + 255) / 256), 256>>>();

    dim3 gs(10, 1, 24);
    k_gemmsym<<<gs, 256>>>(Y, Y, cov, Y, 1);
    k_gemmsym<<<gs, 256>>>(Y, cov, aw, cov, 0);
    float* Yc = aw; float* Zc = cov;
    float* fr[4] = {Y, Z, Tt, aw1};
    for (int it = 0; it < 14; it++) {
        float* M = fr[0]; float* P = fr[1]; float* Yn = fr[2]; float* Zn = fr[3];
        k_gemmsym<<<gs, 256>>>(Zc, Yc, M, Zc, 0);
        k_gemmsym<<<gs, 256>>>(M, M, P, M, 1);
        k_gemmsym<<<gs, 256>>>(Yc, P, Yn, Yc, 0);
        k_gemmsym<<<gs, 256>>>(P, Zc, Zn, P, 0);
        fr[0] = Yc; fr[1] = Zc; fr[2] = M; fr[3] = P;
        Yc = Yn; Zc = Zn;
    }

    k_gemm16<<<dim3(4, 4, 12), 256>>>(Yc + (size_t)12 * MS, MS, Zc, MS, 0,
                                      Tm, MS, 512, 1.f, 1);
    float* tp = fr[0];
    k_gemm16<<<dim3(8, 4, 12), 256>>>(Tm, MS, f4c, 524288, 1, tp, 524288, 1024, 1.f, 0);
    k_gemv<<<12, 512>>>();
    k_comb<<<(2097152 + 255) / 256, 256>>>(tp);

    conv(f4t, b0, in[10], in[11], 512, 256, 32, 1);
    up(b0, b1, 256, 64);
    conv(b1, b0, in[12], in[13], 256, 128, 64, 1);
    up(b0, b1, 128, 128);
    conv(b1, b0, in[14], in[15], 128, 64, 128, 1);
    up(b0, b1, 64, 256);
    conv(b1, dec, in[16], in[17], 64, 3, 256, 0);

    enc(dec, f4e, st + 2 * 3840, st + 3 * 3840);

    k_closs<<<1, 1024>>>();
    k_final<<<1, 256>>>((float*)d_out);
}

// round 11
// speedup vs baseline: 1.7450x; 1.0543x over previous
#include <cuda_runtime.h>
#include <math.h>

#define MS 262144
__device__ float g_b0[16777216];
__device__ float g_b1[16777216];
__device__ float g_f4c[2097152];
__device__ float g_f4s[2097152];
__device__ float g_f4t[2097152];
__device__ float g_f4e[2097152];
__device__ float g_dec[786432];
__device__ float g_fT[4194304];
__device__ float g_cent[12288];
__device__ int   g_asg[8192];
__device__ float g_cnt[24];
__device__ float g_aw[12582912];
__device__ float g_cov[6291456];
__device__ float g_Y[6291456];
__device__ float g_Z[6291456];
__device__ float g_Tt[6291456];
__device__ float g_nrm[24];
__device__ float g_Tm[3145728];
__device__ float g_vv[6144];
__device__ float g_st[15360];
__device__ double g_part[256];

__constant__ int c_pi[10] = {0,0,0,0,1,1,1,2,2,3};
__constant__ int c_pj[10] = {0,1,2,3,1,2,3,2,3,3};

// ---------- implicit-GEMM conv 3x3 SAME (Cin>=64, Cout>=64) ----------
__global__ void __launch_bounds__(256) k_cgemm(
    const float* __restrict__ in, const float* __restrict__ w,
    const float* __restrict__ bias, float* __restrict__ out,
    int Cin, int Cout, int H, int relu)
{
    __shared__ float sA[2][16][128], sB[2][16][128];
    int K = Cin * 9, HH = H * H;
    int m0 = blockIdx.y * 128, n0 = blockIdx.x * 128;
    int tid = threadIdx.x;
    int ar = tid >> 1, ac = (tid & 1) * 8;
    int brk = tid >> 4, bcg = (tid & 15) * 8;
    int ty = tid >> 4, tx = tid & 15;
    int b = n0 / HH, rem0 = n0 - b * HH;
    int cy[8], cx[8];
#pragma unroll
    for (int j = 0; j < 8; j++) {
        int rem = rem0 + bcg + j;
        int yy = rem / H;
        cy[j] = yy; cx[j] = rem - yy * H;
    }
    const float* inb = in + (size_t)b * Cin * HH;
    float acc[8][8];
#pragma unroll
    for (int a = 0; a < 8; a++)
#pragma unroll
        for (int q = 0; q < 8; q++) acc[a][q] = 0.f;
    float ra[8], rb[8];
    int aok = (m0 + ar) < Cout;
    const float* awp = w + (size_t)(aok ? m0 + ar : 0) * K + ac;
    if (aok) { *(float4*)ra = *(const float4*)awp; *(float4*)(ra+4) = *(const float4*)(awp+4); }
    else { for (int i = 0; i < 8; i++) ra[i] = 0.f; }
    {
        int k = brk;
        int ic = k / 9, rs = k - ic * 9;
        int dy = rs / 3 - 1, dx = rs - (rs / 3) * 3 - 1;
        const float* ip = inb + (size_t)ic * HH;
#pragma unroll
        for (int j = 0; j < 8; j++) {
            int yy = cy[j] + dy, xx = cx[j] + dx;
            rb[j] = (yy >= 0 && yy < H && xx >= 0 && xx < H) ? ip[yy * H + xx] : 0.f;
        }
    }
    int nk = K / 16;
#pragma unroll
    for (int i = 0; i < 8; i++) sA[0][ac + i][ar] = ra[i];
#pragma unroll
    for (int j = 0; j < 8; j++) sB[0][brk][bcg + j] = rb[j];
    __syncthreads();
    for (int s = 0; s < nk; s++) {
        int buf = s & 1;
        if (s + 1 < nk) {
            int k0 = (s + 1) * 16;
            if (aok) { *(float4*)ra = *(const float4*)(awp + k0); *(float4*)(ra+4) = *(const float4*)(awp + k0 + 4); }
            int k = k0 + brk;
            int ic = k / 9, rs = k - ic * 9;
            int dy = rs / 3 - 1, dx = rs - (rs / 3) * 3 - 1;
            const float* ip = inb + (size_t)ic * HH;
#pragma unroll
            for (int j = 0; j < 8; j++) {
                int yy = cy[j] + dy, xx = cx[j] + dx;
                rb[j] = (yy >= 0 && yy < H && xx >= 0 && xx < H) ? ip[yy * H + xx] : 0.f;
            }
        }
#pragma unroll
        for (int k = 0; k < 16; k++) {
            float av[8], bv[8];
            *(float4*)av = *(float4*)&sA[buf][k][ty * 8]; *(float4*)(av+4) = *(float4*)&sA[buf][k][ty * 8 + 4];
            *(float4*)bv = *(float4*)&sB[buf][k][tx * 8]; *(float4*)(bv+4) = *(float4*)&sB[buf][k][tx * 8 + 4];
#pragma unroll
            for (int a = 0; a < 8; a++)
#pragma unroll
                for (int q = 0; q < 8; q++) acc[a][q] += av[a] * bv[q];
        }
        if (s + 1 < nk) {
            int nb = buf ^ 1;
#pragma unroll
            for (int i = 0; i < 8; i++) sA[nb][ac + i][ar] = ra[i];
#pragma unroll
            for (int j = 0; j < 8; j++) sB[nb][brk][bcg + j] = rb[j];
            __syncthreads();
        }
    }
#pragma unroll
    for (int a = 0; a < 8; a++) {
        int oc = m0 + ty * 8 + a;
        if (oc >= Cout) break;
        float bv = bias[oc];
        float* op = out + ((size_t)b * Cout + oc) * HH;
#pragma unroll
        for (int q = 0; q < 8; q++) {
            float v = acc[a][q] + bv;
            if (relu) v = fmaxf(v, 0.f);
            op[rem0 + tx * 8 + q] = v;
        }
    }
}

template<int OCB>
__global__ void __launch_bounds__(256) k_conv(const float* __restrict__ in,
    const float* __restrict__ w, const float* __restrict__ bias,
    float* __restrict__ out, int Cin, int Cout, int H, int relu)
{
    __shared__ float sI[34][36];
    __shared__ float sW[OCB][9];
    int tiles = H >> 5;
    int bx = blockIdx.x % tiles, by = blockIdx.x / tiles;
    int x0 = bx * 32, y0 = by * 32;
    int oc0 = blockIdx.y * OCB, b = blockIdx.z;
    int tid = threadIdx.x;
    int lx = (tid & 15) * 2, ly = (tid >> 4) * 2;
    float acc[OCB][4];
#pragma unroll
    for (int o = 0; o < OCB; o++) { acc[o][0]=0.f; acc[o][1]=0.f; acc[o][2]=0.f; acc[o][3]=0.f; }
    const float* ib = in + (size_t)b * Cin * H * H;
    for (int ic = 0; ic < Cin; ic++) {
        __syncthreads();
        const float* ip = ib + (size_t)ic * H * H;
        for (int i = tid; i < 34 * 34; i += 256) {
            int yy = i / 34, xx = i - yy * 34;
            int gy = y0 + yy - 1, gx = x0 + xx - 1;
            sI[yy][xx] = (gy >= 0 && gy < H && gx >= 0 && gx < H) ? ip[gy * H + gx] : 0.f;
        }
        if (tid < OCB * 9) {
            int oc = tid / 9, tt = tid - oc * 9;
            sW[oc][tt] = (oc0 + oc < Cout) ? w[((size_t)(oc0 + oc) * Cin + ic) * 9 + tt] : 0.f;
        }
        __syncthreads();
        float win[4][4];
#pragma unroll
        for (int r = 0; r < 4; r++)
#pragma unroll
            for (int s = 0; s < 4; s++) win[r][s] = sI[ly + r][lx + s];
#pragma unroll
        for (int o = 0; o < OCB; o++) {
            float w0=sW[o][0],w1=sW[o][1],w2=sW[o][2],w3=sW[o][3],w4=sW[o][4];
            float w5=sW[o][5],w6=sW[o][6],w7=sW[o][7],w8=sW[o][8];
#pragma unroll
            for (int p = 0; p < 4; p++) {
                int pr = p >> 1, pc = p & 1;
                acc[o][p] += win[pr][pc]*w0 + win[pr][pc+1]*w1 + win[pr][pc+2]*w2
                           + win[pr+1][pc]*w3 + win[pr+1][pc+1]*w4 + win[pr+1][pc+2]*w5
                           + win[pr+2][pc]*w6 + win[pr+2][pc+1]*w7 + win[pr+2][pc+2]*w8;
            }
        }
    }
#pragma unroll
    for (int o = 0; o < OCB; o++) {
        int oc = oc0 + o;
        if (oc >= Cout) break;
        float bv = bias[oc];
        float* op = out + ((size_t)b * Cout + oc) * H * H;
#pragma unroll
        for (int p = 0; p < 4; p++) {
            float v = acc[o][p] + bv;
            if (relu) v = fmaxf(v, 0.f);
            op[(y0 + ly + (p >> 1)) * H + x0 + lx + (p & 1)] = v;
        }
    }
}

__global__ void k_pool(const float* __restrict__ in, float* __restrict__ out, int C, int Ho) {
    int i = blockIdx.x * 256 + threadIdx.x;
    int tot = 4 * C * Ho * Ho; if (i >= tot) return;
    int x = i % Ho, y = (i / Ho) % Ho; int bc = i / (Ho * Ho);
    int Hi = Ho * 2;
    const float* p = in + (size_t)bc * Hi * Hi;
    out[i] = (p[(2*y)*Hi + 2*x] + p[(2*y)*Hi + 2*x+1] + p[(2*y+1)*Hi + 2*x] + p[(2*y+1)*Hi + 2*x+1]) * 0.25f;
}

__global__ void k_up(const float* __restrict__ in, float* __restrict__ out, int C, int Ho) {
    int i = blockIdx.x * 256 + threadIdx.x;
    int tot = 4 * C * Ho * Ho; if (i >= tot) return;
    int x = i % Ho, y = (i / Ho) % Ho; int bc = i / (Ho * Ho);
    int Hi = Ho >> 1;
    out[i] = in[(size_t)bc * Hi * Hi + (y >> 1) * Hi + (x >> 1)];
}

__global__ void __launch_bounds__(256) k_stats(const float* __restrict__ in, int HW,
                                               float* __restrict__ mo, float* __restrict__ so) {
    __shared__ double red[256];
    int bc = blockIdx.x;
    const float* p = in + (size_t)bc * HW;
    double s = 0;
    for (int i = threadIdx.x; i < HW; i += 256) s += p[i];
    red[threadIdx.x] = s; __syncthreads();
    for (int o = 128; o > 0; o >>= 1) { if (threadIdx.x < o) red[threadIdx.x] += red[threadIdx.x + o]; __syncthreads(); }
    double m = red[0] / HW;
    __syncthreads();
    double v = 0;
    for (int i = threadIdx.x; i < HW; i += 256) { double d = p[i] - m; v += d * d; }
    red[threadIdx.x] = v; __syncthreads();
    for (int o = 128; o > 0; o >>= 1) { if (threadIdx.x < o) red[threadIdx.x] += red[threadIdx.x + o]; __syncthreads(); }
    if (threadIdx.x == 0) { mo[bc] = (float)m; so[bc] = (float)sqrt(red[0] / HW); }
}

__global__ void k_transp() {
    __shared__ float t[32][33];
    int sb = blockIdx.x, c0 = blockIdx.y * 32, n0 = blockIdx.z * 32;
    const float* f = (sb >= 4 ? g_f4s + (size_t)(sb - 4) * 524288 : g_f4c + (size_t)sb * 524288);
    int tx = threadIdx.x, ty = threadIdx.y;
    for (int j = 0; j < 32; j += 8) t[ty + j][tx] = f[(c0 + ty + j) * 1024 + n0 + tx];
    __syncthreads();
    for (int j = 0; j < 32; j += 8) g_fT[(size_t)sb * 524288 + (size_t)(n0 + ty + j) * 512 + c0 + tx] = t[tx][ty + j];
}

// fused k-means: 11 x (assign + update) per block (= per sb), state in smem
__global__ void __launch_bounds__(1024) k_kmeans() {
    __shared__ float sc[3][512];
    __shared__ int sa[1024];
    int sb = blockIdx.x, tid = threadIdx.x;
    const float* f = (sb >= 4 ? g_f4s + (size_t)(sb - 4) * 524288 : g_f4c + (size_t)sb * 524288);
    const float* ft = g_fT + (size_t)sb * 524288;
    if (tid < 512) {
        sc[0][tid] = f[tid * 1024 + 0];
        sc[1][tid] = f[tid * 1024 + 1];
        sc[2][tid] = f[tid * 1024 + 2];
    }
    __syncthreads();
    int n0c = 0, n1c = 0, n2c = 0;
    for (int it = 0; it < 11; it++) {
        {
            int n = tid;
            float d0 = 0, d1 = 0, d2 = 0;
            for (int c = 0; c < 512; c++) {
                float v = f[c * 1024 + n];
                float a = v - sc[0][c], b = v - sc[1][c], e = v - sc[2][c];
                d0 += a * a; d1 += b * b; d2 += e * e;
            }
            int a = 0; float best = d0;
            if (d1 < best) { best = d1; a = 1; }
            if (d2 < best) { a = 2; }
            sa[n] = a;
        }
        __syncthreads();
        if (tid < 512) {
            float s0 = 0, s1 = 0, s2 = 0; int c0 = 0, c1 = 0, c2 = 0;
            for (int n = 0; n < 1024; n++) {
                float v = ft[n * 512 + tid];
                int a = sa[n];
                if (a == 0) { s0 += v; c0++; } else if (a == 1) { s1 += v; c1++; } else { s2 += v; c2++; }
            }
            sc[0][tid] = s0 / ((float)c0 + 1e-6f);
            sc[1][tid] = s1 / ((float)c1 + 1e-6f);
            sc[2][tid] = s2 / ((float)c2 + 1e-6f);
            n0c = c0; n1c = c1; n2c = c2;
        }
        __syncthreads();
    }
    if (tid < 512) {
        g_cent[sb * 1536 + tid] = sc[0][tid];
        g_cent[sb * 1536 + 512 + tid] = sc[1][tid];
        g_cent[sb * 1536 + 1024 + tid] = sc[2][tid];
        if (tid < 3) g_cnt[sb * 3 + tid] = (float)(tid == 0 ? n0c : (tid == 1 ? n1c : n2c));
    }
    g_asg[sb * 1024 + tid] = sa[tid];
}

__global__ void k_aw() {
    int i = blockIdx.x * 256 + threadIdx.x;
    if (i >= 12582912) return;
    int n = i & 1023, c = (i >> 10) & 511, m = i >> 19;
    int k = m % 3, sb = m / 3;
    const float* f = (sb >= 4 ? g_f4s + (size_t)(sb - 4) * 524288 : g_f4c + (size_t)sb * 524288);
    int a = g_asg[sb * 1024 + n];
    g_aw[i] = (a == k) ? f[c * 1024 + n] - g_cent[sb * 1536 + k * 512 + c] : 0.f;
}

__global__ void __launch_bounds__(256) k_covg() {
    __shared__ float sA[16][128], sB[16][128];
    int m = blockIdx.z;
    const float* A = g_aw + (size_t)m * 524288;
    int bi = c_pi[blockIdx.x], bj = c_pj[blockIdx.x];
    int i0 = bi * 128, j0 = bj * 128;
    int tid = threadIdx.x;
    int ar = tid >> 1, ac = (tid & 1) * 8;
    int ty = tid >> 4, tx = tid & 15;
    float acc[8][8];
#pragma unroll
    for (int a = 0; a < 8; a++)
#pragma unroll
        for (int b = 0; b < 8; b++) acc[a][b] = 0.f;
    float4 ra0 = *(const float4*)&A[(size_t)(i0 + ar) * 1024 + ac];
    float4 ra1 = *(const float4*)&A[(size_t)(i0 + ar) * 1024 + ac + 4];
    float4 rb0 = *(const float4*)&A[(size_t)(j0 + ar) * 1024 + ac];
    float4 rb1 = *(const float4*)&A[(size_t)(j0 + ar) * 1024 + ac + 4];
    for (int k0 = 0; k0 < 1024; k0 += 16) {
        sA[ac+0][ar]=ra0.x; sA[ac+1][ar]=ra0.y; sA[ac+2][ar]=ra0.z; sA[ac+3][ar]=ra0.w;
        sA[ac+4][ar]=ra1.x; sA[ac+5][ar]=ra1.y; sA[ac+6][ar]=ra1.z; sA[ac+7][ar]=ra1.w;
        sB[ac+0][ar]=rb0.x; sB[ac+1][ar]=rb0.y; sB[ac+2][ar]=rb0.z; sB[ac+3][ar]=rb0.w;
        sB[ac+4][ar]=rb1.x; sB[ac+5][ar]=rb1.y; sB[ac+6][ar]=rb1.z; sB[ac+7][ar]=rb1.w;
        __syncthreads();
        if (k0 + 16 < 1024) {
            ra0 = *(const float4*)&A[(size_t)(i0 + ar) * 1024 + k0 + 16 + ac];
            ra1 = *(const float4*)&A[(size_t)(i0 + ar) * 1024 + k0 + 16 + ac + 4];
            rb0 = *(const float4*)&A[(size_t)(j0 + ar) * 1024 + k0 + 16 + ac];
            rb1 = *(const float4*)&A[(size_t)(j0 + ar) * 1024 + k0 + 16 + ac + 4];
        }
#pragma unroll
        for (int k = 0; k < 16; k++) {
            float av[8], bv[8];
            *(float4*)av = *(float4*)&sA[k][ty * 8]; *(float4*)(av+4) = *(float4*)&sA[k][ty * 8 + 4];
            *(float4*)bv = *(float4*)&sB[k][tx * 8]; *(float4*)(bv+4) = *(float4*)&sB[k][tx * 8 + 4];
#pragma unroll
            for (int a = 0; a < 8; a++)
#pragma unroll
                for (int b = 0; b < 8; b++) acc[a][b] += av[a] * bv[b];
        }
        __syncthreads();
    }
    float nc = g_cnt[m] + 1e-6f;
    float* C = g_cov + (size_t)m * MS;
#pragma unroll
    for (int a = 0; a < 8; a++)
#pragma unroll
        for (int b = 0; b < 8; b++) {
            int gi = i0 + ty * 8 + a, gj = j0 + tx * 8 + b;
            float v = acc[a][b] / nc + (gi == gj ? 0.1f : 0.f);
            C[gi * 512 + gj] = v;
            if (bi != bj) C[gj * 512 + gi] = v;
        }
}

__global__ void __launch_bounds__(256) k_norm() {
    __shared__ float red[256];
    int m = blockIdx.x;
    const float* A = g_cov + (size_t)m * MS;
    float mx = 0;
    for (int r = threadIdx.x; r < 512; r += 256) {
        float s = 0;
        for (int c = 0; c < 512; c++) s += fabsf(A[r * 512 + c]);
        mx = fmaxf(mx, s);
    }
    red[threadIdx.x] = mx; __syncthreads();
    for (int o = 128; o > 0; o >>= 1) { if (threadIdx.x < o) red[threadIdx.x] = fmaxf(red[threadIdx.x], red[threadIdx.x + o]); __syncthreads(); }
    if (threadIdx.x == 0) g_nrm[m] = red[0];
}

__global__ void k_nsinit() {
    int i = blockIdx.x * 256 + threadIdx.x;
    if (i >= 6291456) return;
    int m = i >> 18;
    g_Y[i] = g_cov[i] / g_nrm[m];
}

// symmetric batched SGEMM 512^3, double-buffered; polymode: C=(15I-10Mp+3AB)/8
__global__ void __launch_bounds__(256) k_gemmsym(
    const float* __restrict__ A, const float* __restrict__ B,
    float* __restrict__ C, const float* __restrict__ Mp, int polymode)
{
    __shared__ float sA[2][16][128], sB[2][16][128];
    int z = blockIdx.z;
    const float* Ab = A + (size_t)z * MS;
    const float* Bb = B + (size_t)z * MS;
    float* Cb = C + (size_t)z * MS;
    const float* Mb = Mp + (size_t)z * MS;
    int bi = c_pi[blockIdx.x], bj = c_pj[blockIdx.x];
    int m0 = bi * 128, n0 = bj * 128;
    int tid = threadIdx.x;
    int ar = tid >> 1, ac = (tid & 1) * 8;
    int br = tid >> 4, bc = (tid & 15) * 8;
    int ty = tid >> 4, tx = tid & 15;
    float acc[8][8];
#pragma unroll
    for (int a = 0; a < 8; a++)
#pragma unroll
        for (int b = 0; b < 8; b++) acc[a][b] = 0.f;
    float4 ra0 = *(const float4*)&Ab[(size_t)(m0 + ar) * 512 + ac];
    float4 ra1 = *(const float4*)&Ab[(size_t)(m0 + ar) * 512 + ac + 4];
    float4 rb0 = *(const float4*)&Bb[(size_t)br * 512 + n0 + bc];
    float4 rb1 = *(const float4*)&Bb[(size_t)br * 512 + n0 + bc + 4];
    sA[0][ac+0][ar]=ra0.x; sA[0][ac+1][ar]=ra0.y; sA[0][ac+2][ar]=ra0.z; sA[0][ac+3][ar]=ra0.w;
    sA[0][ac+4][ar]=ra1.x; sA[0][ac+5][ar]=ra1.y; sA[0][ac+6][ar]=ra1.z; sA[0][ac+7][ar]=ra1.w;
    *(float4*)&sB[0][br][bc] = rb0; *(float4*)&sB[0][br][bc + 4] = rb1;
    __syncthreads();
    for (int s = 0; s < 32; s++) {
        int buf = s & 1;
        if (s < 31) {
            int k0 = (s + 1) * 16;
            ra0 = *(const float4*)&Ab[(size_t)(m0 + ar) * 512 + k0 + ac];
            ra1 = *(const float4*)&Ab[(size_t)(m0 + ar) * 512 + k0 + ac + 4];
            rb0 = *(const float4*)&Bb[(size_t)(k0 + br) * 512 + n0 + bc];
            rb1 = *(const float4*)&Bb[(size_t)(k0 + br) * 512 + n0 + bc + 4];
        }
#pragma unroll
        for (int k = 0; k < 16; k++) {
            float av[8], bv[8];
            *(float4*)av = *(float4*)&sA[buf][k][ty * 8]; *(float4*)(av+4) = *(float4*)&sA[buf][k][ty * 8 + 4];
            *(float4*)bv = *(float4*)&sB[buf][k][tx * 8]; *(float4*)(bv+4) = *(float4*)&sB[buf][k][tx * 8 + 4];
#pragma unroll
            for (int a = 0; a < 8; a++)
#pragma unroll
                for (int b = 0; b < 8; b++) acc[a][b] += av[a] * bv[b];
        }
        if (s < 31) {
            int nb = buf ^ 1;
            sA[nb][ac+0][ar]=ra0.x; sA[nb][ac+1][ar]=ra0.y; sA[nb][ac+2][ar]=ra0.z; sA[nb][ac+3][ar]=ra0.w;
            sA[nb][ac+4][ar]=ra1.x; sA[nb][ac+5][ar]=ra1.y; sA[nb][ac+6][ar]=ra1.z; sA[nb][ac+7][ar]=ra1.w;
            *(float4*)&sB[nb][br][bc] = rb0; *(float4*)&sB[nb][br][bc + 4] = rb1;
            __syncthreads();
        }
    }
#pragma unroll
    for (int a = 0; a < 8; a++) {
        int gi = m0 + ty * 8 + a;
#pragma unroll
        for (int b = 0; b < 8; b++) {
            int gj = n0 + tx * 8 + b;
            float v = acc[a][b];
            if (polymode)
                v = ((gi == gj ? 15.f : 0.f) - 10.f * Mb[(size_t)gi * 512 + gj] + 3.f * v) * 0.125f;
            Cb[(size_t)gi * 512 + gj] = v;
            if (bi != bj) Cb[(size_t)gj * 512 + gi] = v;
        }
    }
}

__global__ void __launch_bounds__(256) k_gemm16(
    const float* __restrict__ A, int strA, const float* __restrict__ B, int strB, int bdiv,
    float* __restrict__ C, int strC, int N, float alpha, int nrmmode)
{
    __shared__ float sA[2][16][128], sB[2][16][128];
    int z = blockIdx.z;
    const float* Ab = A + (size_t)z * strA;
    const float* Bb = B + (size_t)(bdiv ? z / 3 : z) * strB;
    float* Cb = C + (size_t)z * strC;
    if (nrmmode) alpha = sqrtf(g_nrm[12 + z] / g_nrm[z]);
    int m0 = blockIdx.y * 128, n0 = blockIdx.x * 128;
    int tid = threadIdx.x;
    int ar = tid >> 1, ac = (tid & 1) * 8;
    int br = tid >> 4, bc = (tid & 15) * 8;
    int ty = tid >> 4, tx = tid & 15;
    float acc[8][8];
#pragma unroll
    for (int a = 0; a < 8; a++)
#pragma unroll
        for (int b = 0; b < 8; b++) acc[a][b] = 0.f;
    float4 ra0 = *(const float4*)&Ab[(size_t)(m0 + ar) * 512 + ac];
    float4 ra1 = *(const float4*)&Ab[(size_t)(m0 + ar) * 512 + ac + 4];
    float4 rb0 = *(const float4*)&Bb[(size_t)br * N + n0 + bc];
    float4 rb1 = *(const float4*)&Bb[(size_t)br * N + n0 + bc + 4];
    sA[0][ac+0][ar]=ra0.x; sA[0][ac+1][ar]=ra0.y; sA[0][ac+2][ar]=ra0.z; sA[0][ac+3][ar]=ra0.w;
    sA[0][ac+4][ar]=ra1.x; sA[0][ac+5][ar]=ra1.y; sA[0][ac+6][ar]=ra1.z; sA[0][ac+7][ar]=ra1.w;
    *(float4*)&sB[0][br][bc] = rb0; *(float4*)&sB[0][br][bc + 4] = rb1;
    __syncthreads();
    for (int s = 0; s < 32; s++) {
        int buf = s & 1;
        if (s < 31) {
            int k0 = (s + 1) * 16;
            ra0 = *(const float4*)&Ab[(size_t)(m0 + ar) * 512 + k0 + ac];
            ra1 = *(const float4*)&Ab[(size_t)(m0 + ar) * 512 + k0 + ac + 4];
            rb0 = *(const float4*)&Bb[(size_t)(k0 + br) * N + n0 + bc];
            rb1 = *(const float4*)&Bb[(size_t)(k0 + br) * N + n0 + bc + 4];
        }
#pragma unroll
        for (int k = 0; k < 16; k++) {
            float av[8], bv[8];
            *(float4*)av = *(float4*)&sA[buf][k][ty * 8]; *(float4*)(av+4) = *(float4*)&sA[buf][k][ty * 8 + 4];
            *(float4*)bv = *(float4*)&sB[buf][k][tx * 8]; *(float4*)(bv+4) = *(float4*)&sB[buf][k][tx * 8 + 4];
#pragma unroll
            for (int a = 0; a < 8; a++)
#pragma unroll
                for (int b = 0; b < 8; b++) acc[a][b] += av[a] * bv[b];
        }
        if (s < 31) {
            int nb = buf ^ 1;
            sA[nb][ac+0][ar]=ra0.x; sA[nb][ac+1][ar]=ra0.y; sA[nb][ac+2][ar]=ra0.z; sA[nb][ac+3][ar]=ra0.w;
            sA[nb][ac+4][ar]=ra1.x; sA[nb][ac+5][ar]=ra1.y; sA[nb][ac+6][ar]=ra1.z; sA[nb][ac+7][ar]=ra1.w;
            *(float4*)&sB[nb][br][bc] = rb0; *(float4*)&sB[nb][br][bc + 4] = rb1;
            __syncthreads();
        }
    }
#pragma unroll
    for (int a = 0; a < 8; a++) {
        int gm = m0 + ty * 8 + a;
#pragma unroll
        for (int b = 0; b < 8; b++) {
            int gn = n0 + tx * 8 + b;
            Cb[(size_t)gm * N + gn] = alpha * acc[a][b];
        }
    }
}

__global__ void __launch_bounds__(512) k_gemv() {
    __shared__ float mu[512];
    int z = blockIdx.x;
    int b = z / 3, k = z % 3;
    int tid = threadIdx.x;
    mu[tid] = g_cent[b * 1536 + k * 512 + tid];
    __syncthreads();
    const float* T = g_Tm + (size_t)z * MS;
    int warp = tid >> 5, lane = tid & 31;
    for (int c = warp; c < 512; c += 16) {
        float s = 0;
        for (int d = lane; d < 512; d += 32) s += T[c * 512 + d] * mu[d];
#pragma unroll
        for (int o = 16; o > 0; o >>= 1) s += __shfl_down_sync(0xffffffff, s, o);
        if (lane == 0) g_vv[z * 512 + c] = s;
    }
}

__global__ void k_comb(const float* __restrict__ tp) {
    int i = blockIdx.x * 256 + threadIdx.x;
    if (i >= 2097152) return;
    int n = i & 1023, c = (i >> 10) & 511, b = i >> 19;
    int a = g_asg[b * 1024 + n];
    int z = b * 3 + a;
    float val = tp[(size_t)z * 524288 + c * 1024 + n] - g_vv[z * 512 + c]
              + g_cent[(4 + b) * 1536 + a * 512 + c];
    g_f4t[i] = 0.6f * val + 0.4f * g_f4c[i];
}

// stage-1 content loss: 256 blocks x 8192 elements
__global__ void __launch_bounds__(256) k_closs1() {
    __shared__ double red[256];
    int start = blockIdx.x * 8192;
    double s = 0;
    for (int i = threadIdx.x; i < 8192; i += 256) {
        float d = g_f4e[start + i] - g_f4c[start + i];
        s += (double)d * d;
    }
    red[threadIdx.x] = s; __syncthreads();
    for (int o = 128; o > 0; o >>= 1) { if (threadIdx.x < o) red[threadIdx.x] += red[threadIdx.x + o]; __syncthreads(); }
    if (threadIdx.x == 0) g_part[blockIdx.x] = red[0];
}

__global__ void __launch_bounds__(256) k_final(float* out) {
    __shared__ double red[256];
    __shared__ double slv;
    __shared__ double closs;
    const int off[5] = {0, 256, 768, 1792, 3840};
    if (threadIdx.x == 0) slv = 0;
    red[threadIdx.x] = g_part[threadIdx.x];
    __syncthreads();
    for (int o = 128; o > 0; o >>= 1) { if (threadIdx.x < o) red[threadIdx.x] += red[threadIdx.x + o]; __syncthreads(); }
    if (threadIdx.x == 0) closs = red[0] / 2097152.0;
    __syncthreads();
    for (int l = 0; l < 4; l++) {
        int o0 = off[l], sz = off[l + 1] - off[l];
        double s = 0;
        for (int i = threadIdx.x; i < sz; i += 256) {
            float dm = g_st[2 * 3840 + o0 + i] - g_st[0 * 3840 + o0 + i];
            float ds = g_st[3 * 3840 + o0 + i] - g_st[1 * 3840 + o0 + i];
            s += (double)dm * dm + (double)ds * ds;
        }
        red[threadIdx.x] = s; __syncthreads();
        for (int o = 128; o > 0; o >>= 1) { if (threadIdx.x < o) red[threadIdx.x] += red[threadIdx.x + o]; __syncthreads(); }
        if (threadIdx.x == 0) slv += red[0] / sz;
        __syncthreads();
    }
    if (threadIdx.x == 0) out[0] = (float)closs + 0.01f * (float)slv;
}

extern "C" void kernel_launch(void* const* d_in, const int* in_sizes, int n_in,
                              void* d_out, int out_size) {
    (void)in_sizes; (void)n_in; (void)out_size;
    const float* in[18];
    for (int i = 0; i < 18; i++) in[i] = (const float*)d_in[i];

    float *b0, *b1, *f4c, *f4s, *f4t, *f4e, *dec, *Y, *Z, *Tt, *cov, *aw, *Tm, *st;
    cudaGetSymbolAddress((void**)&b0, g_b0);
    cudaGetSymbolAddress((void**)&b1, g_b1);
    cudaGetSymbolAddress((void**)&f4c, g_f4c);
    cudaGetSymbolAddress((void**)&f4s, g_f4s);
    cudaGetSymbolAddress((void**)&f4t, g_f4t);
    cudaGetSymbolAddress((void**)&f4e, g_f4e);
    cudaGetSymbolAddress((void**)&dec, g_dec);
    cudaGetSymbolAddress((void**)&Y, g_Y);
    cudaGetSymbolAddress((void**)&Z, g_Z);
    cudaGetSymbolAddress((void**)&Tt, g_Tt);
    cudaGetSymbolAddress((void**)&cov, g_cov);
    cudaGetSymbolAddress((void**)&aw, g_aw);
    cudaGetSymbolAddress((void**)&Tm, g_Tm);
    cudaGetSymbolAddress((void**)&st, g_st);
    float* aw1 = aw + 6291456;

    auto conv = [&](const float* i0, float* o, const float* w, const float* bb,
                    int Cin, int Cout, int H, int relu) {
        if (Cin >= 64 && Cout >= 64) {
            dim3 g((4 * H * H) / 128, (Cout + 127) / 128, 1);
            k_cgemm<<<g, 256>>>(i0, w, bb, o, Cin, Cout, H, relu);
        } else if (H >= 64) {
            dim3 g((H / 32) * (H / 32), (Cout + 15) / 16, 4);
            k_conv<16><<<g, 256>>>(i0, w, bb, o, Cin, Cout, H, relu);
        } else {
            dim3 g((H / 32) * (H / 32), (Cout + 7) / 8, 4);
            k_conv<8><<<g, 256>>>(i0, w, bb, o, Cin, Cout, H, relu);
        }
    };
    auto pool = [&](const float* i0, float* o, int C, int Ho) {
        int tot = 4 * C * Ho * Ho; k_pool<<<(tot + 255) / 256, 256>>>(i0, o, C, Ho);
    };
    auto up = [&](const float* i0, float* o, int C, int Ho) {
        int tot = 4 * C * Ho * Ho; k_up<<<(tot + 255) / 256, 256>>>(i0, o, C, Ho);
    };
    auto enc = [&](const float* x, float* f4, float* mo, float* so) {
        conv(x, b0, in[2], in[3], 3, 64, 256, 1);
        if (mo) k_stats<<<4 * 64, 256>>>(b0, 65536, mo, so);
        pool(b0, b1, 64, 128);
        conv(b1, b0, in[4], in[5], 64, 128, 128, 1);
        if (mo) k_stats<<<4 * 128, 256>>>(b0, 16384, mo + 256, so + 256);
        pool(b0, b1, 128, 64);
        conv(b1, b0, in[6], in[7], 128, 256, 64, 1);
        if (mo) k_stats<<<4 * 256, 256>>>(b0, 4096, mo + 768, so + 768);
        pool(b0, b1, 256, 32);
        conv(b1, f4, in[8], in[9], 256, 512, 32, 1);
        if (mo) k_stats<<<4 * 512, 256>>>(f4, 1024, mo + 1792, so + 1792);
    };

    enc(in[0], f4c, 0, 0);
    enc(in[1], f4s, st + 0, st + 3840);

    k_transp<<<dim3(8, 16, 32), dim3(32, 8)>>>();
    k_kmeans<<<8, 1024>>>();

    k_aw<<<(12582912 + 255) / 256, 256>>>();
    k_covg<<<dim3(10, 1, 24), 256>>>();
    k_norm<<<24, 256>>>();
    k_nsinit<<<((6291456 + 255) / 256), 256>>>();

    dim3 gs(10, 1, 24);
    k_gemmsym<<<gs, 256>>>(Y, Y, cov, Y, 1);
    k_gemmsym<<<gs, 256>>>(Y, cov, aw, cov, 0);
    float* Yc = aw; float* Zc = cov;
    float* fr[4] = {Y, Z, Tt, aw1};
    for (int it = 0; it < 14; it++) {
        float* M = fr[0]; float* P = fr[1]; float* Yn = fr[2]; float* Zn = fr[3];
        k_gemmsym<<<gs, 256>>>(Zc, Yc, M, Zc, 0);
        k_gemmsym<<<gs, 256>>>(M, M, P, M, 1);
        k_gemmsym<<<gs, 256>>>(Yc, P, Yn, Yc, 0);
        k_gemmsym<<<gs, 256>>>(P, Zc, Zn, P, 0);
        fr[0] = Yc; fr[1] = Zc; fr[2] = M; fr[3] = P;
        Yc = Yn; Zc = Zn;
    }

    k_gemm16<<<dim3(4, 4, 12), 256>>>(Yc + (size_t)12 * MS, MS, Zc, MS, 0,
                                      Tm, MS, 512, 1.f, 1);
    float* tp = fr[0];
    k_gemm16<<<dim3(8, 4, 12), 256>>>(Tm, MS, f4c, 524288, 1, tp, 524288, 1024, 1.f, 0);
    k_gemv<<<12, 512>>>();
    k_comb<<<(2097152 + 255) / 256, 256>>>(tp);

    conv(f4t, b0, in[10], in[11], 512, 256, 32, 1);
    up(b0, b1, 256, 64);
    conv(b1, b0, in[12], in[13], 256, 128, 64, 1);
    up(b0, b1, 128, 128);
    conv(b1, b0, in[14], in[15], 128, 64, 128, 1);
    up(b0, b1, 64, 256);
    conv(b1, dec, in[16], in[17], 64, 3, 256, 0);

    enc(dec, f4e, st + 2 * 3840, st + 3 * 3840);

    k_closs1<<<256, 256>>>();
    k_final<<<1, 256>>>((float*)d_out);
}

// round 12
// speedup vs baseline: 1.7778x; 1.0188x over previous
#include <cuda_runtime.h>
#include <math.h>

#define MS 262144
__device__ float g_b0[33554432];
__device__ float g_b1[33554432];
__device__ float g_in8[1572864];
__device__ float g_f4[4194304];      // [8][512][1024] content 0-3, style 4-7
__device__ float g_f4t[2097152];
__device__ float g_f4e[2097152];
__device__ float g_dec[786432];
__device__ float g_fT[4194304];
__device__ float g_cent[12288];
__device__ int   g_asg[8192];
__device__ float g_cnt[24];
__device__ float g_aw[12582912];
__device__ float g_cov[6291456];
__device__ float g_Y[6291456];
__device__ float g_Z[6291456];
__device__ float g_Tt[6291456];
__device__ float g_nrm[24];
__device__ float g_Tm[3145728];
__device__ float g_vv[6144];
__device__ float g_st[15360];
__device__ double g_part[256];

__constant__ int c_pi[10] = {0,0,0,0,1,1,1,2,2,3};
__constant__ int c_pj[10] = {0,1,2,3,1,2,3,2,3,3};

__global__ void k_dummy() { g_part[threadIdx.x] = 0.0; }

// ---------- implicit-GEMM conv 3x3 SAME ----------
__global__ void __launch_bounds__(256) k_cgemm(
    const float* __restrict__ in, const float* __restrict__ w,
    const float* __restrict__ bias, float* __restrict__ out,
    int Cin, int Cout, int H, int relu)
{
    __shared__ float sA[2][16][128], sB[2][16][128];
    int K = Cin * 9, HH = H * H;
    int m0 = blockIdx.y * 128, n0 = blockIdx.x * 128;
    int tid = threadIdx.x;
    int ar = tid >> 1, ac = (tid & 1) * 8;
    int brk = tid >> 4, bcg = (tid & 15) * 8;
    int ty = tid >> 4, tx = tid & 15;
    int b = n0 / HH, rem0 = n0 - b * HH;
    int cy[8], cx[8];
#pragma unroll
    for (int j = 0; j < 8; j++) {
        int rem = rem0 + bcg + j;
        int yy = rem / H;
        cy[j] = yy; cx[j] = rem - yy * H;
    }
    const float* inb = in + (size_t)b * Cin * HH;
    float acc[8][8];
#pragma unroll
    for (int a = 0; a < 8; a++)
#pragma unroll
        for (int q = 0; q < 8; q++) acc[a][q] = 0.f;
    float ra[8], rb[8];
    int aok = (m0 + ar) < Cout;
    const float* awp = w + (size_t)(aok ? m0 + ar : 0) * K + ac;
    if (aok) { *(float4*)ra = *(const float4*)awp; *(float4*)(ra+4) = *(const float4*)(awp+4); }
    else { for (int i = 0; i < 8; i++) ra[i] = 0.f; }
    {
        int k = brk;
        int ic = k / 9, rs = k - ic * 9;
        int dy = rs / 3 - 1, dx = rs - (rs / 3) * 3 - 1;
        const float* ip = inb + (size_t)ic * HH;
#pragma unroll
        for (int j = 0; j < 8; j++) {
            int yy = cy[j] + dy, xx = cx[j] + dx;
            rb[j] = (yy >= 0 && yy < H && xx >= 0 && xx < H) ? ip[yy * H + xx] : 0.f;
        }
    }
    int nk = K / 16;
#pragma unroll
    for (int i = 0; i < 8; i++) sA[0][ac + i][ar] = ra[i];
#pragma unroll
    for (int j = 0; j < 8; j++) sB[0][brk][bcg + j] = rb[j];
    __syncthreads();
    for (int s = 0; s < nk; s++) {
        int buf = s & 1;
        if (s + 1 < nk) {
            int k0 = (s + 1) * 16;
            if (aok) { *(float4*)ra = *(const float4*)(awp + k0); *(float4*)(ra+4) = *(const float4*)(awp + k0 + 4); }
            int k = k0 + brk;
            int ic = k / 9, rs = k - ic * 9;
            int dy = rs / 3 - 1, dx = rs - (rs / 3) * 3 - 1;
            const float* ip = inb + (size_t)ic * HH;
#pragma unroll
            for (int j = 0; j < 8; j++) {
                int yy = cy[j] + dy, xx = cx[j] + dx;
                rb[j] = (yy >= 0 && yy < H && xx >= 0 && xx < H) ? ip[yy * H + xx] : 0.f;
            }
        }
#pragma unroll
        for (int k = 0; k < 16; k++) {
            float av[8], bv[8];
            *(float4*)av = *(float4*)&sA[buf][k][ty * 8]; *(float4*)(av+4) = *(float4*)&sA[buf][k][ty * 8 + 4];
            *(float4*)bv = *(float4*)&sB[buf][k][tx * 8]; *(float4*)(bv+4) = *(float4*)&sB[buf][k][tx * 8 + 4];
#pragma unroll
            for (int a = 0; a < 8; a++)
#pragma unroll
                for (int q = 0; q < 8; q++) acc[a][q] += av[a] * bv[q];
        }
        if (s + 1 < nk) {
            int nb = buf ^ 1;
#pragma unroll
            for (int i = 0; i < 8; i++) sA[nb][ac + i][ar] = ra[i];
#pragma unroll
            for (int j = 0; j < 8; j++) sB[nb][brk][bcg + j] = rb[j];
            __syncthreads();
        }
    }
#pragma unroll
    for (int a = 0; a < 8; a++) {
        int oc = m0 + ty * 8 + a;
        if (oc >= Cout) break;
        float bv = bias[oc];
        float* op = out + ((size_t)b * Cout + oc) * HH;
#pragma unroll
        for (int q = 0; q < 8; q++) {
            float v = acc[a][q] + bv;
            if (relu) v = fmaxf(v, 0.f);
            op[rem0 + tx * 8 + q] = v;
        }
    }
}

template<int OCB>
__global__ void __launch_bounds__(256) k_conv(const float* __restrict__ in,
    const float* __restrict__ w, const float* __restrict__ bias,
    float* __restrict__ out, int Cin, int Cout, int H, int relu)
{
    __shared__ float sI[34][36];
    __shared__ float sW[OCB][9];
    int tiles = H >> 5;
    int bx = blockIdx.x % tiles, by = blockIdx.x / tiles;
    int x0 = bx * 32, y0 = by * 32;
    int oc0 = blockIdx.y * OCB, b = blockIdx.z;
    int tid = threadIdx.x;
    int lx = (tid & 15) * 2, ly = (tid >> 4) * 2;
    float acc[OCB][4];
#pragma unroll
    for (int o = 0; o < OCB; o++) { acc[o][0]=0.f; acc[o][1]=0.f; acc[o][2]=0.f; acc[o][3]=0.f; }
    const float* ib = in + (size_t)b * Cin * H * H;
    for (int ic = 0; ic < Cin; ic++) {
        __syncthreads();
        const float* ip = ib + (size_t)ic * H * H;
        for (int i = tid; i < 34 * 34; i += 256) {
            int yy = i / 34, xx = i - yy * 34;
            int gy = y0 + yy - 1, gx = x0 + xx - 1;
            sI[yy][xx] = (gy >= 0 && gy < H && gx >= 0 && gx < H) ? ip[gy * H + gx] : 0.f;
        }
        if (tid < OCB * 9) {
            int oc = tid / 9, tt = tid - oc * 9;
            sW[oc][tt] = (oc0 + oc < Cout) ? w[((size_t)(oc0 + oc) * Cin + ic) * 9 + tt] : 0.f;
        }
        __syncthreads();
        float win[4][4];
#pragma unroll
        for (int r = 0; r < 4; r++)
#pragma unroll
            for (int s = 0; s < 4; s++) win[r][s] = sI[ly + r][lx + s];
#pragma unroll
        for (int o = 0; o < OCB; o++) {
            float w0=sW[o][0],w1=sW[o][1],w2=sW[o][2],w3=sW[o][3],w4=sW[o][4];
            float w5=sW[o][5],w6=sW[o][6],w7=sW[o][7],w8=sW[o][8];
#pragma unroll
            for (int p = 0; p < 4; p++) {
                int pr = p >> 1, pc = p & 1;
                acc[o][p] += win[pr][pc]*w0 + win[pr][pc+1]*w1 + win[pr][pc+2]*w2
                           + win[pr+1][pc]*w3 + win[pr+1][pc+1]*w4 + win[pr+1][pc+2]*w5
                           + win[pr+2][pc]*w6 + win[pr+2][pc+1]*w7 + win[pr+2][pc+2]*w8;
            }
        }
    }
#pragma unroll
    for (int o = 0; o < OCB; o++) {
        int oc = oc0 + o;
        if (oc >= Cout) break;
        float bv = bias[oc];
        float* op = out + ((size_t)b * Cout + oc) * H * H;
#pragma unroll
        for (int p = 0; p < 4; p++) {
            float v = acc[o][p] + bv;
            if (relu) v = fmaxf(v, 0.f);
            op[(y0 + ly + (p >> 1)) * H + x0 + lx + (p & 1)] = v;
        }
    }
}

template<int HO>
__global__ void k_pool(const float* __restrict__ in, float* __restrict__ out, int tot) {
    int i = blockIdx.x * 256 + threadIdx.x;
    if (i >= tot) return;
    int x = i % HO, y = (i / HO) % HO; int bc = i / (HO * HO);
    const int Hi = HO * 2;
    const float* p = in + (size_t)bc * Hi * Hi;
    out[i] = (p[(2*y)*Hi + 2*x] + p[(2*y)*Hi + 2*x+1] + p[(2*y+1)*Hi + 2*x] + p[(2*y+1)*Hi + 2*x+1]) * 0.25f;
}

template<int HO>
__global__ void k_up(const float* __restrict__ in, float* __restrict__ out, int tot) {
    int i = blockIdx.x * 256 + threadIdx.x;
    if (i >= tot) return;
    int x = i % HO, y = (i / HO) % HO; int bc = i / (HO * HO);
    const int Hi = HO >> 1;
    out[i] = in[(size_t)bc * Hi * Hi + (y >> 1) * Hi + (x >> 1)];
}

__global__ void __launch_bounds__(256) k_stats(const float* __restrict__ in, int HW,
                                               float* __restrict__ mo, float* __restrict__ so) {
    __shared__ double red[256];
    int bc = blockIdx.x;
    const float* p = in + (size_t)bc * HW;
    double s = 0;
    for (int i = threadIdx.x; i < HW; i += 256) s += p[i];
    red[threadIdx.x] = s; __syncthreads();
    for (int o = 128; o > 0; o >>= 1) { if (threadIdx.x < o) red[threadIdx.x] += red[threadIdx.x + o]; __syncthreads(); }
    double m = red[0] / HW;
    __syncthreads();
    double v = 0;
    for (int i = threadIdx.x; i < HW; i += 256) { double d = p[i] - m; v += d * d; }
    red[threadIdx.x] = v; __syncthreads();
    for (int o = 128; o > 0; o >>= 1) { if (threadIdx.x < o) red[threadIdx.x] += red[threadIdx.x + o]; __syncthreads(); }
    if (threadIdx.x == 0) { mo[bc] = (float)m; so[bc] = (float)sqrt(red[0] / HW); }
}

__global__ void k_transp() {
    __shared__ float t[32][33];
    int sb = blockIdx.x, c0 = blockIdx.y * 32, n0 = blockIdx.z * 32;
    const float* f = g_f4 + (size_t)sb * 524288;
    int tx = threadIdx.x, ty = threadIdx.y;
    for (int j = 0; j < 32; j += 8) t[ty + j][tx] = f[(c0 + ty + j) * 1024 + n0 + tx];
    __syncthreads();
    for (int j = 0; j < 32; j += 8) g_fT[(size_t)sb * 524288 + (size_t)(n0 + ty + j) * 512 + c0 + tx] = t[tx][ty + j];
}

__global__ void __launch_bounds__(1024) k_kmeans() {
    __shared__ float sc[3][512];
    __shared__ int sa[1024];
    int sb = blockIdx.x, tid = threadIdx.x;
    const float* f = g_f4 + (size_t)sb * 524288;
    const float* ft = g_fT + (size_t)sb * 524288;
    if (tid < 512) {
        sc[0][tid] = f[tid * 1024 + 0];
        sc[1][tid] = f[tid * 1024 + 1];
        sc[2][tid] = f[tid * 1024 + 2];
    }
    __syncthreads();
    int n0c = 0, n1c = 0, n2c = 0;
    for (int it = 0; it < 11; it++) {
        {
            int n = tid;
            float d0 = 0, d1 = 0, d2 = 0;
            for (int c = 0; c < 512; c++) {
                float v = f[c * 1024 + n];
                float a = v - sc[0][c], b = v - sc[1][c], e = v - sc[2][c];
                d0 += a * a; d1 += b * b; d2 += e * e;
            }
            int a = 0; float best = d0;
            if (d1 < best) { best = d1; a = 1; }
            if (d2 < best) { a = 2; }
            sa[n] = a;
        }
        __syncthreads();
        if (tid < 512) {
            float s0 = 0, s1 = 0, s2 = 0; int c0 = 0, c1 = 0, c2 = 0;
            for (int n = 0; n < 1024; n++) {
                float v = ft[n * 512 + tid];
                int a = sa[n];
                if (a == 0) { s0 += v; c0++; } else if (a == 1) { s1 += v; c1++; } else { s2 += v; c2++; }
            }
            sc[0][tid] = s0 / ((float)c0 + 1e-6f);
            sc[1][tid] = s1 / ((float)c1 + 1e-6f);
            sc[2][tid] = s2 / ((float)c2 + 1e-6f);
            n0c = c0; n1c = c1; n2c = c2;
        }
        __syncthreads();
    }
    if (tid < 512) {
        g_cent[sb * 1536 + tid] = sc[0][tid];
        g_cent[sb * 1536 + 512 + tid] = sc[1][tid];
        g_cent[sb * 1536 + 1024 + tid] = sc[2][tid];
        if (tid < 3) g_cnt[sb * 3 + tid] = (float)(tid == 0 ? n0c : (tid == 1 ? n1c : n2c));
    }
    g_asg[sb * 1024 + tid] = sa[tid];
}

__global__ void k_aw() {
    int i = blockIdx.x * 256 + threadIdx.x;
    if (i >= 12582912) return;
    int n = i & 1023, c = (i >> 10) & 511, m = i >> 19;
    int k = m % 3, sb = m / 3;
    const float* f = g_f4 + (size_t)sb * 524288;
    int a = g_asg[sb * 1024 + n];
    g_aw[i] = (a == k) ? f[c * 1024 + n] - g_cent[sb * 1536 + k * 512 + c] : 0.f;
}

__global__ void __launch_bounds__(256) k_covg() {
    __shared__ float sA[16][128], sB[16][128];
    int m = blockIdx.z;
    const float* A = g_aw + (size_t)m * 524288;
    int bi = c_pi[blockIdx.x], bj = c_pj[blockIdx.x];
    int i0 = bi * 128, j0 = bj * 128;
    int tid = threadIdx.x;
    int ar = tid >> 1, ac = (tid & 1) * 8;
    int ty = tid >> 4, tx = tid & 15;
    float acc[8][8];
#pragma unroll
    for (int a = 0; a < 8; a++)
#pragma unroll
        for (int b = 0; b < 8; b++) acc[a][b] = 0.f;
    float4 ra0 = *(const float4*)&A[(size_t)(i0 + ar) * 1024 + ac];
    float4 ra1 = *(const float4*)&A[(size_t)(i0 + ar) * 1024 + ac + 4];
    float4 rb0 = *(const float4*)&A[(size_t)(j0 + ar) * 1024 + ac];
    float4 rb1 = *(const float4*)&A[(size_t)(j0 + ar) * 1024 + ac + 4];
    for (int k0 = 0; k0 < 1024; k0 += 16) {
        sA[ac+0][ar]=ra0.x; sA[ac+1][ar]=ra0.y; sA[ac+2][ar]=ra0.z; sA[ac+3][ar]=ra0.w;
        sA[ac+4][ar]=ra1.x; sA[ac+5][ar]=ra1.y; sA[ac+6][ar]=ra1.z; sA[ac+7][ar]=ra1.w;
        sB[ac+0][ar]=rb0.x; sB[ac+1][ar]=rb0.y; sB[ac+2][ar]=rb0.z; sB[ac+3][ar]=rb0.w;
        sB[ac+4][ar]=rb1.x; sB[ac+5][ar]=rb1.y; sB[ac+6][ar]=rb1.z; sB[ac+7][ar]=rb1.w;
        __syncthreads();
        if (k0 + 16 < 1024) {
            ra0 = *(const float4*)&A[(size_t)(i0 + ar) * 1024 + k0 + 16 + ac];
            ra1 = *(const float4*)&A[(size_t)(i0 + ar) * 1024 + k0 + 16 + ac + 4];
            rb0 = *(const float4*)&A[(size_t)(j0 + ar) * 1024 + k0 + 16 + ac];
            rb1 = *(const float4*)&A[(size_t)(j0 + ar) * 1024 + k0 + 16 + ac + 4];
        }
#pragma unroll
        for (int k = 0; k < 16; k++) {
            float av[8], bv[8];
            *(float4*)av = *(float4*)&sA[k][ty * 8]; *(float4*)(av+4) = *(float4*)&sA[k][ty * 8 + 4];
            *(float4*)bv = *(float4*)&sB[k][tx * 8]; *(float4*)(bv+4) = *(float4*)&sB[k][tx * 8 + 4];
#pragma unroll
            for (int a = 0; a < 8; a++)
#pragma unroll
                for (int b = 0; b < 8; b++) acc[a][b] += av[a] * bv[b];
        }
        __syncthreads();
    }
    float nc = g_cnt[m] + 1e-6f;
    float* C = g_cov + (size_t)m * MS;
#pragma unroll
    for (int a = 0; a < 8; a++)
#pragma unroll
        for (int b = 0; b < 8; b++) {
            int gi = i0 + ty * 8 + a, gj = j0 + tx * 8 + b;
            float v = acc[a][b] / nc + (gi == gj ? 0.1f : 0.f);
            C[gi * 512 + gj] = v;
            if (bi != bj) C[gj * 512 + gi] = v;
        }
}

__global__ void __launch_bounds__(256) k_norm() {
    __shared__ float red[256];
    int m = blockIdx.x;
    const float* A = g_cov + (size_t)m * MS;
    float mx = 0;
    for (int r = threadIdx.x; r < 512; r += 256) {
        float s = 0;
        for (int c = 0; c < 512; c++) s += fabsf(A[r * 512 + c]);
        mx = fmaxf(mx, s);
    }
    red[threadIdx.x] = mx; __syncthreads();
    for (int o = 128; o > 0; o >>= 1) { if (threadIdx.x < o) red[threadIdx.x] = fmaxf(red[threadIdx.x], red[threadIdx.x + o]); __syncthreads(); }
    if (threadIdx.x == 0) g_nrm[m] = red[0];
}

__global__ void k_nsinit() {
    int i = blockIdx.x * 256 + threadIdx.x;
    if (i >= 6291456) return;
    int m = i >> 18;
    g_Y[i] = g_cov[i] / g_nrm[m];
}

__global__ void __launch_bounds__(256) k_gemmsym(
    const float* __restrict__ A, const float* __restrict__ B,
    float* __restrict__ C, const float* __restrict__ Mp, int polymode)
{
    __shared__ float sA[2][16][128], sB[2][16][128];
    int z = blockIdx.z;
    const float* Ab = A + (size_t)z * MS;
    const float* Bb = B + (size_t)z * MS;
    float* Cb = C + (size_t)z * MS;
    const float* Mb = Mp + (size_t)z * MS;
    int bi = c_pi[blockIdx.x], bj = c_pj[blockIdx.x];
    int m0 = bi * 128, n0 = bj * 128;
    int tid = threadIdx.x;
    int ar = tid >> 1, ac = (tid & 1) * 8;
    int br = tid >> 4, bc = (tid & 15) * 8;
    int ty = tid >> 4, tx = tid & 15;
    float acc[8][8];
#pragma unroll
    for (int a = 0; a < 8; a++)
#pragma unroll
        for (int b = 0; b < 8; b++) acc[a][b] = 0.f;
    float4 ra0 = *(const float4*)&Ab[(size_t)(m0 + ar) * 512 + ac];
    float4 ra1 = *(const float4*)&Ab[(size_t)(m0 + ar) * 512 + ac + 4];
    float4 rb0 = *(const float4*)&Bb[(size_t)br * 512 + n0 + bc];
    float4 rb1 = *(const float4*)&Bb[(size_t)br * 512 + n0 + bc + 4];
    sA[0][ac+0][ar]=ra0.x; sA[0][ac+1][ar]=ra0.y; sA[0][ac+2][ar]=ra0.z; sA[0][ac+3][ar]=ra0.w;
    sA[0][ac+4][ar]=ra1.x; sA[0][ac+5][ar]=ra1.y; sA[0][ac+6][ar]=ra1.z; sA[0][ac+7][ar]=ra1.w;
    *(float4*)&sB[0][br][bc] = rb0; *(float4*)&sB[0][br][bc + 4] = rb1;
    __syncthreads();
    for (int s = 0; s < 32; s++) {
        int buf = s & 1;
        if (s < 31) {
            int k0 = (s + 1) * 16;
            ra0 = *(const float4*)&Ab[(size_t)(m0 + ar) * 512 + k0 + ac];
            ra1 = *(const float4*)&Ab[(size_t)(m0 + ar) * 512 + k0 + ac + 4];
            rb0 = *(const float4*)&Bb[(size_t)(k0 + br) * 512 + n0 + bc];
            rb1 = *(const float4*)&Bb[(size_t)(k0 + br) * 512 + n0 + bc + 4];
        }
#pragma unroll
        for (int k = 0; k < 16; k++) {
            float av[8], bv[8];
            *(float4*)av = *(float4*)&sA[buf][k][ty * 8]; *(float4*)(av+4) = *(float4*)&sA[buf][k][ty * 8 + 4];
            *(float4*)bv = *(float4*)&sB[buf][k][tx * 8]; *(float4*)(bv+4) = *(float4*)&sB[buf][k][tx * 8 + 4];
#pragma unroll
            for (int a = 0; a < 8; a++)
#pragma unroll
                for (int b = 0; b < 8; b++) acc[a][b] += av[a] * bv[b];
        }
        if (s < 31) {
            int nb = buf ^ 1;
            sA[nb][ac+0][ar]=ra0.x; sA[nb][ac+1][ar]=ra0.y; sA[nb][ac+2][ar]=ra0.z; sA[nb][ac+3][ar]=ra0.w;
            sA[nb][ac+4][ar]=ra1.x; sA[nb][ac+5][ar]=ra1.y; sA[nb][ac+6][ar]=ra1.z; sA[nb][ac+7][ar]=ra1.w;
            *(float4*)&sB[nb][br][bc] = rb0; *(float4*)&sB[nb][br][bc + 4] = rb1;
            __syncthreads();
        }
    }
#pragma unroll
    for (int a = 0; a < 8; a++) {
        int gi = m0 + ty * 8 + a;
#pragma unroll
        for (int b = 0; b < 8; b++) {
            int gj = n0 + tx * 8 + b;
            float v = acc[a][b];
            if (polymode)
                v = ((gi == gj ? 15.f : 0.f) - 10.f * Mb[(size_t)gi * 512 + gj] + 3.f * v) * 0.125f;
            Cb[(size_t)gi * 512 + gj] = v;
            if (bi != bj) Cb[(size_t)gj * 512 + gi] = v;
        }
    }
}

__global__ void __launch_bounds__(256) k_gemm16(
    const float* __restrict__ A, int strA, const float* __restrict__ B, int strB, int bdiv,
    float* __restrict__ C, int strC, int N, float alpha, int nrmmode)
{
    __shared__ float sA[2][16][128], sB[2][16][128];
    int z = blockIdx.z;
    const float* Ab = A + (size_t)z * strA;
    const float* Bb = B + (size_t)(bdiv ? z / 3 : z) * strB;
    float* Cb = C + (size_t)z * strC;
    if (nrmmode) alpha = sqrtf(g_nrm[12 + z] / g_nrm[z]);
    int m0 = blockIdx.y * 128, n0 = blockIdx.x * 128;
    int tid = threadIdx.x;
    int ar = tid >> 1, ac = (tid & 1) * 8;
    int br = tid >> 4, bc = (tid & 15) * 8;
    int ty = tid >> 4, tx = tid & 15;
    float acc[8][8];
#pragma unroll
    for (int a = 0; a < 8; a++)
#pragma unroll
        for (int b = 0; b < 8; b++) acc[a][b] = 0.f;
    float4 ra0 = *(const float4*)&Ab[(size_t)(m0 + ar) * 512 + ac];
    float4 ra1 = *(const float4*)&Ab[(size_t)(m0 + ar) * 512 + ac + 4];
    float4 rb0 = *(const float4*)&Bb[(size_t)br * N + n0 + bc];
    float4 rb1 = *(const float4*)&Bb[(size_t)br * N + n0 + bc + 4];
    sA[0][ac+0][ar]=ra0.x; sA[0][ac+1][ar]=ra0.y; sA[0][ac+2][ar]=ra0.z; sA[0][ac+3][ar]=ra0.w;
    sA[0][ac+4][ar]=ra1.x; sA[0][ac+5][ar]=ra1.y; sA[0][ac+6][ar]=ra1.z; sA[0][ac+7][ar]=ra1.w;
    *(float4*)&sB[0][br][bc] = rb0; *(float4*)&sB[0][br][bc + 4] = rb1;
    __syncthreads();
    for (int s = 0; s < 32; s++) {
        int buf = s & 1;
        if (s < 31) {
            int k0 = (s + 1) * 16;
            ra0 = *(const float4*)&Ab[(size_t)(m0 + ar) * 512 + k0 + ac];
            ra1 = *(const float4*)&Ab[(size_t)(m0 + ar) * 512 + k0 + ac + 4];
            rb0 = *(const float4*)&Bb[(size_t)(k0 + br) * N + n0 + bc];
            rb1 = *(const float4*)&Bb[(size_t)(k0 + br) * N + n0 + bc + 4];
        }
#pragma unroll
        for (int k = 0; k < 16; k++) {
            float av[8], bv[8];
            *(float4*)av = *(float4*)&sA[buf][k][ty * 8]; *(float4*)(av+4) = *(float4*)&sA[buf][k][ty * 8 + 4];
            *(float4*)bv = *(float4*)&sB[buf][k][tx * 8]; *(float4*)(bv+4) = *(float4*)&sB[buf][k][tx * 8 + 4];
#pragma unroll
            for (int a = 0; a < 8; a++)
#pragma unroll
                for (int b = 0; b < 8; b++) acc[a][b] += av[a] * bv[b];
        }
        if (s < 31) {
            int nb = buf ^ 1;
            sA[nb][ac+0][ar]=ra0.x; sA[nb][ac+1][ar]=ra0.y; sA[nb][ac+2][ar]=ra0.z; sA[nb][ac+3][ar]=ra0.w;
            sA[nb][ac+4][ar]=ra1.x; sA[nb][ac+5][ar]=ra1.y; sA[nb][ac+6][ar]=ra1.z; sA[nb][ac+7][ar]=ra1.w;
            *(float4*)&sB[nb][br][bc] = rb0; *(float4*)&sB[nb][br][bc + 4] = rb1;
            __syncthreads();
        }
    }
#pragma unroll
    for (int a = 0; a < 8; a++) {
        int gm = m0 + ty * 8 + a;
#pragma unroll
        for (int b = 0; b < 8; b++) {
            int gn = n0 + tx * 8 + b;
            Cb[(size_t)gm * N + gn] = alpha * acc[a][b];
        }
    }
}

__global__ void __launch_bounds__(512) k_gemv() {
    __shared__ float mu[512];
    int z = blockIdx.x;
    int b = z / 3, k = z % 3;
    int tid = threadIdx.x;
    mu[tid] = g_cent[b * 1536 + k * 512 + tid];
    __syncthreads();
    const float* T = g_Tm + (size_t)z * MS;
    int warp = tid >> 5, lane = tid & 31;
    for (int c = warp; c < 512; c += 16) {
        float s = 0;
        for (int d = lane; d < 512; d += 32) s += T[c * 512 + d] * mu[d];
#pragma unroll
        for (int o = 16; o > 0; o >>= 1) s += __shfl_down_sync(0xffffffff, s, o);
        if (lane == 0) g_vv[z * 512 + c] = s;
    }
}

__global__ void k_comb(const float* __restrict__ tp) {
    int i = blockIdx.x * 256 + threadIdx.x;
    if (i >= 2097152) return;
    int n = i & 1023, c = (i >> 10) & 511, b = i >> 19;
    int a = g_asg[b * 1024 + n];
    int z = b * 3 + a;
    float val = tp[(size_t)z * 524288 + c * 1024 + n] - g_vv[z * 512 + c]
              + g_cent[(4 + b) * 1536 + a * 512 + c];
    g_f4t[i] = 0.6f * val + 0.4f * g_f4[i];
}

__global__ void __launch_bounds__(256) k_closs1() {
    __shared__ double red[256];
    int start = blockIdx.x * 8192;
    double s = 0;
    for (int i = threadIdx.x; i < 8192; i += 256) {
        float d = g_f4e[start + i] - g_f4[start + i];
        s += (double)d * d;
    }
    red[threadIdx.x] = s; __syncthreads();
    for (int o = 128; o > 0; o >>= 1) { if (threadIdx.x < o) red[threadIdx.x] += red[threadIdx.x + o]; __syncthreads(); }
    if (threadIdx.x == 0) g_part[blockIdx.x] = red[0];
}

__global__ void __launch_bounds__(256) k_final(float* out) {
    __shared__ double red[256];
    __shared__ double slv;
    __shared__ double closs;
    const int off[5] = {0, 256, 768, 1792, 3840};
    if (threadIdx.x == 0) slv = 0;
    red[threadIdx.x] = g_part[threadIdx.x];
    __syncthreads();
    for (int o = 128; o > 0; o >>= 1) { if (threadIdx.x < o) red[threadIdx.x] += red[threadIdx.x + o]; __syncthreads(); }
    if (threadIdx.x == 0) closs = red[0] / 2097152.0;
    __syncthreads();
    for (int l = 0; l < 4; l++) {
        int o0 = off[l], sz = off[l + 1] - off[l];
        double s = 0;
        for (int i = threadIdx.x; i < sz; i += 256) {
            float dm = g_st[2 * 3840 + o0 + i] - g_st[0 * 3840 + o0 + i];
            float ds = g_st[3 * 3840 + o0 + i] - g_st[1 * 3840 + o0 + i];
            s += (double)dm * dm + (double)ds * ds;
        }
        red[threadIdx.x] = s; __syncthreads();
        for (int o = 128; o > 0; o >>= 1) { if (threadIdx.x < o) red[threadIdx.x] += red[threadIdx.x + o]; __syncthreads(); }
        if (threadIdx.x == 0) slv += red[0] / sz;
        __syncthreads();
    }
    if (threadIdx.x == 0) out[0] = (float)closs + 0.01f * (float)slv;
}

extern "C" void kernel_launch(void* const* d_in, const int* in_sizes, int n_in,
                              void* d_out, int out_size) {
    (void)in_sizes; (void)n_in; (void)out_size;
    const float* in[18];
    for (int i = 0; i < 18; i++) in[i] = (const float*)d_in[i];

    float *b0, *b1, *in8, *f4, *f4t, *f4e, *dec, *Y, *Z, *Tt, *cov, *aw, *Tm, *st;
    cudaGetSymbolAddress((void**)&b0, g_b0);
    cudaGetSymbolAddress((void**)&b1, g_b1);
    cudaGetSymbolAddress((void**)&in8, g_in8);
    cudaGetSymbolAddress((void**)&f4, g_f4);
    cudaGetSymbolAddress((void**)&f4t, g_f4t);
    cudaGetSymbolAddress((void**)&f4e, g_f4e);
    cudaGetSymbolAddress((void**)&dec, g_dec);
    cudaGetSymbolAddress((void**)&Y, g_Y);
    cudaGetSymbolAddress((void**)&Z, g_Z);
    cudaGetSymbolAddress((void**)&Tt, g_Tt);
    cudaGetSymbolAddress((void**)&cov, g_cov);
    cudaGetSymbolAddress((void**)&aw, g_aw);
    cudaGetSymbolAddress((void**)&Tm, g_Tm);
    cudaGetSymbolAddress((void**)&st, g_st);
    float* aw1 = aw + 6291456;

    auto conv = [&](const float* i0, float* o, const float* w, const float* bb,
                    int Cin, int Cout, int H, int relu, int B) {
        if (Cin >= 64 && Cout >= 64) {
            dim3 g((B * H * H) / 128, (Cout + 127) / 128, 1);
            k_cgemm<<<g, 256>>>(i0, w, bb, o, Cin, Cout, H, relu);
        } else if (H >= 64) {
            dim3 g((H / 32) * (H / 32), (Cout + 15) / 16, B);
            k_conv<16><<<g, 256>>>(i0, w, bb, o, Cin, Cout, H, relu);
        } else {
            dim3 g((H / 32) * (H / 32), (Cout + 7) / 8, B);
            k_conv<8><<<g, 256>>>(i0, w, bb, o, Cin, Cout, H, relu);
        }
    };
    auto pool = [&](const float* i0, float* o, int C, int Ho, int B) {
        int tot = B * C * Ho * Ho; int g = (tot + 255) / 256;
        if (Ho == 128) k_pool<128><<<g, 256>>>(i0, o, tot);
        else if (Ho == 64) k_pool<64><<<g, 256>>>(i0, o, tot);
        else k_pool<32><<<g, 256>>>(i0, o, tot);
    };
    auto up = [&](const float* i0, float* o, int C, int Ho) {
        int tot = 4 * C * Ho * Ho; int g = (tot + 255) / 256;
        if (Ho == 64) k_up<64><<<g, 256>>>(i0, o, tot);
        else if (Ho == 128) k_up<128><<<g, 256>>>(i0, o, tot);
        else k_up<256><<<g, 256>>>(i0, o, tot);
    };
    auto enc = [&](const float* x, int B, float* f4o, float* mo, float* so, int soff) {
        conv(x, b0, in[2], in[3], 3, 64, 256, 1, B);
        if (mo) k_stats<<<4 * 64, 256>>>(b0 + (size_t)soff * 64 * 65536, 65536, mo, so);
        pool(b0, b1, 64, 128, B);
        conv(b1, b0, in[4], in[5], 64, 128, 128, 1, B);
        if (mo) k_stats<<<4 * 128, 256>>>(b0 + (size_t)soff * 128 * 16384, 16384, mo + 256, so + 256);
        pool(b0, b1, 128, 64, B);
        conv(b1, b0, in[6], in[7], 128, 256, 64, 1, B);
        if (mo) k_stats<<<4 * 256, 256>>>(b0 + (size_t)soff * 256 * 4096, 4096, mo + 768, so + 768);
        pool(b0, b1, 256, 32, B);
        conv(b1, f4o, in[8], in[9], 256, 512, 32, 1, B);
        if (mo) k_stats<<<4 * 512, 256>>>(f4o + (size_t)soff * 512 * 1024, 1024, mo + 1792, so + 1792);
    };

    cudaMemcpyAsync(in8, in[0], 786432 * 4, cudaMemcpyDeviceToDevice);
    cudaMemcpyAsync(in8 + 786432, in[1], 786432 * 4, cudaMemcpyDeviceToDevice);
    k_dummy<<<1, 256>>>();

    // batch-8 encode (content 0-3, style 4-7); style stats via soff=4
    enc(in8, 8, f4, st + 0, st + 3840, 4);

    k_transp<<<dim3(8, 16, 32), dim3(32, 8)>>>();
    k_kmeans<<<8, 1024>>>();

    k_aw<<<(12582912 + 255) / 256, 256>>>();
    k_covg<<<dim3(10, 1, 24), 256>>>();
    k_norm<<<24, 256>>>();
    k_nsinit<<<((6291456 + 255) / 256), 256>>>();

    dim3 gs(10, 1, 24);
    k_gemmsym<<<gs, 256>>>(Y, Y, cov, Y, 1);
    k_gemmsym<<<gs, 256>>>(Y, cov, aw, cov, 0);
    float* Yc = aw; float* Zc = cov;
    float* fr[4] = {Y, Z, Tt, aw1};
    for (int it = 0; it < 14; it++) {
        float* M = fr[0]; float* P = fr[1]; float* Yn = fr[2]; float* Zn = fr[3];
        k_gemmsym<<<gs, 256>>>(Zc, Yc, M, Zc, 0);
        k_gemmsym<<<gs, 256>>>(M, M, P, M, 1);
        if (it < 13) {
            k_gemmsym<<<gs, 256>>>(Yc, P, Yn, Yc, 0);
            k_gemmsym<<<gs, 256>>>(P, Zc, Zn, P, 0);
        } else {
            size_t so12 = (size_t)12 * MS;
            k_gemmsym<<<dim3(10, 1, 12), 256>>>(Yc + so12, P + so12, Yn + so12, Yc + so12, 0);
            k_gemmsym<<<dim3(10, 1, 12), 256>>>(P, Zc, Zn, P, 0);
        }
        fr[0] = Yc; fr[1] = Zc; fr[2] = M; fr[3] = P;
        Yc = Yn; Zc = Zn;
    }

    k_gemm16<<<dim3(4, 4, 12), 256>>>(Yc + (size_t)12 * MS, MS, Zc, MS, 0,
                                      Tm, MS, 512, 1.f, 1);
    float* tp = fr[0];
    k_gemm16<<<dim3(8, 4, 12), 256>>>(Tm, MS, f4, 524288, 1, tp, 524288, 1024, 1.f, 0);
    k_gemv<<<12, 512>>>();
    k_comb<<<(2097152 + 255) / 256, 256>>>(tp);

    conv(f4t, b0, in[10], in[11], 512, 256, 32, 1, 4);
    up(b0, b1, 256, 64);
    conv(b1, b0, in[12], in[13], 256, 128, 64, 1, 4);
    up(b0, b1, 128, 128);
    conv(b1, b0, in[14], in[15], 128, 64, 128, 1, 4);
    up(b0, b1, 64, 256);
    conv(b1, dec, in[16], in[17], 64, 3, 256, 0, 4);

    enc(dec, 4, f4e, st + 2 * 3840, st + 3 * 3840, 0);

    k_closs1<<<256, 256>>>();
    k_final<<<1, 256>>>((float*)d_out);
}

// round 13
// speedup vs baseline: 2.0413x; 1.1482x over previous
#include <cuda_runtime.h>
#include <math.h>

#define MS 262144
__device__ float g_b0[33554432];
__device__ float g_b1[33554432];
__device__ float g_in8[1572864];
__device__ float g_f4[4194304];
__device__ float g_f4t[2097152];
__device__ float g_f4e[2097152];
__device__ float g_dec[786432];
__device__ float g_fT[4194304];
__device__ float g_cent[12288];
__device__ int   g_asg[8192];
__device__ float g_cnt[24];
__device__ float g_aw[12582912];
__device__ float g_cov[6291456];
__device__ float g_Y[6291456];
__device__ float g_Z[6291456];
__device__ float g_Tt[6291456];
__device__ float g_nrm[24];
__device__ float g_Tm[3145728];
__device__ float g_vv[6144];
__device__ float g_st[15360];
__device__ double g_part[256];

__constant__ int c_pi[10] = {0,0,0,0,1,1,1,2,2,3};
__constant__ int c_pj[10] = {0,1,2,3,1,2,3,2,3,3};

__global__ void k_dummy() { g_part[threadIdx.x] = 0.0; }

// ---------- implicit-GEMM conv 3x3 SAME ----------
__global__ void __launch_bounds__(256, 2) k_cgemm(
    const float* __restrict__ in, const float* __restrict__ w,
    const float* __restrict__ bias, float* __restrict__ out,
    int Cin, int Cout, int H, int relu)
{
    __shared__ float sA[2][16][128], sB[2][16][128];
    int K = Cin * 9, HH = H * H;
    int m0 = blockIdx.y * 128, n0 = blockIdx.x * 128;
    int tid = threadIdx.x;
    int ar = tid >> 1, ac = (tid & 1) * 8;
    int brk = tid >> 4, bcg = (tid & 15) * 8;
    int ty = tid >> 4, tx = tid & 15;
    int b = n0 / HH, rem0 = n0 - b * HH;
    int cy[8], cx[8];
#pragma unroll
    for (int j = 0; j < 8; j++) {
        int rem = rem0 + bcg + j;
        int yy = rem / H;
        cy[j] = yy; cx[j] = rem - yy * H;
    }
    const float* inb = in + (size_t)b * Cin * HH;
    float acc[8][8];
#pragma unroll
    for (int a = 0; a < 8; a++)
#pragma unroll
        for (int q = 0; q < 8; q++) acc[a][q] = 0.f;
    float ra[8], rb[8];
    int aok = (m0 + ar) < Cout;
    const float* awp = w + (size_t)(aok ? m0 + ar : 0) * K + ac;
    if (aok) { *(float4*)ra = *(const float4*)awp; *(float4*)(ra+4) = *(const float4*)(awp+4); }
    else { for (int i = 0; i < 8; i++) ra[i] = 0.f; }
    {
        int k = brk;
        int ic = k / 9, rs = k - ic * 9;
        int dy = rs / 3 - 1, dx = rs - (rs / 3) * 3 - 1;
        const float* ip = inb + (size_t)ic * HH;
#pragma unroll
        for (int j = 0; j < 8; j++) {
            int yy = cy[j] + dy, xx = cx[j] + dx;
            rb[j] = (yy >= 0 && yy < H && xx >= 0 && xx < H) ? ip[yy * H + xx] : 0.f;
        }
    }
    int nk = K / 16;
#pragma unroll
    for (int i = 0; i < 8; i++) sA[0][ac + i][ar] = ra[i];
#pragma unroll
    for (int j = 0; j < 8; j++) sB[0][brk][bcg + j] = rb[j];
    __syncthreads();
    for (int s = 0; s < nk; s++) {
        int buf = s & 1;
        if (s + 1 < nk) {
            int k0 = (s + 1) * 16;
            if (aok) { *(float4*)ra = *(const float4*)(awp + k0); *(float4*)(ra+4) = *(const float4*)(awp + k0 + 4); }
            int k = k0 + brk;
            int ic = k / 9, rs = k - ic * 9;
            int dy = rs / 3 - 1, dx = rs - (rs / 3) * 3 - 1;
            const float* ip = inb + (size_t)ic * HH;
#pragma unroll
            for (int j = 0; j < 8; j++) {
                int yy = cy[j] + dy, xx = cx[j] + dx;
                rb[j] = (yy >= 0 && yy < H && xx >= 0 && xx < H) ? ip[yy * H + xx] : 0.f;
            }
        }
#pragma unroll
        for (int k = 0; k < 16; k++) {
            float av[8], bv[8];
            *(float4*)av = *(float4*)&sA[buf][k][ty * 8]; *(float4*)(av+4) = *(float4*)&sA[buf][k][ty * 8 + 4];
            *(float4*)bv = *(float4*)&sB[buf][k][tx * 8]; *(float4*)(bv+4) = *(float4*)&sB[buf][k][tx * 8 + 4];
#pragma unroll
            for (int a = 0; a < 8; a++)
#pragma unroll
                for (int q = 0; q < 8; q++) acc[a][q] += av[a] * bv[q];
        }
        if (s + 1 < nk) {
            int nb = buf ^ 1;
#pragma unroll
            for (int i = 0; i < 8; i++) sA[nb][ac + i][ar] = ra[i];
#pragma unroll
            for (int j = 0; j < 8; j++) sB[nb][brk][bcg + j] = rb[j];
            __syncthreads();
        }
    }
#pragma unroll
    for (int a = 0; a < 8; a++) {
        int oc = m0 + ty * 8 + a;
        if (oc >= Cout) break;
        float bv = bias[oc];
        float* op = out + ((size_t)b * Cout + oc) * HH;
#pragma unroll
        for (int q = 0; q < 8; q++) {
            float v = acc[a][q] + bv;
            if (relu) v = fmaxf(v, 0.f);
            op[rem0 + tx * 8 + q] = v;
        }
    }
}

template<int OCB>
__global__ void __launch_bounds__(256) k_conv(const float* __restrict__ in,
    const float* __restrict__ w, const float* __restrict__ bias,
    float* __restrict__ out, int Cin, int Cout, int H, int relu)
{
    __shared__ float sI[34][36];
    __shared__ float sW[OCB][9];
    int tiles = H >> 5;
    int bx = blockIdx.x % tiles, by = blockIdx.x / tiles;
    int x0 = bx * 32, y0 = by * 32;
    int oc0 = blockIdx.y * OCB, b = blockIdx.z;
    int tid = threadIdx.x;
    int lx = (tid & 15) * 2, ly = (tid >> 4) * 2;
    float acc[OCB][4];
#pragma unroll
    for (int o = 0; o < OCB; o++) { acc[o][0]=0.f; acc[o][1]=0.f; acc[o][2]=0.f; acc[o][3]=0.f; }
    const float* ib = in + (size_t)b * Cin * H * H;
    for (int ic = 0; ic < Cin; ic++) {
        __syncthreads();
        const float* ip = ib + (size_t)ic * H * H;
        for (int i = tid; i < 34 * 34; i += 256) {
            int yy = i / 34, xx = i - yy * 34;
            int gy = y0 + yy - 1, gx = x0 + xx - 1;
            sI[yy][xx] = (gy >= 0 && gy < H && gx >= 0 && gx < H) ? ip[gy * H + gx] : 0.f;
        }
        if (tid < OCB * 9) {
            int oc = tid / 9, tt = tid - oc * 9;
            sW[oc][tt] = (oc0 + oc < Cout) ? w[((size_t)(oc0 + oc) * Cin + ic) * 9 + tt] : 0.f;
        }
        __syncthreads();
        float win[4][4];
#pragma unroll
        for (int r = 0; r < 4; r++)
#pragma unroll
            for (int s = 0; s < 4; s++) win[r][s] = sI[ly + r][lx + s];
#pragma unroll
        for (int o = 0; o < OCB; o++) {
            float w0=sW[o][0],w1=sW[o][1],w2=sW[o][2],w3=sW[o][3],w4=sW[o][4];
            float w5=sW[o][5],w6=sW[o][6],w7=sW[o][7],w8=sW[o][8];
#pragma unroll
            for (int p = 0; p < 4; p++) {
                int pr = p >> 1, pc = p & 1;
                acc[o][p] += win[pr][pc]*w0 + win[pr][pc+1]*w1 + win[pr][pc+2]*w2
                           + win[pr+1][pc]*w3 + win[pr+1][pc+1]*w4 + win[pr+1][pc+2]*w5
                           + win[pr+2][pc]*w6 + win[pr+2][pc+1]*w7 + win[pr+2][pc+2]*w8;
            }
        }
    }
#pragma unroll
    for (int o = 0; o < OCB; o++) {
        int oc = oc0 + o;
        if (oc >= Cout) break;
        float bv = bias[oc];
        float* op = out + ((size_t)b * Cout + oc) * H * H;
#pragma unroll
        for (int p = 0; p < 4; p++) {
            float v = acc[o][p] + bv;
            if (relu) v = fmaxf(v, 0.f);
            op[(y0 + ly + (p >> 1)) * H + x0 + lx + (p & 1)] = v;
        }
    }
}

template<int HO>
__global__ void k_pool(const float* __restrict__ in, float* __restrict__ out, int tot) {
    int i = blockIdx.x * 256 + threadIdx.x;
    if (i >= tot) return;
    int x = i % HO, y = (i / HO) % HO; int bc = i / (HO * HO);
    const int Hi = HO * 2;
    const float* p = in + (size_t)bc * Hi * Hi;
    out[i] = (p[(2*y)*Hi + 2*x] + p[(2*y)*Hi + 2*x+1] + p[(2*y+1)*Hi + 2*x] + p[(2*y+1)*Hi + 2*x+1]) * 0.25f;
}

template<int HO>
__global__ void k_up(const float* __restrict__ in, float* __restrict__ out, int tot) {
    int i = blockIdx.x * 256 + threadIdx.x;
    if (i >= tot) return;
    int x = i % HO, y = (i / HO) % HO; int bc = i / (HO * HO);
    const int Hi = HO >> 1;
    out[i] = in[(size_t)bc * Hi * Hi + (y >> 1) * Hi + (x >> 1)];
}

__global__ void __launch_bounds__(256) k_stats(const float* __restrict__ in, int HW,
                                               float* __restrict__ mo, float* __restrict__ so) {
    __shared__ double red[256];
    int bc = blockIdx.x;
    const float* p = in + (size_t)bc * HW;
    double s = 0;
    for (int i = threadIdx.x; i < HW; i += 256) s += p[i];
    red[threadIdx.x] = s; __syncthreads();
    for (int o = 128; o > 0; o >>= 1) { if (threadIdx.x < o) red[threadIdx.x] += red[threadIdx.x + o]; __syncthreads(); }
    double m = red[0] / HW;
    __syncthreads();
    double v = 0;
    for (int i = threadIdx.x; i < HW; i += 256) { double d = p[i] - m; v += d * d; }
    red[threadIdx.x] = v; __syncthreads();
    for (int o = 128; o > 0; o >>= 1) { if (threadIdx.x < o) red[threadIdx.x] += red[threadIdx.x + o]; __syncthreads(); }
    if (threadIdx.x == 0) { mo[bc] = (float)m; so[bc] = (float)sqrt(red[0] / HW); }
}

__global__ void k_transp() {
    __shared__ float t[32][33];
    int sb = blockIdx.x, c0 = blockIdx.y * 32, n0 = blockIdx.z * 32;
    const float* f = g_f4 + (size_t)sb * 524288;
    int tx = threadIdx.x, ty = threadIdx.y;
    for (int j = 0; j < 32; j += 8) t[ty + j][tx] = f[(c0 + ty + j) * 1024 + n0 + tx];
    __syncthreads();
    for (int j = 0; j < 32; j += 8) g_fT[(size_t)sb * 524288 + (size_t)(n0 + ty + j) * 512 + c0 + tx] = t[tx][ty + j];
}

__global__ void __launch_bounds__(1024) k_kmeans() {
    __shared__ float sc[3][512];
    __shared__ int sa[1024];
    int sb = blockIdx.x, tid = threadIdx.x;
    const float* f = g_f4 + (size_t)sb * 524288;
    const float* ft = g_fT + (size_t)sb * 524288;
    if (tid < 512) {
        sc[0][tid] = f[tid * 1024 + 0];
        sc[1][tid] = f[tid * 1024 + 1];
        sc[2][tid] = f[tid * 1024 + 2];
    }
    __syncthreads();
    int n0c = 0, n1c = 0, n2c = 0;
    for (int it = 0; it < 11; it++) {
        {
            int n = tid;
            float d0 = 0, d1 = 0, d2 = 0;
            for (int c = 0; c < 512; c++) {
                float v = f[c * 1024 + n];
                float a = v - sc[0][c], b = v - sc[1][c], e = v - sc[2][c];
                d0 += a * a; d1 += b * b; d2 += e * e;
            }
            int a = 0; float best = d0;
            if (d1 < best) { best = d1; a = 1; }
            if (d2 < best) { a = 2; }
            sa[n] = a;
        }
        __syncthreads();
        if (tid < 512) {
            float s0 = 0, s1 = 0, s2 = 0; int c0 = 0, c1 = 0, c2 = 0;
            for (int n = 0; n < 1024; n++) {
                float v = ft[n * 512 + tid];
                int a = sa[n];
                if (a == 0) { s0 += v; c0++; } else if (a == 1) { s1 += v; c1++; } else { s2 += v; c2++; }
            }
            sc[0][tid] = s0 / ((float)c0 + 1e-6f);
            sc[1][tid] = s1 / ((float)c1 + 1e-6f);
            sc[2][tid] = s2 / ((float)c2 + 1e-6f);
            n0c = c0; n1c = c1; n2c = c2;
        }
        __syncthreads();
    }
    if (tid < 512) {
        g_cent[sb * 1536 + tid] = sc[0][tid];
        g_cent[sb * 1536 + 512 + tid] = sc[1][tid];
        g_cent[sb * 1536 + 1024 + tid] = sc[2][tid];
        if (tid < 3) g_cnt[sb * 3 + tid] = (float)(tid == 0 ? n0c : (tid == 1 ? n1c : n2c));
    }
    g_asg[sb * 1024 + tid] = sa[tid];
}

__global__ void k_aw() {
    int i = blockIdx.x * 256 + threadIdx.x;
    if (i >= 12582912) return;
    int n = i & 1023, c = (i >> 10) & 511, m = i >> 19;
    int k = m % 3, sb = m / 3;
    const float* f = g_f4 + (size_t)sb * 524288;
    int a = g_asg[sb * 1024 + n];
    g_aw[i] = (a == k) ? f[c * 1024 + n] - g_cent[sb * 1536 + k * 512 + c] : 0.f;
}

__global__ void __launch_bounds__(256, 2) k_covg() {
    __shared__ float sA[16][128], sB[16][128];
    int m = blockIdx.z;
    const float* A = g_aw + (size_t)m * 524288;
    int bi = c_pi[blockIdx.x], bj = c_pj[blockIdx.x];
    int i0 = bi * 128, j0 = bj * 128;
    int tid = threadIdx.x;
    int ar = tid >> 1, ac = (tid & 1) * 8;
    int ty = tid >> 4, tx = tid & 15;
    float acc[8][8];
#pragma unroll
    for (int a = 0; a < 8; a++)
#pragma unroll
        for (int b = 0; b < 8; b++) acc[a][b] = 0.f;
    float4 ra0 = *(const float4*)&A[(size_t)(i0 + ar) * 1024 + ac];
    float4 ra1 = *(const float4*)&A[(size_t)(i0 + ar) * 1024 + ac + 4];
    float4 rb0 = *(const float4*)&A[(size_t)(j0 + ar) * 1024 + ac];
    float4 rb1 = *(const float4*)&A[(size_t)(j0 + ar) * 1024 + ac + 4];
    for (int k0 = 0; k0 < 1024; k0 += 16) {
        sA[ac+0][ar]=ra0.x; sA[ac+1][ar]=ra0.y; sA[ac+2][ar]=ra0.z; sA[ac+3][ar]=ra0.w;
        sA[ac+4][ar]=ra1.x; sA[ac+5][ar]=ra1.y; sA[ac+6][ar]=ra1.z; sA[ac+7][ar]=ra1.w;
        sB[ac+0][ar]=rb0.x; sB[ac+1][ar]=rb0.y; sB[ac+2][ar]=rb0.z; sB[ac+3][ar]=rb0.w;
        sB[ac+4][ar]=rb1.x; sB[ac+5][ar]=rb1.y; sB[ac+6][ar]=rb1.z; sB[ac+7][ar]=rb1.w;
        __syncthreads();
        if (k0 + 16 < 1024) {
            ra0 = *(const float4*)&A[(size_t)(i0 + ar) * 1024 + k0 + 16 + ac];
            ra1 = *(const float4*)&A[(size_t)(i0 + ar) * 1024 + k0 + 16 + ac + 4];
            rb0 = *(const float4*)&A[(size_t)(j0 + ar) * 1024 + k0 + 16 + ac];
            rb1 = *(const float4*)&A[(size_t)(j0 + ar) * 1024 + k0 + 16 + ac + 4];
        }
#pragma unroll
        for (int k = 0; k < 16; k++) {
            float av[8], bv[8];
            *(float4*)av = *(float4*)&sA[k][ty * 8]; *(float4*)(av+4) = *(float4*)&sA[k][ty * 8 + 4];
            *(float4*)bv = *(float4*)&sB[k][tx * 8]; *(float4*)(bv+4) = *(float4*)&sB[k][tx * 8 + 4];
#pragma unroll
            for (int a = 0; a < 8; a++)
#pragma unroll
                for (int b = 0; b < 8; b++) acc[a][b] += av[a] * bv[b];
        }
        __syncthreads();
    }
    float nc = g_cnt[m] + 1e-6f;
    float* C = g_cov + (size_t)m * MS;
#pragma unroll
    for (int a = 0; a < 8; a++)
#pragma unroll
        for (int b = 0; b < 8; b++) {
            int gi = i0 + ty * 8 + a, gj = j0 + tx * 8 + b;
            float v = acc[a][b] / nc + (gi == gj ? 0.1f : 0.f);
            C[gi * 512 + gj] = v;
            if (bi != bj) C[gj * 512 + gi] = v;
        }
}

__global__ void __launch_bounds__(256) k_norm() {
    __shared__ float red[256];
    int m = blockIdx.x;
    const float* A = g_cov + (size_t)m * MS;
    float mx = 0;
    for (int r = threadIdx.x; r < 512; r += 256) {
        float s = 0;
        for (int c = 0; c < 512; c++) s += fabsf(A[r * 512 + c]);
        mx = fmaxf(mx, s);
    }
    red[threadIdx.x] = mx; __syncthreads();
    for (int o = 128; o > 0; o >>= 1) { if (threadIdx.x < o) red[threadIdx.x] = fmaxf(red[threadIdx.x], red[threadIdx.x + o]); __syncthreads(); }
    if (threadIdx.x == 0) g_nrm[m] = red[0];
}

__global__ void k_nsinit() {
    int i = blockIdx.x * 256 + threadIdx.x;
    if (i >= 6291456) return;
    int m = i >> 18;
    g_Y[i] = g_cov[i] / g_nrm[m];
}

__global__ void __launch_bounds__(256, 2) k_gemmsym(
    const float* __restrict__ A, const float* __restrict__ B,
    float* __restrict__ C, const float* __restrict__ Mp, int polymode)
{
    __shared__ float sA[2][16][128], sB[2][16][128];
    int z = blockIdx.z;
    const float* Ab = A + (size_t)z * MS;
    const float* Bb = B + (size_t)z * MS;
    float* Cb = C + (size_t)z * MS;
    const float* Mb = Mp + (size_t)z * MS;
    int bi = c_pi[blockIdx.x], bj = c_pj[blockIdx.x];
    int m0 = bi * 128, n0 = bj * 128;
    int tid = threadIdx.x;
    int ar = tid >> 1, ac = (tid & 1) * 8;
    int br = tid >> 4, bc = (tid & 15) * 8;
    int ty = tid >> 4, tx = tid & 15;
    float acc[8][8];
#pragma unroll
    for (int a = 0; a < 8; a++)
#pragma unroll
        for (int b = 0; b < 8; b++) acc[a][b] = 0.f;
    float4 ra0 = *(const float4*)&Ab[(size_t)(m0 + ar) * 512 + ac];
    float4 ra1 = *(const float4*)&Ab[(size_t)(m0 + ar) * 512 + ac + 4];
    float4 rb0 = *(const float4*)&Bb[(size_t)br * 512 + n0 + bc];
    float4 rb1 = *(const float4*)&Bb[(size_t)br * 512 + n0 + bc + 4];
    sA[0][ac+0][ar]=ra0.x; sA[0][ac+1][ar]=ra0.y; sA[0][ac+2][ar]=ra0.z; sA[0][ac+3][ar]=ra0.w;
    sA[0][ac+4][ar]=ra1.x; sA[0][ac+5][ar]=ra1.y; sA[0][ac+6][ar]=ra1.z; sA[0][ac+7][ar]=ra1.w;
    *(float4*)&sB[0][br][bc] = rb0; *(float4*)&sB[0][br][bc + 4] = rb1;
    __syncthreads();
    for (int s = 0; s < 32; s++) {
        int buf = s & 1;
        if (s < 31) {
            int k0 = (s + 1) * 16;
            ra0 = *(const float4*)&Ab[(size_t)(m0 + ar) * 512 + k0 + ac];
            ra1 = *(const float4*)&Ab[(size_t)(m0 + ar) * 512 + k0 + ac + 4];
            rb0 = *(const float4*)&Bb[(size_t)(k0 + br) * 512 + n0 + bc];
            rb1 = *(const float4*)&Bb[(size_t)(k0 + br) * 512 + n0 + bc + 4];
        }
#pragma unroll
        for (int k = 0; k < 16; k++) {
            float av[8], bv[8];
            *(float4*)av = *(float4*)&sA[buf][k][ty * 8]; *(float4*)(av+4) = *(float4*)&sA[buf][k][ty * 8 + 4];
            *(float4*)bv = *(float4*)&sB[buf][k][tx * 8]; *(float4*)(bv+4) = *(float4*)&sB[buf][k][tx * 8 + 4];
#pragma unroll
            for (int a = 0; a < 8; a++)
#pragma unroll
                for (int b = 0; b < 8; b++) acc[a][b] += av[a] * bv[b];
        }
        if (s < 31) {
            int nb = buf ^ 1;
            sA[nb][ac+0][ar]=ra0.x; sA[nb][ac+1][ar]=ra0.y; sA[nb][ac+2][ar]=ra0.z; sA[nb][ac+3][ar]=ra0.w;
            sA[nb][ac+4][ar]=ra1.x; sA[nb][ac+5][ar]=ra1.y; sA[nb][ac+6][ar]=ra1.z; sA[nb][ac+7][ar]=ra1.w;
            *(float4*)&sB[nb][br][bc] = rb0; *(float4*)&sB[nb][br][bc + 4] = rb1;
            __syncthreads();
        }
    }
#pragma unroll
    for (int a = 0; a < 8; a++) {
        int gi = m0 + ty * 8 + a;
#pragma unroll
        for (int b = 0; b < 8; b++) {
            int gj = n0 + tx * 8 + b;
            float v = acc[a][b];
            if (polymode)
                v = ((gi == gj ? 15.f : 0.f) - 10.f * Mb[(size_t)gi * 512 + gj] + 3.f * v) * 0.125f;
            Cb[(size_t)gi * 512 + gj] = v;
            if (bi != bj) Cb[(size_t)gj * 512 + gi] = v;
        }
    }
}

__global__ void __launch_bounds__(256, 2) k_gemm16(
    const float* __restrict__ A, int strA, const float* __restrict__ B, int strB, int bdiv,
    float* __restrict__ C, int strC, int N, float alpha, int nrmmode)
{
    __shared__ float sA[2][16][128], sB[2][16][128];
    int z = blockIdx.z;
    const float* Ab = A + (size_t)z * strA;
    const float* Bb = B + (size_t)(bdiv ? z / 3 : z) * strB;
    float* Cb = C + (size_t)z * strC;
    if (nrmmode) alpha = sqrtf(g_nrm[12 + z] / g_nrm[z]);
    int m0 = blockIdx.y * 128, n0 = blockIdx.x * 128;
    int tid = threadIdx.x;
    int ar = tid >> 1, ac = (tid & 1) * 8;
    int br = tid >> 4, bc = (tid & 15) * 8;
    int ty = tid >> 4, tx = tid & 15;
    float acc[8][8];
#pragma unroll
    for (int a = 0; a < 8; a++)
#pragma unroll
        for (int b = 0; b < 8; b++) acc[a][b] = 0.f;
    float4 ra0 = *(const float4*)&Ab[(size_t)(m0 + ar) * 512 + ac];
    float4 ra1 = *(const float4*)&Ab[(size_t)(m0 + ar) * 512 + ac + 4];
    float4 rb0 = *(const float4*)&Bb[(size_t)br * N + n0 + bc];
    float4 rb1 = *(const float4*)&Bb[(size_t)br * N + n0 + bc + 4];
    sA[0][ac+0][ar]=ra0.x; sA[0][ac+1][ar]=ra0.y; sA[0][ac+2][ar]=ra0.z; sA[0][ac+3][ar]=ra0.w;
    sA[0][ac+4][ar]=ra1.x; sA[0][ac+5][ar]=ra1.y; sA[0][ac+6][ar]=ra1.z; sA[0][ac+7][ar]=ra1.w;
    *(float4*)&sB[0][br][bc] = rb0; *(float4*)&sB[0][br][bc + 4] = rb1;
    __syncthreads();
    for (int s = 0; s < 32; s++) {
        int buf = s & 1;
        if (s < 31) {
            int k0 = (s + 1) * 16;
            ra0 = *(const float4*)&Ab[(size_t)(m0 + ar) * 512 + k0 + ac];
            ra1 = *(const float4*)&Ab[(size_t)(m0 + ar) * 512 + k0 + ac + 4];
            rb0 = *(const float4*)&Bb[(size_t)(k0 + br) * N + n0 + bc];
            rb1 = *(const float4*)&Bb[(size_t)(k0 + br) * N + n0 + bc + 4];
        }
#pragma unroll
        for (int k = 0; k < 16; k++) {
            float av[8], bv[8];
            *(float4*)av = *(float4*)&sA[buf][k][ty * 8]; *(float4*)(av+4) = *(float4*)&sA[buf][k][ty * 8 + 4];
            *(float4*)bv = *(float4*)&sB[buf][k][tx * 8]; *(float4*)(bv+4) = *(float4*)&sB[buf][k][tx * 8 + 4];
#pragma unroll
            for (int a = 0; a < 8; a++)
#pragma unroll
                for (int b = 0; b < 8; b++) acc[a][b] += av[a] * bv[b];
        }
        if (s < 31) {
            int nb = buf ^ 1;
            sA[nb][ac+0][ar]=ra0.x; sA[nb][ac+1][ar]=ra0.y; sA[nb][ac+2][ar]=ra0.z; sA[nb][ac+3][ar]=ra0.w;
            sA[nb][ac+4][ar]=ra1.x; sA[nb][ac+5][ar]=ra1.y; sA[nb][ac+6][ar]=ra1.z; sA[nb][ac+7][ar]=ra1.w;
            *(float4*)&sB[nb][br][bc] = rb0; *(float4*)&sB[nb][br][bc + 4] = rb1;
            __syncthreads();
        }
    }
#pragma unroll
    for (int a = 0; a < 8; a++) {
        int gm = m0 + ty * 8 + a;
#pragma unroll
        for (int b = 0; b < 8; b++) {
            int gn = n0 + tx * 8 + b;
            Cb[(size_t)gm * N + gn] = alpha * acc[a][b];
        }
    }
}

__global__ void __launch_bounds__(512) k_gemv() {
    __shared__ float mu[512];
    int z = blockIdx.x;
    int b = z / 3, k = z % 3;
    int tid = threadIdx.x;
    mu[tid] = g_cent[b * 1536 + k * 512 + tid];
    __syncthreads();
    const float* T = g_Tm + (size_t)z * MS;
    int warp = tid >> 5, lane = tid & 31;
    for (int c = warp; c < 512; c += 16) {
        float s = 0;
        for (int d = lane; d < 512; d += 32) s += T[c * 512 + d] * mu[d];
#pragma unroll
        for (int o = 16; o > 0; o >>= 1) s += __shfl_down_sync(0xffffffff, s, o);
        if (lane == 0) g_vv[z * 512 + c] = s;
    }
}

__global__ void k_comb(const float* __restrict__ tp) {
    int i = blockIdx.x * 256 + threadIdx.x;
    if (i >= 2097152) return;
    int n = i & 1023, c = (i >> 10) & 511, b = i >> 19;
    int a = g_asg[b * 1024 + n];
    int z = b * 3 + a;
    float val = tp[(size_t)z * 524288 + c * 1024 + n] - g_vv[z * 512 + c]
              + g_cent[(4 + b) * 1536 + a * 512 + c];
    g_f4t[i] = 0.6f * val + 0.4f * g_f4[i];
}

__global__ void __launch_bounds__(256) k_closs1() {
    __shared__ double red[256];
    int start = blockIdx.x * 8192;
    double s = 0;
    for (int i = threadIdx.x; i < 8192; i += 256) {
        float d = g_f4e[start + i] - g_f4[start + i];
        s += (double)d * d;
    }
    red[threadIdx.x] = s; __syncthreads();
    for (int o = 128; o > 0; o >>= 1) { if (threadIdx.x < o) red[threadIdx.x] += red[threadIdx.x + o]; __syncthreads(); }
    if (threadIdx.x == 0) g_part[blockIdx.x] = red[0];
}

__global__ void __launch_bounds__(256) k_final(float* out) {
    __shared__ double red[256];
    __shared__ double slv;
    __shared__ double closs;
    const int off[5] = {0, 256, 768, 1792, 3840};
    if (threadIdx.x == 0) slv = 0;
    red[threadIdx.x] = g_part[threadIdx.x];
    __syncthreads();
    for (int o = 128; o > 0; o >>= 1) { if (threadIdx.x < o) red[threadIdx.x] += red[threadIdx.x + o]; __syncthreads(); }
    if (threadIdx.x == 0) closs = red[0] / 2097152.0;
    __syncthreads();
    for (int l = 0; l < 4; l++) {
        int o0 = off[l], sz = off[l + 1] - off[l];
        double s = 0;
        for (int i = threadIdx.x; i < sz; i += 256) {
            float dm = g_st[2 * 3840 + o0 + i] - g_st[0 * 3840 + o0 + i];
            float ds = g_st[3 * 3840 + o0 + i] - g_st[1 * 3840 + o0 + i];
            s += (double)dm * dm + (double)ds * ds;
        }
        red[threadIdx.x] = s; __syncthreads();
        for (int o = 128; o > 0; o >>= 1) { if (threadIdx.x < o) red[threadIdx.x] += red[threadIdx.x + o]; __syncthreads(); }
        if (threadIdx.x == 0) slv += red[0] / sz;
        __syncthreads();
    }
    if (threadIdx.x == 0) out[0] = (float)closs + 0.01f * (float)slv;
}

extern "C" void kernel_launch(void* const* d_in, const int* in_sizes, int n_in,
                              void* d_out, int out_size) {
    (void)in_sizes; (void)n_in; (void)out_size;
    const float* in[18];
    for (int i = 0; i < 18; i++) in[i] = (const float*)d_in[i];

    float *b0, *b1, *in8, *f4, *f4t, *f4e, *dec, *Y, *Z, *Tt, *cov, *aw, *Tm, *st;
    cudaGetSymbolAddress((void**)&b0, g_b0);
    cudaGetSymbolAddress((void**)&b1, g_b1);
    cudaGetSymbolAddress((void**)&in8, g_in8);
    cudaGetSymbolAddress((void**)&f4, g_f4);
    cudaGetSymbolAddress((void**)&f4t, g_f4t);
    cudaGetSymbolAddress((void**)&f4e, g_f4e);
    cudaGetSymbolAddress((void**)&dec, g_dec);
    cudaGetSymbolAddress((void**)&Y, g_Y);
    cudaGetSymbolAddress((void**)&Z, g_Z);
    cudaGetSymbolAddress((void**)&Tt, g_Tt);
    cudaGetSymbolAddress((void**)&cov, g_cov);
    cudaGetSymbolAddress((void**)&aw, g_aw);
    cudaGetSymbolAddress((void**)&Tm, g_Tm);
    cudaGetSymbolAddress((void**)&st, g_st);
    float* aw1 = aw + 6291456;

    auto conv = [&](const float* i0, float* o, const float* w, const float* bb,
                    int Cin, int Cout, int H, int relu, int B) {
        if (Cin >= 64 && Cout >= 64) {
            dim3 g((B * H * H) / 128, (Cout + 127) / 128, 1);
            k_cgemm<<<g, 256>>>(i0, w, bb, o, Cin, Cout, H, relu);
        } else if (H >= 64) {
            dim3 g((H / 32) * (H / 32), (Cout + 15) / 16, B);
            k_conv<16><<<g, 256>>>(i0, w, bb, o, Cin, Cout, H, relu);
        } else {
            dim3 g((H / 32) * (H / 32), (Cout + 7) / 8, B);
            k_conv<8><<<g, 256>>>(i0, w, bb, o, Cin, Cout, H, relu);
        }
    };
    auto pool = [&](const float* i0, float* o, int C, int Ho, int B) {
        int tot = B * C * Ho * Ho; int g = (tot + 255) / 256;
        if (Ho == 128) k_pool<128><<<g, 256>>>(i0, o, tot);
        else if (Ho == 64) k_pool<64><<<g, 256>>>(i0, o, tot);
        else k_pool<32><<<g, 256>>>(i0, o, tot);
    };
    auto up = [&](const float* i0, float* o, int C, int Ho) {
        int tot = 4 * C * Ho * Ho; int g = (tot + 255) / 256;
        if (Ho == 64) k_up<64><<<g, 256>>>(i0, o, tot);
        else if (Ho == 128) k_up<128><<<g, 256>>>(i0, o, tot);
        else k_up<256><<<g, 256>>>(i0, o, tot);
    };
    auto enc = [&](const float* x, int B, float* f4o, float* mo, float* so, int soff) {
        conv(x, b0, in[2], in[3], 3, 64, 256, 1, B);
        if (mo) k_stats<<<4 * 64, 256>>>(b0 + (size_t)soff * 64 * 65536, 65536, mo, so);
        pool(b0, b1, 64, 128, B);
        conv(b1, b0, in[4], in[5], 64, 128, 128, 1, B);
        if (mo) k_stats<<<4 * 128, 256>>>(b0 + (size_t)soff * 128 * 16384, 16384, mo + 256, so + 256);
        pool(b0, b1, 128, 64, B);
        conv(b1, b0, in[6], in[7], 128, 256, 64, 1, B);
        if (mo) k_stats<<<4 * 256, 256>>>(b0 + (size_t)soff * 256 * 4096, 4096, mo + 768, so + 768);
        pool(b0, b1, 256, 32, B);
        conv(b1, f4o, in[8], in[9], 256, 512, 32, 1, B);
        if (mo) k_stats<<<4 * 512, 256>>>(f4o + (size_t)soff * 512 * 1024, 1024, mo + 1792, so + 1792);
    };

    cudaMemcpyAsync(in8, in[0], 786432 * 4, cudaMemcpyDeviceToDevice);
    cudaMemcpyAsync(in8 + 786432, in[1], 786432 * 4, cudaMemcpyDeviceToDevice);
    k_dummy<<<1, 256>>>();
    k_dummy<<<1, 256>>>();

    enc(in8, 8, f4, st + 0, st + 3840, 4);

    k_transp<<<dim3(8, 16, 32), dim3(32, 8)>>>();
    k_kmeans<<<8, 1024>>>();

    k_aw<<<(12582912 + 255) / 256, 256>>>();
    k_covg<<<dim3(10, 1, 24), 256>>>();
    k_norm<<<24, 256>>>();
    k_nsinit<<<((6291456 + 255) / 256), 256>>>();

    dim3 gs(10, 1, 24);
    k_gemmsym<<<gs, 256>>>(Y, Y, cov, Y, 1);
    k_gemmsym<<<gs, 256>>>(Y, cov, aw, cov, 0);
    float* Yc = aw; float* Zc = cov;
    float* fr[4] = {Y, Z, Tt, aw1};
    for (int it = 0; it < 14; it++) {
        float* M = fr[0]; float* P = fr[1]; float* Yn = fr[2]; float* Zn = fr[3];
        k_gemmsym<<<gs, 256>>>(Zc, Yc, M, Zc, 0);
        k_gemmsym<<<gs, 256>>>(M, M, P, M, 1);
        if (it < 13) {
            k_gemmsym<<<gs, 256>>>(Yc, P, Yn, Yc, 0);
            k_gemmsym<<<gs, 256>>>(P, Zc, Zn, P, 0);
        } else {
            size_t so12 = (size_t)12 * MS;
            k_gemmsym<<<dim3(10, 1, 12), 256>>>(Yc + so12, P + so12, Yn + so12, Yc + so12, 0);
            k_gemmsym<<<dim3(10, 1, 12), 256>>>(P, Zc, Zn, P, 0);
        }
        fr[0] = Yc; fr[1] = Zc; fr[2] = M; fr[3] = P;
        Yc = Yn; Zc = Zn;
    }

    k_gemm16<<<dim3(4, 4, 12), 256>>>(Yc + (size_t)12 * MS, MS, Zc, MS, 0,
                                      Tm, MS, 512, 1.f, 1);
    float* tp = fr[0];
    k_gemm16<<<dim3(8, 4, 12), 256>>>(Tm, MS, f4, 524288, 1, tp, 524288, 1024, 1.f, 0);
    k_gemv<<<12, 512>>>();
    k_comb<<<(2097152 + 255) / 256, 256>>>(tp);

    conv(f4t, b0, in[10], in[11], 512, 256, 32, 1, 4);
    up(b0, b1, 256, 64);
    conv(b1, b0, in[12], in[13], 256, 128, 64, 1, 4);
    up(b0, b1, 128, 128);
    conv(b1, b0, in[14], in[15], 128, 64, 128, 1, 4);
    up(b0, b1, 64, 256);
    conv(b1, dec, in[16], in[17], 64, 3, 256, 0, 4);

    enc(dec, 4, f4e, st + 2 * 3840, st + 3 * 3840, 0);

    k_closs1<<<256, 256>>>();
    k_final<<<1, 256>>>((float*)d_out);
}

// round 14
// speedup vs baseline: 2.0932x; 1.0254x over previous
#include <cuda_runtime.h>
#include <math.h>

#define MS 262144
__device__ float g_b0[33554432];
__device__ float g_b1[33554432];
__device__ float g_in8[1572864];
__device__ float g_f4[4194304];
__device__ float g_f4t[2097152];
__device__ float g_f4e[2097152];
__device__ float g_dec[786432];
__device__ float g_fT[4194304];
__device__ float g_cent[12288];
__device__ int   g_asg[8192];
__device__ float g_cnt[24];
__device__ float g_aw[12582912];
__device__ float g_cov[6291456];
__device__ float g_Y[6291456];
__device__ float g_Z[6291456];
__device__ float g_Tt[6291456];
__device__ float g_nrm[24];
__device__ float g_Tm[3145728];
__device__ float g_vv[6144];
__device__ float g_st[15360];
__device__ double g_part[256];

__constant__ int c_pi[10] = {0,0,0,0,1,1,1,2,2,3};
__constant__ int c_pj[10] = {0,1,2,3,1,2,3,2,3,3};

__global__ void k_dummy() { g_part[threadIdx.x] = 0.0; }

// ---------- implicit-GEMM conv 3x3, 128x128 tile ----------
__global__ void __launch_bounds__(256, 2) k_cgemm(
    const float* __restrict__ in, const float* __restrict__ w,
    const float* __restrict__ bias, float* __restrict__ out,
    int Cin, int Cout, int H, int relu)
{
    __shared__ float sA[2][16][128], sB[2][16][128];
    int K = Cin * 9, HH = H * H;
    int m0 = blockIdx.y * 128, n0 = blockIdx.x * 128;
    int tid = threadIdx.x;
    int ar = tid >> 1, ac = (tid & 1) * 8;
    int brk = tid >> 4, bcg = (tid & 15) * 8;
    int ty = tid >> 4, tx = tid & 15;
    int b = n0 / HH, rem0 = n0 - b * HH;
    int cy[8], cx[8];
#pragma unroll
    for (int j = 0; j < 8; j++) {
        int rem = rem0 + bcg + j;
        int yy = rem / H;
        cy[j] = yy; cx[j] = rem - yy * H;
    }
    const float* inb = in + (size_t)b * Cin * HH;
    float acc[8][8];
#pragma unroll
    for (int a = 0; a < 8; a++)
#pragma unroll
        for (int q = 0; q < 8; q++) acc[a][q] = 0.f;
    float ra[8], rb[8];
    int aok = (m0 + ar) < Cout;
    const float* awp = w + (size_t)(aok ? m0 + ar : 0) * K + ac;
    if (aok) { *(float4*)ra = *(const float4*)awp; *(float4*)(ra+4) = *(const float4*)(awp+4); }
    else { for (int i = 0; i < 8; i++) ra[i] = 0.f; }
    {
        int k = brk;
        int ic = k / 9, rs = k - ic * 9;
        int dy = rs / 3 - 1, dx = rs - (rs / 3) * 3 - 1;
        const float* ip = inb + (size_t)ic * HH;
#pragma unroll
        for (int j = 0; j < 8; j++) {
            int yy = cy[j] + dy, xx = cx[j] + dx;
            rb[j] = (yy >= 0 && yy < H && xx >= 0 && xx < H) ? ip[yy * H + xx] : 0.f;
        }
    }
    int nk = K / 16;
#pragma unroll
    for (int i = 0; i < 8; i++) sA[0][ac + i][ar] = ra[i];
#pragma unroll
    for (int j = 0; j < 8; j++) sB[0][brk][bcg + j] = rb[j];
    __syncthreads();
    for (int s = 0; s < nk; s++) {
        int buf = s & 1;
        if (s + 1 < nk) {
            int k0 = (s + 1) * 16;
            if (aok) { *(float4*)ra = *(const float4*)(awp + k0); *(float4*)(ra+4) = *(const float4*)(awp + k0 + 4); }
            int k = k0 + brk;
            int ic = k / 9, rs = k - ic * 9;
            int dy = rs / 3 - 1, dx = rs - (rs / 3) * 3 - 1;
            const float* ip = inb + (size_t)ic * HH;
#pragma unroll
            for (int j = 0; j < 8; j++) {
                int yy = cy[j] + dy, xx = cx[j] + dx;
                rb[j] = (yy >= 0 && yy < H && xx >= 0 && xx < H) ? ip[yy * H + xx] : 0.f;
            }
        }
#pragma unroll
        for (int k = 0; k < 16; k++) {
            float av[8], bv[8];
            *(float4*)av = *(float4*)&sA[buf][k][ty * 8]; *(float4*)(av+4) = *(float4*)&sA[buf][k][ty * 8 + 4];
            *(float4*)bv = *(float4*)&sB[buf][k][tx * 8]; *(float4*)(bv+4) = *(float4*)&sB[buf][k][tx * 8 + 4];
#pragma unroll
            for (int a = 0; a < 8; a++)
#pragma unroll
                for (int q = 0; q < 8; q++) acc[a][q] += av[a] * bv[q];
        }
        if (s + 1 < nk) {
            int nb = buf ^ 1;
#pragma unroll
            for (int i = 0; i < 8; i++) sA[nb][ac + i][ar] = ra[i];
#pragma unroll
            for (int j = 0; j < 8; j++) sB[nb][brk][bcg + j] = rb[j];
            __syncthreads();
        }
    }
#pragma unroll
    for (int a = 0; a < 8; a++) {
        int oc = m0 + ty * 8 + a;
        if (oc >= Cout) break;
        float bv = bias[oc];
        float* op = out + ((size_t)b * Cout + oc) * HH;
#pragma unroll
        for (int q = 0; q < 8; q++) {
            float v = acc[a][q] + bv;
            if (relu) v = fmaxf(v, 0.f);
            op[rem0 + tx * 8 + q] = v;
        }
    }
}

// ---------- implicit-GEMM conv 3x3, 64x64 tile (small grids) ----------
__global__ void __launch_bounds__(256, 4) k_cgemm64(
    const float* __restrict__ in, const float* __restrict__ w,
    const float* __restrict__ bias, float* __restrict__ out,
    int Cin, int Cout, int H, int relu)
{
    __shared__ float sA[2][16][64], sB[2][16][64];
    int K = Cin * 9, HH = H * H;
    int m0 = blockIdx.y * 64, n0 = blockIdx.x * 64;
    int tid = threadIdx.x;
    int ar = tid >> 2, ac = (tid & 3) * 4;
    int brk = tid >> 4, bcg = (tid & 15) * 4;
    int ty = tid >> 4, tx = tid & 15;
    int b = n0 / HH, rem0 = n0 - b * HH;
    int cy[4], cx[4];
#pragma unroll
    for (int j = 0; j < 4; j++) {
        int rem = rem0 + bcg + j;
        int yy = rem / H;
        cy[j] = yy; cx[j] = rem - yy * H;
    }
    const float* inb = in + (size_t)b * Cin * HH;
    float acc[4][4];
#pragma unroll
    for (int a = 0; a < 4; a++)
#pragma unroll
        for (int q = 0; q < 4; q++) acc[a][q] = 0.f;
    float ra[4], rb[4];
    int aok = (m0 + ar) < Cout;
    const float* awp = w + (size_t)(aok ? m0 + ar : 0) * K + ac;
    if (aok) *(float4*)ra = *(const float4*)awp;
    else { for (int i = 0; i < 4; i++) ra[i] = 0.f; }
    {
        int k = brk;
        int ic = k / 9, rs = k - ic * 9;
        int dy = rs / 3 - 1, dx = rs - (rs / 3) * 3 - 1;
        const float* ip = inb + (size_t)ic * HH;
#pragma unroll
        for (int j = 0; j < 4; j++) {
            int yy = cy[j] + dy, xx = cx[j] + dx;
            rb[j] = (yy >= 0 && yy < H && xx >= 0 && xx < H) ? ip[yy * H + xx] : 0.f;
        }
    }
    int nk = K / 16;
#pragma unroll
    for (int i = 0; i < 4; i++) sA[0][ac + i][ar] = ra[i];
#pragma unroll
    for (int j = 0; j < 4; j++) sB[0][brk][bcg + j] = rb[j];
    __syncthreads();
    for (int s = 0; s < nk; s++) {
        int buf = s & 1;
        if (s + 1 < nk) {
            int k0 = (s + 1) * 16;
            if (aok) *(float4*)ra = *(const float4*)(awp + k0);
            int k = k0 + brk;
            int ic = k / 9, rs = k - ic * 9;
            int dy = rs / 3 - 1, dx = rs - (rs / 3) * 3 - 1;
            const float* ip = inb + (size_t)ic * HH;
#pragma unroll
            for (int j = 0; j < 4; j++) {
                int yy = cy[j] + dy, xx = cx[j] + dx;
                rb[j] = (yy >= 0 && yy < H && xx >= 0 && xx < H) ? ip[yy * H + xx] : 0.f;
            }
        }
#pragma unroll
        for (int k = 0; k < 16; k++) {
            float av[4], bv[4];
            *(float4*)av = *(float4*)&sA[buf][k][ty * 4];
            *(float4*)bv = *(float4*)&sB[buf][k][tx * 4];
#pragma unroll
            for (int a = 0; a < 4; a++)
#pragma unroll
                for (int q = 0; q < 4; q++) acc[a][q] += av[a] * bv[q];
        }
        if (s + 1 < nk) {
            int nb = buf ^ 1;
#pragma unroll
            for (int i = 0; i < 4; i++) sA[nb][ac + i][ar] = ra[i];
#pragma unroll
            for (int j = 0; j < 4; j++) sB[nb][brk][bcg + j] = rb[j];
            __syncthreads();
        }
    }
#pragma unroll
    for (int a = 0; a < 4; a++) {
        int oc = m0 + ty * 4 + a;
        if (oc >= Cout) break;
        float bv = bias[oc];
        float* op = out + ((size_t)b * Cout + oc) * HH;
#pragma unroll
        for (int q = 0; q < 4; q++) {
            float v = acc[a][q] + bv;
            if (relu) v = fmaxf(v, 0.f);
            op[rem0 + tx * 4 + q] = v;
        }
    }
}

template<int OCB>
__global__ void __launch_bounds__(256) k_conv(const float* __restrict__ in,
    const float* __restrict__ w, const float* __restrict__ bias,
    float* __restrict__ out, int Cin, int Cout, int H, int relu)
{
    __shared__ float sI[34][36];
    __shared__ float sW[OCB][9];
    int tiles = H >> 5;
    int bx = blockIdx.x % tiles, by = blockIdx.x / tiles;
    int x0 = bx * 32, y0 = by * 32;
    int oc0 = blockIdx.y * OCB, b = blockIdx.z;
    int tid = threadIdx.x;
    int lx = (tid & 15) * 2, ly = (tid >> 4) * 2;
    float acc[OCB][4];
#pragma unroll
    for (int o = 0; o < OCB; o++) { acc[o][0]=0.f; acc[o][1]=0.f; acc[o][2]=0.f; acc[o][3]=0.f; }
    const float* ib = in + (size_t)b * Cin * H * H;
    for (int ic = 0; ic < Cin; ic++) {
        __syncthreads();
        const float* ip = ib + (size_t)ic * H * H;
        for (int i = tid; i < 34 * 34; i += 256) {
            int yy = i / 34, xx = i - yy * 34;
            int gy = y0 + yy - 1, gx = x0 + xx - 1;
            sI[yy][xx] = (gy >= 0 && gy < H && gx >= 0 && gx < H) ? ip[gy * H + gx] : 0.f;
        }
        if (tid < OCB * 9) {
            int oc = tid / 9, tt = tid - oc * 9;
            sW[oc][tt] = (oc0 + oc < Cout) ? w[((size_t)(oc0 + oc) * Cin + ic) * 9 + tt] : 0.f;
        }
        __syncthreads();
        float win[4][4];
#pragma unroll
        for (int r = 0; r < 4; r++)
#pragma unroll
            for (int s = 0; s < 4; s++) win[r][s] = sI[ly + r][lx + s];
#pragma unroll
        for (int o = 0; o < OCB; o++) {
            float w0=sW[o][0],w1=sW[o][1],w2=sW[o][2],w3=sW[o][3],w4=sW[o][4];
            float w5=sW[o][5],w6=sW[o][6],w7=sW[o][7],w8=sW[o][8];
#pragma unroll
            for (int p = 0; p < 4; p++) {
                int pr = p >> 1, pc = p & 1;
                acc[o][p] += win[pr][pc]*w0 + win[pr][pc+1]*w1 + win[pr][pc+2]*w2
                           + win[pr+1][pc]*w3 + win[pr+1][pc+1]*w4 + win[pr+1][pc+2]*w5
                           + win[pr+2][pc]*w6 + win[pr+2][pc+1]*w7 + win[pr+2][pc+2]*w8;
            }
        }
    }
#pragma unroll
    for (int o = 0; o < OCB; o++) {
        int oc = oc0 + o;
        if (oc >= Cout) break;
        float bv = bias[oc];
        float* op = out + ((size_t)b * Cout + oc) * H * H;
#pragma unroll
        for (int p = 0; p < 4; p++) {
            float v = acc[o][p] + bv;
            if (relu) v = fmaxf(v, 0.f);
            op[(y0 + ly + (p >> 1)) * H + x0 + lx + (p & 1)] = v;
        }
    }
}

template<int HO>
__global__ void k_pool(const float* __restrict__ in, float* __restrict__ out, int tot) {
    int i = blockIdx.x * 256 + threadIdx.x;
    if (i >= tot) return;
    int x = i % HO, y = (i / HO) % HO; int bc = i / (HO * HO);
    const int Hi = HO * 2;
    const float* p = in + (size_t)bc * Hi * Hi;
    out[i] = (p[(2*y)*Hi + 2*x] + p[(2*y)*Hi + 2*x+1] + p[(2*y+1)*Hi + 2*x] + p[(2*y+1)*Hi + 2*x+1]) * 0.25f;
}

template<int HO>
__global__ void k_up(const float* __restrict__ in, float* __restrict__ out, int tot) {
    int i = blockIdx.x * 256 + threadIdx.x;
    if (i >= tot) return;
    int x = i % HO, y = (i / HO) % HO; int bc = i / (HO * HO);
    const int Hi = HO >> 1;
    out[i] = in[(size_t)bc * Hi * Hi + (y >> 1) * Hi + (x >> 1)];
}

// high-MLP two-pass stats: float4 loads, 4 independent double accumulators
__global__ void __launch_bounds__(256) k_stats(const float* __restrict__ in, int HW,
                                               float* __restrict__ mo, float* __restrict__ so) {
    __shared__ double red[256];
    int bc = blockIdx.x, tid = threadIdx.x;
    const float* p = in + (size_t)bc * HW;
    double a0 = 0, a1 = 0, a2 = 0, a3 = 0;
#pragma unroll 4
    for (int i = tid * 4; i < HW; i += 1024) {
        float4 v = *(const float4*)(p + i);
        a0 += v.x; a1 += v.y; a2 += v.z; a3 += v.w;
    }
    red[tid] = (a0 + a1) + (a2 + a3); __syncthreads();
    for (int o = 128; o > 0; o >>= 1) { if (tid < o) red[tid] += red[tid + o]; __syncthreads(); }
    double m = red[0] / HW;
    __syncthreads();
    a0 = a1 = a2 = a3 = 0;
#pragma unroll 4
    for (int i = tid * 4; i < HW; i += 1024) {
        float4 v = *(const float4*)(p + i);
        double d0 = v.x - m, d1 = v.y - m, d2 = v.z - m, d3 = v.w - m;
        a0 += d0 * d0; a1 += d1 * d1; a2 += d2 * d2; a3 += d3 * d3;
    }
    red[tid] = (a0 + a1) + (a2 + a3); __syncthreads();
    for (int o = 128; o > 0; o >>= 1) { if (tid < o) red[tid] += red[tid + o]; __syncthreads(); }
    if (tid == 0) { mo[bc] = (float)m; so[bc] = (float)sqrt(red[0] / HW); }
}

__global__ void k_transp() {
    __shared__ float t[32][33];
    int sb = blockIdx.x, c0 = blockIdx.y * 32, n0 = blockIdx.z * 32;
    const float* f = g_f4 + (size_t)sb * 524288;
    int tx = threadIdx.x, ty = threadIdx.y;
    for (int j = 0; j < 32; j += 8) t[ty + j][tx] = f[(c0 + ty + j) * 1024 + n0 + tx];
    __syncthreads();
    for (int j = 0; j < 32; j += 8) g_fT[(size_t)sb * 524288 + (size_t)(n0 + ty + j) * 512 + c0 + tx] = t[tx][ty + j];
}

__global__ void __launch_bounds__(1024) k_kmeans() {
    __shared__ float sc[3][512];
    __shared__ int sa[1024];
    int sb = blockIdx.x, tid = threadIdx.x;
    const float* f = g_f4 + (size_t)sb * 524288;
    const float* ft = g_fT + (size_t)sb * 524288;
    if (tid < 512) {
        sc[0][tid] = f[tid * 1024 + 0];
        sc[1][tid] = f[tid * 1024 + 1];
        sc[2][tid] = f[tid * 1024 + 2];
    }
    __syncthreads();
    int n0c = 0, n1c = 0, n2c = 0;
    for (int it = 0; it < 11; it++) {
        {
            int n = tid;
            float d0 = 0, d1 = 0, d2 = 0;
            for (int c = 0; c < 512; c++) {
                float v = f[c * 1024 + n];
                float a = v - sc[0][c], b = v - sc[1][c], e = v - sc[2][c];
                d0 += a * a; d1 += b * b; d2 += e * e;
            }
            int a = 0; float best = d0;
            if (d1 < best) { best = d1; a = 1; }
            if (d2 < best) { a = 2; }
            sa[n] = a;
        }
        __syncthreads();
        if (tid < 512) {
            float s0 = 0, s1 = 0, s2 = 0; int c0 = 0, c1 = 0, c2 = 0;
            for (int n = 0; n < 1024; n++) {
                float v = ft[n * 512 + tid];
                int a = sa[n];
                if (a == 0) { s0 += v; c0++; } else if (a == 1) { s1 += v; c1++; } else { s2 += v; c2++; }
            }
            sc[0][tid] = s0 / ((float)c0 + 1e-6f);
            sc[1][tid] = s1 / ((float)c1 + 1e-6f);
            sc[2][tid] = s2 / ((float)c2 + 1e-6f);
            n0c = c0; n1c = c1; n2c = c2;
        }
        __syncthreads();
    }
    if (tid < 512) {
        g_cent[sb * 1536 + tid] = sc[0][tid];
        g_cent[sb * 1536 + 512 + tid] = sc[1][tid];
        g_cent[sb * 1536 + 1024 + tid] = sc[2][tid];
        if (tid < 3) g_cnt[sb * 3 + tid] = (float)(tid == 0 ? n0c : (tid == 1 ? n1c : n2c));
    }
    g_asg[sb * 1024 + tid] = sa[tid];
}

__global__ void k_aw() {
    int i = blockIdx.x * 256 + threadIdx.x;
    if (i >= 12582912) return;
    int n = i & 1023, c = (i >> 10) & 511, m = i >> 19;
    int k = m % 3, sb = m / 3;
    const float* f = g_f4 + (size_t)sb * 524288;
    int a = g_asg[sb * 1024 + n];
    g_aw[i] = (a == k) ? f[c * 1024 + n] - g_cent[sb * 1536 + k * 512 + c] : 0.f;
}

__global__ void __launch_bounds__(256, 2) k_covg() {
    __shared__ float sA[16][128], sB[16][128];
    int m = blockIdx.z;
    const float* A = g_aw + (size_t)m * 524288;
    int bi = c_pi[blockIdx.x], bj = c_pj[blockIdx.x];
    int i0 = bi * 128, j0 = bj * 128;
    int tid = threadIdx.x;
    int ar = tid >> 1, ac = (tid & 1) * 8;
    int ty = tid >> 4, tx = tid & 15;
    float acc[8][8];
#pragma unroll
    for (int a = 0; a < 8; a++)
#pragma unroll
        for (int b = 0; b < 8; b++) acc[a][b] = 0.f;
    float4 ra0 = *(const float4*)&A[(size_t)(i0 + ar) * 1024 + ac];
    float4 ra1 = *(const float4*)&A[(size_t)(i0 + ar) * 1024 + ac + 4];
    float4 rb0 = *(const float4*)&A[(size_t)(j0 + ar) * 1024 + ac];
    float4 rb1 = *(const float4*)&A[(size_t)(j0 + ar) * 1024 + ac + 4];
    for (int k0 = 0; k0 < 1024; k0 += 16) {
        sA[ac+0][ar]=ra0.x; sA[ac+1][ar]=ra0.y; sA[ac+2][ar]=ra0.z; sA[ac+3][ar]=ra0.w;
        sA[ac+4][ar]=ra1.x; sA[ac+5][ar]=ra1.y; sA[ac+6][ar]=ra1.z; sA[ac+7][ar]=ra1.w;
        sB[ac+0][ar]=rb0.x; sB[ac+1][ar]=rb0.y; sB[ac+2][ar]=rb0.z; sB[ac+3][ar]=rb0.w;
        sB[ac+4][ar]=rb1.x; sB[ac+5][ar]=rb1.y; sB[ac+6][ar]=rb1.z; sB[ac+7][ar]=rb1.w;
        __syncthreads();
        if (k0 + 16 < 1024) {
            ra0 = *(const float4*)&A[(size_t)(i0 + ar) * 1024 + k0 + 16 + ac];
            ra1 = *(const float4*)&A[(size_t)(i0 + ar) * 1024 + k0 + 16 + ac + 4];
            rb0 = *(const float4*)&A[(size_t)(j0 + ar) * 1024 + k0 + 16 + ac];
            rb1 = *(const float4*)&A[(size_t)(j0 + ar) * 1024 + k0 + 16 + ac + 4];
        }
#pragma unroll
        for (int k = 0; k < 16; k++) {
            float av[8], bv[8];
            *(float4*)av = *(float4*)&sA[k][ty * 8]; *(float4*)(av+4) = *(float4*)&sA[k][ty * 8 + 4];
            *(float4*)bv = *(float4*)&sB[k][tx * 8]; *(float4*)(bv+4) = *(float4*)&sB[k][tx * 8 + 4];
#pragma unroll
            for (int a = 0; a < 8; a++)
#pragma unroll
                for (int b = 0; b < 8; b++) acc[a][b] += av[a] * bv[b];
        }
        __syncthreads();
    }
    float nc = g_cnt[m] + 1e-6f;
    float* C = g_cov + (size_t)m * MS;
#pragma unroll
    for (int a = 0; a < 8; a++)
#pragma unroll
        for (int b = 0; b < 8; b++) {
            int gi = i0 + ty * 8 + a, gj = j0 + tx * 8 + b;
            float v = acc[a][b] / nc + (gi == gj ? 0.1f : 0.f);
            C[gi * 512 + gj] = v;
            if (bi != bj) C[gj * 512 + gi] = v;
        }
}

__global__ void __launch_bounds__(256) k_norm() {
    __shared__ float red[256];
    int m = blockIdx.x;
    const float* A = g_cov + (size_t)m * MS;
    float mx = 0;
    for (int r = threadIdx.x; r < 512; r += 256) {
        float s = 0;
        for (int c = 0; c < 512; c++) s += fabsf(A[r * 512 + c]);
        mx = fmaxf(mx, s);
    }
    red[threadIdx.x] = mx; __syncthreads();
    for (int o = 128; o > 0; o >>= 1) { if (threadIdx.x < o) red[threadIdx.x] = fmaxf(red[threadIdx.x], red[threadIdx.x + o]); __syncthreads(); }
    if (threadIdx.x == 0) g_nrm[m] = red[0];
}

__global__ void k_nsinit() {
    int i = blockIdx.x * 256 + threadIdx.x;
    if (i >= 6291456) return;
    int m = i >> 18;
    g_Y[i] = g_cov[i] / g_nrm[m];
}

__global__ void __launch_bounds__(256, 2) k_gemmsym(
    const float* __restrict__ A, const float* __restrict__ B,
    float* __restrict__ C, const float* __restrict__ Mp, int polymode)
{
    __shared__ float sA[2][16][128], sB[2][16][128];
    int z = blockIdx.z;
    const float* Ab = A + (size_t)z * MS;
    const float* Bb = B + (size_t)z * MS;
    float* Cb = C + (size_t)z * MS;
    const float* Mb = Mp + (size_t)z * MS;
    int bi = c_pi[blockIdx.x], bj = c_pj[blockIdx.x];
    int m0 = bi * 128, n0 = bj * 128;
    int tid = threadIdx.x;
    int ar = tid >> 1, ac = (tid & 1) * 8;
    int br = tid >> 4, bc = (tid & 15) * 8;
    int ty = tid >> 4, tx = tid & 15;
    float acc[8][8];
#pragma unroll
    for (int a = 0; a < 8; a++)
#pragma unroll
        for (int b = 0; b < 8; b++) acc[a][b] = 0.f;
    float4 ra0 = *(const float4*)&Ab[(size_t)(m0 + ar) * 512 + ac];
    float4 ra1 = *(const float4*)&Ab[(size_t)(m0 + ar) * 512 + ac + 4];
    float4 rb0 = *(const float4*)&Bb[(size_t)br * 512 + n0 + bc];
    float4 rb1 = *(const float4*)&Bb[(size_t)br * 512 + n0 + bc + 4];
    sA[0][ac+0][ar]=ra0.x; sA[0][ac+1][ar]=ra0.y; sA[0][ac+2][ar]=ra0.z; sA[0][ac+3][ar]=ra0.w;
    sA[0][ac+4][ar]=ra1.x; sA[0][ac+5][ar]=ra1.y; sA[0][ac+6][ar]=ra1.z; sA[0][ac+7][ar]=ra1.w;
    *(float4*)&sB[0][br][bc] = rb0; *(float4*)&sB[0][br][bc + 4] = rb1;
    __syncthreads();
    for (int s = 0; s < 32; s++) {
        int buf = s & 1;
        if (s < 31) {
            int k0 = (s + 1) * 16;
            ra0 = *(const float4*)&Ab[(size_t)(m0 + ar) * 512 + k0 + ac];
            ra1 = *(const float4*)&Ab[(size_t)(m0 + ar) * 512 + k0 + ac + 4];
            rb0 = *(const float4*)&Bb[(size_t)(k0 + br) * 512 + n0 + bc];
            rb1 = *(const float4*)&Bb[(size_t)(k0 + br) * 512 + n0 + bc + 4];
        }
#pragma unroll
        for (int k = 0; k < 16; k++) {
            float av[8], bv[8];
            *(float4*)av = *(float4*)&sA[buf][k][ty * 8]; *(float4*)(av+4) = *(float4*)&sA[buf][k][ty * 8 + 4];
            *(float4*)bv = *(float4*)&sB[buf][k][tx * 8]; *(float4*)(bv+4) = *(float4*)&sB[buf][k][tx * 8 + 4];
#pragma unroll
            for (int a = 0; a < 8; a++)
#pragma unroll
                for (int b = 0; b < 8; b++) acc[a][b] += av[a] * bv[b];
        }
        if (s < 31) {
            int nb = buf ^ 1;
            sA[nb][ac+0][ar]=ra0.x; sA[nb][ac+1][ar]=ra0.y; sA[nb][ac+2][ar]=ra0.z; sA[nb][ac+3][ar]=ra0.w;
            sA[nb][ac+4][ar]=ra1.x; sA[nb][ac+5][ar]=ra1.y; sA[nb][ac+6][ar]=ra1.z; sA[nb][ac+7][ar]=ra1.w;
            *(float4*)&sB[nb][br][bc] = rb0; *(float4*)&sB[nb][br][bc + 4] = rb1;
            __syncthreads();
        }
    }
#pragma unroll
    for (int a = 0; a < 8; a++) {
        int gi = m0 + ty * 8 + a;
#pragma unroll
        for (int b = 0; b < 8; b++) {
            int gj = n0 + tx * 8 + b;
            float v = acc[a][b];
            if (polymode)
                v = ((gi == gj ? 15.f : 0.f) - 10.f * Mb[(size_t)gi * 512 + gj] + 3.f * v) * 0.125f;
            Cb[(size_t)gi * 512 + gj] = v;
            if (bi != bj) Cb[(size_t)gj * 512 + gi] = v;
        }
    }
}

__global__ void __launch_bounds__(256, 2) k_gemm16(
    const float* __restrict__ A, int strA, const float* __restrict__ B, int strB, int bdiv,
    float* __restrict__ C, int strC, int N, float alpha, int nrmmode)
{
    __shared__ float sA[2][16][128], sB[2][16][128];
    int z = blockIdx.z;
    const float* Ab = A + (size_t)z * strA;
    const float* Bb = B + (size_t)(bdiv ? z / 3 : z) * strB;
    float* Cb = C + (size_t)z * strC;
    if (nrmmode) alpha = sqrtf(g_nrm[12 + z] / g_nrm[z]);
    int m0 = blockIdx.y * 128, n0 = blockIdx.x * 128;
    int tid = threadIdx.x;
    int ar = tid >> 1, ac = (tid & 1) * 8;
    int br = tid >> 4, bc = (tid & 15) * 8;
    int ty = tid >> 4, tx = tid & 15;
    float acc[8][8];
#pragma unroll
    for (int a = 0; a < 8; a++)
#pragma unroll
        for (int b = 0; b < 8; b++) acc[a][b] = 0.f;
    float4 ra0 = *(const float4*)&Ab[(size_t)(m0 + ar) * 512 + ac];
    float4 ra1 = *(const float4*)&Ab[(size_t)(m0 + ar) * 512 + ac + 4];
    float4 rb0 = *(const float4*)&Bb[(size_t)br * N + n0 + bc];
    float4 rb1 = *(const float4*)&Bb[(size_t)br * N + n0 + bc + 4];
    sA[0][ac+0][ar]=ra0.x; sA[0][ac+1][ar]=ra0.y; sA[0][ac+2][ar]=ra0.z; sA[0][ac+3][ar]=ra0.w;
    sA[0][ac+4][ar]=ra1.x; sA[0][ac+5][ar]=ra1.y; sA[0][ac+6][ar]=ra1.z; sA[0][ac+7][ar]=ra1.w;
    *(float4*)&sB[0][br][bc] = rb0; *(float4*)&sB[0][br][bc + 4] = rb1;
    __syncthreads();
    for (int s = 0; s < 32; s++) {
        int buf = s & 1;
        if (s < 31) {
            int k0 = (s + 1) * 16;
            ra0 = *(const float4*)&Ab[(size_t)(m0 + ar) * 512 + k0 + ac];
            ra1 = *(const float4*)&Ab[(size_t)(m0 + ar) * 512 + k0 + ac + 4];
            rb0 = *(const float4*)&Bb[(size_t)(k0 + br) * N + n0 + bc];
            rb1 = *(const float4*)&Bb[(size_t)(k0 + br) * N + n0 + bc + 4];
        }
#pragma unroll
        for (int k = 0; k < 16; k++) {
            float av[8], bv[8];
            *(float4*)av = *(float4*)&sA[buf][k][ty * 8]; *(float4*)(av+4) = *(float4*)&sA[buf][k][ty * 8 + 4];
            *(float4*)bv = *(float4*)&sB[buf][k][tx * 8]; *(float4*)(bv+4) = *(float4*)&sB[buf][k][tx * 8 + 4];
#pragma unroll
            for (int a = 0; a < 8; a++)
#pragma unroll
                for (int b = 0; b < 8; b++) acc[a][b] += av[a] * bv[b];
        }
        if (s < 31) {
            int nb = buf ^ 1;
            sA[nb][ac+0][ar]=ra0.x; sA[nb][ac+1][ar]=ra0.y; sA[nb][ac+2][ar]=ra0.z; sA[nb][ac+3][ar]=ra0.w;
            sA[nb][ac+4][ar]=ra1.x; sA[nb][ac+5][ar]=ra1.y; sA[nb][ac+6][ar]=ra1.z; sA[nb][ac+7][ar]=ra1.w;
            *(float4*)&sB[nb][br][bc] = rb0; *(float4*)&sB[nb][br][bc + 4] = rb1;
            __syncthreads();
        }
    }
#pragma unroll
    for (int a = 0; a < 8; a++) {
        int gm = m0 + ty * 8 + a;
#pragma unroll
        for (int b = 0; b < 8; b++) {
            int gn = n0 + tx * 8 + b;
            Cb[(size_t)gm * N + gn] = alpha * acc[a][b];
        }
    }
}

__global__ void __launch_bounds__(512) k_gemv() {
    __shared__ float mu[512];
    int z = blockIdx.x;
    int b = z / 3, k = z % 3;
    int tid = threadIdx.x;
    mu[tid] = g_cent[b * 1536 + k * 512 + tid];
    __syncthreads();
    const float* T = g_Tm + (size_t)z * MS;
    int warp = tid >> 5, lane = tid & 31;
    for (int c = warp; c < 512; c += 16) {
        float s = 0;
        for (int d = lane; d < 512; d += 32) s += T[c * 512 + d] * mu[d];
#pragma unroll
        for (int o = 16; o > 0; o >>= 1) s += __shfl_down_sync(0xffffffff, s, o);
        if (lane == 0) g_vv[z * 512 + c] = s;
    }
}

__global__ void k_comb(const float* __restrict__ tp) {
    int i = blockIdx.x * 256 + threadIdx.x;
    if (i >= 2097152) return;
    int n = i & 1023, c = (i >> 10) & 511, b = i >> 19;
    int a = g_asg[b * 1024 + n];
    int z = b * 3 + a;
    float val = tp[(size_t)z * 524288 + c * 1024 + n] - g_vv[z * 512 + c]
              + g_cent[(4 + b) * 1536 + a * 512 + c];
    g_f4t[i] = 0.6f * val + 0.4f * g_f4[i];
}

__global__ void __launch_bounds__(256) k_closs1() {
    __shared__ double red[256];
    int start = blockIdx.x * 8192;
    double s = 0;
    for (int i = threadIdx.x; i < 8192; i += 256) {
        float d = g_f4e[start + i] - g_f4[start + i];
        s += (double)d * d;
    }
    red[threadIdx.x] = s; __syncthreads();
    for (int o = 128; o > 0; o >>= 1) { if (threadIdx.x < o) red[threadIdx.x] += red[threadIdx.x + o]; __syncthreads(); }
    if (threadIdx.x == 0) g_part[blockIdx.x] = red[0];
}

__global__ void __launch_bounds__(256) k_final(float* out) {
    __shared__ double red[256];
    __shared__ double slv;
    __shared__ double closs;
    const int off[5] = {0, 256, 768, 1792, 3840};
    if (threadIdx.x == 0) slv = 0;
    red[threadIdx.x] = g_part[threadIdx.x];
    __syncthreads();
    for (int o = 128; o > 0; o >>= 1) { if (threadIdx.x < o) red[threadIdx.x] += red[threadIdx.x + o]; __syncthreads(); }
    if (threadIdx.x == 0) closs = red[0] / 2097152.0;
    __syncthreads();
    for (int l = 0; l < 4; l++) {
        int o0 = off[l], sz = off[l + 1] - off[l];
        double s = 0;
        for (int i = threadIdx.x; i < sz; i += 256) {
            float dm = g_st[2 * 3840 + o0 + i] - g_st[0 * 3840 + o0 + i];
            float ds = g_st[3 * 3840 + o0 + i] - g_st[1 * 3840 + o0 + i];
            s += (double)dm * dm + (double)ds * ds;
        }
        red[threadIdx.x] = s; __syncthreads();
        for (int o = 128; o > 0; o >>= 1) { if (threadIdx.x < o) red[threadIdx.x] += red[threadIdx.x + o]; __syncthreads(); }
        if (threadIdx.x == 0) slv += red[0] / sz;
        __syncthreads();
    }
    if (threadIdx.x == 0) out[0] = (float)closs + 0.01f * (float)slv;
}

extern "C" void kernel_launch(void* const* d_in, const int* in_sizes, int n_in,
                              void* d_out, int out_size) {
    (void)in_sizes; (void)n_in; (void)out_size;
    const float* in[18];
    for (int i = 0; i < 18; i++) in[i] = (const float*)d_in[i];

    float *b0, *b1, *in8, *f4, *f4t, *f4e, *dec, *Y, *Z, *Tt, *cov, *aw, *Tm, *st;
    cudaGetSymbolAddress((void**)&b0, g_b0);
    cudaGetSymbolAddress((void**)&b1, g_b1);
    cudaGetSymbolAddress((void**)&in8, g_in8);
    cudaGetSymbolAddress((void**)&f4, g_f4);
    cudaGetSymbolAddress((void**)&f4t, g_f4t);
    cudaGetSymbolAddress((void**)&f4e, g_f4e);
    cudaGetSymbolAddress((void**)&dec, g_dec);
    cudaGetSymbolAddress((void**)&Y, g_Y);
    cudaGetSymbolAddress((void**)&Z, g_Z);
    cudaGetSymbolAddress((void**)&Tt, g_Tt);
    cudaGetSymbolAddress((void**)&cov, g_cov);
    cudaGetSymbolAddress((void**)&aw, g_aw);
    cudaGetSymbolAddress((void**)&Tm, g_Tm);
    cudaGetSymbolAddress((void**)&st, g_st);
    float* aw1 = aw + 6291456;

    auto conv = [&](const float* i0, float* o, const float* w, const float* bb,
                    int Cin, int Cout, int H, int relu, int B) {
        if (Cin >= 64 && Cout >= 64) {
            int bx = (B * H * H) / 128, by = (Cout + 127) / 128;
            if (bx * by >= 148) {
                k_cgemm<<<dim3(bx, by, 1), 256>>>(i0, w, bb, o, Cin, Cout, H, relu);
            } else {
                dim3 g((B * H * H) / 64, (Cout + 63) / 64, 1);
                k_cgemm64<<<g, 256>>>(i0, w, bb, o, Cin, Cout, H, relu);
            }
        } else if (H >= 64) {
            dim3 g((H / 32) * (H / 32), (Cout + 15) / 16, B);
            k_conv<16><<<g, 256>>>(i0, w, bb, o, Cin, Cout, H, relu);
        } else {
            dim3 g((H / 32) * (H / 32), (Cout + 7) / 8, B);
            k_conv<8><<<g, 256>>>(i0, w, bb, o, Cin, Cout, H, relu);
        }
    };
    auto pool = [&](const float* i0, float* o, int C, int Ho, int B) {
        int tot = B * C * Ho * Ho; int g = (tot + 255) / 256;
        if (Ho == 128) k_pool<128><<<g, 256>>>(i0, o, tot);
        else if (Ho == 64) k_pool<64><<<g, 256>>>(i0, o, tot);
        else k_pool<32><<<g, 256>>>(i0, o, tot);
    };
    auto up = [&](const float* i0, float* o, int C, int Ho) {
        int tot = 4 * C * Ho * Ho; int g = (tot + 255) / 256;
        if (Ho == 64) k_up<64><<<g, 256>>>(i0, o, tot);
        else if (Ho == 128) k_up<128><<<g, 256>>>(i0, o, tot);
        else k_up<256><<<g, 256>>>(i0, o, tot);
    };
    auto enc = [&](const float* x, int B, float* f4o, float* mo, float* so, int soff) {
        conv(x, b0, in[2], in[3], 3, 64, 256, 1, B);
        if (mo) k_stats<<<4 * 64, 256>>>(b0 + (size_t)soff * 64 * 65536, 65536, mo, so);
        pool(b0, b1, 64, 128, B);
        conv(b1, b0, in[4], in[5], 64, 128, 128, 1, B);
        if (mo) k_stats<<<4 * 128, 256>>>(b0 + (size_t)soff * 128 * 16384, 16384, mo + 256, so + 256);
        pool(b0, b1, 128, 64, B);
        conv(b1, b0, in[6], in[7], 128, 256, 64, 1, B);
        if (mo) k_stats<<<4 * 256, 256>>>(b0 + (size_t)soff * 256 * 4096, 4096, mo + 768, so + 768);
        pool(b0, b1, 256, 32, B);
        conv(b1, f4o, in[8], in[9], 256, 512, 32, 1, B);
        if (mo) k_stats<<<4 * 512, 256>>>(f4o + (size_t)soff * 512 * 1024, 1024, mo + 1792, so + 1792);
    };

    cudaMemcpyAsync(in8, in[0], 786432 * 4, cudaMemcpyDeviceToDevice);
    cudaMemcpyAsync(in8 + 786432, in[1], 786432 * 4, cudaMemcpyDeviceToDevice);
    k_dummy<<<1, 256>>>();
    k_dummy<<<1, 256>>>();

    enc(in8, 8, f4, st + 0, st + 3840, 4);

    k_transp<<<dim3(8, 16, 32), dim3(32, 8)>>>();
    k_kmeans<<<8, 1024>>>();

    k_aw<<<(12582912 + 255) / 256, 256>>>();
    k_covg<<<dim3(10, 1, 24), 256>>>();
    k_norm<<<24, 256>>>();
    k_nsinit<<<((6291456 + 255) / 256), 256>>>();

    dim3 gs(10, 1, 24);
    k_gemmsym<<<gs, 256>>>(Y, Y, cov, Y, 1);
    k_gemmsym<<<gs, 256>>>(Y, cov, aw, cov, 0);
    float* Yc = aw; float* Zc = cov;
    float* fr[4] = {Y, Z, Tt, aw1};
    for (int it = 0; it < 14; it++) {
        float* M = fr[0]; float* P = fr[1]; float* Yn = fr[2]; float* Zn = fr[3];
        k_gemmsym<<<gs, 256>>>(Zc, Yc, M, Zc, 0);
        k_gemmsym<<<gs, 256>>>(M, M, P, M, 1);
        if (it < 13) {
            k_gemmsym<<<gs, 256>>>(Yc, P, Yn, Yc, 0);
            k_gemmsym<<<gs, 256>>>(P, Zc, Zn, P, 0);
        } else {
            size_t so12 = (size_t)12 * MS;
            k_gemmsym<<<dim3(10, 1, 12), 256>>>(Yc + so12, P + so12, Yn + so12, Yc + so12, 0);
            k_gemmsym<<<dim3(10, 1, 12), 256>>>(P, Zc, Zn, P, 0);
        }
        fr[0] = Yc; fr[1] = Zc; fr[2] = M; fr[3] = P;
        Yc = Yn; Zc = Zn;
    }

    k_gemm16<<<dim3(4, 4, 12), 256>>>(Yc + (size_t)12 * MS, MS, Zc, MS, 0,
                                      Tm, MS, 512, 1.f, 1);
    float* tp = fr[0];
    k_gemm16<<<dim3(8, 4, 12), 256>>>(Tm, MS, f4, 524288, 1, tp, 524288, 1024, 1.f, 0);
    k_gemv<<<12, 512>>>();
    k_comb<<<(2097152 + 255) / 256, 256>>>(tp);

    conv(f4t, b0, in[10], in[11], 512, 256, 32, 1, 4);
    up(b0, b1, 256, 64);
    conv(b1, b0, in[12], in[13], 256, 128, 64, 1, 4);
    up(b0, b1, 128, 128);
    conv(b1, b0, in[14], in[15], 128, 64, 128, 1, 4);
    up(b0, b1, 64, 256);
    conv(b1, dec, in[16], in[17], 64, 3, 256, 0, 4);

    enc(dec, 4, f4e, st + 2 * 3840, st + 3 * 3840, 0);

    k_closs1<<<256, 256>>>();
    k_final<<<1, 256>>>((float*)d_out);
}

// round 15
// speedup vs baseline: 2.1396x; 1.0222x over previous
#include <cuda_runtime.h>
#include <math.h>

#define MS 262144
__device__ float g_b0[33554432];
__device__ float g_b1[33554432];
__device__ float g_in8[1572864];
__device__ float g_f4[4194304];
__device__ float g_f4t[2097152];
__device__ float g_f4e[2097152];
__device__ float g_dec[786432];
__device__ float g_fT[4194304];
__device__ float g_cent[12288];
__device__ int   g_asg[8192];
__device__ float g_cnt[24];
__device__ float g_aw[12582912];
__device__ float g_cov[6291456];
__device__ float g_Y[6291456];
__device__ float g_Z[6291456];
__device__ float g_Tt[6291456];
__device__ float g_nrm[24];
__device__ float g_Tm[3145728];
__device__ float g_vv[6144];
__device__ float g_st[15360];
__device__ double g_part[256];

__constant__ int c_pi[10] = {0,0,0,0,1,1,1,2,2,3};
__constant__ int c_pj[10] = {0,1,2,3,1,2,3,2,3,3};

__global__ void k_dummy() { g_part[threadIdx.x] = 0.0; }

// ---------- implicit-GEMM conv 3x3, 128x128 tile ----------
__global__ void __launch_bounds__(256, 2) k_cgemm(
    const float* __restrict__ in, const float* __restrict__ w,
    const float* __restrict__ bias, float* __restrict__ out,
    int Cin, int Cout, int H, int relu)
{
    __shared__ float sA[2][16][128], sB[2][16][128];
    int K = Cin * 9, HH = H * H;
    int m0 = blockIdx.y * 128, n0 = blockIdx.x * 128;
    int tid = threadIdx.x;
    int ar = tid >> 1, ac = (tid & 1) * 8;
    int brk = tid >> 4, bcg = (tid & 15) * 8;
    int ty = tid >> 4, tx = tid & 15;
    int b = n0 / HH, rem0 = n0 - b * HH;
    int cy[8], cx[8];
#pragma unroll
    for (int j = 0; j < 8; j++) {
        int rem = rem0 + bcg + j;
        int yy = rem / H;
        cy[j] = yy; cx[j] = rem - yy * H;
    }
    const float* inb = in + (size_t)b * Cin * HH;
    float acc[8][8];
#pragma unroll
    for (int a = 0; a < 8; a++)
#pragma unroll
        for (int q = 0; q < 8; q++) acc[a][q] = 0.f;
    float ra[8], rb[8];
    int aok = (m0 + ar) < Cout;
    const float* awp = w + (size_t)(aok ? m0 + ar : 0) * K + ac;
    if (aok) { *(float4*)ra = *(const float4*)awp; *(float4*)(ra+4) = *(const float4*)(awp+4); }
    else { for (int i = 0; i < 8; i++) ra[i] = 0.f; }
    {
        int k = brk;
        int ic = k / 9, rs = k - ic * 9;
        int dy = rs / 3 - 1, dx = rs - (rs / 3) * 3 - 1;
        const float* ip = inb + (size_t)ic * HH;
#pragma unroll
        for (int j = 0; j < 8; j++) {
            int yy = cy[j] + dy, xx = cx[j] + dx;
            rb[j] = (yy >= 0 && yy < H && xx >= 0 && xx < H) ? ip[yy * H + xx] : 0.f;
        }
    }
    int nk = K / 16;
#pragma unroll
    for (int i = 0; i < 8; i++) sA[0][ac + i][ar] = ra[i];
#pragma unroll
    for (int j = 0; j < 8; j++) sB[0][brk][bcg + j] = rb[j];
    __syncthreads();
    for (int s = 0; s < nk; s++) {
        int buf = s & 1;
        if (s + 1 < nk) {
            int k0 = (s + 1) * 16;
            if (aok) { *(float4*)ra = *(const float4*)(awp + k0); *(float4*)(ra+4) = *(const float4*)(awp + k0 + 4); }
            int k = k0 + brk;
            int ic = k / 9, rs = k - ic * 9;
            int dy = rs / 3 - 1, dx = rs - (rs / 3) * 3 - 1;
            const float* ip = inb + (size_t)ic * HH;
#pragma unroll
            for (int j = 0; j < 8; j++) {
                int yy = cy[j] + dy, xx = cx[j] + dx;
                rb[j] = (yy >= 0 && yy < H && xx >= 0 && xx < H) ? ip[yy * H + xx] : 0.f;
            }
        }
#pragma unroll
        for (int k = 0; k < 16; k++) {
            float av[8], bv[8];
            *(float4*)av = *(float4*)&sA[buf][k][ty * 8]; *(float4*)(av+4) = *(float4*)&sA[buf][k][ty * 8 + 4];
            *(float4*)bv = *(float4*)&sB[buf][k][tx * 8]; *(float4*)(bv+4) = *(float4*)&sB[buf][k][tx * 8 + 4];
#pragma unroll
            for (int a = 0; a < 8; a++)
#pragma unroll
                for (int q = 0; q < 8; q++) acc[a][q] += av[a] * bv[q];
        }
        if (s + 1 < nk) {
            int nb = buf ^ 1;
#pragma unroll
            for (int i = 0; i < 8; i++) sA[nb][ac + i][ar] = ra[i];
#pragma unroll
            for (int j = 0; j < 8; j++) sB[nb][brk][bcg + j] = rb[j];
            __syncthreads();
        }
    }
#pragma unroll
    for (int a = 0; a < 8; a++) {
        int oc = m0 + ty * 8 + a;
        if (oc >= Cout) break;
        float bv = bias[oc];
        float* op = out + ((size_t)b * Cout + oc) * HH;
#pragma unroll
        for (int q = 0; q < 8; q++) {
            float v = acc[a][q] + bv;
            if (relu) v = fmaxf(v, 0.f);
            op[rem0 + tx * 8 + q] = v;
        }
    }
}

// ---------- implicit-GEMM conv 3x3, 64x64 tile (small grids) ----------
__global__ void __launch_bounds__(256, 4) k_cgemm64(
    const float* __restrict__ in, const float* __restrict__ w,
    const float* __restrict__ bias, float* __restrict__ out,
    int Cin, int Cout, int H, int relu)
{
    __shared__ float sA[2][16][64], sB[2][16][64];
    int K = Cin * 9, HH = H * H;
    int m0 = blockIdx.y * 64, n0 = blockIdx.x * 64;
    int tid = threadIdx.x;
    int ar = tid >> 2, ac = (tid & 3) * 4;
    int brk = tid >> 4, bcg = (tid & 15) * 4;
    int ty = tid >> 4, tx = tid & 15;
    int b = n0 / HH, rem0 = n0 - b * HH;
    int cy[4], cx[4];
#pragma unroll
    for (int j = 0; j < 4; j++) {
        int rem = rem0 + bcg + j;
        int yy = rem / H;
        cy[j] = yy; cx[j] = rem - yy * H;
    }
    const float* inb = in + (size_t)b * Cin * HH;
    float acc[4][4];
#pragma unroll
    for (int a = 0; a < 4; a++)
#pragma unroll
        for (int q = 0; q < 4; q++) acc[a][q] = 0.f;
    float ra[4], rb[4];
    int aok = (m0 + ar) < Cout;
    const float* awp = w + (size_t)(aok ? m0 + ar : 0) * K + ac;
    if (aok) *(float4*)ra = *(const float4*)awp;
    else { for (int i = 0; i < 4; i++) ra[i] = 0.f; }
    {
        int k = brk;
        int ic = k / 9, rs = k - ic * 9;
        int dy = rs / 3 - 1, dx = rs - (rs / 3) * 3 - 1;
        const float* ip = inb + (size_t)ic * HH;
#pragma unroll
        for (int j = 0; j < 4; j++) {
            int yy = cy[j] + dy, xx = cx[j] + dx;
            rb[j] = (yy >= 0 && yy < H && xx >= 0 && xx < H) ? ip[yy * H + xx] : 0.f;
        }
    }
    int nk = K / 16;
#pragma unroll
    for (int i = 0; i < 4; i++) sA[0][ac + i][ar] = ra[i];
#pragma unroll
    for (int j = 0; j < 4; j++) sB[0][brk][bcg + j] = rb[j];
    __syncthreads();
    for (int s = 0; s < nk; s++) {
        int buf = s & 1;
        if (s + 1 < nk) {
            int k0 = (s + 1) * 16;
            if (aok) *(float4*)ra = *(const float4*)(awp + k0);
            int k = k0 + brk;
            int ic = k / 9, rs = k - ic * 9;
            int dy = rs / 3 - 1, dx = rs - (rs / 3) * 3 - 1;
            const float* ip = inb + (size_t)ic * HH;
#pragma unroll
            for (int j = 0; j < 4; j++) {
                int yy = cy[j] + dy, xx = cx[j] + dx;
                rb[j] = (yy >= 0 && yy < H && xx >= 0 && xx < H) ? ip[yy * H + xx] : 0.f;
            }
        }
#pragma unroll
        for (int k = 0; k < 16; k++) {
            float av[4], bv[4];
            *(float4*)av = *(float4*)&sA[buf][k][ty * 4];
            *(float4*)bv = *(float4*)&sB[buf][k][tx * 4];
#pragma unroll
            for (int a = 0; a < 4; a++)
#pragma unroll
                for (int q = 0; q < 4; q++) acc[a][q] += av[a] * bv[q];
        }
        if (s + 1 < nk) {
            int nb = buf ^ 1;
#pragma unroll
            for (int i = 0; i < 4; i++) sA[nb][ac + i][ar] = ra[i];
#pragma unroll
            for (int j = 0; j < 4; j++) sB[nb][brk][bcg + j] = rb[j];
            __syncthreads();
        }
    }
#pragma unroll
    for (int a = 0; a < 4; a++) {
        int oc = m0 + ty * 4 + a;
        if (oc >= Cout) break;
        float bv = bias[oc];
        float* op = out + ((size_t)b * Cout + oc) * HH;
#pragma unroll
        for (int q = 0; q < 4; q++) {
            float v = acc[a][q] + bv;
            if (relu) v = fmaxf(v, 0.f);
            op[rem0 + tx * 4 + q] = v;
        }
    }
}

template<int OCB>
__global__ void __launch_bounds__(256) k_conv(const float* __restrict__ in,
    const float* __restrict__ w, const float* __restrict__ bias,
    float* __restrict__ out, int Cin, int Cout, int H, int relu)
{
    __shared__ float sI[34][36];
    __shared__ float sW[OCB][9];
    int tiles = H >> 5;
    int bx = blockIdx.x % tiles, by = blockIdx.x / tiles;
    int x0 = bx * 32, y0 = by * 32;
    int oc0 = blockIdx.y * OCB, b = blockIdx.z;
    int tid = threadIdx.x;
    int lx = (tid & 15) * 2, ly = (tid >> 4) * 2;
    float acc[OCB][4];
#pragma unroll
    for (int o = 0; o < OCB; o++) { acc[o][0]=0.f; acc[o][1]=0.f; acc[o][2]=0.f; acc[o][3]=0.f; }
    const float* ib = in + (size_t)b * Cin * H * H;
    for (int ic = 0; ic < Cin; ic++) {
        __syncthreads();
        const float* ip = ib + (size_t)ic * H * H;
        for (int i = tid; i < 34 * 34; i += 256) {
            int yy = i / 34, xx = i - yy * 34;
            int gy = y0 + yy - 1, gx = x0 + xx - 1;
            sI[yy][xx] = (gy >= 0 && gy < H && gx >= 0 && gx < H) ? ip[gy * H + gx] : 0.f;
        }
        if (tid < OCB * 9) {
            int oc = tid / 9, tt = tid - oc * 9;
            sW[oc][tt] = (oc0 + oc < Cout) ? w[((size_t)(oc0 + oc) * Cin + ic) * 9 + tt] : 0.f;
        }
        __syncthreads();
        float win[4][4];
#pragma unroll
        for (int r = 0; r < 4; r++)
#pragma unroll
            for (int s = 0; s < 4; s++) win[r][s] = sI[ly + r][lx + s];
#pragma unroll
        for (int o = 0; o < OCB; o++) {
            float w0=sW[o][0],w1=sW[o][1],w2=sW[o][2],w3=sW[o][3],w4=sW[o][4];
            float w5=sW[o][5],w6=sW[o][6],w7=sW[o][7],w8=sW[o][8];
#pragma unroll
            for (int p = 0; p < 4; p++) {
                int pr = p >> 1, pc = p & 1;
                acc[o][p] += win[pr][pc]*w0 + win[pr][pc+1]*w1 + win[pr][pc+2]*w2
                           + win[pr+1][pc]*w3 + win[pr+1][pc+1]*w4 + win[pr+1][pc+2]*w5
                           + win[pr+2][pc]*w6 + win[pr+2][pc+1]*w7 + win[pr+2][pc+2]*w8;
            }
        }
    }
#pragma unroll
    for (int o = 0; o < OCB; o++) {
        int oc = oc0 + o;
        if (oc >= Cout) break;
        float bv = bias[oc];
        float* op = out + ((size_t)b * Cout + oc) * H * H;
#pragma unroll
        for (int p = 0; p < 4; p++) {
            float v = acc[o][p] + bv;
            if (relu) v = fmaxf(v, 0.f);
            op[(y0 + ly + (p >> 1)) * H + x0 + lx + (p & 1)] = v;
        }
    }
}

template<int HO>
__global__ void k_pool(const float* __restrict__ in, float* __restrict__ out, int tot) {
    int i = blockIdx.x * 256 + threadIdx.x;
    if (i >= tot) return;
    int x = i % HO, y = (i / HO) % HO; int bc = i / (HO * HO);
    const int Hi = HO * 2;
    const float* p = in + (size_t)bc * Hi * Hi;
    out[i] = (p[(2*y)*Hi + 2*x] + p[(2*y)*Hi + 2*x+1] + p[(2*y+1)*Hi + 2*x] + p[(2*y+1)*Hi + 2*x+1]) * 0.25f;
}

template<int HO>
__global__ void k_up(const float* __restrict__ in, float* __restrict__ out, int tot) {
    int i = blockIdx.x * 256 + threadIdx.x;
    if (i >= tot) return;
    int x = i % HO, y = (i / HO) % HO; int bc = i / (HO * HO);
    const int Hi = HO >> 1;
    out[i] = in[(size_t)bc * Hi * Hi + (y >> 1) * Hi + (x >> 1)];
}

// single-pass stats: compile-time trip count, batched float4 loads
template<int HW, int TPB>
__global__ void __launch_bounds__(TPB) k_stats2(const float* __restrict__ in,
                                                float* __restrict__ mo, float* __restrict__ so) {
    __shared__ double rs[TPB], rq[TPB];
    int bc = blockIdx.x, tid = threadIdx.x;
    const float* p = in + (size_t)bc * HW;
    constexpr int IT = HW / (TPB * 4);
    double s = 0, q = 0;
#pragma unroll
    for (int i = 0; i < IT; i++) {
        float4 v = *(const float4*)(p + (i * TPB + tid) * 4);
        s += (double)v.x + (double)v.y + (double)v.z + (double)v.w;
        q += (double)v.x * v.x + (double)v.y * v.y + (double)v.z * v.z + (double)v.w * v.w;
    }
    rs[tid] = s; rq[tid] = q; __syncthreads();
    for (int o = TPB / 2; o > 0; o >>= 1) {
        if (tid < o) { rs[tid] += rs[tid + o]; rq[tid] += rq[tid + o]; }
        __syncthreads();
    }
    if (tid == 0) {
        double m = rs[0] / HW;
        double var = rq[0] / HW - m * m;
        mo[bc] = (float)m;
        so[bc] = (float)sqrt(var > 0.0 ? var : 0.0);
    }
}

__global__ void k_transp() {
    __shared__ float t[32][33];
    int sb = blockIdx.x, c0 = blockIdx.y * 32, n0 = blockIdx.z * 32;
    const float* f = g_f4 + (size_t)sb * 524288;
    int tx = threadIdx.x, ty = threadIdx.y;
    for (int j = 0; j < 32; j += 8) t[ty + j][tx] = f[(c0 + ty + j) * 1024 + n0 + tx];
    __syncthreads();
    for (int j = 0; j < 32; j += 8) g_fT[(size_t)sb * 524288 + (size_t)(n0 + ty + j) * 512 + c0 + tx] = t[tx][ty + j];
}

__global__ void k_cent0() {
    int i = blockIdx.x * 256 + threadIdx.x;
    if (i >= 12288) return;
    int c = i & 511, k = (i >> 9) % 3, sb = i / 1536;
    const float* f = g_f4 + (size_t)sb * 524288;
    g_cent[i] = f[c * 1024 + k];
}

__global__ void __launch_bounds__(256) k_assign2() {
    __shared__ float sc[3][512];
    int sb = blockIdx.x >> 2;
    int n = (blockIdx.x & 3) * 256 + threadIdx.x;
    for (int i = threadIdx.x; i < 1536; i += 256) ((float*)sc)[i] = g_cent[sb * 1536 + i];
    __syncthreads();
    const float* f = g_f4 + (size_t)sb * 524288;
    float d0 = 0, d1 = 0, d2 = 0;
    for (int c = 0; c < 512; c++) {
        float v = f[c * 1024 + n];
        float a = v - sc[0][c], b = v - sc[1][c], e = v - sc[2][c];
        d0 += a * a; d1 += b * b; d2 += e * e;
    }
    int a = 0; float best = d0;
    if (d1 < best) { best = d1; a = 1; }
    if (d2 < best) { a = 2; }
    g_asg[sb * 1024 + n] = a;
}

__global__ void __launch_bounds__(128) k_update2() {
    __shared__ int sa[1024];
    int sb = blockIdx.x >> 2;
    int c = (blockIdx.x & 3) * 128 + threadIdx.x;
    for (int i = threadIdx.x; i < 1024; i += 128) sa[i] = g_asg[sb * 1024 + i];
    __syncthreads();
    const float* ft = g_fT + (size_t)sb * 524288;
    float s0 = 0, s1 = 0, s2 = 0; int c0 = 0, c1 = 0, c2 = 0;
    for (int n = 0; n < 1024; n++) {
        float v = ft[n * 512 + c];
        int a = sa[n];
        if (a == 0) { s0 += v; c0++; } else if (a == 1) { s1 += v; c1++; } else { s2 += v; c2++; }
    }
    g_cent[sb * 1536 + c]        = s0 / ((float)c0 + 1e-6f);
    g_cent[sb * 1536 + 512 + c]  = s1 / ((float)c1 + 1e-6f);
    g_cent[sb * 1536 + 1024 + c] = s2 / ((float)c2 + 1e-6f);
    if ((blockIdx.x & 3) == 0 && threadIdx.x < 3)
        g_cnt[sb * 3 + threadIdx.x] = (float)(threadIdx.x == 0 ? c0 : (threadIdx.x == 1 ? c1 : c2));
}

__global__ void k_aw() {
    int i = blockIdx.x * 256 + threadIdx.x;
    if (i >= 12582912) return;
    int n = i & 1023, c = (i >> 10) & 511, m = i >> 19;
    int k = m % 3, sb = m / 3;
    const float* f = g_f4 + (size_t)sb * 524288;
    int a = g_asg[sb * 1024 + n];
    g_aw[i] = (a == k) ? f[c * 1024 + n] - g_cent[sb * 1536 + k * 512 + c] : 0.f;
}

__global__ void __launch_bounds__(256, 2) k_covg() {
    __shared__ float sA[16][128], sB[16][128];
    int m = blockIdx.z;
    const float* A = g_aw + (size_t)m * 524288;
    int bi = c_pi[blockIdx.x], bj = c_pj[blockIdx.x];
    int i0 = bi * 128, j0 = bj * 128;
    int tid = threadIdx.x;
    int ar = tid >> 1, ac = (tid & 1) * 8;
    int ty = tid >> 4, tx = tid & 15;
    float acc[8][8];
#pragma unroll
    for (int a = 0; a < 8; a++)
#pragma unroll
        for (int b = 0; b < 8; b++) acc[a][b] = 0.f;
    float4 ra0 = *(const float4*)&A[(size_t)(i0 + ar) * 1024 + ac];
    float4 ra1 = *(const float4*)&A[(size_t)(i0 + ar) * 1024 + ac + 4];
    float4 rb0 = *(const float4*)&A[(size_t)(j0 + ar) * 1024 + ac];
    float4 rb1 = *(const float4*)&A[(size_t)(j0 + ar) * 1024 + ac + 4];
    for (int k0 = 0; k0 < 1024; k0 += 16) {
        sA[ac+0][ar]=ra0.x; sA[ac+1][ar]=ra0.y; sA[ac+2][ar]=ra0.z; sA[ac+3][ar]=ra0.w;
        sA[ac+4][ar]=ra1.x; sA[ac+5][ar]=ra1.y; sA[ac+6][ar]=ra1.z; sA[ac+7][ar]=ra1.w;
        sB[ac+0][ar]=rb0.x; sB[ac+1][ar]=rb0.y; sB[ac+2][ar]=rb0.z; sB[ac+3][ar]=rb0.w;
        sB[ac+4][ar]=rb1.x; sB[ac+5][ar]=rb1.y; sB[ac+6][ar]=rb1.z; sB[ac+7][ar]=rb1.w;
        __syncthreads();
        if (k0 + 16 < 1024) {
            ra0 = *(const float4*)&A[(size_t)(i0 + ar) * 1024 + k0 + 16 + ac];
            ra1 = *(const float4*)&A[(size_t)(i0 + ar) * 1024 + k0 + 16 + ac + 4];
            rb0 = *(const float4*)&A[(size_t)(j0 + ar) * 1024 + k0 + 16 + ac];
            rb1 = *(const float4*)&A[(size_t)(j0 + ar) * 1024 + k0 + 16 + ac + 4];
        }
#pragma unroll
        for (int k = 0; k < 16; k++) {
            float av[8], bv[8];
            *(float4*)av = *(float4*)&sA[k][ty * 8]; *(float4*)(av+4) = *(float4*)&sA[k][ty * 8 + 4];
            *(float4*)bv = *(float4*)&sB[k][tx * 8]; *(float4*)(bv+4) = *(float4*)&sB[k][tx * 8 + 4];
#pragma unroll
            for (int a = 0; a < 8; a++)
#pragma unroll
                for (int b = 0; b < 8; b++) acc[a][b] += av[a] * bv[b];
        }
        __syncthreads();
    }
    float nc = g_cnt[m] + 1e-6f;
    float* C = g_cov + (size_t)m * MS;
#pragma unroll
    for (int a = 0; a < 8; a++)
#pragma unroll
        for (int b = 0; b < 8; b++) {
            int gi = i0 + ty * 8 + a, gj = j0 + tx * 8 + b;
            float v = acc[a][b] / nc + (gi == gj ? 0.1f : 0.f);
            C[gi * 512 + gj] = v;
            if (bi != bj) C[gj * 512 + gi] = v;
        }
}

__global__ void __launch_bounds__(256) k_norm() {
    __shared__ float red[256];
    int m = blockIdx.x;
    const float* A = g_cov + (size_t)m * MS;
    float mx = 0;
    for (int r = threadIdx.x; r < 512; r += 256) {
        float s = 0;
        for (int c = 0; c < 512; c++) s += fabsf(A[r * 512 + c]);
        mx = fmaxf(mx, s);
    }
    red[threadIdx.x] = mx; __syncthreads();
    for (int o = 128; o > 0; o >>= 1) { if (threadIdx.x < o) red[threadIdx.x] = fmaxf(red[threadIdx.x], red[threadIdx.x + o]); __syncthreads(); }
    if (threadIdx.x == 0) g_nrm[m] = red[0];
}

__global__ void k_nsinit() {
    int i = blockIdx.x * 256 + threadIdx.x;
    if (i >= 6291456) return;
    int m = i >> 18;
    g_Y[i] = g_cov[i] / g_nrm[m];
}

__global__ void __launch_bounds__(256, 2) k_gemmsym(
    const float* __restrict__ A, const float* __restrict__ B,
    float* __restrict__ C, const float* __restrict__ Mp, int polymode)
{
    __shared__ float sA[2][16][128], sB[2][16][128];
    int z = blockIdx.z;
    const float* Ab = A + (size_t)z * MS;
    const float* Bb = B + (size_t)z * MS;
    float* Cb = C + (size_t)z * MS;
    const float* Mb = Mp + (size_t)z * MS;
    int bi = c_pi[blockIdx.x], bj = c_pj[blockIdx.x];
    int m0 = bi * 128, n0 = bj * 128;
    int tid = threadIdx.x;
    int ar = tid >> 1, ac = (tid & 1) * 8;
    int br = tid >> 4, bc = (tid & 15) * 8;
    int ty = tid >> 4, tx = tid & 15;
    float acc[8][8];
#pragma unroll
    for (int a = 0; a < 8; a++)
#pragma unroll
        for (int b = 0; b < 8; b++) acc[a][b] = 0.f;
    float4 ra0 = *(const float4*)&Ab[(size_t)(m0 + ar) * 512 + ac];
    float4 ra1 = *(const float4*)&Ab[(size_t)(m0 + ar) * 512 + ac + 4];
    float4 rb0 = *(const float4*)&Bb[(size_t)br * 512 + n0 + bc];
    float4 rb1 = *(const float4*)&Bb[(size_t)br * 512 + n0 + bc + 4];
    sA[0][ac+0][ar]=ra0.x; sA[0][ac+1][ar]=ra0.y; sA[0][ac+2][ar]=ra0.z; sA[0][ac+3][ar]=ra0.w;
    sA[0][ac+4][ar]=ra1.x; sA[0][ac+5][ar]=ra1.y; sA[0][ac+6][ar]=ra1.z; sA[0][ac+7][ar]=ra1.w;
    *(float4*)&sB[0][br][bc] = rb0; *(float4*)&sB[0][br][bc + 4] = rb1;
    __syncthreads();
    for (int s = 0; s < 32; s++) {
        int buf = s & 1;
        if (s < 31) {
            int k0 = (s + 1) * 16;
            ra0 = *(const float4*)&Ab[(size_t)(m0 + ar) * 512 + k0 + ac];
            ra1 = *(const float4*)&Ab[(size_t)(m0 + ar) * 512 + k0 + ac + 4];
            rb0 = *(const float4*)&Bb[(size_t)(k0 + br) * 512 + n0 + bc];
            rb1 = *(const float4*)&Bb[(size_t)(k0 + br) * 512 + n0 + bc + 4];
        }
#pragma unroll
        for (int k = 0; k < 16; k++) {
            float av[8], bv[8];
            *(float4*)av = *(float4*)&sA[buf][k][ty * 8]; *(float4*)(av+4) = *(float4*)&sA[buf][k][ty * 8 + 4];
            *(float4*)bv = *(float4*)&sB[buf][k][tx * 8]; *(float4*)(bv+4) = *(float4*)&sB[buf][k][tx * 8 + 4];
#pragma unroll
            for (int a = 0; a < 8; a++)
#pragma unroll
                for (int b = 0; b < 8; b++) acc[a][b] += av[a] * bv[b];
        }
        if (s < 31) {
            int nb = buf ^ 1;
            sA[nb][ac+0][ar]=ra0.x; sA[nb][ac+1][ar]=ra0.y; sA[nb][ac+2][ar]=ra0.z; sA[nb][ac+3][ar]=ra0.w;
            sA[nb][ac+4][ar]=ra1.x; sA[nb][ac+5][ar]=ra1.y; sA[nb][ac+6][ar]=ra1.z; sA[nb][ac+7][ar]=ra1.w;
            *(float4*)&sB[nb][br][bc] = rb0; *(float4*)&sB[nb][br][bc + 4] = rb1;
            __syncthreads();
        }
    }
#pragma unroll
    for (int a = 0; a < 8; a++) {
        int gi = m0 + ty * 8 + a;
#pragma unroll
        for (int b = 0; b < 8; b++) {
            int gj = n0 + tx * 8 + b;
            float v = acc[a][b];
            if (polymode)
                v = ((gi == gj ? 15.f : 0.f) - 10.f * Mb[(size_t)gi * 512 + gj] + 3.f * v) * 0.125f;
            Cb[(size_t)gi * 512 + gj] = v;
            if (bi != bj) Cb[(size_t)gj * 512 + gi] = v;
        }
    }
}

__global__ void __launch_bounds__(256, 2) k_gemm16(
    const float* __restrict__ A, int strA, const float* __restrict__ B, int strB, int bdiv,
    float* __restrict__ C, int strC, int N, float alpha, int nrmmode)
{
    __shared__ float sA[2][16][128], sB[2][16][128];
    int z = blockIdx.z;
    const float* Ab = A + (size_t)z * strA;
    const float* Bb = B + (size_t)(bdiv ? z / 3 : z) * strB;
    float* Cb = C + (size_t)z * strC;
    if (nrmmode) alpha = sqrtf(g_nrm[12 + z] / g_nrm[z]);
    int m0 = blockIdx.y * 128, n0 = blockIdx.x * 128;
    int tid = threadIdx.x;
    int ar = tid >> 1, ac = (tid & 1) * 8;
    int br = tid >> 4, bc = (tid & 15) * 8;
    int ty = tid >> 4, tx = tid & 15;
    float acc[8][8];
#pragma unroll
    for (int a = 0; a < 8; a++)
#pragma unroll
        for (int b = 0; b < 8; b++) acc[a][b] = 0.f;
    float4 ra0 = *(const float4*)&Ab[(size_t)(m0 + ar) * 512 + ac];
    float4 ra1 = *(const float4*)&Ab[(size_t)(m0 + ar) * 512 + ac + 4];
    float4 rb0 = *(const float4*)&Bb[(size_t)br * N + n0 + bc];
    float4 rb1 = *(const float4*)&Bb[(size_t)br * N + n0 + bc + 4];
    sA[0][ac+0][ar]=ra0.x; sA[0][ac+1][ar]=ra0.y; sA[0][ac+2][ar]=ra0.z; sA[0][ac+3][ar]=ra0.w;
    sA[0][ac+4][ar]=ra1.x; sA[0][ac+5][ar]=ra1.y; sA[0][ac+6][ar]=ra1.z; sA[0][ac+7][ar]=ra1.w;
    *(float4*)&sB[0][br][bc] = rb0; *(float4*)&sB[0][br][bc + 4] = rb1;
    __syncthreads();
    for (int s = 0; s < 32; s++) {
        int buf = s & 1;
        if (s < 31) {
            int k0 = (s + 1) * 16;
            ra0 = *(const float4*)&Ab[(size_t)(m0 + ar) * 512 + k0 + ac];
            ra1 = *(const float4*)&Ab[(size_t)(m0 + ar) * 512 + k0 + ac + 4];
            rb0 = *(const float4*)&Bb[(size_t)(k0 + br) * N + n0 + bc];
            rb1 = *(const float4*)&Bb[(size_t)(k0 + br) * N + n0 + bc + 4];
        }
#pragma unroll
        for (int k = 0; k < 16; k++) {
            float av[8], bv[8];
            *(float4*)av = *(float4*)&sA[buf][k][ty * 8]; *(float4*)(av+4) = *(float4*)&sA[buf][k][ty * 8 + 4];
            *(float4*)bv = *(float4*)&sB[buf][k][tx * 8]; *(float4*)(bv+4) = *(float4*)&sB[buf][k][tx * 8 + 4];
#pragma unroll
            for (int a = 0; a < 8; a++)
#pragma unroll
                for (int b = 0; b < 8; b++) acc[a][b] += av[a] * bv[b];
        }
        if (s < 31) {
            int nb = buf ^ 1;
            sA[nb][ac+0][ar]=ra0.x; sA[nb][ac+1][ar]=ra0.y; sA[nb][ac+2][ar]=ra0.z; sA[nb][ac+3][ar]=ra0.w;
            sA[nb][ac+4][ar]=ra1.x; sA[nb][ac+5][ar]=ra1.y; sA[nb][ac+6][ar]=ra1.z; sA[nb][ac+7][ar]=ra1.w;
            *(float4*)&sB[nb][br][bc] = rb0; *(float4*)&sB[nb][br][bc + 4] = rb1;
            __syncthreads();
        }
    }
#pragma unroll
    for (int a = 0; a < 8; a++) {
        int gm = m0 + ty * 8 + a;
#pragma unroll
        for (int b = 0; b < 8; b++) {
            int gn = n0 + tx * 8 + b;
            Cb[(size_t)gm * N + gn] = alpha * acc[a][b];
        }
    }
}

__global__ void __launch_bounds__(512) k_gemv() {
    __shared__ float mu[512];
    int z = blockIdx.x;
    int b = z / 3, k = z % 3;
    int tid = threadIdx.x;
    mu[tid] = g_cent[b * 1536 + k * 512 + tid];
    __syncthreads();
    const float* T = g_Tm + (size_t)z * MS;
    int warp = tid >> 5, lane = tid & 31;
    for (int c = warp; c < 512; c += 16) {
        float s = 0;
        for (int d = lane; d < 512; d += 32) s += T[c * 512 + d] * mu[d];
#pragma unroll
        for (int o = 16; o > 0; o >>= 1) s += __shfl_down_sync(0xffffffff, s, o);
        if (lane == 0) g_vv[z * 512 + c] = s;
    }
}

__global__ void k_comb(const float* __restrict__ tp) {
    int i = blockIdx.x * 256 + threadIdx.x;
    if (i >= 2097152) return;
    int n = i & 1023, c = (i >> 10) & 511, b = i >> 19;
    int a = g_asg[b * 1024 + n];
    int z = b * 3 + a;
    float val = tp[(size_t)z * 524288 + c * 1024 + n] - g_vv[z * 512 + c]
              + g_cent[(4 + b) * 1536 + a * 512 + c];
    g_f4t[i] = 0.6f * val + 0.4f * g_f4[i];
}

__global__ void __launch_bounds__(256) k_closs1() {
    __shared__ double red[256];
    int start = blockIdx.x * 8192;
    double s = 0;
    for (int i = threadIdx.x; i < 8192; i += 256) {
        float d = g_f4e[start + i] - g_f4[start + i];
        s += (double)d * d;
    }
    red[threadIdx.x] = s; __syncthreads();
    for (int o = 128; o > 0; o >>= 1) { if (threadIdx.x < o) red[threadIdx.x] += red[threadIdx.x + o]; __syncthreads(); }
    if (threadIdx.x == 0) g_part[blockIdx.x] = red[0];
}

__global__ void __launch_bounds__(256) k_final(float* out) {
    __shared__ double red[256];
    __shared__ double slv;
    __shared__ double closs;
    const int off[5] = {0, 256, 768, 1792, 3840};
    if (threadIdx.x == 0) slv = 0;
    red[threadIdx.x] = g_part[threadIdx.x];
    __syncthreads();
    for (int o = 128; o > 0; o >>= 1) { if (threadIdx.x < o) red[threadIdx.x] += red[threadIdx.x + o]; __syncthreads(); }
    if (threadIdx.x == 0) closs = red[0] / 2097152.0;
    __syncthreads();
    for (int l = 0; l < 4; l++) {
        int o0 = off[l], sz = off[l + 1] - off[l];
        double s = 0;
        for (int i = threadIdx.x; i < sz; i += 256) {
            float dm = g_st[2 * 3840 + o0 + i] - g_st[0 * 3840 + o0 + i];
            float ds = g_st[3 * 3840 + o0 + i] - g_st[1 * 3840 + o0 + i];
            s += (double)dm * dm + (double)ds * ds;
        }
        red[threadIdx.x] = s; __syncthreads();
        for (int o = 128; o > 0; o >>= 1) { if (threadIdx.x < o) red[threadIdx.x] += red[threadIdx.x + o]; __syncthreads(); }
        if (threadIdx.x == 0) slv += red[0] / sz;
        __syncthreads();
    }
    if (threadIdx.x == 0) out[0] = (float)closs + 0.01f * (float)slv;
}

extern "C" void kernel_launch(void* const* d_in, const int* in_sizes, int n_in,
                              void* d_out, int out_size) {
    (void)in_sizes; (void)n_in; (void)out_size;
    const float* in[18];
    for (int i = 0; i < 18; i++) in[i] = (const float*)d_in[i];

    float *b0, *b1, *in8, *f4, *f4t, *f4e, *dec, *Y, *Z, *Tt, *cov, *aw, *Tm, *st;
    cudaGetSymbolAddress((void**)&b0, g_b0);
    cudaGetSymbolAddress((void**)&b1, g_b1);
    cudaGetSymbolAddress((void**)&in8, g_in8);
    cudaGetSymbolAddress((void**)&f4, g_f4);
    cudaGetSymbolAddress((void**)&f4t, g_f4t);
    cudaGetSymbolAddress((void**)&f4e, g_f4e);
    cudaGetSymbolAddress((void**)&dec, g_dec);
    cudaGetSymbolAddress((void**)&Y, g_Y);
    cudaGetSymbolAddress((void**)&Z, g_Z);
    cudaGetSymbolAddress((void**)&Tt, g_Tt);
    cudaGetSymbolAddress((void**)&cov, g_cov);
    cudaGetSymbolAddress((void**)&aw, g_aw);
    cudaGetSymbolAddress((void**)&Tm, g_Tm);
    cudaGetSymbolAddress((void**)&st, g_st);
    float* aw1 = aw + 6291456;

    auto conv = [&](const float* i0, float* o, const float* w, const float* bb,
                    int Cin, int Cout, int H, int relu, int B) {
        if (Cin >= 64 && Cout >= 64) {
            int bx = (B * H * H) / 128, by = (Cout + 127) / 128;
            if (bx * by >= 148) {
                k_cgemm<<<dim3(bx, by, 1), 256>>>(i0, w, bb, o, Cin, Cout, H, relu);
            } else {
                dim3 g((B * H * H) / 64, (Cout + 63) / 64, 1);
                k_cgemm64<<<g, 256>>>(i0, w, bb, o, Cin, Cout, H, relu);
            }
        } else if (H >= 64) {
            dim3 g((H / 32) * (H / 32), (Cout + 15) / 16, B);
            k_conv<16><<<g, 256>>>(i0, w, bb, o, Cin, Cout, H, relu);
        } else {
            dim3 g((H / 32) * (H / 32), (Cout + 7) / 8, B);
            k_conv<8><<<g, 256>>>(i0, w, bb, o, Cin, Cout, H, relu);
        }
    };
    auto pool = [&](const float* i0, float* o, int C, int Ho, int B) {
        int tot = B * C * Ho * Ho; int g = (tot + 255) / 256;
        if (Ho == 128) k_pool<128><<<g, 256>>>(i0, o, tot);
        else if (Ho == 64) k_pool<64><<<g, 256>>>(i0, o, tot);
        else k_pool<32><<<g, 256>>>(i0, o, tot);
    };
    auto up = [&](const float* i0, float* o, int C, int Ho) {
        int tot = 4 * C * Ho * Ho; int g = (tot + 255) / 256;
        if (Ho == 64) k_up<64><<<g, 256>>>(i0, o, tot);
        else if (Ho == 128) k_up<128><<<g, 256>>>(i0, o, tot);
        else k_up<256><<<g, 256>>>(i0, o, tot);
    };
    auto enc = [&](const float* x, int B, float* f4o, float* mo, float* so, int soff) {
        conv(x, b0, in[2], in[3], 3, 64, 256, 1, B);
        if (mo) k_stats2<65536, 1024><<<256, 1024>>>(b0 + (size_t)soff * 64 * 65536, mo, so);
        pool(b0, b1, 64, 128, B);
        conv(b1, b0, in[4], in[5], 64, 128, 128, 1, B);
        if (mo) k_stats2<16384, 1024><<<512, 1024>>>(b0 + (size_t)soff * 128 * 16384, mo + 256, so + 256);
        pool(b0, b1, 128, 64, B);
        conv(b1, b0, in[6], in[7], 128, 256, 64, 1, B);
        if (mo) k_stats2<4096, 256><<<1024, 256>>>(b0 + (size_t)soff * 256 * 4096, mo + 768, so + 768);
        pool(b0, b1, 256, 32, B);
        conv(b1, f4o, in[8], in[9], 256, 512, 32, 1, B);
        if (mo) k_stats2<1024, 256><<<2048, 256>>>(f4o + (size_t)soff * 512 * 1024, mo + 1792, so + 1792);
    };

    cudaMemcpyAsync(in8, in[0], 786432 * 4, cudaMemcpyDeviceToDevice);
    cudaMemcpyAsync(in8 + 786432, in[1], 786432 * 4, cudaMemcpyDeviceToDevice);
    k_dummy<<<1, 256>>>();
    k_dummy<<<1, 256>>>();

    enc(in8, 8, f4, st + 0, st + 3840, 4);

    k_transp<<<dim3(8, 16, 32), dim3(32, 8)>>>();
    k_cent0<<<48, 256>>>();
    for (int it = 0; it < 11; it++) {
        k_assign2<<<32, 256>>>();
        k_update2<<<32, 128>>>();
    }

    k_aw<<<(12582912 + 255) / 256, 256>>>();
    k_covg<<<dim3(10, 1, 24), 256>>>();
    k_norm<<<24, 256>>>();
    k_nsinit<<<((6291456 + 255) / 256), 256>>>();

    dim3 gs(10, 1, 24);
    k_gemmsym<<<gs, 256>>>(Y, Y, cov, Y, 1);
    k_gemmsym<<<gs, 256>>>(Y, cov, aw, cov, 0);
    float* Yc = aw; float* Zc = cov;
    float* fr[4] = {Y, Z, Tt, aw1};
    for (int it = 0; it < 14; it++) {
        float* M = fr[0]; float* P = fr[1]; float* Yn = fr[2]; float* Zn = fr[3];
        k_gemmsym<<<gs, 256>>>(Zc, Yc, M, Zc, 0);
        k_gemmsym<<<gs, 256>>>(M, M, P, M, 1);
        if (it < 13) {
            k_gemmsym<<<gs, 256>>>(Yc, P, Yn, Yc, 0);
            k_gemmsym<<<gs, 256>>>(P, Zc, Zn, P, 0);
        } else {
            size_t so12 = (size_t)12 * MS;
            k_gemmsym<<<dim3(10, 1, 12), 256>>>(Yc + so12, P + so12, Yn + so12, Yc + so12, 0);
            k_gemmsym<<<dim3(10, 1, 12), 256>>>(P, Zc, Zn, P, 0);
        }
        fr[0] = Yc; fr[1] = Zc; fr[2] = M; fr[3] = P;
        Yc = Yn; Zc = Zn;
    }

    k_gemm16<<<dim3(4, 4, 12), 256>>>(Yc + (size_t)12 * MS, MS, Zc, MS, 0,
                                      Tm, MS, 512, 1.f, 1);
    float* tp = fr[0];
    k_gemm16<<<dim3(8, 4, 12), 256>>>(Tm, MS, f4, 524288, 1, tp, 524288, 1024, 1.f, 0);
    k_gemv<<<12, 512>>>();
    k_comb<<<(2097152 + 255) / 256, 256>>>(tp);

    conv(f4t, b0, in[10], in[11], 512, 256, 32, 1, 4);
    up(b0, b1, 256, 64);
    conv(b1, b0, in[12], in[13], 256, 128, 64, 1, 4);
    up(b0, b1, 128, 128);
    conv(b1, b0, in[14], in[15], 128, 64, 128, 1, 4);
    up(b0, b1, 64, 256);
    conv(b1, dec, in[16], in[17], 64, 3, 256, 0, 4);

    enc(dec, 4, f4e, st + 2 * 3840, st + 3 * 3840, 0);

    k_closs1<<<256, 256>>>();
    k_final<<<1, 256>>>((float*)d_out);
}

// round 16
// speedup vs baseline: 2.2421x; 1.0479x over previous
#include <cuda_runtime.h>
#include <math.h>

#define MS 262144
__device__ float g_b0[33554432];
__device__ float g_b1[33554432];
__device__ float g_in8[1572864];
__device__ float g_f4[4194304];
__device__ float g_f4t[2097152];
__device__ float g_f4e[2097152];
__device__ float g_dec[786432];
__device__ float g_fT[4194304];
__device__ float g_cent[12288];
__device__ int   g_asg[8192];
__device__ float g_cnt[24];
__device__ float g_aw[12582912];
__device__ float g_cov[6291456];
__device__ float g_Y[6291456];
__device__ float g_Z[6291456];
__device__ float g_Tt[6291456];
__device__ float g_nrm[24];
__device__ float g_Tm[3145728];
__device__ float g_vv[6144];
__device__ float g_st[15360];
__device__ double g_part[256];

__constant__ int c_pi[10] = {0,0,0,0,1,1,1,2,2,3};
__constant__ int c_pj[10] = {0,1,2,3,1,2,3,2,3,3};

__global__ void k_dummy() { g_part[threadIdx.x] = 0.0; }

// ---------- implicit-GEMM conv 3x3, 128x128 tile; ups folds repeat-2 upsample ----------
__global__ void __launch_bounds__(256, 2) k_cgemm(
    const float* __restrict__ in, const float* __restrict__ w,
    const float* __restrict__ bias, float* __restrict__ out,
    int Cin, int Cout, int H, int relu, int ups)
{
    __shared__ float sA[2][16][128], sB[2][16][128];
    int K = Cin * 9, HH = H * H;
    int Hi = H >> ups, HHi = Hi * Hi;
    int m0 = blockIdx.y * 128, n0 = blockIdx.x * 128;
    int tid = threadIdx.x;
    int ar = tid >> 1, ac = (tid & 1) * 8;
    int brk = tid >> 4, bcg = (tid & 15) * 8;
    int ty = tid >> 4, tx = tid & 15;
    int b = n0 / HH, rem0 = n0 - b * HH;
    int cy[8], cx[8];
#pragma unroll
    for (int j = 0; j < 8; j++) {
        int rem = rem0 + bcg + j;
        int yy = rem / H;
        cy[j] = yy; cx[j] = rem - yy * H;
    }
    const float* inb = in + (size_t)b * Cin * HHi;
    float acc[8][8];
#pragma unroll
    for (int a = 0; a < 8; a++)
#pragma unroll
        for (int q = 0; q < 8; q++) acc[a][q] = 0.f;
    float ra[8], rb[8];
    int aok = (m0 + ar) < Cout;
    const float* awp = w + (size_t)(aok ? m0 + ar : 0) * K + ac;
    if (aok) { *(float4*)ra = *(const float4*)awp; *(float4*)(ra+4) = *(const float4*)(awp+4); }
    else { for (int i = 0; i < 8; i++) ra[i] = 0.f; }
    {
        int k = brk;
        int ic = k / 9, rs = k - ic * 9;
        int dy = rs / 3 - 1, dx = rs - (rs / 3) * 3 - 1;
        const float* ip = inb + (size_t)ic * HHi;
#pragma unroll
        for (int j = 0; j < 8; j++) {
            int yy = cy[j] + dy, xx = cx[j] + dx;
            rb[j] = (yy >= 0 && yy < H && xx >= 0 && xx < H) ? ip[(yy >> ups) * Hi + (xx >> ups)] : 0.f;
        }
    }
    int nk = K / 16;
#pragma unroll
    for (int i = 0; i < 8; i++) sA[0][ac + i][ar] = ra[i];
#pragma unroll
    for (int j = 0; j < 8; j++) sB[0][brk][bcg + j] = rb[j];
    __syncthreads();
    for (int s = 0; s < nk; s++) {
        int buf = s & 1;
        if (s + 1 < nk) {
            int k0 = (s + 1) * 16;
            if (aok) { *(float4*)ra = *(const float4*)(awp + k0); *(float4*)(ra+4) = *(const float4*)(awp + k0 + 4); }
            int k = k0 + brk;
            int ic = k / 9, rs = k - ic * 9;
            int dy = rs / 3 - 1, dx = rs - (rs / 3) * 3 - 1;
            const float* ip = inb + (size_t)ic * HHi;
#pragma unroll
            for (int j = 0; j < 8; j++) {
                int yy = cy[j] + dy, xx = cx[j] + dx;
                rb[j] = (yy >= 0 && yy < H && xx >= 0 && xx < H) ? ip[(yy >> ups) * Hi + (xx >> ups)] : 0.f;
            }
        }
#pragma unroll
        for (int k = 0; k < 16; k++) {
            float av[8], bv[8];
            *(float4*)av = *(float4*)&sA[buf][k][ty * 8]; *(float4*)(av+4) = *(float4*)&sA[buf][k][ty * 8 + 4];
            *(float4*)bv = *(float4*)&sB[buf][k][tx * 8]; *(float4*)(bv+4) = *(float4*)&sB[buf][k][tx * 8 + 4];
#pragma unroll
            for (int a = 0; a < 8; a++)
#pragma unroll
                for (int q = 0; q < 8; q++) acc[a][q] += av[a] * bv[q];
        }
        if (s + 1 < nk) {
            int nb = buf ^ 1;
#pragma unroll
            for (int i = 0; i < 8; i++) sA[nb][ac + i][ar] = ra[i];
#pragma unroll
            for (int j = 0; j < 8; j++) sB[nb][brk][bcg + j] = rb[j];
            __syncthreads();
        }
    }
#pragma unroll
    for (int a = 0; a < 8; a++) {
        int oc = m0 + ty * 8 + a;
        if (oc >= Cout) break;
        float bv = bias[oc];
        float* op = out + ((size_t)b * Cout + oc) * HH;
#pragma unroll
        for (int q = 0; q < 8; q++) {
            float v = acc[a][q] + bv;
            if (relu) v = fmaxf(v, 0.f);
            op[rem0 + tx * 8 + q] = v;
        }
    }
}

// ---------- implicit-GEMM conv 3x3, 64x64 tile (small grids) ----------
__global__ void __launch_bounds__(256, 4) k_cgemm64(
    const float* __restrict__ in, const float* __restrict__ w,
    const float* __restrict__ bias, float* __restrict__ out,
    int Cin, int Cout, int H, int relu, int ups)
{
    __shared__ float sA[2][16][64], sB[2][16][64];
    int K = Cin * 9, HH = H * H;
    int Hi = H >> ups, HHi = Hi * Hi;
    int m0 = blockIdx.y * 64, n0 = blockIdx.x * 64;
    int tid = threadIdx.x;
    int ar = tid >> 2, ac = (tid & 3) * 4;
    int brk = tid >> 4, bcg = (tid & 15) * 4;
    int ty = tid >> 4, tx = tid & 15;
    int b = n0 / HH, rem0 = n0 - b * HH;
    int cy[4], cx[4];
#pragma unroll
    for (int j = 0; j < 4; j++) {
        int rem = rem0 + bcg + j;
        int yy = rem / H;
        cy[j] = yy; cx[j] = rem - yy * H;
    }
    const float* inb = in + (size_t)b * Cin * HHi;
    float acc[4][4];
#pragma unroll
    for (int a = 0; a < 4; a++)
#pragma unroll
        for (int q = 0; q < 4; q++) acc[a][q] = 0.f;
    float ra[4], rb[4];
    int aok = (m0 + ar) < Cout;
    const float* awp = w + (size_t)(aok ? m0 + ar : 0) * K + ac;
    if (aok) *(float4*)ra = *(const float4*)awp;
    else { for (int i = 0; i < 4; i++) ra[i] = 0.f; }
    {
        int k = brk;
        int ic = k / 9, rs = k - ic * 9;
        int dy = rs / 3 - 1, dx = rs - (rs / 3) * 3 - 1;
        const float* ip = inb + (size_t)ic * HHi;
#pragma unroll
        for (int j = 0; j < 4; j++) {
            int yy = cy[j] + dy, xx = cx[j] + dx;
            rb[j] = (yy >= 0 && yy < H && xx >= 0 && xx < H) ? ip[(yy >> ups) * Hi + (xx >> ups)] : 0.f;
        }
    }
    int nk = K / 16;
#pragma unroll
    for (int i = 0; i < 4; i++) sA[0][ac + i][ar] = ra[i];
#pragma unroll
    for (int j = 0; j < 4; j++) sB[0][brk][bcg + j] = rb[j];
    __syncthreads();
    for (int s = 0; s < nk; s++) {
        int buf = s & 1;
        if (s + 1 < nk) {
            int k0 = (s + 1) * 16;
            if (aok) *(float4*)ra = *(const float4*)(awp + k0);
            int k = k0 + brk;
            int ic = k / 9, rs = k - ic * 9;
            int dy = rs / 3 - 1, dx = rs - (rs / 3) * 3 - 1;
            const float* ip = inb + (size_t)ic * HHi;
#pragma unroll
            for (int j = 0; j < 4; j++) {
                int yy = cy[j] + dy, xx = cx[j] + dx;
                rb[j] = (yy >= 0 && yy < H && xx >= 0 && xx < H) ? ip[(yy >> ups) * Hi + (xx >> ups)] : 0.f;
            }
        }
#pragma unroll
        for (int k = 0; k < 16; k++) {
            float av[4], bv[4];
            *(float4*)av = *(float4*)&sA[buf][k][ty * 4];
            *(float4*)bv = *(float4*)&sB[buf][k][tx * 4];
#pragma unroll
            for (int a = 0; a < 4; a++)
#pragma unroll
                for (int q = 0; q < 4; q++) acc[a][q] += av[a] * bv[q];
        }
        if (s + 1 < nk) {
            int nb = buf ^ 1;
#pragma unroll
            for (int i = 0; i < 4; i++) sA[nb][ac + i][ar] = ra[i];
#pragma unroll
            for (int j = 0; j < 4; j++) sB[nb][brk][bcg + j] = rb[j];
            __syncthreads();
        }
    }
#pragma unroll
    for (int a = 0; a < 4; a++) {
        int oc = m0 + ty * 4 + a;
        if (oc >= Cout) break;
        float bv = bias[oc];
        float* op = out + ((size_t)b * Cout + oc) * HH;
#pragma unroll
        for (int q = 0; q < 4; q++) {
            float v = acc[a][q] + bv;
            if (relu) v = fmaxf(v, 0.f);
            op[rem0 + tx * 4 + q] = v;
        }
    }
}

template<int OCB>
__global__ void __launch_bounds__(256) k_conv(const float* __restrict__ in,
    const float* __restrict__ w, const float* __restrict__ bias,
    float* __restrict__ out, int Cin, int Cout, int H, int relu, int ups)
{
    __shared__ float sI[34][36];
    __shared__ float sW[OCB][9];
    int Hi = H >> ups, HHi = Hi * Hi;
    int tiles = H >> 5;
    int bx = blockIdx.x % tiles, by = blockIdx.x / tiles;
    int x0 = bx * 32, y0 = by * 32;
    int oc0 = blockIdx.y * OCB, b = blockIdx.z;
    int tid = threadIdx.x;
    int lx = (tid & 15) * 2, ly = (tid >> 4) * 2;
    float acc[OCB][4];
#pragma unroll
    for (int o = 0; o < OCB; o++) { acc[o][0]=0.f; acc[o][1]=0.f; acc[o][2]=0.f; acc[o][3]=0.f; }
    const float* ib = in + (size_t)b * Cin * HHi;
    for (int ic = 0; ic < Cin; ic++) {
        __syncthreads();
        const float* ip = ib + (size_t)ic * HHi;
        for (int i = tid; i < 34 * 34; i += 256) {
            int yy = i / 34, xx = i - yy * 34;
            int gy = y0 + yy - 1, gx = x0 + xx - 1;
            sI[yy][xx] = (gy >= 0 && gy < H && gx >= 0 && gx < H) ? ip[(gy >> ups) * Hi + (gx >> ups)] : 0.f;
        }
        if (tid < OCB * 9) {
            int oc = tid / 9, tt = tid - oc * 9;
            sW[oc][tt] = (oc0 + oc < Cout) ? w[((size_t)(oc0 + oc) * Cin + ic) * 9 + tt] : 0.f;
        }
        __syncthreads();
        float win[4][4];
#pragma unroll
        for (int r = 0; r < 4; r++)
#pragma unroll
            for (int s = 0; s < 4; s++) win[r][s] = sI[ly + r][lx + s];
#pragma unroll
        for (int o = 0; o < OCB; o++) {
            float w0=sW[o][0],w1=sW[o][1],w2=sW[o][2],w3=sW[o][3],w4=sW[o][4];
            float w5=sW[o][5],w6=sW[o][6],w7=sW[o][7],w8=sW[o][8];
#pragma unroll
            for (int p = 0; p < 4; p++) {
                int pr = p >> 1, pc = p & 1;
                acc[o][p] += win[pr][pc]*w0 + win[pr][pc+1]*w1 + win[pr][pc+2]*w2
                           + win[pr+1][pc]*w3 + win[pr+1][pc+1]*w4 + win[pr+1][pc+2]*w5
                           + win[pr+2][pc]*w6 + win[pr+2][pc+1]*w7 + win[pr+2][pc+2]*w8;
            }
        }
    }
#pragma unroll
    for (int o = 0; o < OCB; o++) {
        int oc = oc0 + o;
        if (oc >= Cout) break;
        float bv = bias[oc];
        float* op = out + ((size_t)b * Cout + oc) * H * H;
#pragma unroll
        for (int p = 0; p < 4; p++) {
            float v = acc[o][p] + bv;
            if (relu) v = fmaxf(v, 0.f);
            op[(y0 + ly + (p >> 1)) * H + x0 + lx + (p & 1)] = v;
        }
    }
}

template<int HO>
__global__ void k_pool(const float* __restrict__ in, float* __restrict__ out, int tot) {
    int i = blockIdx.x * 256 + threadIdx.x;
    if (i >= tot) return;
    int x = i % HO, y = (i / HO) % HO; int bc = i / (HO * HO);
    const int Hi = HO * 2;
    const float* p = in + (size_t)bc * Hi * Hi;
    out[i] = (p[(2*y)*Hi + 2*x] + p[(2*y)*Hi + 2*x+1] + p[(2*y+1)*Hi + 2*x] + p[(2*y+1)*Hi + 2*x+1]) * 0.25f;
}

// single-pass stats: fp32 per-thread partials, double block-reduce
template<int HW, int TPB>
__global__ void __launch_bounds__(TPB) k_stats2(const float* __restrict__ in,
                                                float* __restrict__ mo, float* __restrict__ so) {
    __shared__ double rs[TPB], rq[TPB];
    int bc = blockIdx.x, tid = threadIdx.x;
    const float* p = in + (size_t)bc * HW;
    constexpr int IT = HW / (TPB * 4);
    float s0 = 0, s1 = 0, s2 = 0, s3 = 0;
    float q0 = 0, q1 = 0, q2 = 0, q3 = 0;
#pragma unroll
    for (int i = 0; i < IT; i++) {
        float4 v = *(const float4*)(p + (i * TPB + tid) * 4);
        s0 += v.x; s1 += v.y; s2 += v.z; s3 += v.w;
        q0 += v.x * v.x; q1 += v.y * v.y; q2 += v.z * v.z; q3 += v.w * v.w;
    }
    rs[tid] = (double)(s0 + s1) + (double)(s2 + s3);
    rq[tid] = (double)(q0 + q1) + (double)(q2 + q3);
    __syncthreads();
    for (int o = TPB / 2; o > 0; o >>= 1) {
        if (tid < o) { rs[tid] += rs[tid + o]; rq[tid] += rq[tid + o]; }
        __syncthreads();
    }
    if (tid == 0) {
        double m = rs[0] / HW;
        double var = rq[0] / HW - m * m;
        mo[bc] = (float)m;
        so[bc] = (float)sqrt(var > 0.0 ? var : 0.0);
    }
}

__global__ void k_transp() {
    __shared__ float t[32][33];
    int sb = blockIdx.x, c0 = blockIdx.y * 32, n0 = blockIdx.z * 32;
    const float* f = g_f4 + (size_t)sb * 524288;
    int tx = threadIdx.x, ty = threadIdx.y;
    for (int j = 0; j < 32; j += 8) t[ty + j][tx] = f[(c0 + ty + j) * 1024 + n0 + tx];
    __syncthreads();
    for (int j = 0; j < 32; j += 8) g_fT[(size_t)sb * 524288 + (size_t)(n0 + ty + j) * 512 + c0 + tx] = t[tx][ty + j];
}

__global__ void k_cent0() {
    int i = blockIdx.x * 256 + threadIdx.x;
    if (i >= 12288) return;
    int c = i & 511, k = (i >> 9) % 3, sb = i / 1536;
    const float* f = g_f4 + (size_t)sb * 524288;
    g_cent[i] = f[c * 1024 + k];
}

__global__ void __launch_bounds__(256) k_assign2() {
    __shared__ float sc[3][512];
    int sb = blockIdx.x >> 2;
    int n = (blockIdx.x & 3) * 256 + threadIdx.x;
    for (int i = threadIdx.x; i < 1536; i += 256) ((float*)sc)[i] = g_cent[sb * 1536 + i];
    __syncthreads();
    const float* f = g_f4 + (size_t)sb * 524288;
    float d0 = 0, d1 = 0, d2 = 0;
    for (int c = 0; c < 512; c++) {
        float v = f[c * 1024 + n];
        float a = v - sc[0][c], b = v - sc[1][c], e = v - sc[2][c];
        d0 += a * a; d1 += b * b; d2 += e * e;
    }
    int a = 0; float best = d0;
    if (d1 < best) { best = d1; a = 1; }
    if (d2 < best) { a = 2; }
    g_asg[sb * 1024 + n] = a;
}

__global__ void __launch_bounds__(128) k_update2() {
    __shared__ int sa[1024];
    int sb = blockIdx.x >> 2;
    int c = (blockIdx.x & 3) * 128 + threadIdx.x;
    for (int i = threadIdx.x; i < 1024; i += 128) sa[i] = g_asg[sb * 1024 + i];
    __syncthreads();
    const float* ft = g_fT + (size_t)sb * 524288;
    float s0 = 0, s1 = 0, s2 = 0; int c0 = 0, c1 = 0, c2 = 0;
    for (int n = 0; n < 1024; n++) {
        float v = ft[n * 512 + c];
        int a = sa[n];
        if (a == 0) { s0 += v; c0++; } else if (a == 1) { s1 += v; c1++; } else { s2 += v; c2++; }
    }
    g_cent[sb * 1536 + c]        = s0 / ((float)c0 + 1e-6f);
    g_cent[sb * 1536 + 512 + c]  = s1 / ((float)c1 + 1e-6f);
    g_cent[sb * 1536 + 1024 + c] = s2 / ((float)c2 + 1e-6f);
    if ((blockIdx.x & 3) == 0 && threadIdx.x < 3)
        g_cnt[sb * 3 + threadIdx.x] = (float)(threadIdx.x == 0 ? c0 : (threadIdx.x == 1 ? c1 : c2));
}

__global__ void k_aw() {
    int i = blockIdx.x * 256 + threadIdx.x;
    if (i >= 12582912) return;
    int n = i & 1023, c = (i >> 10) & 511, m = i >> 19;
    int k = m % 3, sb = m / 3;
    const float* f = g_f4 + (size_t)sb * 524288;
    int a = g_asg[sb * 1024 + n];
    g_aw[i] = (a == k) ? f[c * 1024 + n] - g_cent[sb * 1536 + k * 512 + c] : 0.f;
}

__global__ void __launch_bounds__(256, 2) k_covg() {
    __shared__ float sA[16][128], sB[16][128];
    int m = blockIdx.z;
    const float* A = g_aw + (size_t)m * 524288;
    int bi = c_pi[blockIdx.x], bj = c_pj[blockIdx.x];
    int i0 = bi * 128, j0 = bj * 128;
    int tid = threadIdx.x;
    int ar = tid >> 1, ac = (tid & 1) * 8;
    int ty = tid >> 4, tx = tid & 15;
    float acc[8][8];
#pragma unroll
    for (int a = 0; a < 8; a++)
#pragma unroll
        for (int b = 0; b < 8; b++) acc[a][b] = 0.f;
    float4 ra0 = *(const float4*)&A[(size_t)(i0 + ar) * 1024 + ac];
    float4 ra1 = *(const float4*)&A[(size_t)(i0 + ar) * 1024 + ac + 4];
    float4 rb0 = *(const float4*)&A[(size_t)(j0 + ar) * 1024 + ac];
    float4 rb1 = *(const float4*)&A[(size_t)(j0 + ar) * 1024 + ac + 4];
    for (int k0 = 0; k0 < 1024; k0 += 16) {
        sA[ac+0][ar]=ra0.x; sA[ac+1][ar]=ra0.y; sA[ac+2][ar]=ra0.z; sA[ac+3][ar]=ra0.w;
        sA[ac+4][ar]=ra1.x; sA[ac+5][ar]=ra1.y; sA[ac+6][ar]=ra1.z; sA[ac+7][ar]=ra1.w;
        sB[ac+0][ar]=rb0.x; sB[ac+1][ar]=rb0.y; sB[ac+2][ar]=rb0.z; sB[ac+3][ar]=rb0.w;
        sB[ac+4][ar]=rb1.x; sB[ac+5][ar]=rb1.y; sB[ac+6][ar]=rb1.z; sB[ac+7][ar]=rb1.w;
        __syncthreads();
        if (k0 + 16 < 1024) {
            ra0 = *(const float4*)&A[(size_t)(i0 + ar) * 1024 + k0 + 16 + ac];
            ra1 = *(const float4*)&A[(size_t)(i0 + ar) * 1024 + k0 + 16 + ac + 4];
            rb0 = *(const float4*)&A[(size_t)(j0 + ar) * 1024 + k0 + 16 + ac];
            rb1 = *(const float4*)&A[(size_t)(j0 + ar) * 1024 + k0 + 16 + ac + 4];
        }
#pragma unroll
        for (int k = 0; k < 16; k++) {
            float av[8], bv[8];
            *(float4*)av = *(float4*)&sA[k][ty * 8]; *(float4*)(av+4) = *(float4*)&sA[k][ty * 8 + 4];
            *(float4*)bv = *(float4*)&sB[k][tx * 8]; *(float4*)(bv+4) = *(float4*)&sB[k][tx * 8 + 4];
#pragma unroll
            for (int a = 0; a < 8; a++)
#pragma unroll
                for (int b = 0; b < 8; b++) acc[a][b] += av[a] * bv[b];
        }
        __syncthreads();
    }
    float nc = g_cnt[m] + 1e-6f;
    float* C = g_cov + (size_t)m * MS;
#pragma unroll
    for (int a = 0; a < 8; a++)
#pragma unroll
        for (int b = 0; b < 8; b++) {
            int gi = i0 + ty * 8 + a, gj = j0 + tx * 8 + b;
            float v = acc[a][b] / nc + (gi == gj ? 0.1f : 0.f);
            C[gi * 512 + gj] = v;
            if (bi != bj) C[gj * 512 + gi] = v;
        }
}

__global__ void __launch_bounds__(256) k_norm() {
    __shared__ float red[256];
    int m = blockIdx.x;
    const float* A = g_cov + (size_t)m * MS;
    float mx = 0;
    for (int r = threadIdx.x; r < 512; r += 256) {
        float s = 0;
        for (int c = 0; c < 512; c++) s += fabsf(A[r * 512 + c]);
        mx = fmaxf(mx, s);
    }
    red[threadIdx.x] = mx; __syncthreads();
    for (int o = 128; o > 0; o >>= 1) { if (threadIdx.x < o) red[threadIdx.x] = fmaxf(red[threadIdx.x], red[threadIdx.x + o]); __syncthreads(); }
    if (threadIdx.x == 0) g_nrm[m] = red[0];
}

__global__ void k_nsinit() {
    int i = blockIdx.x * 256 + threadIdx.x;
    if (i >= 6291456) return;
    int m = i >> 18;
    g_Y[i] = g_cov[i] / g_nrm[m];
}

__global__ void __launch_bounds__(256, 2) k_gemmsym(
    const float* __restrict__ A, const float* __restrict__ B,
    float* __restrict__ C, const float* __restrict__ Mp, int polymode)
{
    __shared__ float sA[2][16][128], sB[2][16][128];
    int z = blockIdx.z;
    const float* Ab = A + (size_t)z * MS;
    const float* Bb = B + (size_t)z * MS;
    float* Cb = C + (size_t)z * MS;
    const float* Mb = Mp + (size_t)z * MS;
    int bi = c_pi[blockIdx.x], bj = c_pj[blockIdx.x];
    int m0 = bi * 128, n0 = bj * 128;
    int tid = threadIdx.x;
    int ar = tid >> 1, ac = (tid & 1) * 8;
    int br = tid >> 4, bc = (tid & 15) * 8;
    int ty = tid >> 4, tx = tid & 15;
    float acc[8][8];
#pragma unroll
    for (int a = 0; a < 8; a++)
#pragma unroll
        for (int b = 0; b < 8; b++) acc[a][b] = 0.f;
    float4 ra0 = *(const float4*)&Ab[(size_t)(m0 + ar) * 512 + ac];
    float4 ra1 = *(const float4*)&Ab[(size_t)(m0 + ar) * 512 + ac + 4];
    float4 rb0 = *(const float4*)&Bb[(size_t)br * 512 + n0 + bc];
    float4 rb1 = *(const float4*)&Bb[(size_t)br * 512 + n0 + bc + 4];
    sA[0][ac+0][ar]=ra0.x; sA[0][ac+1][ar]=ra0.y; sA[0][ac+2][ar]=ra0.z; sA[0][ac+3][ar]=ra0.w;
    sA[0][ac+4][ar]=ra1.x; sA[0][ac+5][ar]=ra1.y; sA[0][ac+6][ar]=ra1.z; sA[0][ac+7][ar]=ra1.w;
    *(float4*)&sB[0][br][bc] = rb0; *(float4*)&sB[0][br][bc + 4] = rb1;
    __syncthreads();
    for (int s = 0; s < 32; s++) {
        int buf = s & 1;
        if (s < 31) {
            int k0 = (s + 1) * 16;
            ra0 = *(const float4*)&Ab[(size_t)(m0 + ar) * 512 + k0 + ac];
            ra1 = *(const float4*)&Ab[(size_t)(m0 + ar) * 512 + k0 + ac + 4];
            rb0 = *(const float4*)&Bb[(size_t)(k0 + br) * 512 + n0 + bc];
            rb1 = *(const float4*)&Bb[(size_t)(k0 + br) * 512 + n0 + bc + 4];
        }
#pragma unroll
        for (int k = 0; k < 16; k++) {
            float av[8], bv[8];
            *(float4*)av = *(float4*)&sA[buf][k][ty * 8]; *(float4*)(av+4) = *(float4*)&sA[buf][k][ty * 8 + 4];
            *(float4*)bv = *(float4*)&sB[buf][k][tx * 8]; *(float4*)(bv+4) = *(float4*)&sB[buf][k][tx * 8 + 4];
#pragma unroll
            for (int a = 0; a < 8; a++)
#pragma unroll
                for (int b = 0; b < 8; b++) acc[a][b] += av[a] * bv[b];
        }
        if (s < 31) {
            int nb = buf ^ 1;
            sA[nb][ac+0][ar]=ra0.x; sA[nb][ac+1][ar]=ra0.y; sA[nb][ac+2][ar]=ra0.z; sA[nb][ac+3][ar]=ra0.w;
            sA[nb][ac+4][ar]=ra1.x; sA[nb][ac+5][ar]=ra1.y; sA[nb][ac+6][ar]=ra1.z; sA[nb][ac+7][ar]=ra1.w;
            *(float4*)&sB[nb][br][bc] = rb0; *(float4*)&sB[nb][br][bc + 4] = rb1;
            __syncthreads();
        }
    }
#pragma unroll
    for (int a = 0; a < 8; a++) {
        int gi = m0 + ty * 8 + a;
#pragma unroll
        for (int b = 0; b < 8; b++) {
            int gj = n0 + tx * 8 + b;
            float v = acc[a][b];
            if (polymode)
                v = ((gi == gj ? 15.f : 0.f) - 10.f * Mb[(size_t)gi * 512 + gj] + 3.f * v) * 0.125f;
            Cb[(size_t)gi * 512 + gj] = v;
            if (bi != bj) Cb[(size_t)gj * 512 + gi] = v;
        }
    }
}

__global__ void __launch_bounds__(256, 2) k_gemm16(
    const float* __restrict__ A, int strA, const float* __restrict__ B, int strB, int bdiv,
    float* __restrict__ C, int strC, int N, float alpha, int nrmmode)
{
    __shared__ float sA[2][16][128], sB[2][16][128];
    int z = blockIdx.z;
    const float* Ab = A + (size_t)z * strA;
    const float* Bb = B + (size_t)(bdiv ? z / 3 : z) * strB;
    float* Cb = C + (size_t)z * strC;
    if (nrmmode) alpha = sqrtf(g_nrm[12 + z] / g_nrm[z]);
    int m0 = blockIdx.y * 128, n0 = blockIdx.x * 128;
    int tid = threadIdx.x;
    int ar = tid >> 1, ac = (tid & 1) * 8;
    int br = tid >> 4, bc = (tid & 15) * 8;
    int ty = tid >> 4, tx = tid & 15;
    float acc[8][8];
#pragma unroll
    for (int a = 0; a < 8; a++)
#pragma unroll
        for (int b = 0; b < 8; b++) acc[a][b] = 0.f;
    float4 ra0 = *(const float4*)&Ab[(size_t)(m0 + ar) * 512 + ac];
    float4 ra1 = *(const float4*)&Ab[(size_t)(m0 + ar) * 512 + ac + 4];
    float4 rb0 = *(const float4*)&Bb[(size_t)br * N + n0 + bc];
    float4 rb1 = *(const float4*)&Bb[(size_t)br * N + n0 + bc + 4];
    sA[0][ac+0][ar]=ra0.x; sA[0][ac+1][ar]=ra0.y; sA[0][ac+2][ar]=ra0.z; sA[0][ac+3][ar]=ra0.w;
    sA[0][ac+4][ar]=ra1.x; sA[0][ac+5][ar]=ra1.y; sA[0][ac+6][ar]=ra1.z; sA[0][ac+7][ar]=ra1.w;
    *(float4*)&sB[0][br][bc] = rb0; *(float4*)&sB[0][br][bc + 4] = rb1;
    __syncthreads();
    for (int s = 0; s < 32; s++) {
        int buf = s & 1;
        if (s < 31) {
            int k0 = (s + 1) * 16;
            ra0 = *(const float4*)&Ab[(size_t)(m0 + ar) * 512 + k0 + ac];
            ra1 = *(const float4*)&Ab[(size_t)(m0 + ar) * 512 + k0 + ac + 4];
            rb0 = *(const float4*)&Bb[(size_t)(k0 + br) * N + n0 + bc];
            rb1 = *(const float4*)&Bb[(size_t)(k0 + br) * N + n0 + bc + 4];
        }
#pragma unroll
        for (int k = 0; k < 16; k++) {
            float av[8], bv[8];
            *(float4*)av = *(float4*)&sA[buf][k][ty * 8]; *(float4*)(av+4) = *(float4*)&sA[buf][k][ty * 8 + 4];
            *(float4*)bv = *(float4*)&sB[buf][k][tx * 8]; *(float4*)(bv+4) = *(float4*)&sB[buf][k][tx * 8 + 4];
#pragma unroll
            for (int a = 0; a < 8; a++)
#pragma unroll
                for (int b = 0; b < 8; b++) acc[a][b] += av[a] * bv[b];
        }
        if (s < 31) {
            int nb = buf ^ 1;
            sA[nb][ac+0][ar]=ra0.x; sA[nb][ac+1][ar]=ra0.y; sA[nb][ac+2][ar]=ra0.z; sA[nb][ac+3][ar]=ra0.w;
            sA[nb][ac+4][ar]=ra1.x; sA[nb][ac+5][ar]=ra1.y; sA[nb][ac+6][ar]=ra1.z; sA[nb][ac+7][ar]=ra1.w;
            *(float4*)&sB[nb][br][bc] = rb0; *(float4*)&sB[nb][br][bc + 4] = rb1;
            __syncthreads();
        }
    }
#pragma unroll
    for (int a = 0; a < 8; a++) {
        int gm = m0 + ty * 8 + a;
#pragma unroll
        for (int b = 0; b < 8; b++) {
            int gn = n0 + tx * 8 + b;
            Cb[(size_t)gm * N + gn] = alpha * acc[a][b];
        }
    }
}

__global__ void __launch_bounds__(512) k_gemv() {
    __shared__ float mu[512];
    int z = blockIdx.x;
    int b = z / 3, k = z % 3;
    int tid = threadIdx.x;
    mu[tid] = g_cent[b * 1536 + k * 512 + tid];
    __syncthreads();
    const float* T = g_Tm + (size_t)z * MS;
    int warp = tid >> 5, lane = tid & 31;
    for (int c = warp; c < 512; c += 16) {
        float s = 0;
        for (int d = lane; d < 512; d += 32) s += T[c * 512 + d] * mu[d];
#pragma unroll
        for (int o = 16; o > 0; o >>= 1) s += __shfl_down_sync(0xffffffff, s, o);
        if (lane == 0) g_vv[z * 512 + c] = s;
    }
}

__global__ void k_comb(const float* __restrict__ tp) {
    int i = blockIdx.x * 256 + threadIdx.x;
    if (i >= 2097152) return;
    int n = i & 1023, c = (i >> 10) & 511, b = i >> 19;
    int a = g_asg[b * 1024 + n];
    int z = b * 3 + a;
    float val = tp[(size_t)z * 524288 + c * 1024 + n] - g_vv[z * 512 + c]
              + g_cent[(4 + b) * 1536 + a * 512 + c];
    g_f4t[i] = 0.6f * val + 0.4f * g_f4[i];
}

__global__ void __launch_bounds__(256) k_closs1() {
    __shared__ double red[256];
    int start = blockIdx.x * 8192;
    float s0 = 0, s1 = 0;
    for (int i = threadIdx.x * 2; i < 8192; i += 512) {
        float d0 = g_f4e[start + i] - g_f4[start + i];
        float d1 = g_f4e[start + i + 1] - g_f4[start + i + 1];
        s0 += d0 * d0; s1 += d1 * d1;
    }
    red[threadIdx.x] = (double)s0 + (double)s1; __syncthreads();
    for (int o = 128; o > 0; o >>= 1) { if (threadIdx.x < o) red[threadIdx.x] += red[threadIdx.x + o]; __syncthreads(); }
    if (threadIdx.x == 0) g_part[blockIdx.x] = red[0];
}

__global__ void __launch_bounds__(256) k_final(float* out) {
    __shared__ double red[256];
    __shared__ double slv;
    __shared__ double closs;
    const int off[5] = {0, 256, 768, 1792, 3840};
    if (threadIdx.x == 0) slv = 0;
    red[threadIdx.x] = g_part[threadIdx.x];
    __syncthreads();
    for (int o = 128; o > 0; o >>= 1) { if (threadIdx.x < o) red[threadIdx.x] += red[threadIdx.x + o]; __syncthreads(); }
    if (threadIdx.x == 0) closs = red[0] / 2097152.0;
    __syncthreads();
    for (int l = 0; l < 4; l++) {
        int o0 = off[l], sz = off[l + 1] - off[l];
        double s = 0;
        for (int i = threadIdx.x; i < sz; i += 256) {
            float dm = g_st[2 * 3840 + o0 + i] - g_st[0 * 3840 + o0 + i];
            float ds = g_st[3 * 3840 + o0 + i] - g_st[1 * 3840 + o0 + i];
            s += (double)dm * dm + (double)ds * ds;
        }
        red[threadIdx.x] = s; __syncthreads();
        for (int o = 128; o > 0; o >>= 1) { if (threadIdx.x < o) red[threadIdx.x] += red[threadIdx.x + o]; __syncthreads(); }
        if (threadIdx.x == 0) slv += red[0] / sz;
        __syncthreads();
    }
    if (threadIdx.x == 0) out[0] = (float)closs + 0.01f * (float)slv;
}

extern "C" void kernel_launch(void* const* d_in, const int* in_sizes, int n_in,
                              void* d_out, int out_size) {
    (void)in_sizes; (void)n_in; (void)out_size;
    const float* in[18];
    for (int i = 0; i < 18; i++) in[i] = (const float*)d_in[i];

    float *b0, *b1, *in8, *f4, *f4t, *f4e, *dec, *Y, *Z, *Tt, *cov, *aw, *Tm, *st;
    cudaGetSymbolAddress((void**)&b0, g_b0);
    cudaGetSymbolAddress((void**)&b1, g_b1);
    cudaGetSymbolAddress((void**)&in8, g_in8);
    cudaGetSymbolAddress((void**)&f4, g_f4);
    cudaGetSymbolAddress((void**)&f4t, g_f4t);
    cudaGetSymbolAddress((void**)&f4e, g_f4e);
    cudaGetSymbolAddress((void**)&dec, g_dec);
    cudaGetSymbolAddress((void**)&Y, g_Y);
    cudaGetSymbolAddress((void**)&Z, g_Z);
    cudaGetSymbolAddress((void**)&Tt, g_Tt);
    cudaGetSymbolAddress((void**)&cov, g_cov);
    cudaGetSymbolAddress((void**)&aw, g_aw);
    cudaGetSymbolAddress((void**)&Tm, g_Tm);
    cudaGetSymbolAddress((void**)&st, g_st);
    float* aw1 = aw + 6291456;

    auto conv = [&](const float* i0, float* o, const float* w, const float* bb,
                    int Cin, int Cout, int H, int relu, int B, int ups) {
        if (Cin >= 64 && Cout >= 64) {
            int bx = (B * H * H) / 128, by = (Cout + 127) / 128;
            if (bx * by >= 148) {
                k_cgemm<<<dim3(bx, by, 1), 256>>>(i0, w, bb, o, Cin, Cout, H, relu, ups);
            } else {
                dim3 g((B * H * H) / 64, (Cout + 63) / 64, 1);
                k_cgemm64<<<g, 256>>>(i0, w, bb, o, Cin, Cout, H, relu, ups);
            }
        } else if (H >= 64) {
            dim3 g((H / 32) * (H / 32), (Cout + 15) / 16, B);
            k_conv<16><<<g, 256>>>(i0, w, bb, o, Cin, Cout, H, relu, ups);
        } else {
            dim3 g((H / 32) * (H / 32), (Cout + 7) / 8, B);
            k_conv<8><<<g, 256>>>(i0, w, bb, o, Cin, Cout, H, relu, ups);
        }
    };
    auto pool = [&](const float* i0, float* o, int C, int Ho, int B) {
        int tot = B * C * Ho * Ho; int g = (tot + 255) / 256;
        if (Ho == 128) k_pool<128><<<g, 256>>>(i0, o, tot);
        else if (Ho == 64) k_pool<64><<<g, 256>>>(i0, o, tot);
        else k_pool<32><<<g, 256>>>(i0, o, tot);
    };
    auto enc = [&](const float* x, int B, float* f4o, float* mo, float* so, int soff) {
        conv(x, b0, in[2], in[3], 3, 64, 256, 1, B, 0);
        if (mo) k_stats2<65536, 1024><<<256, 1024>>>(b0 + (size_t)soff * 64 * 65536, mo, so);
        pool(b0, b1, 64, 128, B);
        conv(b1, b0, in[4], in[5], 64, 128, 128, 1, B, 0);
        if (mo) k_stats2<16384, 1024><<<512, 1024>>>(b0 + (size_t)soff * 128 * 16384, mo + 256, so + 256);
        pool(b0, b1, 128, 64, B);
        conv(b1, b0, in[6], in[7], 128, 256, 64, 1, B, 0);
        if (mo) k_stats2<4096, 256><<<1024, 256>>>(b0 + (size_t)soff * 256 * 4096, mo + 768, so + 768);
        pool(b0, b1, 256, 32, B);
        conv(b1, f4o, in[8], in[9], 256, 512, 32, 1, B, 0);
        if (mo) k_stats2<1024, 256><<<2048, 256>>>(f4o + (size_t)soff * 512 * 1024, mo + 1792, so + 1792);
    };

    cudaMemcpyAsync(in8, in[0], 786432 * 4, cudaMemcpyDeviceToDevice);
    cudaMemcpyAsync(in8 + 786432, in[1], 786432 * 4, cudaMemcpyDeviceToDevice);
    k_dummy<<<1, 256>>>();
    k_dummy<<<1, 256>>>();

    enc(in8, 8, f4, st + 0, st + 3840, 4);

    k_transp<<<dim3(8, 16, 32), dim3(32, 8)>>>();
    k_cent0<<<48, 256>>>();
    for (int it = 0; it < 11; it++) {
        k_assign2<<<32, 256>>>();
        k_update2<<<32, 128>>>();
    }

    k_aw<<<(12582912 + 255) / 256, 256>>>();
    k_covg<<<dim3(10, 1, 24), 256>>>();
    k_norm<<<24, 256>>>();
    k_nsinit<<<((6291456 + 255) / 256), 256>>>();

    dim3 gs(10, 1, 24);
    k_gemmsym<<<gs, 256>>>(Y, Y, cov, Y, 1);
    k_gemmsym<<<gs, 256>>>(Y, cov, aw, cov, 0);
    float* Yc = aw; float* Zc = cov;
    float* fr[4] = {Y, Z, Tt, aw1};
    for (int it = 0; it < 14; it++) {
        float* M = fr[0]; float* P = fr[1]; float* Yn = fr[2]; float* Zn = fr[3];
        k_gemmsym<<<gs, 256>>>(Zc, Yc, M, Zc, 0);
        k_gemmsym<<<gs, 256>>>(M, M, P, M, 1);
        if (it < 13) {
            k_gemmsym<<<gs, 256>>>(Yc, P, Yn, Yc, 0);
            k_gemmsym<<<gs, 256>>>(P, Zc, Zn, P, 0);
        } else {
            size_t so12 = (size_t)12 * MS;
            k_gemmsym<<<dim3(10, 1, 12), 256>>>(Yc + so12, P + so12, Yn + so12, Yc + so12, 0);
            k_gemmsym<<<dim3(10, 1, 12), 256>>>(P, Zc, Zn, P, 0);
        }
        fr[0] = Yc; fr[1] = Zc; fr[2] = M; fr[3] = P;
        Yc = Yn; Zc = Zn;
    }

    k_gemm16<<<dim3(4, 4, 12), 256>>>(Yc + (size_t)12 * MS, MS, Zc, MS, 0,
                                      Tm, MS, 512, 1.f, 1);
    float* tp = fr[0];
    k_gemm16<<<dim3(8, 4, 12), 256>>>(Tm, MS, f4, 524288, 1, tp, 524288, 1024, 1.f, 0);
    k_gemv<<<12, 512>>>();
    k_comb<<<(2097152 + 255) / 256, 256>>>(tp);

    // decoder with upsample folded into conv gather
    conv(f4t, b0, in[10], in[11], 512, 256, 32, 1, 4, 0);
    conv(b0, b1, in[12], in[13], 256, 128, 64, 1, 4, 1);
    conv(b1, b0, in[14], in[15], 128, 64, 128, 1, 4, 1);
    conv(b0, dec, in[16], in[17], 64, 3, 256, 0, 4, 1);

    enc(dec, 4, f4e, st + 2 * 3840, st + 3 * 3840, 0);

    k_closs1<<<256, 256>>>();
    k_final<<<1, 256>>>((float*)d_out);
}

// round 17
// speedup vs baseline: 2.2582x; 1.0072x over previous
#include <cuda_runtime.h>
#include <math.h>

#define MS 262144
__device__ float g_b0[33554432];
__device__ float g_b1[33554432];
__device__ float g_in8[1572864];
__device__ float g_f4[4194304];
__device__ float g_f4t[2097152];
__device__ float g_f4e[2097152];
__device__ float g_dec[786432];
__device__ float g_fT[4194304];
__device__ float g_cent[12288];
__device__ int   g_asg[8192];
__device__ float g_cnt[24];
__device__ float g_aw[12582912];
__device__ float g_cov[6291456];
__device__ float g_Y[6291456];
__device__ float g_Z[6291456];
__device__ float g_Tt[6291456];
__device__ float g_nrm[24];
__device__ float g_Tm[3145728];
__device__ float g_vv[6144];
__device__ float g_st[15360];
__device__ double g_part[256];

__constant__ int c_pi[10] = {0,0,0,0,1,1,1,2,2,3};
__constant__ int c_pj[10] = {0,1,2,3,1,2,3,2,3,3};

__global__ void k_dummy() { g_part[threadIdx.x] = 0.0; }

// ---------- implicit-GEMM conv 3x3, 128x128 tile; ups folds repeat-2 upsample ----------
__global__ void __launch_bounds__(256, 2) k_cgemm(
    const float* __restrict__ in, const float* __restrict__ w,
    const float* __restrict__ bias, float* __restrict__ out,
    int Cin, int Cout, int H, int relu, int ups)
{
    __shared__ float sA[2][16][128], sB[2][16][128];
    int K = Cin * 9, HH = H * H;
    int Hi = H >> ups, HHi = Hi * Hi;
    int m0 = blockIdx.y * 128, n0 = blockIdx.x * 128;
    int tid = threadIdx.x;
    int ar = tid >> 1, ac = (tid & 1) * 8;
    int brk = tid >> 4, bcg = (tid & 15) * 8;
    int ty = tid >> 4, tx = tid & 15;
    int b = n0 / HH, rem0 = n0 - b * HH;
    int cy[8], cx[8];
#pragma unroll
    for (int j = 0; j < 8; j++) {
        int rem = rem0 + bcg + j;
        int yy = rem / H;
        cy[j] = yy; cx[j] = rem - yy * H;
    }
    const float* inb = in + (size_t)b * Cin * HHi;
    float acc[8][8];
#pragma unroll
    for (int a = 0; a < 8; a++)
#pragma unroll
        for (int q = 0; q < 8; q++) acc[a][q] = 0.f;
    float ra[8], rb[8];
    int aok = (m0 + ar) < Cout;
    const float* awp = w + (size_t)(aok ? m0 + ar : 0) * K + ac;
    if (aok) { *(float4*)ra = *(const float4*)awp; *(float4*)(ra+4) = *(const float4*)(awp+4); }
    else { for (int i = 0; i < 8; i++) ra[i] = 0.f; }
    {
        int k = brk;
        int ic = k / 9, rs = k - ic * 9;
        int dy = rs / 3 - 1, dx = rs - (rs / 3) * 3 - 1;
        const float* ip = inb + (size_t)ic * HHi;
#pragma unroll
        for (int j = 0; j < 8; j++) {
            int yy = cy[j] + dy, xx = cx[j] + dx;
            rb[j] = (yy >= 0 && yy < H && xx >= 0 && xx < H) ? ip[(yy >> ups) * Hi + (xx >> ups)] : 0.f;
        }
    }
    int nk = K / 16;
#pragma unroll
    for (int i = 0; i < 8; i++) sA[0][ac + i][ar] = ra[i];
#pragma unroll
    for (int j = 0; j < 8; j++) sB[0][brk][bcg + j] = rb[j];
    __syncthreads();
    for (int s = 0; s < nk; s++) {
        int buf = s & 1;
        if (s + 1 < nk) {
            int k0 = (s + 1) * 16;
            if (aok) { *(float4*)ra = *(const float4*)(awp + k0); *(float4*)(ra+4) = *(const float4*)(awp + k0 + 4); }
            int k = k0 + brk;
            int ic = k / 9, rs = k - ic * 9;
            int dy = rs / 3 - 1, dx = rs - (rs / 3) * 3 - 1;
            const float* ip = inb + (size_t)ic * HHi;
#pragma unroll
            for (int j = 0; j < 8; j++) {
                int yy = cy[j] + dy, xx = cx[j] + dx;
                rb[j] = (yy >= 0 && yy < H && xx >= 0 && xx < H) ? ip[(yy >> ups) * Hi + (xx >> ups)] : 0.f;
            }
        }
#pragma unroll
        for (int k = 0; k < 16; k++) {
            float av[8], bv[8];
            *(float4*)av = *(float4*)&sA[buf][k][ty * 8]; *(float4*)(av+4) = *(float4*)&sA[buf][k][ty * 8 + 4];
            *(float4*)bv = *(float4*)&sB[buf][k][tx * 8]; *(float4*)(bv+4) = *(float4*)&sB[buf][k][tx * 8 + 4];
#pragma unroll
            for (int a = 0; a < 8; a++)
#pragma unroll
                for (int q = 0; q < 8; q++) acc[a][q] += av[a] * bv[q];
        }
        if (s + 1 < nk) {
            int nb = buf ^ 1;
#pragma unroll
            for (int i = 0; i < 8; i++) sA[nb][ac + i][ar] = ra[i];
#pragma unroll
            for (int j = 0; j < 8; j++) sB[nb][brk][bcg + j] = rb[j];
            __syncthreads();
        }
    }
#pragma unroll
    for (int a = 0; a < 8; a++) {
        int oc = m0 + ty * 8 + a;
        if (oc >= Cout) break;
        float bv = bias[oc];
        float* op = out + ((size_t)b * Cout + oc) * HH;
#pragma unroll
        for (int q = 0; q < 8; q++) {
            float v = acc[a][q] + bv;
            if (relu) v = fmaxf(v, 0.f);
            op[rem0 + tx * 8 + q] = v;
        }
    }
}

// ---------- implicit-GEMM conv 3x3, 64x64 tile (small grids) ----------
__global__ void __launch_bounds__(256, 4) k_cgemm64(
    const float* __restrict__ in, const float* __restrict__ w,
    const float* __restrict__ bias, float* __restrict__ out,
    int Cin, int Cout, int H, int relu, int ups)
{
    __shared__ float sA[2][16][64], sB[2][16][64];
    int K = Cin * 9, HH = H * H;
    int Hi = H >> ups, HHi = Hi * Hi;
    int m0 = blockIdx.y * 64, n0 = blockIdx.x * 64;
    int tid = threadIdx.x;
    int ar = tid >> 2, ac = (tid & 3) * 4;
    int brk = tid >> 4, bcg = (tid & 15) * 4;
    int ty = tid >> 4, tx = tid & 15;
    int b = n0 / HH, rem0 = n0 - b * HH;
    int cy[4], cx[4];
#pragma unroll
    for (int j = 0; j < 4; j++) {
        int rem = rem0 + bcg + j;
        int yy = rem / H;
        cy[j] = yy; cx[j] = rem - yy * H;
    }
    const float* inb = in + (size_t)b * Cin * HHi;
    float acc[4][4];
#pragma unroll
    for (int a = 0; a < 4; a++)
#pragma unroll
        for (int q = 0; q < 4; q++) acc[a][q] = 0.f;
    float ra[4], rb[4];
    int aok = (m0 + ar) < Cout;
    const float* awp = w + (size_t)(aok ? m0 + ar : 0) * K + ac;
    if (aok) *(float4*)ra = *(const float4*)awp;
    else { for (int i = 0; i < 4; i++) ra[i] = 0.f; }
    {
        int k = brk;
        int ic = k / 9, rs = k - ic * 9;
        int dy = rs / 3 - 1, dx = rs - (rs / 3) * 3 - 1;
        const float* ip = inb + (size_t)ic * HHi;
#pragma unroll
        for (int j = 0; j < 4; j++) {
            int yy = cy[j] + dy, xx = cx[j] + dx;
            rb[j] = (yy >= 0 && yy < H && xx >= 0 && xx < H) ? ip[(yy >> ups) * Hi + (xx >> ups)] : 0.f;
        }
    }
    int nk = K / 16;
#pragma unroll
    for (int i = 0; i < 4; i++) sA[0][ac + i][ar] = ra[i];
#pragma unroll
    for (int j = 0; j < 4; j++) sB[0][brk][bcg + j] = rb[j];
    __syncthreads();
    for (int s = 0; s < nk; s++) {
        int buf = s & 1;
        if (s + 1 < nk) {
            int k0 = (s + 1) * 16;
            if (aok) *(float4*)ra = *(const float4*)(awp + k0);
            int k = k0 + brk;
            int ic = k / 9, rs = k - ic * 9;
            int dy = rs / 3 - 1, dx = rs - (rs / 3) * 3 - 1;
            const float* ip = inb + (size_t)ic * HHi;
#pragma unroll
            for (int j = 0; j < 4; j++) {
                int yy = cy[j] + dy, xx = cx[j] + dx;
                rb[j] = (yy >= 0 && yy < H && xx >= 0 && xx < H) ? ip[(yy >> ups) * Hi + (xx >> ups)] : 0.f;
            }
        }
#pragma unroll
        for (int k = 0; k < 16; k++) {
            float av[4], bv[4];
            *(float4*)av = *(float4*)&sA[buf][k][ty * 4];
            *(float4*)bv = *(float4*)&sB[buf][k][tx * 4];
#pragma unroll
            for (int a = 0; a < 4; a++)
#pragma unroll
                for (int q = 0; q < 4; q++) acc[a][q] += av[a] * bv[q];
        }
        if (s + 1 < nk) {
            int nb = buf ^ 1;
#pragma unroll
            for (int i = 0; i < 4; i++) sA[nb][ac + i][ar] = ra[i];
#pragma unroll
            for (int j = 0; j < 4; j++) sB[nb][brk][bcg + j] = rb[j];
            __syncthreads();
        }
    }
#pragma unroll
    for (int a = 0; a < 4; a++) {
        int oc = m0 + ty * 4 + a;
        if (oc >= Cout) break;
        float bv = bias[oc];
        float* op = out + ((size_t)b * Cout + oc) * HH;
#pragma unroll
        for (int q = 0; q < 4; q++) {
            float v = acc[a][q] + bv;
            if (relu) v = fmaxf(v, 0.f);
            op[rem0 + tx * 4 + q] = v;
        }
    }
}

template<int OCB>
__global__ void __launch_bounds__(256) k_conv(const float* __restrict__ in,
    const float* __restrict__ w, const float* __restrict__ bias,
    float* __restrict__ out, int Cin, int Cout, int H, int relu, int ups)
{
    __shared__ float sI[34][36];
    __shared__ float sW[OCB][9];
    int Hi = H >> ups, HHi = Hi * Hi;
    int tiles = H >> 5;
    int bx = blockIdx.x % tiles, by = blockIdx.x / tiles;
    int x0 = bx * 32, y0 = by * 32;
    int oc0 = blockIdx.y * OCB, b = blockIdx.z;
    int tid = threadIdx.x;
    int lx = (tid & 15) * 2, ly = (tid >> 4) * 2;
    float acc[OCB][4];
#pragma unroll
    for (int o = 0; o < OCB; o++) { acc[o][0]=0.f; acc[o][1]=0.f; acc[o][2]=0.f; acc[o][3]=0.f; }
    const float* ib = in + (size_t)b * Cin * HHi;
    for (int ic = 0; ic < Cin; ic++) {
        __syncthreads();
        const float* ip = ib + (size_t)ic * HHi;
        for (int i = tid; i < 34 * 34; i += 256) {
            int yy = i / 34, xx = i - yy * 34;
            int gy = y0 + yy - 1, gx = x0 + xx - 1;
            sI[yy][xx] = (gy >= 0 && gy < H && gx >= 0 && gx < H) ? ip[(gy >> ups) * Hi + (gx >> ups)] : 0.f;
        }
        if (tid < OCB * 9) {
            int oc = tid / 9, tt = tid - oc * 9;
            sW[oc][tt] = (oc0 + oc < Cout) ? w[((size_t)(oc0 + oc) * Cin + ic) * 9 + tt] : 0.f;
        }
        __syncthreads();
        float win[4][4];
#pragma unroll
        for (int r = 0; r < 4; r++)
#pragma unroll
            for (int s = 0; s < 4; s++) win[r][s] = sI[ly + r][lx + s];
#pragma unroll
        for (int o = 0; o < OCB; o++) {
            float w0=sW[o][0],w1=sW[o][1],w2=sW[o][2],w3=sW[o][3],w4=sW[o][4];
            float w5=sW[o][5],w6=sW[o][6],w7=sW[o][7],w8=sW[o][8];
#pragma unroll
            for (int p = 0; p < 4; p++) {
                int pr = p >> 1, pc = p & 1;
                acc[o][p] += win[pr][pc]*w0 + win[pr][pc+1]*w1 + win[pr][pc+2]*w2
                           + win[pr+1][pc]*w3 + win[pr+1][pc+1]*w4 + win[pr+1][pc+2]*w5
                           + win[pr+2][pc]*w6 + win[pr+2][pc+1]*w7 + win[pr+2][pc+2]*w8;
            }
        }
    }
#pragma unroll
    for (int o = 0; o < OCB; o++) {
        int oc = oc0 + o;
        if (oc >= Cout) break;
        float bv = bias[oc];
        float* op = out + ((size_t)b * Cout + oc) * H * H;
#pragma unroll
        for (int p = 0; p < 4; p++) {
            float v = acc[o][p] + bv;
            if (relu) v = fmaxf(v, 0.f);
            op[(y0 + ly + (p >> 1)) * H + x0 + lx + (p & 1)] = v;
        }
    }
}

template<int HO>
__global__ void k_pool(const float* __restrict__ in, float* __restrict__ out, int tot) {
    int i = blockIdx.x * 256 + threadIdx.x;
    if (i >= tot) return;
    int x = i % HO, y = (i / HO) % HO; int bc = i / (HO * HO);
    const int Hi = HO * 2;
    const float* p = in + (size_t)bc * Hi * Hi;
    out[i] = (p[(2*y)*Hi + 2*x] + p[(2*y)*Hi + 2*x+1] + p[(2*y+1)*Hi + 2*x] + p[(2*y+1)*Hi + 2*x+1]) * 0.25f;
}

template<int HW, int TPB>
__global__ void __launch_bounds__(TPB) k_stats2(const float* __restrict__ in,
                                                float* __restrict__ mo, float* __restrict__ so) {
    __shared__ double rs[TPB], rq[TPB];
    int bc = blockIdx.x, tid = threadIdx.x;
    const float* p = in + (size_t)bc * HW;
    constexpr int IT = HW / (TPB * 4);
    float s0 = 0, s1 = 0, s2 = 0, s3 = 0;
    float q0 = 0, q1 = 0, q2 = 0, q3 = 0;
#pragma unroll
    for (int i = 0; i < IT; i++) {
        float4 v = *(const float4*)(p + (i * TPB + tid) * 4);
        s0 += v.x; s1 += v.y; s2 += v.z; s3 += v.w;
        q0 += v.x * v.x; q1 += v.y * v.y; q2 += v.z * v.z; q3 += v.w * v.w;
    }
    rs[tid] = (double)(s0 + s1) + (double)(s2 + s3);
    rq[tid] = (double)(q0 + q1) + (double)(q2 + q3);
    __syncthreads();
    for (int o = TPB / 2; o > 0; o >>= 1) {
        if (tid < o) { rs[tid] += rs[tid + o]; rq[tid] += rq[tid + o]; }
        __syncthreads();
    }
    if (tid == 0) {
        double m = rs[0] / HW;
        double var = rq[0] / HW - m * m;
        mo[bc] = (float)m;
        so[bc] = (float)sqrt(var > 0.0 ? var : 0.0);
    }
}

__global__ void k_transp() {
    __shared__ float t[32][33];
    int sb = blockIdx.x, c0 = blockIdx.y * 32, n0 = blockIdx.z * 32;
    const float* f = g_f4 + (size_t)sb * 524288;
    int tx = threadIdx.x, ty = threadIdx.y;
    for (int j = 0; j < 32; j += 8) t[ty + j][tx] = f[(c0 + ty + j) * 1024 + n0 + tx];
    __syncthreads();
    for (int j = 0; j < 32; j += 8) g_fT[(size_t)sb * 524288 + (size_t)(n0 + ty + j) * 512 + c0 + tx] = t[tx][ty + j];
}

__global__ void k_cent0() {
    int i = blockIdx.x * 256 + threadIdx.x;
    if (i >= 12288) return;
    int c = i & 511, k = (i >> 9) % 3, sb = i / 1536;
    const float* f = g_f4 + (size_t)sb * 524288;
    g_cent[i] = f[c * 1024 + k];
}

__global__ void __launch_bounds__(256) k_assign2() {
    __shared__ float sc[3][512];
    int sb = blockIdx.x >> 2;
    int n = (blockIdx.x & 3) * 256 + threadIdx.x;
    for (int i = threadIdx.x; i < 1536; i += 256) ((float*)sc)[i] = g_cent[sb * 1536 + i];
    __syncthreads();
    const float* f = g_f4 + (size_t)sb * 524288;
    float d0 = 0, d1 = 0, d2 = 0;
    for (int c = 0; c < 512; c++) {
        float v = f[c * 1024 + n];
        float a = v - sc[0][c], b = v - sc[1][c], e = v - sc[2][c];
        d0 += a * a; d1 += b * b; d2 += e * e;
    }
    int a = 0; float best = d0;
    if (d1 < best) { best = d1; a = 1; }
    if (d2 < best) { a = 2; }
    g_asg[sb * 1024 + n] = a;
}

__global__ void __launch_bounds__(128) k_update2() {
    __shared__ int sa[1024];
    int sb = blockIdx.x >> 2;
    int c = (blockIdx.x & 3) * 128 + threadIdx.x;
    for (int i = threadIdx.x; i < 1024; i += 128) sa[i] = g_asg[sb * 1024 + i];
    __syncthreads();
    const float* ft = g_fT + (size_t)sb * 524288;
    float s0 = 0, s1 = 0, s2 = 0; int c0 = 0, c1 = 0, c2 = 0;
    for (int n = 0; n < 1024; n++) {
        float v = ft[n * 512 + c];
        int a = sa[n];
        if (a == 0) { s0 += v; c0++; } else if (a == 1) { s1 += v; c1++; } else { s2 += v; c2++; }
    }
    g_cent[sb * 1536 + c]        = s0 / ((float)c0 + 1e-6f);
    g_cent[sb * 1536 + 512 + c]  = s1 / ((float)c1 + 1e-6f);
    g_cent[sb * 1536 + 1024 + c] = s2 / ((float)c2 + 1e-6f);
    if ((blockIdx.x & 3) == 0 && threadIdx.x < 3)
        g_cnt[sb * 3 + threadIdx.x] = (float)(threadIdx.x == 0 ? c0 : (threadIdx.x == 1 ? c1 : c2));
}

__global__ void k_aw() {
    int i = blockIdx.x * 256 + threadIdx.x;
    if (i >= 12582912) return;
    int n = i & 1023, c = (i >> 10) & 511, m = i >> 19;
    int k = m % 3, sb = m / 3;
    const float* f = g_f4 + (size_t)sb * 524288;
    int a = g_asg[sb * 1024 + n];
    g_aw[i] = (a == k) ? f[c * 1024 + n] - g_cent[sb * 1536 + k * 512 + c] : 0.f;
}

__global__ void __launch_bounds__(256, 2) k_covg() {
    __shared__ float sA[16][128], sB[16][128];
    int m = blockIdx.z;
    const float* A = g_aw + (size_t)m * 524288;
    int bi = c_pi[blockIdx.x], bj = c_pj[blockIdx.x];
    int i0 = bi * 128, j0 = bj * 128;
    int tid = threadIdx.x;
    int ar = tid >> 1, ac = (tid & 1) * 8;
    int ty = tid >> 4, tx = tid & 15;
    float acc[8][8];
#pragma unroll
    for (int a = 0; a < 8; a++)
#pragma unroll
        for (int b = 0; b < 8; b++) acc[a][b] = 0.f;
    float4 ra0 = *(const float4*)&A[(size_t)(i0 + ar) * 1024 + ac];
    float4 ra1 = *(const float4*)&A[(size_t)(i0 + ar) * 1024 + ac + 4];
    float4 rb0 = *(const float4*)&A[(size_t)(j0 + ar) * 1024 + ac];
    float4 rb1 = *(const float4*)&A[(size_t)(j0 + ar) * 1024 + ac + 4];
    for (int k0 = 0; k0 < 1024; k0 += 16) {
        sA[ac+0][ar]=ra0.x; sA[ac+1][ar]=ra0.y; sA[ac+2][ar]=ra0.z; sA[ac+3][ar]=ra0.w;
        sA[ac+4][ar]=ra1.x; sA[ac+5][ar]=ra1.y; sA[ac+6][ar]=ra1.z; sA[ac+7][ar]=ra1.w;
        sB[ac+0][ar]=rb0.x; sB[ac+1][ar]=rb0.y; sB[ac+2][ar]=rb0.z; sB[ac+3][ar]=rb0.w;
        sB[ac+4][ar]=rb1.x; sB[ac+5][ar]=rb1.y; sB[ac+6][ar]=rb1.z; sB[ac+7][ar]=rb1.w;
        __syncthreads();
        if (k0 + 16 < 1024) {
            ra0 = *(const float4*)&A[(size_t)(i0 + ar) * 1024 + k0 + 16 + ac];
            ra1 = *(const float4*)&A[(size_t)(i0 + ar) * 1024 + k0 + 16 + ac + 4];
            rb0 = *(const float4*)&A[(size_t)(j0 + ar) * 1024 + k0 + 16 + ac];
            rb1 = *(const float4*)&A[(size_t)(j0 + ar) * 1024 + k0 + 16 + ac + 4];
        }
#pragma unroll
        for (int k = 0; k < 16; k++) {
            float av[8], bv[8];
            *(float4*)av = *(float4*)&sA[k][ty * 8]; *(float4*)(av+4) = *(float4*)&sA[k][ty * 8 + 4];
            *(float4*)bv = *(float4*)&sB[k][tx * 8]; *(float4*)(bv+4) = *(float4*)&sB[k][tx * 8 + 4];
#pragma unroll
            for (int a = 0; a < 8; a++)
#pragma unroll
                for (int b = 0; b < 8; b++) acc[a][b] += av[a] * bv[b];
        }
        __syncthreads();
    }
    float nc = g_cnt[m] + 1e-6f;
    float* C = g_cov + (size_t)m * MS;
#pragma unroll
    for (int a = 0; a < 8; a++)
#pragma unroll
        for (int b = 0; b < 8; b++) {
            int gi = i0 + ty * 8 + a, gj = j0 + tx * 8 + b;
            float v = acc[a][b] / nc + (gi == gj ? 0.1f : 0.f);
            C[gi * 512 + gj] = v;
            if (bi != bj) C[gj * 512 + gi] = v;
        }
}

__global__ void __launch_bounds__(256) k_norm() {
    __shared__ float red[256];
    int m = blockIdx.x;
    const float* A = g_cov + (size_t)m * MS;
    float mx = 0;
    for (int r = threadIdx.x; r < 512; r += 256) {
        float s = 0;
        for (int c = 0; c < 512; c++) s += fabsf(A[r * 512 + c]);
        mx = fmaxf(mx, s);
    }
    red[threadIdx.x] = mx; __syncthreads();
    for (int o = 128; o > 0; o >>= 1) { if (threadIdx.x < o) red[threadIdx.x] = fmaxf(red[threadIdx.x], red[threadIdx.x + o]); __syncthreads(); }
    if (threadIdx.x == 0) g_nrm[m] = red[0];
}

__global__ void k_nsinit() {
    int i = blockIdx.x * 256 + threadIdx.x;
    if (i >= 6291456) return;
    int m = i >> 18;
    g_Y[i] = g_cov[i] / g_nrm[m];
}

__global__ void __launch_bounds__(256, 2) k_gemmsym(
    const float* __restrict__ A, const float* __restrict__ B,
    float* __restrict__ C, const float* __restrict__ Mp, int polymode)
{
    __shared__ float sA[2][16][128], sB[2][16][128];
    int z = blockIdx.z;
    const float* Ab = A + (size_t)z * MS;
    const float* Bb = B + (size_t)z * MS;
    float* Cb = C + (size_t)z * MS;
    const float* Mb = Mp + (size_t)z * MS;
    int bi = c_pi[blockIdx.x], bj = c_pj[blockIdx.x];
    int m0 = bi * 128, n0 = bj * 128;
    int tid = threadIdx.x;
    int ar = tid >> 1, ac = (tid & 1) * 8;
    int br = tid >> 4, bc = (tid & 15) * 8;
    int ty = tid >> 4, tx = tid & 15;
    float acc[8][8];
#pragma unroll
    for (int a = 0; a < 8; a++)
#pragma unroll
        for (int b = 0; b < 8; b++) acc[a][b] = 0.f;
    float4 ra0 = *(const float4*)&Ab[(size_t)(m0 + ar) * 512 + ac];
    float4 ra1 = *(const float4*)&Ab[(size_t)(m0 + ar) * 512 + ac + 4];
    float4 rb0 = *(const float4*)&Bb[(size_t)br * 512 + n0 + bc];
    float4 rb1 = *(const float4*)&Bb[(size_t)br * 512 + n0 + bc + 4];
    sA[0][ac+0][ar]=ra0.x; sA[0][ac+1][ar]=ra0.y; sA[0][ac+2][ar]=ra0.z; sA[0][ac+3][ar]=ra0.w;
    sA[0][ac+4][ar]=ra1.x; sA[0][ac+5][ar]=ra1.y; sA[0][ac+6][ar]=ra1.z; sA[0][ac+7][ar]=ra1.w;
    *(float4*)&sB[0][br][bc] = rb0; *(float4*)&sB[0][br][bc + 4] = rb1;
    __syncthreads();
    for (int s = 0; s < 32; s++) {
        int buf = s & 1;
        if (s < 31) {
            int k0 = (s + 1) * 16;
            ra0 = *(const float4*)&Ab[(size_t)(m0 + ar) * 512 + k0 + ac];
            ra1 = *(const float4*)&Ab[(size_t)(m0 + ar) * 512 + k0 + ac + 4];
            rb0 = *(const float4*)&Bb[(size_t)(k0 + br) * 512 + n0 + bc];
            rb1 = *(const float4*)&Bb[(size_t)(k0 + br) * 512 + n0 + bc + 4];
        }
#pragma unroll
        for (int k = 0; k < 16; k++) {
            float av[8], bv[8];
            *(float4*)av = *(float4*)&sA[buf][k][ty * 8]; *(float4*)(av+4) = *(float4*)&sA[buf][k][ty * 8 + 4];
            *(float4*)bv = *(float4*)&sB[buf][k][tx * 8]; *(float4*)(bv+4) = *(float4*)&sB[buf][k][tx * 8 + 4];
#pragma unroll
            for (int a = 0; a < 8; a++)
#pragma unroll
                for (int b = 0; b < 8; b++) acc[a][b] += av[a] * bv[b];
        }
        if (s < 31) {
            int nb = buf ^ 1;
            sA[nb][ac+0][ar]=ra0.x; sA[nb][ac+1][ar]=ra0.y; sA[nb][ac+2][ar]=ra0.z; sA[nb][ac+3][ar]=ra0.w;
            sA[nb][ac+4][ar]=ra1.x; sA[nb][ac+5][ar]=ra1.y; sA[nb][ac+6][ar]=ra1.z; sA[nb][ac+7][ar]=ra1.w;
            *(float4*)&sB[nb][br][bc] = rb0; *(float4*)&sB[nb][br][bc + 4] = rb1;
            __syncthreads();
        }
    }
#pragma unroll
    for (int a = 0; a < 8; a++) {
        int gi = m0 + ty * 8 + a;
#pragma unroll
        for (int b = 0; b < 8; b++) {
            int gj = n0 + tx * 8 + b;
            float v = acc[a][b];
            if (polymode)
                v = ((gi == gj ? 15.f : 0.f) - 10.f * Mb[(size_t)gi * 512 + gj] + 3.f * v) * 0.125f;
            Cb[(size_t)gi * 512 + gj] = v;
            if (bi != bj) Cb[(size_t)gj * 512 + gi] = v;
        }
    }
}

// fused dual symmetric GEMM: z < n1 -> C1 = A1@B1 ; else C2 = A2@B2 (both mirror)
__global__ void __launch_bounds__(256, 2) k_gemmsym2(
    const float* __restrict__ A1, const float* __restrict__ B1, float* __restrict__ C1, int n1,
    const float* __restrict__ A2, const float* __restrict__ B2, float* __restrict__ C2)
{
    __shared__ float sA[2][16][128], sB[2][16][128];
    int z = blockIdx.z;
    const float* Ab; const float* Bb; float* Cb;
    if (z < n1) {
        Ab = A1 + (size_t)z * MS; Bb = B1 + (size_t)z * MS; Cb = C1 + (size_t)z * MS;
    } else {
        int zz = z - n1;
        Ab = A2 + (size_t)zz * MS; Bb = B2 + (size_t)zz * MS; Cb = C2 + (size_t)zz * MS;
    }
    int bi = c_pi[blockIdx.x], bj = c_pj[blockIdx.x];
    int m0 = bi * 128, n0 = bj * 128;
    int tid = threadIdx.x;
    int ar = tid >> 1, ac = (tid & 1) * 8;
    int br = tid >> 4, bc = (tid & 15) * 8;
    int ty = tid >> 4, tx = tid & 15;
    float acc[8][8];
#pragma unroll
    for (int a = 0; a < 8; a++)
#pragma unroll
        for (int b = 0; b < 8; b++) acc[a][b] = 0.f;
    float4 ra0 = *(const float4*)&Ab[(size_t)(m0 + ar) * 512 + ac];
    float4 ra1 = *(const float4*)&Ab[(size_t)(m0 + ar) * 512 + ac + 4];
    float4 rb0 = *(const float4*)&Bb[(size_t)br * 512 + n0 + bc];
    float4 rb1 = *(const float4*)&Bb[(size_t)br * 512 + n0 + bc + 4];
    sA[0][ac+0][ar]=ra0.x; sA[0][ac+1][ar]=ra0.y; sA[0][ac+2][ar]=ra0.z; sA[0][ac+3][ar]=ra0.w;
    sA[0][ac+4][ar]=ra1.x; sA[0][ac+5][ar]=ra1.y; sA[0][ac+6][ar]=ra1.z; sA[0][ac+7][ar]=ra1.w;
    *(float4*)&sB[0][br][bc] = rb0; *(float4*)&sB[0][br][bc + 4] = rb1;
    __syncthreads();
    for (int s = 0; s < 32; s++) {
        int buf = s & 1;
        if (s < 31) {
            int k0 = (s + 1) * 16;
            ra0 = *(const float4*)&Ab[(size_t)(m0 + ar) * 512 + k0 + ac];
            ra1 = *(const float4*)&Ab[(size_t)(m0 + ar) * 512 + k0 + ac + 4];
            rb0 = *(const float4*)&Bb[(size_t)(k0 + br) * 512 + n0 + bc];
            rb1 = *(const float4*)&Bb[(size_t)(k0 + br) * 512 + n0 + bc + 4];
        }
#pragma unroll
        for (int k = 0; k < 16; k++) {
            float av[8], bv[8];
            *(float4*)av = *(float4*)&sA[buf][k][ty * 8]; *(float4*)(av+4) = *(float4*)&sA[buf][k][ty * 8 + 4];
            *(float4*)bv = *(float4*)&sB[buf][k][tx * 8]; *(float4*)(bv+4) = *(float4*)&sB[buf][k][tx * 8 + 4];
#pragma unroll
            for (int a = 0; a < 8; a++)
#pragma unroll
                for (int b = 0; b < 8; b++) acc[a][b] += av[a] * bv[b];
        }
        if (s < 31) {
            int nb = buf ^ 1;
            sA[nb][ac+0][ar]=ra0.x; sA[nb][ac+1][ar]=ra0.y; sA[nb][ac+2][ar]=ra0.z; sA[nb][ac+3][ar]=ra0.w;
            sA[nb][ac+4][ar]=ra1.x; sA[nb][ac+5][ar]=ra1.y; sA[nb][ac+6][ar]=ra1.z; sA[nb][ac+7][ar]=ra1.w;
            *(float4*)&sB[nb][br][bc] = rb0; *(float4*)&sB[nb][br][bc + 4] = rb1;
            __syncthreads();
        }
    }
#pragma unroll
    for (int a = 0; a < 8; a++) {
        int gi = m0 + ty * 8 + a;
#pragma unroll
        for (int b = 0; b < 8; b++) {
            int gj = n0 + tx * 8 + b;
            float v = acc[a][b];
            Cb[(size_t)gi * 512 + gj] = v;
            if (bi != bj) Cb[(size_t)gj * 512 + gi] = v;
        }
    }
}

__global__ void __launch_bounds__(256, 2) k_gemm16(
    const float* __restrict__ A, int strA, const float* __restrict__ B, int strB, int bdiv,
    float* __restrict__ C, int strC, int N, float alpha, int nrmmode)
{
    __shared__ float sA[2][16][128], sB[2][16][128];
    int z = blockIdx.z;
    const float* Ab = A + (size_t)z * strA;
    const float* Bb = B + (size_t)(bdiv ? z / 3 : z) * strB;
    float* Cb = C + (size_t)z * strC;
    if (nrmmode) alpha = sqrtf(g_nrm[12 + z] / g_nrm[z]);
    int m0 = blockIdx.y * 128, n0 = blockIdx.x * 128;
    int tid = threadIdx.x;
    int ar = tid >> 1, ac = (tid & 1) * 8;
    int br = tid >> 4, bc = (tid & 15) * 8;
    int ty = tid >> 4, tx = tid & 15;
    float acc[8][8];
#pragma unroll
    for (int a = 0; a < 8; a++)
#pragma unroll
        for (int b = 0; b < 8; b++) acc[a][b] = 0.f;
    float4 ra0 = *(const float4*)&Ab[(size_t)(m0 + ar) * 512 + ac];
    float4 ra1 = *(const float4*)&Ab[(size_t)(m0 + ar) * 512 + ac + 4];
    float4 rb0 = *(const float4*)&Bb[(size_t)br * N + n0 + bc];
    float4 rb1 = *(const float4*)&Bb[(size_t)br * N + n0 + bc + 4];
    sA[0][ac+0][ar]=ra0.x; sA[0][ac+1][ar]=ra0.y; sA[0][ac+2][ar]=ra0.z; sA[0][ac+3][ar]=ra0.w;
    sA[0][ac+4][ar]=ra1.x; sA[0][ac+5][ar]=ra1.y; sA[0][ac+6][ar]=ra1.z; sA[0][ac+7][ar]=ra1.w;
    *(float4*)&sB[0][br][bc] = rb0; *(float4*)&sB[0][br][bc + 4] = rb1;
    __syncthreads();
    for (int s = 0; s < 32; s++) {
        int buf = s & 1;
        if (s < 31) {
            int k0 = (s + 1) * 16;
            ra0 = *(const float4*)&Ab[(size_t)(m0 + ar) * 512 + k0 + ac];
            ra1 = *(const float4*)&Ab[(size_t)(m0 + ar) * 512 + k0 + ac + 4];
            rb0 = *(const float4*)&Bb[(size_t)(k0 + br) * N + n0 + bc];
            rb1 = *(const float4*)&Bb[(size_t)(k0 + br) * N + n0 + bc + 4];
        }
#pragma unroll
        for (int k = 0; k < 16; k++) {
            float av[8], bv[8];
            *(float4*)av = *(float4*)&sA[buf][k][ty * 8]; *(float4*)(av+4) = *(float4*)&sA[buf][k][ty * 8 + 4];
            *(float4*)bv = *(float4*)&sB[buf][k][tx * 8]; *(float4*)(bv+4) = *(float4*)&sB[buf][k][tx * 8 + 4];
#pragma unroll
            for (int a = 0; a < 8; a++)
#pragma unroll
                for (int b = 0; b < 8; b++) acc[a][b] += av[a] * bv[b];
        }
        if (s < 31) {
            int nb = buf ^ 1;
            sA[nb][ac+0][ar]=ra0.x; sA[nb][ac+1][ar]=ra0.y; sA[nb][ac+2][ar]=ra0.z; sA[nb][ac+3][ar]=ra0.w;
            sA[nb][ac+4][ar]=ra1.x; sA[nb][ac+5][ar]=ra1.y; sA[nb][ac+6][ar]=ra1.z; sA[nb][ac+7][ar]=ra1.w;
            *(float4*)&sB[nb][br][bc] = rb0; *(float4*)&sB[nb][br][bc + 4] = rb1;
            __syncthreads();
        }
    }
#pragma unroll
    for (int a = 0; a < 8; a++) {
        int gm = m0 + ty * 8 + a;
#pragma unroll
        for (int b = 0; b < 8; b++) {
            int gn = n0 + tx * 8 + b;
            Cb[(size_t)gm * N + gn] = alpha * acc[a][b];
        }
    }
}

__global__ void __launch_bounds__(512) k_gemv() {
    __shared__ float mu[512];
    int z = blockIdx.x;
    int b = z / 3, k = z % 3;
    int tid = threadIdx.x;
    mu[tid] = g_cent[b * 1536 + k * 512 + tid];
    __syncthreads();
    const float* T = g_Tm + (size_t)z * MS;
    int warp = tid >> 5, lane = tid & 31;
    for (int c = warp; c < 512; c += 16) {
        float s = 0;
        for (int d = lane; d < 512; d += 32) s += T[c * 512 + d] * mu[d];
#pragma unroll
        for (int o = 16; o > 0; o >>= 1) s += __shfl_down_sync(0xffffffff, s, o);
        if (lane == 0) g_vv[z * 512 + c] = s;
    }
}

__global__ void k_comb(const float* __restrict__ tp) {
    int i = blockIdx.x * 256 + threadIdx.x;
    if (i >= 2097152) return;
    int n = i & 1023, c = (i >> 10) & 511, b = i >> 19;
    int a = g_asg[b * 1024 + n];
    int z = b * 3 + a;
    float val = tp[(size_t)z * 524288 + c * 1024 + n] - g_vv[z * 512 + c]
              + g_cent[(4 + b) * 1536 + a * 512 + c];
    g_f4t[i] = 0.6f * val + 0.4f * g_f4[i];
}

__global__ void __launch_bounds__(256) k_closs1() {
    __shared__ double red[256];
    int start = blockIdx.x * 8192;
    float s0 = 0, s1 = 0;
    for (int i = threadIdx.x * 2; i < 8192; i += 512) {
        float d0 = g_f4e[start + i] - g_f4[start + i];
        float d1 = g_f4e[start + i + 1] - g_f4[start + i + 1];
        s0 += d0 * d0; s1 += d1 * d1;
    }
    red[threadIdx.x] = (double)s0 + (double)s1; __syncthreads();
    for (int o = 128; o > 0; o >>= 1) { if (threadIdx.x < o) red[threadIdx.x] += red[threadIdx.x + o]; __syncthreads(); }
    if (threadIdx.x == 0) g_part[blockIdx.x] = red[0];
}

__global__ void __launch_bounds__(256) k_final(float* out) {
    __shared__ double red[256];
    __shared__ double slv;
    __shared__ double closs;
    const int off[5] = {0, 256, 768, 1792, 3840};
    if (threadIdx.x == 0) slv = 0;
    red[threadIdx.x] = g_part[threadIdx.x];
    __syncthreads();
    for (int o = 128; o > 0; o >>= 1) { if (threadIdx.x < o) red[threadIdx.x] += red[threadIdx.x + o]; __syncthreads(); }
    if (threadIdx.x == 0) closs = red[0] / 2097152.0;
    __syncthreads();
    for (int l = 0; l < 4; l++) {
        int o0 = off[l], sz = off[l + 1] - off[l];
        double s = 0;
        for (int i = threadIdx.x; i < sz; i += 256) {
            float dm = g_st[2 * 3840 + o0 + i] - g_st[0 * 3840 + o0 + i];
            float ds = g_st[3 * 3840 + o0 + i] - g_st[1 * 3840 + o0 + i];
            s += (double)dm * dm + (double)ds * ds;
        }
        red[threadIdx.x] = s; __syncthreads();
        for (int o = 128; o > 0; o >>= 1) { if (threadIdx.x < o) red[threadIdx.x] += red[threadIdx.x + o]; __syncthreads(); }
        if (threadIdx.x == 0) slv += red[0] / sz;
        __syncthreads();
    }
    if (threadIdx.x == 0) out[0] = (float)closs + 0.01f * (float)slv;
}

extern "C" void kernel_launch(void* const* d_in, const int* in_sizes, int n_in,
                              void* d_out, int out_size) {
    (void)in_sizes; (void)n_in; (void)out_size;
    const float* in[18];
    for (int i = 0; i < 18; i++) in[i] = (const float*)d_in[i];

    float *b0, *b1, *in8, *f4, *f4t, *f4e, *dec, *Y, *Z, *Tt, *cov, *aw, *Tm, *st;
    cudaGetSymbolAddress((void**)&b0, g_b0);
    cudaGetSymbolAddress((void**)&b1, g_b1);
    cudaGetSymbolAddress((void**)&in8, g_in8);
    cudaGetSymbolAddress((void**)&f4, g_f4);
    cudaGetSymbolAddress((void**)&f4t, g_f4t);
    cudaGetSymbolAddress((void**)&f4e, g_f4e);
    cudaGetSymbolAddress((void**)&dec, g_dec);
    cudaGetSymbolAddress((void**)&Y, g_Y);
    cudaGetSymbolAddress((void**)&Z, g_Z);
    cudaGetSymbolAddress((void**)&Tt, g_Tt);
    cudaGetSymbolAddress((void**)&cov, g_cov);
    cudaGetSymbolAddress((void**)&aw, g_aw);
    cudaGetSymbolAddress((void**)&Tm, g_Tm);
    cudaGetSymbolAddress((void**)&st, g_st);
    float* aw1 = aw + 6291456;

    auto conv = [&](const float* i0, float* o, const float* w, const float* bb,
                    int Cin, int Cout, int H, int relu, int B, int ups) {
        if (Cin >= 64 && Cout >= 64) {
            int bx = (B * H * H) / 128, by = (Cout + 127) / 128;
            if (bx * by >= 148) {
                k_cgemm<<<dim3(bx, by, 1), 256>>>(i0, w, bb, o, Cin, Cout, H, relu, ups);
            } else {
                dim3 g((B * H * H) / 64, (Cout + 63) / 64, 1);
                k_cgemm64<<<g, 256>>>(i0, w, bb, o, Cin, Cout, H, relu, ups);
            }
        } else if (H >= 64) {
            dim3 g((H / 32) * (H / 32), (Cout + 15) / 16, B);
            k_conv<16><<<g, 256>>>(i0, w, bb, o, Cin, Cout, H, relu, ups);
        } else {
            dim3 g((H / 32) * (H / 32), (Cout + 7) / 8, B);
            k_conv<8><<<g, 256>>>(i0, w, bb, o, Cin, Cout, H, relu, ups);
        }
    };
    auto pool = [&](const float* i0, float* o, int C, int Ho, int B) {
        int tot = B * C * Ho * Ho; int g = (tot + 255) / 256;
        if (Ho == 128) k_pool<128><<<g, 256>>>(i0, o, tot);
        else if (Ho == 64) k_pool<64><<<g, 256>>>(i0, o, tot);
        else k_pool<32><<<g, 256>>>(i0, o, tot);
    };
    auto enc = [&](const float* x, int B, float* f4o, float* mo, float* so, int soff) {
        conv(x, b0, in[2], in[3], 3, 64, 256, 1, B, 0);
        if (mo) k_stats2<65536, 1024><<<256, 1024>>>(b0 + (size_t)soff * 64 * 65536, mo, so);
        pool(b0, b1, 64, 128, B);
        conv(b1, b0, in[4], in[5], 64, 128, 128, 1, B, 0);
        if (mo) k_stats2<16384, 1024><<<512, 1024>>>(b0 + (size_t)soff * 128 * 16384, mo + 256, so + 256);
        pool(b0, b1, 128, 64, B);
        conv(b1, b0, in[6], in[7], 128, 256, 64, 1, B, 0);
        if (mo) k_stats2<4096, 256><<<1024, 256>>>(b0 + (size_t)soff * 256 * 4096, mo + 768, so + 768);
        pool(b0, b1, 256, 32, B);
        conv(b1, f4o, in[8], in[9], 256, 512, 32, 1, B, 0);
        if (mo) k_stats2<1024, 256><<<2048, 256>>>(f4o + (size_t)soff * 512 * 1024, mo + 1792, so + 1792);
    };

    cudaMemcpyAsync(in8, in[0], 786432 * 4, cudaMemcpyDeviceToDevice);
    cudaMemcpyAsync(in8 + 786432, in[1], 786432 * 4, cudaMemcpyDeviceToDevice);
    k_dummy<<<1, 256>>>();
    k_dummy<<<1, 256>>>();

    enc(in8, 8, f4, st + 0, st + 3840, 4);

    k_transp<<<dim3(8, 16, 32), dim3(32, 8)>>>();
    k_cent0<<<48, 256>>>();
    for (int it = 0; it < 11; it++) {
        k_assign2<<<32, 256>>>();
        k_update2<<<32, 128>>>();
    }

    k_aw<<<(12582912 + 255) / 256, 256>>>();
    k_covg<<<dim3(10, 1, 24), 256>>>();
    k_norm<<<24, 256>>>();
    k_nsinit<<<((6291456 + 255) / 256), 256>>>();

    dim3 gs(10, 1, 24);
    k_gemmsym<<<gs, 256>>>(Y, Y, cov, Y, 1);
    k_gemmsym<<<gs, 256>>>(Y, cov, aw, cov, 0);
    float* Yc = aw; float* Zc = cov;
    float* fr[4] = {Y, Z, Tt, aw1};
    for (int it = 0; it < 14; it++) {
        float* M = fr[0]; float* P = fr[1]; float* Yn = fr[2]; float* Zn = fr[3];
        k_gemmsym<<<gs, 256>>>(Zc, Yc, M, Zc, 0);
        k_gemmsym<<<gs, 256>>>(M, M, P, M, 1);
        if (it < 13) {
            k_gemmsym2<<<dim3(10, 1, 48), 256>>>(Yc, P, Yn, 24, P, Zc, Zn);
        } else {
            size_t so12 = (size_t)12 * MS;
            k_gemmsym2<<<dim3(10, 1, 36), 256>>>(Yc + so12, P + so12, Yn + so12, 12, P, Zc, Zn);
        }
        fr[0] = Yc; fr[1] = Zc; fr[2] = M; fr[3] = P;
        Yc = Yn; Zc = Zn;
    }

    k_gemm16<<<dim3(4, 4, 12), 256>>>(Yc + (size_t)12 * MS, MS, Zc, MS, 0,
                                      Tm, MS, 512, 1.f, 1);
    float* tp = fr[0];
    k_gemm16<<<dim3(8, 4, 12), 256>>>(Tm, MS, f4, 524288, 1, tp, 524288, 1024, 1.f, 0);
    k_gemv<<<12, 512>>>();
    k_comb<<<(2097152 + 255) / 256, 256>>>(tp);

    conv(f4t, b0, in[10], in[11], 512, 256, 32, 1, 4, 0);
    conv(b0, b1, in[12], in[13], 256, 128, 64, 1, 4, 1);
    conv(b1, b0, in[14], in[15], 128, 64, 128, 1, 4, 1);
    conv(b0, dec, in[16], in[17], 64, 3, 256, 0, 4, 1);

    enc(dec, 4, f4e, st + 2 * 3840, st + 3 * 3840, 0);

    k_closs1<<<256, 256>>>();
    k_final<<<1, 256>>>((float*)d_out);
}